// round 1
// baseline (speedup 1.0000x reference)
#include <cuda_runtime.h>
#include <cuda_bf16.h>
#include <math.h>

#define B_  2
#define S_  1024
#define E_  2048
#define H_  16
#define HD_ 128
#define ROT_ 64
#define NROWS (B_ * S_)      // 2048
#define EPS_ 1e-12f

// ---------------- scratch (static device globals; no allocs allowed) --------
__device__ float g_tq[NROWS * E_];   // q proj, (b*S+s, h*HD+d)
__device__ float g_tk[NROWS * E_];
__device__ float g_tv[NROWS * E_];
__device__ float g_qn[B_ * H_ * S_ * HD_];  // (b,h,s,d) after rope+norm+mask
__device__ float g_kn[B_ * H_ * S_ * HD_];
__device__ float g_vs[B_ * H_ * S_ * HD_];  // v / denom * mask
__device__ float g_ao[NROWS * E_];   // attention output, (b*S+s, h*HD+d)
__device__ float g_counts[B_ * S_];

// ---------------- mask prefix scan (counts) ---------------------------------
__global__ void counts_kernel(const float* __restrict__ mask, float* __restrict__ counts) {
    __shared__ float sh[S_];
    int b = blockIdx.x;
    int t = threadIdx.x;
    sh[t] = (mask[b * S_ + t] == 0.0f) ? 1.0f : 0.0f;
    __syncthreads();
    for (int off = 1; off < S_; off <<= 1) {
        float add = (t >= off) ? sh[t - off] : 0.0f;
        __syncthreads();
        sh[t] += add;
        __syncthreads();
    }
    counts[b * S_ + t] = sh[t];
}

// ---------------- fp32 SGEMM, C[m,n] = sum_k A[m,k] * W[n,k] (NT) ----------
#define BM 128
#define BN 128
#define BK 8
#define TM 8
#define TN 8

__global__ __launch_bounds__(256) void gemm_nt(const float* __restrict__ A,
                                               const float* __restrict__ W,
                                               float* __restrict__ C,
                                               int M, int N, int K) {
    __shared__ float As[BK][BM];
    __shared__ float Bs[BK][BN];
    int tid = threadIdx.x;
    int tx = tid % 16;          // n microtile
    int ty = tid / 16;          // m microtile
    int bm = blockIdx.y * BM;
    int bn = blockIdx.x * BN;

    int lr = tid >> 1;          // 0..127 row within tile
    int lc = (tid & 1) * 4;     // 0 or 4 (k offset)
    const float* Aptr = A + (size_t)(bm + lr) * K + lc;
    const float* Wptr = W + (size_t)(bn + lr) * K + lc;

    float acc[TM][TN];
#pragma unroll
    for (int i = 0; i < TM; i++)
#pragma unroll
        for (int j = 0; j < TN; j++) acc[i][j] = 0.0f;

    for (int k0 = 0; k0 < K; k0 += BK) {
        float4 av = *(const float4*)(Aptr + k0);
        float4 wv = *(const float4*)(Wptr + k0);
        As[lc + 0][lr] = av.x; As[lc + 1][lr] = av.y;
        As[lc + 2][lr] = av.z; As[lc + 3][lr] = av.w;
        Bs[lc + 0][lr] = wv.x; Bs[lc + 1][lr] = wv.y;
        Bs[lc + 2][lr] = wv.z; Bs[lc + 3][lr] = wv.w;
        __syncthreads();
#pragma unroll
        for (int kk = 0; kk < BK; kk++) {
            float4 a0 = *(const float4*)&As[kk][ty * TM];
            float4 a1 = *(const float4*)&As[kk][ty * TM + 4];
            float4 b0 = *(const float4*)&Bs[kk][tx * TN];
            float4 b1 = *(const float4*)&Bs[kk][tx * TN + 4];
            float a[TM] = {a0.x, a0.y, a0.z, a0.w, a1.x, a1.y, a1.z, a1.w};
            float b[TN] = {b0.x, b0.y, b0.z, b0.w, b1.x, b1.y, b1.z, b1.w};
#pragma unroll
            for (int i = 0; i < TM; i++)
#pragma unroll
                for (int j = 0; j < TN; j++) acc[i][j] += a[i] * b[j];
        }
        __syncthreads();
    }
#pragma unroll
    for (int i = 0; i < TM; i++) {
        float* cp = C + (size_t)(bm + ty * TM + i) * N + bn + tx * TN;
        float4 c0 = {acc[i][0], acc[i][1], acc[i][2], acc[i][3]};
        float4 c1 = {acc[i][4], acc[i][5], acc[i][6], acc[i][7]};
        *(float4*)(cp) = c0;
        *(float4*)(cp + 4) = c1;
    }
}

// ---------------- RoPE + L2 norm + mask + v scaling -------------------------
// One warp per (b,s,h). 4 warps / block.
__global__ __launch_bounds__(128) void rope_norm_kernel(
    const float* __restrict__ tq, const float* __restrict__ tk,
    const float* __restrict__ tv, const float* __restrict__ mask,
    const float* __restrict__ norm_const, const int* __restrict__ pos_ids,
    const float* __restrict__ counts,
    float* __restrict__ Qn, float* __restrict__ Kn, float* __restrict__ Vs) {
    int warp = threadIdx.x >> 5;
    int lane = threadIdx.x & 31;
    int gw = blockIdx.x * 4 + warp;       // 0 .. B*S*H-1
    int h = gw % H_;
    int bs = gw / H_;                      // b*S + s
    int b = bs / S_;
    int s = bs % S_;

    int d0 = lane * 4;
    size_t src = (size_t)bs * E_ + h * HD_ + d0;
    float4 q4 = *(const float4*)(tq + src);
    float4 k4 = *(const float4*)(tk + src);
    float4 v4 = *(const float4*)(tv + src);

    if (d0 < ROT_) {
        float fpos = (float)pos_ids[bs];
        int i0 = lane * 2, i1 = lane * 2 + 1;
        float log1e4 = 9.210340371976184f;  // ln(10000)
        float th0 = fpos * __expf(-log1e4 * (2.0f * i0) / (float)ROT_);
        float th1 = fpos * __expf(-log1e4 * (2.0f * i1) / (float)ROT_);
        float c0 = cosf(th0), s0 = sinf(th0);
        float c1 = cosf(th1), s1 = sinf(th1);
        float qx = q4.x * c0 - q4.y * s0;
        float qy = q4.y * c0 + q4.x * s0;
        float qz = q4.z * c1 - q4.w * s1;
        float qw = q4.w * c1 + q4.z * s1;
        q4 = make_float4(qx, qy, qz, qw);
        float kx = k4.x * c0 - k4.y * s0;
        float ky = k4.y * c0 + k4.x * s0;
        float kz = k4.z * c1 - k4.w * s1;
        float kw = k4.w * c1 + k4.z * s1;
        k4 = make_float4(kx, ky, kz, kw);
    }

    // L2 norms over 128 dims (warp reduce)
    float sq = q4.x * q4.x + q4.y * q4.y + q4.z * q4.z + q4.w * q4.w;
    float sk = k4.x * k4.x + k4.y * k4.y + k4.z * k4.z + k4.w * k4.w;
#pragma unroll
    for (int off = 16; off > 0; off >>= 1) {
        sq += __shfl_xor_sync(0xffffffffu, sq, off);
        sk += __shfl_xor_sync(0xffffffffu, sk, off);
    }
    float nq = fmaxf(sqrtf(sq), EPS_);
    float nk = fmaxf(sqrtf(sk), EPS_);

    float m = (mask[bs] == 0.0f) ? 1.0f : 0.0f;
    float sclq = m / nq;
    float sclk = m / nk;

    float nc = norm_const[h];
    float p = 1.0f / (1.0f + expf(-nc));
    float den = fmaxf(powf(counts[bs], p), 1.0f);
    float sclv = m / den;

    size_t dst = (((size_t)(b * H_ + h)) * S_ + s) * HD_ + d0;
    *(float4*)(Qn + dst) = make_float4(q4.x * sclq, q4.y * sclq, q4.z * sclq, q4.w * sclq);
    *(float4*)(Kn + dst) = make_float4(k4.x * sclk, k4.y * sclk, k4.z * sclk, k4.w * sclk);
    *(float4*)(Vs + dst) = make_float4(v4.x * sclv, v4.y * sclv, v4.z * sclv, v4.w * sclv);
}

// ---------------- causal no-softmax attention -------------------------------
// O[b,h,q,:] = sum_{k<=q} (Q[q].K[k]) * V[k]
#define AQ 32
#define AKC 16
__global__ __launch_bounds__(256) void attn_kernel(const float* __restrict__ Qn,
                                                   const float* __restrict__ Kn,
                                                   const float* __restrict__ Vs,
                                                   float* __restrict__ O) {
    __shared__ float Qs[AQ][HD_];    // 16 KB
    __shared__ float Ks[AKC][HD_];   // 8 KB
    __shared__ float Vv[AKC][HD_];   // 8 KB
    __shared__ float Ss[AQ][AKC];    // 2 KB

    int bh = blockIdx.y;             // b*H + h
    int q0 = blockIdx.x * AQ;
    int tid = threadIdx.x;
    const float* Qb = Qn + (size_t)bh * S_ * HD_;
    const float* Kb = Kn + (size_t)bh * S_ * HD_;
    const float* Vb = Vs + (size_t)bh * S_ * HD_;

    // load Q tile (32x128 = 1024 float4)
    {
        const float4* src = (const float4*)(Qb + (size_t)q0 * HD_);
        float4* dst = (float4*)&Qs[0][0];
        for (int i = tid; i < AQ * HD_ / 4; i += 256) dst[i] = src[i];
    }

    int tx = tid % 16;   // d microtile: cols tx*8..tx*8+7
    int ty = tid / 16;   // q microtile: rows ty*2, ty*2+1
    float acc[2][8];
#pragma unroll
    for (int i = 0; i < 2; i++)
#pragma unroll
        for (int j = 0; j < 8; j++) acc[i][j] = 0.0f;

    int kend = q0 + AQ;
    for (int kc = 0; kc < kend; kc += AKC) {
        {
            const float4* ks = (const float4*)(Kb + (size_t)kc * HD_);
            const float4* vs = (const float4*)(Vb + (size_t)kc * HD_);
            float4* kd = (float4*)&Ks[0][0];
            float4* vd = (float4*)&Vv[0][0];
            for (int i = tid; i < AKC * HD_ / 4; i += 256) { kd[i] = ks[i]; vd[i] = vs[i]; }
        }
        __syncthreads();
        // S tile: 32x16 = 512 dots, 2 per thread
#pragma unroll
        for (int e = 0; e < 2; e++) {
            int idx = tid * 2 + e;
            int qi = idx / AKC;
            int kj = idx % AKC;
            const float4* qp = (const float4*)&Qs[qi][0];
            const float4* kp = (const float4*)&Ks[kj][0];
            float d = 0.0f;
#pragma unroll
            for (int c = 0; c < HD_ / 4; c++) {
                float4 a = qp[c], bb = kp[c];
                d += a.x * bb.x + a.y * bb.y + a.z * bb.z + a.w * bb.w;
            }
            Ss[qi][kj] = (kc + kj <= q0 + qi) ? d : 0.0f;
        }
        __syncthreads();
        // O += S @ V
#pragma unroll
        for (int kk = 0; kk < AKC; kk++) {
            float4 v0 = *(const float4*)&Vv[kk][tx * 8];
            float4 v1 = *(const float4*)&Vv[kk][tx * 8 + 4];
            float s0 = Ss[ty * 2 + 0][kk];
            float s1 = Ss[ty * 2 + 1][kk];
            acc[0][0] += s0 * v0.x; acc[0][1] += s0 * v0.y;
            acc[0][2] += s0 * v0.z; acc[0][3] += s0 * v0.w;
            acc[0][4] += s0 * v1.x; acc[0][5] += s0 * v1.y;
            acc[0][6] += s0 * v1.z; acc[0][7] += s0 * v1.w;
            acc[1][0] += s1 * v0.x; acc[1][1] += s1 * v0.y;
            acc[1][2] += s1 * v0.z; acc[1][3] += s1 * v0.w;
            acc[1][4] += s1 * v1.x; acc[1][5] += s1 * v1.y;
            acc[1][6] += s1 * v1.z; acc[1][7] += s1 * v1.w;
        }
        __syncthreads();
    }

    // write to (b*S+q)*E + h*HD + d
    int b = bh / H_;
    int h = bh % H_;
#pragma unroll
    for (int e = 0; e < 2; e++) {
        int q = q0 + ty * 2 + e;
        float* op = O + ((size_t)(b * S_ + q)) * E_ + h * HD_ + tx * 8;
        float4 c0 = {acc[e][0], acc[e][1], acc[e][2], acc[e][3]};
        float4 c1 = {acc[e][4], acc[e][5], acc[e][6], acc[e][7]};
        *(float4*)(op) = c0;
        *(float4*)(op + 4) = c1;
    }
}

// ---------------- launcher ---------------------------------------------------
extern "C" void kernel_launch(void* const* d_in, const int* in_sizes, int n_in,
                              void* d_out, int out_size) {
    const float* hs        = (const float*)d_in[0];
    const float* w_q       = (const float*)d_in[1];
    const float* w_k       = (const float*)d_in[2];
    const float* w_v       = (const float*)d_in[3];
    const float* w_o       = (const float*)d_in[4];
    const float* norm_c    = (const float*)d_in[5];
    const float* attn_mask = (const float*)d_in[6];
    const int*   pos_ids   = (const int*)d_in[7];
    float* out = (float*)d_out;

    float *tq, *tk, *tv, *qn, *kn, *vs, *ao, *cnts;
    cudaGetSymbolAddress((void**)&tq, g_tq);
    cudaGetSymbolAddress((void**)&tk, g_tk);
    cudaGetSymbolAddress((void**)&tv, g_tv);
    cudaGetSymbolAddress((void**)&qn, g_qn);
    cudaGetSymbolAddress((void**)&kn, g_kn);
    cudaGetSymbolAddress((void**)&vs, g_vs);
    cudaGetSymbolAddress((void**)&ao, g_ao);
    cudaGetSymbolAddress((void**)&cnts, g_counts);

    counts_kernel<<<B_, S_>>>(attn_mask, cnts);

    dim3 gg(E_ / BN, NROWS / BM);
    gemm_nt<<<gg, 256>>>(hs, w_q, tq, NROWS, E_, E_);
    gemm_nt<<<gg, 256>>>(hs, w_k, tk, NROWS, E_, E_);
    gemm_nt<<<gg, 256>>>(hs, w_v, tv, NROWS, E_, E_);

    rope_norm_kernel<<<(B_ * S_ * H_) / 4, 128>>>(tq, tk, tv, attn_mask, norm_c,
                                                  pos_ids, cnts, qn, kn, vs);

    attn_kernel<<<dim3(S_ / AQ, B_ * H_), 256>>>(qn, kn, vs, ao);

    gemm_nt<<<gg, 256>>>(ao, w_o, out, NROWS, E_, E_);
}

// round 2
// speedup vs baseline: 2.3274x; 2.3274x over previous
#include <cuda_runtime.h>
#include <cuda_bf16.h>
#include <math.h>

#define B_  2
#define S_  1024
#define E_  2048
#define H_  16
#define HD_ 128
#define ROT_ 64
#define NROWS (B_ * S_)      // 2048
#define EPS_ 1e-12f

// ---------------- scratch ----------------------------------------------------
__device__ float g_tq[NROWS * E_];
__device__ float g_tk[NROWS * E_];
__device__ float g_tv[NROWS * E_];
__device__ float g_qn[B_ * H_ * S_ * HD_];
__device__ float g_kn[B_ * H_ * S_ * HD_];
__device__ float g_vs[B_ * H_ * S_ * HD_];
__device__ float g_ao[NROWS * E_];
__device__ float g_counts[B_ * S_];

// ---------------- mask prefix scan ------------------------------------------
__global__ void counts_kernel(const float* __restrict__ mask, float* __restrict__ counts) {
    __shared__ float sh[S_];
    int b = blockIdx.x;
    int t = threadIdx.x;
    sh[t] = (mask[b * S_ + t] == 0.0f) ? 1.0f : 0.0f;
    __syncthreads();
    for (int off = 1; off < S_; off <<= 1) {
        float add = (t >= off) ? sh[t - off] : 0.0f;
        __syncthreads();
        sh[t] += add;
        __syncthreads();
    }
    counts[b * S_ + t] = sh[t];
}

// ---------------- fp32 SGEMM NT, double-buffered ----------------------------
#define BM 128
#define BN 128
#define BK 8

__device__ __forceinline__ void gemm_nt_body(const float* __restrict__ A,
                                             const float* __restrict__ W,
                                             float* __restrict__ C,
                                             int K, int N, int bm, int bn) {
    __shared__ float As[2][BK][BM];
    __shared__ float Bs[2][BK][BN];
    int tid = threadIdx.x;
    int tx = tid % 16;
    int ty = tid / 16;

    int lr = tid >> 1;
    int lc = (tid & 1) * 4;
    const float* Aptr = A + (size_t)(bm + lr) * K + lc;
    const float* Wptr = W + (size_t)(bn + lr) * K + lc;

    float acc[8][8];
#pragma unroll
    for (int i = 0; i < 8; i++)
#pragma unroll
        for (int j = 0; j < 8; j++) acc[i][j] = 0.0f;

    float4 av = *(const float4*)(Aptr);
    float4 wv = *(const float4*)(Wptr);
    As[0][lc + 0][lr] = av.x; As[0][lc + 1][lr] = av.y;
    As[0][lc + 2][lr] = av.z; As[0][lc + 3][lr] = av.w;
    Bs[0][lc + 0][lr] = wv.x; Bs[0][lc + 1][lr] = wv.y;
    Bs[0][lc + 2][lr] = wv.z; Bs[0][lc + 3][lr] = wv.w;
    __syncthreads();

    int nt = K / BK;
    for (int t = 0; t < nt; t++) {
        int cur = t & 1, nxt = cur ^ 1;
        if (t + 1 < nt) {
            av = *(const float4*)(Aptr + (t + 1) * BK);
            wv = *(const float4*)(Wptr + (t + 1) * BK);
        }
#pragma unroll
        for (int kk = 0; kk < BK; kk++) {
            float4 a0 = *(const float4*)&As[cur][kk][ty * 8];
            float4 a1 = *(const float4*)&As[cur][kk][ty * 8 + 4];
            float4 b0 = *(const float4*)&Bs[cur][kk][tx * 8];
            float4 b1 = *(const float4*)&Bs[cur][kk][tx * 8 + 4];
            float a[8] = {a0.x, a0.y, a0.z, a0.w, a1.x, a1.y, a1.z, a1.w};
            float b[8] = {b0.x, b0.y, b0.z, b0.w, b1.x, b1.y, b1.z, b1.w};
#pragma unroll
            for (int i = 0; i < 8; i++)
#pragma unroll
                for (int j = 0; j < 8; j++) acc[i][j] += a[i] * b[j];
        }
        if (t + 1 < nt) {
            As[nxt][lc + 0][lr] = av.x; As[nxt][lc + 1][lr] = av.y;
            As[nxt][lc + 2][lr] = av.z; As[nxt][lc + 3][lr] = av.w;
            Bs[nxt][lc + 0][lr] = wv.x; Bs[nxt][lc + 1][lr] = wv.y;
            Bs[nxt][lc + 2][lr] = wv.z; Bs[nxt][lc + 3][lr] = wv.w;
        }
        __syncthreads();
    }
#pragma unroll
    for (int i = 0; i < 8; i++) {
        float* cp = C + (size_t)(bm + ty * 8 + i) * N + bn + tx * 8;
        float4 c0 = {acc[i][0], acc[i][1], acc[i][2], acc[i][3]};
        float4 c1 = {acc[i][4], acc[i][5], acc[i][6], acc[i][7]};
        *(float4*)(cp) = c0;
        *(float4*)(cp + 4) = c1;
    }
}

__global__ __launch_bounds__(256, 2) void gemm_qkv(const float* __restrict__ A,
                                                   const float* __restrict__ wq,
                                                   const float* __restrict__ wk,
                                                   const float* __restrict__ wv,
                                                   float* __restrict__ cq,
                                                   float* __restrict__ ck,
                                                   float* __restrict__ cv) {
    const float* W = (blockIdx.z == 0) ? wq : (blockIdx.z == 1) ? wk : wv;
    float* C = (blockIdx.z == 0) ? cq : (blockIdx.z == 1) ? ck : cv;
    gemm_nt_body(A, W, C, E_, E_, blockIdx.y * BM, blockIdx.x * BN);
}

__global__ __launch_bounds__(256, 2) void gemm_out(const float* __restrict__ A,
                                                   const float* __restrict__ W,
                                                   float* __restrict__ C) {
    gemm_nt_body(A, W, C, E_, E_, blockIdx.y * BM, blockIdx.x * BN);
}

// ---------------- RoPE + L2 norm + mask + v scaling -------------------------
__global__ __launch_bounds__(128) void rope_norm_kernel(
    const float* __restrict__ tq, const float* __restrict__ tk,
    const float* __restrict__ tv, const float* __restrict__ mask,
    const float* __restrict__ norm_const, const int* __restrict__ pos_ids,
    const float* __restrict__ counts,
    float* __restrict__ Qn, float* __restrict__ Kn, float* __restrict__ Vs) {
    int warp = threadIdx.x >> 5;
    int lane = threadIdx.x & 31;
    int gw = blockIdx.x * 4 + warp;
    int h = gw % H_;
    int bs = gw / H_;
    int b = bs / S_;
    int s = bs % S_;

    int d0 = lane * 4;
    size_t src = (size_t)bs * E_ + h * HD_ + d0;
    float4 q4 = *(const float4*)(tq + src);
    float4 k4 = *(const float4*)(tk + src);
    float4 v4 = *(const float4*)(tv + src);

    if (d0 < ROT_) {
        float fpos = (float)pos_ids[bs];
        int i0 = lane * 2, i1 = lane * 2 + 1;
        float log1e4 = 9.210340371976184f;
        float th0 = fpos * __expf(-log1e4 * (2.0f * i0) / (float)ROT_);
        float th1 = fpos * __expf(-log1e4 * (2.0f * i1) / (float)ROT_);
        float c0 = cosf(th0), s0 = sinf(th0);
        float c1 = cosf(th1), s1 = sinf(th1);
        q4 = make_float4(q4.x * c0 - q4.y * s0, q4.y * c0 + q4.x * s0,
                         q4.z * c1 - q4.w * s1, q4.w * c1 + q4.z * s1);
        k4 = make_float4(k4.x * c0 - k4.y * s0, k4.y * c0 + k4.x * s0,
                         k4.z * c1 - k4.w * s1, k4.w * c1 + k4.z * s1);
    }

    float sq = q4.x * q4.x + q4.y * q4.y + q4.z * q4.z + q4.w * q4.w;
    float sk = k4.x * k4.x + k4.y * k4.y + k4.z * k4.z + k4.w * k4.w;
#pragma unroll
    for (int off = 16; off > 0; off >>= 1) {
        sq += __shfl_xor_sync(0xffffffffu, sq, off);
        sk += __shfl_xor_sync(0xffffffffu, sk, off);
    }
    float nq = fmaxf(sqrtf(sq), EPS_);
    float nk = fmaxf(sqrtf(sk), EPS_);

    float m = (mask[bs] == 0.0f) ? 1.0f : 0.0f;
    float sclq = m / nq;
    float sclk = m / nk;

    float nc = norm_const[h];
    float p = 1.0f / (1.0f + expf(-nc));
    float den = fmaxf(powf(counts[bs], p), 1.0f);
    float sclv = m / den;

    size_t dst = (((size_t)(b * H_ + h)) * S_ + s) * HD_ + d0;
    *(float4*)(Qn + dst) = make_float4(q4.x * sclq, q4.y * sclq, q4.z * sclq, q4.w * sclq);
    *(float4*)(Kn + dst) = make_float4(k4.x * sclk, k4.y * sclk, k4.z * sclk, k4.w * sclk);
    *(float4*)(Vs + dst) = make_float4(v4.x * sclv, v4.y * sclv, v4.z * sclv, v4.w * sclv);
}

// ---------------- causal no-softmax attention (64x64 tiles) ------------------
#define AQ 64
#define AK 64
#define SQ 68   // padded row stride for d-major tiles

// dynamic smem layout (floats):
//  Qs [HD_][SQ]   d-major:  Qs[d*SQ + q]
//  Ks [HD_][SQ]   d-major
//  Vs [AK][HD_]   k-major:  Vs[k*HD_ + d]
//  Ss [AK][SQ]    k-major:  Ss[k*SQ + q]
#define SM_QS   0
#define SM_KS   (HD_ * SQ)
#define SM_VS   (2 * HD_ * SQ)
#define SM_SS   (2 * HD_ * SQ + AK * HD_)
#define SM_TOT  (2 * HD_ * SQ + AK * HD_ + AK * SQ)   // 29952 floats = 119808 B

__global__ __launch_bounds__(256) void attn_kernel(const float* __restrict__ Qn,
                                                   const float* __restrict__ Kn,
                                                   const float* __restrict__ Vv,
                                                   float* __restrict__ O) {
    extern __shared__ float sm[];
    float* Qs = sm + SM_QS;
    float* Ks = sm + SM_KS;
    float* Vs = sm + SM_VS;
    float* Ss = sm + SM_SS;

    int bh = blockIdx.y;
    int qt = (int)gridDim.x - 1 - (int)blockIdx.x;   // big tiles first
    int q0 = qt * AQ;
    int tid = threadIdx.x;
    const float* Qb = Qn + (size_t)bh * S_ * HD_;
    const float* Kb = Kn + (size_t)bh * S_ * HD_;
    const float* Vb = Vv + (size_t)bh * S_ * HD_;

    // load Q tile transposed: 64 rows x 32 float4
    for (int i = tid; i < AQ * (HD_ / 4); i += 256) {
        int q = i >> 5;
        int d4 = i & 31;
        float4 v = ((const float4*)(Qb + (size_t)(q0 + q) * HD_))[d4];
        int d = d4 * 4;
        Qs[(d + 0) * SQ + q] = v.x;
        Qs[(d + 1) * SQ + q] = v.y;
        Qs[(d + 2) * SQ + q] = v.z;
        Qs[(d + 3) * SQ + q] = v.w;
    }

    int kx = tid % 16;          // phase1: k microtile (4 cols)
    int qy = tid / 16;          // phase1: q microtile (4 rows)
    int qy2 = tid % 16;         // phase2: q microtile (4 rows)
    int dx = tid / 16;          // phase2: d microtile (8 cols)

    float o[4][8];
#pragma unroll
    for (int i = 0; i < 4; i++)
#pragma unroll
        for (int j = 0; j < 8; j++) o[i][j] = 0.0f;

    for (int kc = 0; kc <= q0; kc += AK) {
        // --- load K (transposed) and V (straight) chunks
        for (int i = tid; i < AK * (HD_ / 4); i += 256) {
            int kr = i >> 5;
            int d4 = i & 31;
            float4 v = ((const float4*)(Kb + (size_t)(kc + kr) * HD_))[d4];
            int d = d4 * 4;
            Ks[(d + 0) * SQ + kr] = v.x;
            Ks[(d + 1) * SQ + kr] = v.y;
            Ks[(d + 2) * SQ + kr] = v.z;
            Ks[(d + 3) * SQ + kr] = v.w;
        }
        {
            const float4* src = (const float4*)(Vb + (size_t)kc * HD_);
            for (int i = tid; i < AK * HD_ / 4; i += 256)
                ((float4*)Vs)[i] = src[i];
        }
        __syncthreads();

        // --- phase 1: S = Q . K^T  (4q x 4k per thread)
        {
            float c[4][4];
#pragma unroll
            for (int i = 0; i < 4; i++)
#pragma unroll
                for (int j = 0; j < 4; j++) c[i][j] = 0.0f;
#pragma unroll 8
            for (int d = 0; d < HD_; d++) {
                float4 a = *(const float4*)&Qs[d * SQ + qy * 4];
                float4 b = *(const float4*)&Ks[d * SQ + kx * 4];
                float av[4] = {a.x, a.y, a.z, a.w};
                float bv[4] = {b.x, b.y, b.z, b.w};
#pragma unroll
                for (int i = 0; i < 4; i++)
#pragma unroll
                    for (int j = 0; j < 4; j++) c[i][j] += av[i] * bv[j];
            }
            bool diag = (kc == q0);
#pragma unroll
            for (int j = 0; j < 4; j++) {
                float4 st;
                if (diag) {
                    int kg = kc + kx * 4 + j;
                    st.x = (kg <= q0 + qy * 4 + 0) ? c[0][j] : 0.0f;
                    st.y = (kg <= q0 + qy * 4 + 1) ? c[1][j] : 0.0f;
                    st.z = (kg <= q0 + qy * 4 + 2) ? c[2][j] : 0.0f;
                    st.w = (kg <= q0 + qy * 4 + 3) ? c[3][j] : 0.0f;
                } else {
                    st = make_float4(c[0][j], c[1][j], c[2][j], c[3][j]);
                }
                *(float4*)&Ss[(kx * 4 + j) * SQ + qy * 4] = st;
            }
        }
        __syncthreads();

        // --- phase 2: O += S . V  (4q x 8d per thread)
#pragma unroll 8
        for (int k = 0; k < AK; k++) {
            float4 s = *(const float4*)&Ss[k * SQ + qy2 * 4];
            float4 v0 = *(const float4*)&Vs[k * HD_ + dx * 8];
            float4 v1 = *(const float4*)&Vs[k * HD_ + dx * 8 + 4];
            float sv[4] = {s.x, s.y, s.z, s.w};
            float vv[8] = {v0.x, v0.y, v0.z, v0.w, v1.x, v1.y, v1.z, v1.w};
#pragma unroll
            for (int i = 0; i < 4; i++)
#pragma unroll
                for (int j = 0; j < 8; j++) o[i][j] += sv[i] * vv[j];
        }
        __syncthreads();
    }

    // write out: (b*S+q)*E + h*HD + d
    int b = bh / H_;
    int h = bh % H_;
#pragma unroll
    for (int i = 0; i < 4; i++) {
        int q = q0 + qy2 * 4 + i;
        float* op = O + ((size_t)(b * S_ + q)) * E_ + h * HD_ + dx * 8;
        float4 c0 = {o[i][0], o[i][1], o[i][2], o[i][3]};
        float4 c1 = {o[i][4], o[i][5], o[i][6], o[i][7]};
        *(float4*)(op) = c0;
        *(float4*)(op + 4) = c1;
    }
}

// ---------------- launcher ---------------------------------------------------
extern "C" void kernel_launch(void* const* d_in, const int* in_sizes, int n_in,
                              void* d_out, int out_size) {
    const float* hs        = (const float*)d_in[0];
    const float* w_q       = (const float*)d_in[1];
    const float* w_k       = (const float*)d_in[2];
    const float* w_v       = (const float*)d_in[3];
    const float* w_o       = (const float*)d_in[4];
    const float* norm_c    = (const float*)d_in[5];
    const float* attn_mask = (const float*)d_in[6];
    const int*   pos_ids   = (const int*)d_in[7];
    float* out = (float*)d_out;

    float *tq, *tk, *tv, *qn, *kn, *vs, *ao, *cnts;
    cudaGetSymbolAddress((void**)&tq, g_tq);
    cudaGetSymbolAddress((void**)&tk, g_tk);
    cudaGetSymbolAddress((void**)&tv, g_tv);
    cudaGetSymbolAddress((void**)&qn, g_qn);
    cudaGetSymbolAddress((void**)&kn, g_kn);
    cudaGetSymbolAddress((void**)&vs, g_vs);
    cudaGetSymbolAddress((void**)&ao, g_ao);
    cudaGetSymbolAddress((void**)&cnts, g_counts);

    static bool attr_set = false;
    if (!attr_set) {
        cudaFuncSetAttribute(attn_kernel, cudaFuncAttributeMaxDynamicSharedMemorySize,
                             SM_TOT * (int)sizeof(float));
        attr_set = true;
    }

    counts_kernel<<<B_, S_>>>(attn_mask, cnts);

    dim3 gq(E_ / BN, NROWS / BM, 3);
    gemm_qkv<<<gq, 256>>>(hs, w_q, w_k, w_v, tq, tk, tv);

    rope_norm_kernel<<<(B_ * S_ * H_) / 4, 128>>>(tq, tk, tv, attn_mask, norm_c,
                                                  pos_ids, cnts, qn, kn, vs);

    attn_kernel<<<dim3(S_ / AQ, B_ * H_), 256, SM_TOT * sizeof(float)>>>(qn, kn, vs, ao);

    dim3 gg(E_ / BN, NROWS / BM);
    gemm_out<<<gg, 256>>>(ao, w_o, out);
}

// round 4
// speedup vs baseline: 4.2180x; 1.8124x over previous
#include <cuda_runtime.h>
#include <cuda_bf16.h>
#include <math.h>
#include <stdint.h>

#define B_  2
#define S_  1024
#define E_  2048
#define H_  16
#define HD_ 128
#define ROT_ 64
#define NROWS (B_ * S_)
#define EPS_ 1e-12f

// ---------------- scratch ----------------------------------------------------
__device__ float g_tq[NROWS * E_];
__device__ float g_tk[NROWS * E_];
__device__ float g_tv[NROWS * E_];
__device__ float g_qn[B_ * H_ * S_ * HD_];
__device__ float g_kn[B_ * H_ * S_ * HD_];
__device__ float g_vs[B_ * H_ * S_ * HD_];
__device__ float g_ao[NROWS * E_];
__device__ float g_counts[B_ * S_];

// bf16 split scratch (hi / lo)
__device__ __nv_bfloat16 g_hs0[NROWS * E_], g_hs1[NROWS * E_];
__device__ __nv_bfloat16 g_wq0[E_ * E_],   g_wq1[E_ * E_];
__device__ __nv_bfloat16 g_wk0[E_ * E_],   g_wk1[E_ * E_];
__device__ __nv_bfloat16 g_wv0[E_ * E_],   g_wv1[E_ * E_];
__device__ __nv_bfloat16 g_wo0[E_ * E_],   g_wo1[E_ * E_];
__device__ __nv_bfloat16 g_ao0[NROWS * E_], g_ao1[NROWS * E_];

// ---------------- PTX helpers ------------------------------------------------
__device__ __forceinline__ uint32_t smem_u32(const void* p) {
    uint32_t a;
    asm("{ .reg .u64 t; cvta.to.shared.u64 t, %1; cvt.u32.u64 %0, t; }" : "=r"(a) : "l"(p));
    return a;
}
#define CP16(dst, src) asm volatile("cp.async.cg.shared.global [%0], [%1], 16;" :: "r"(dst), "l"(src) : "memory")
#define CP_COMMIT() asm volatile("cp.async.commit_group;" ::: "memory")

#define LDSM4(r0, r1, r2, r3, addr) \
    asm volatile("ldmatrix.sync.aligned.m8n8.x4.shared.b16 {%0,%1,%2,%3}, [%4];" \
        : "=r"(r0), "=r"(r1), "=r"(r2), "=r"(r3) : "r"(addr))

#define MMA16816(c, a, br0, br1) \
    asm volatile("mma.sync.aligned.m16n8k16.row.col.f32.bf16.bf16.f32 " \
        "{%0,%1,%2,%3}, {%4,%5,%6,%7}, {%8,%9}, {%0,%1,%2,%3};" \
        : "+f"((c)[0]), "+f"((c)[1]), "+f"((c)[2]), "+f"((c)[3]) \
        : "r"((a)[0]), "r"((a)[1]), "r"((a)[2]), "r"((a)[3]), "r"(br0), "r"(br1))

// ---------------- split fp32 -> bf16 hi/lo ----------------------------------
__global__ __launch_bounds__(256) void split_kernel(const float* __restrict__ x,
                                                    __nv_bfloat16* __restrict__ hi,
                                                    __nv_bfloat16* __restrict__ lo,
                                                    int n4) {
    for (int i = blockIdx.x * blockDim.x + threadIdx.x; i < n4; i += gridDim.x * blockDim.x) {
        float4 v = ((const float4*)x)[i];
        float vv[4] = {v.x, v.y, v.z, v.w};
        unsigned short hs[4], ls[4];
#pragma unroll
        for (int j = 0; j < 4; j++) {
            __nv_bfloat16 h = __float2bfloat16(vv[j]);
            __nv_bfloat16 l = __float2bfloat16(vv[j] - __bfloat162float(h));
            hs[j] = __bfloat16_as_ushort(h);
            ls[j] = __bfloat16_as_ushort(l);
        }
        uint2 ph = {(uint32_t)hs[0] | ((uint32_t)hs[1] << 16),
                    (uint32_t)hs[2] | ((uint32_t)hs[3] << 16)};
        uint2 pl = {(uint32_t)ls[0] | ((uint32_t)ls[1] << 16),
                    (uint32_t)ls[2] | ((uint32_t)ls[3] << 16)};
        ((uint2*)hi)[i] = ph;
        ((uint2*)lo)[i] = pl;
    }
}

// ---------------- mma.sync bf16x3 GEMM: C[M,N] = A[M,K] . B[N,K]^T ----------
// CTA tile 128x128, 8 warps (2x4), warp tile 64x32, K-chunk 32.
// smem: 4 matrices (A0,A1,B0,B1), each 128 rows x 64B data padded to 80B rows.
#define KCH 32
#define NCHK (E_ / KCH)        // 64
#define ROWB 80
#define MAT_B (128 * ROWB)     // 10240 B
#define STG_B (4 * MAT_B)      // 40960 B
#define MMA_SMEM (2 * STG_B)   // 81920 B

__device__ __forceinline__ void mma_load_chunk(uint32_t base, int t, int tid,
                                               const __nv_bfloat16* a0, const __nv_bfloat16* a1,
                                               const __nv_bfloat16* b0, const __nv_bfloat16* b1) {
    for (int i = tid; i < 512; i += 256) {
        int r = i >> 2, c = i & 3;
        size_t g = (size_t)r * E_ + t * KCH + c * 8;
        uint32_t d = base + r * ROWB + c * 16;
        CP16(d,             a0 + g);
        CP16(d + MAT_B,     a1 + g);
        CP16(d + 2 * MAT_B, b0 + g);
        CP16(d + 3 * MAT_B, b1 + g);
    }
    CP_COMMIT();
}

__device__ __forceinline__ void mma_gemm_body(const __nv_bfloat16* A0, const __nv_bfloat16* A1,
                                              const __nv_bfloat16* B0, const __nv_bfloat16* B1,
                                              float* C, int bm, int bn) {
    extern __shared__ char smc[];
    uint32_t sb = smem_u32(smc);
    int tid = threadIdx.x;
    int lane = tid & 31;
    int wid = tid >> 5;
    int wm = wid >> 2;     // 0..1  (64 rows each)
    int wn = wid & 3;      // 0..3  (32 cols each)

    const __nv_bfloat16* a0 = A0 + (size_t)bm * E_;
    const __nv_bfloat16* a1 = A1 + (size_t)bm * E_;
    const __nv_bfloat16* b0 = B0 + (size_t)bn * E_;
    const __nv_bfloat16* b1 = B1 + (size_t)bn * E_;

    float acc[4][4][4];
#pragma unroll
    for (int i = 0; i < 4; i++)
#pragma unroll
        for (int j = 0; j < 4; j++)
#pragma unroll
            for (int k = 0; k < 4; k++) acc[i][j][k] = 0.0f;

    mma_load_chunk(sb, 0, tid, a0, a1, b0, b1);

    // ldmatrix address components
    int arow = lane & 15;
    int acolb = ((lane >> 4) & 1) * 16;
    int brow = (lane & 7) + ((lane >> 4) << 3);
    int bcolb = ((lane >> 3) & 1) * 16;

    for (int t = 0; t < NCHK; t++) {
        int cur = t & 1;
        if (t + 1 < NCHK) {
            mma_load_chunk(sb + (cur ^ 1) * STG_B, t + 1, tid, a0, a1, b0, b1);
            asm volatile("cp.async.wait_group 1;" ::: "memory");
        } else {
            asm volatile("cp.async.wait_group 0;" ::: "memory");
        }
        __syncthreads();

        uint32_t st = sb + cur * STG_B;
        uint32_t aA0 = st + (wm * 64 + arow) * ROWB + acolb;
        uint32_t aA1 = aA0 + MAT_B;
        uint32_t aB0 = st + 2 * MAT_B + (wn * 32 + brow) * ROWB + bcolb;
        uint32_t aB1 = aB0 + MAT_B;

#pragma unroll
        for (int ks = 0; ks < 2; ks++) {
            uint32_t a0f[4][4], a1f[4][4], b0f[2][4], b1f[2][4];
#pragma unroll
            for (int mt = 0; mt < 4; mt++) {
                uint32_t ad = aA0 + mt * 16 * ROWB + ks * 32;
                LDSM4(a0f[mt][0], a0f[mt][1], a0f[mt][2], a0f[mt][3], ad);
                uint32_t ad1 = aA1 + mt * 16 * ROWB + ks * 32;
                LDSM4(a1f[mt][0], a1f[mt][1], a1f[mt][2], a1f[mt][3], ad1);
            }
#pragma unroll
            for (int np = 0; np < 2; np++) {
                uint32_t bd = aB0 + np * 16 * ROWB + ks * 32;
                LDSM4(b0f[np][0], b0f[np][1], b0f[np][2], b0f[np][3], bd);
                uint32_t bd1 = aB1 + np * 16 * ROWB + ks * 32;
                LDSM4(b1f[np][0], b1f[np][1], b1f[np][2], b1f[np][3], bd1);
            }
#pragma unroll
            for (int mt = 0; mt < 4; mt++) {
#pragma unroll
                for (int nt = 0; nt < 4; nt++) {
                    uint32_t* p0 = &b0f[nt >> 1][(nt & 1) * 2];
                    uint32_t* p1 = &b1f[nt >> 1][(nt & 1) * 2];
                    MMA16816(acc[mt][nt], a0f[mt], p0[0], p0[1]);
                    MMA16816(acc[mt][nt], a0f[mt], p1[0], p1[1]);
                    MMA16816(acc[mt][nt], a1f[mt], p0[0], p0[1]);
                }
            }
        }
        __syncthreads();
    }

    // epilogue
    int row0 = bm + wm * 64 + (lane >> 2);
    int col0 = bn + wn * 32 + (lane & 3) * 2;
#pragma unroll
    for (int mt = 0; mt < 4; mt++) {
#pragma unroll
        for (int nt = 0; nt < 4; nt++) {
            int r = row0 + mt * 16;
            int c = col0 + nt * 8;
            float2 v0 = {acc[mt][nt][0], acc[mt][nt][1]};
            float2 v1 = {acc[mt][nt][2], acc[mt][nt][3]};
            *(float2*)&C[(size_t)r * E_ + c] = v0;
            *(float2*)&C[(size_t)(r + 8) * E_ + c] = v1;
        }
    }
}

__global__ __launch_bounds__(256, 1) void mma_gemm_qkv(
    const __nv_bfloat16* __restrict__ a0, const __nv_bfloat16* __restrict__ a1,
    const __nv_bfloat16* __restrict__ q0, const __nv_bfloat16* __restrict__ q1,
    const __nv_bfloat16* __restrict__ k0, const __nv_bfloat16* __restrict__ k1,
    const __nv_bfloat16* __restrict__ v0, const __nv_bfloat16* __restrict__ v1,
    float* __restrict__ cq, float* __restrict__ ck, float* __restrict__ cv) {
    const __nv_bfloat16* b0 = (blockIdx.z == 0) ? q0 : (blockIdx.z == 1) ? k0 : v0;
    const __nv_bfloat16* b1 = (blockIdx.z == 0) ? q1 : (blockIdx.z == 1) ? k1 : v1;
    float* C = (blockIdx.z == 0) ? cq : (blockIdx.z == 1) ? ck : cv;
    mma_gemm_body(a0, a1, b0, b1, C, blockIdx.y * 128, blockIdx.x * 128);
}

__global__ __launch_bounds__(256, 1) void mma_gemm_one(
    const __nv_bfloat16* __restrict__ a0, const __nv_bfloat16* __restrict__ a1,
    const __nv_bfloat16* __restrict__ b0, const __nv_bfloat16* __restrict__ b1,
    float* __restrict__ C) {
    mma_gemm_body(a0, a1, b0, b1, C, blockIdx.y * 128, blockIdx.x * 128);
}

// ---------------- mask prefix scan ------------------------------------------
__global__ void counts_kernel(const float* __restrict__ mask, float* __restrict__ counts) {
    __shared__ float sh[S_];
    int b = blockIdx.x;
    int t = threadIdx.x;
    sh[t] = (mask[b * S_ + t] == 0.0f) ? 1.0f : 0.0f;
    __syncthreads();
    for (int off = 1; off < S_; off <<= 1) {
        float add = (t >= off) ? sh[t - off] : 0.0f;
        __syncthreads();
        sh[t] += add;
        __syncthreads();
    }
    counts[b * S_ + t] = sh[t];
}

// ---------------- RoPE + L2 norm + mask + v scaling -------------------------
__global__ __launch_bounds__(128) void rope_norm_kernel(
    const float* __restrict__ tq, const float* __restrict__ tk,
    const float* __restrict__ tv, const float* __restrict__ mask,
    const float* __restrict__ norm_const, const int* __restrict__ pos_ids,
    const float* __restrict__ counts,
    float* __restrict__ Qn, float* __restrict__ Kn, float* __restrict__ Vs) {
    int warp = threadIdx.x >> 5;
    int lane = threadIdx.x & 31;
    int gw = blockIdx.x * 4 + warp;
    int h = gw % H_;
    int bs = gw / H_;
    int b = bs / S_;
    int s = bs % S_;

    int d0 = lane * 4;
    size_t src = (size_t)bs * E_ + h * HD_ + d0;
    float4 q4 = *(const float4*)(tq + src);
    float4 k4 = *(const float4*)(tk + src);
    float4 v4 = *(const float4*)(tv + src);

    if (d0 < ROT_) {
        float fpos = (float)pos_ids[bs];
        int i0 = lane * 2, i1 = lane * 2 + 1;
        float log1e4 = 9.210340371976184f;
        float th0 = fpos * __expf(-log1e4 * (2.0f * i0) / (float)ROT_);
        float th1 = fpos * __expf(-log1e4 * (2.0f * i1) / (float)ROT_);
        float c0 = cosf(th0), s0 = sinf(th0);
        float c1 = cosf(th1), s1 = sinf(th1);
        q4 = make_float4(q4.x * c0 - q4.y * s0, q4.y * c0 + q4.x * s0,
                         q4.z * c1 - q4.w * s1, q4.w * c1 + q4.z * s1);
        k4 = make_float4(k4.x * c0 - k4.y * s0, k4.y * c0 + k4.x * s0,
                         k4.z * c1 - k4.w * s1, k4.w * c1 + k4.z * s1);
    }

    float sq = q4.x * q4.x + q4.y * q4.y + q4.z * q4.z + q4.w * q4.w;
    float sk = k4.x * k4.x + k4.y * k4.y + k4.z * k4.z + k4.w * k4.w;
#pragma unroll
    for (int off = 16; off > 0; off >>= 1) {
        sq += __shfl_xor_sync(0xffffffffu, sq, off);
        sk += __shfl_xor_sync(0xffffffffu, sk, off);
    }
    float nq = fmaxf(sqrtf(sq), EPS_);
    float nk = fmaxf(sqrtf(sk), EPS_);

    float m = (mask[bs] == 0.0f) ? 1.0f : 0.0f;
    float sclq = m / nq;
    float sclk = m / nk;

    float nc = norm_const[h];
    float p = 1.0f / (1.0f + expf(-nc));
    float den = fmaxf(powf(counts[bs], p), 1.0f);
    float sclv = m / den;

    size_t dst = (((size_t)(b * H_ + h)) * S_ + s) * HD_ + d0;
    *(float4*)(Qn + dst) = make_float4(q4.x * sclq, q4.y * sclq, q4.z * sclq, q4.w * sclq);
    *(float4*)(Kn + dst) = make_float4(k4.x * sclk, k4.y * sclk, k4.z * sclk, k4.w * sclk);
    *(float4*)(Vs + dst) = make_float4(v4.x * sclv, v4.y * sclv, v4.z * sclv, v4.w * sclv);
}

// ---------------- causal no-softmax attention (64x64 tiles) ------------------
#define AQ 64
#define AK 64
#define SQ 68

#define SM_QS   0
#define SM_KS   (HD_ * SQ)
#define SM_VS   (2 * HD_ * SQ)
#define SM_SS   (2 * HD_ * SQ + AK * HD_)
#define SM_TOT  (2 * HD_ * SQ + AK * HD_ + AK * SQ)

__global__ __launch_bounds__(256) void attn_kernel(const float* __restrict__ Qn,
                                                   const float* __restrict__ Kn,
                                                   const float* __restrict__ Vv,
                                                   float* __restrict__ O) {
    extern __shared__ float smf[];
    float* Qs = smf + SM_QS;
    float* Ks = smf + SM_KS;
    float* Vs = smf + SM_VS;
    float* Ss = smf + SM_SS;

    int bh = blockIdx.y;
    int qt = (int)gridDim.x - 1 - (int)blockIdx.x;
    int q0 = qt * AQ;
    int tid = threadIdx.x;
    const float* Qb = Qn + (size_t)bh * S_ * HD_;
    const float* Kb = Kn + (size_t)bh * S_ * HD_;
    const float* Vb = Vv + (size_t)bh * S_ * HD_;

    for (int i = tid; i < AQ * (HD_ / 4); i += 256) {
        int q = i >> 5;
        int d4 = i & 31;
        float4 v = ((const float4*)(Qb + (size_t)(q0 + q) * HD_))[d4];
        int d = d4 * 4;
        Qs[(d + 0) * SQ + q] = v.x;
        Qs[(d + 1) * SQ + q] = v.y;
        Qs[(d + 2) * SQ + q] = v.z;
        Qs[(d + 3) * SQ + q] = v.w;
    }

    int kx = tid % 16;
    int qy = tid / 16;
    int qy2 = tid % 16;
    int dx = tid / 16;

    float o[4][8];
#pragma unroll
    for (int i = 0; i < 4; i++)
#pragma unroll
        for (int j = 0; j < 8; j++) o[i][j] = 0.0f;

    for (int kc = 0; kc <= q0; kc += AK) {
        for (int i = tid; i < AK * (HD_ / 4); i += 256) {
            int kr = i >> 5;
            int d4 = i & 31;
            float4 v = ((const float4*)(Kb + (size_t)(kc + kr) * HD_))[d4];
            int d = d4 * 4;
            Ks[(d + 0) * SQ + kr] = v.x;
            Ks[(d + 1) * SQ + kr] = v.y;
            Ks[(d + 2) * SQ + kr] = v.z;
            Ks[(d + 3) * SQ + kr] = v.w;
        }
        {
            const float4* src = (const float4*)(Vb + (size_t)kc * HD_);
            for (int i = tid; i < AK * HD_ / 4; i += 256)
                ((float4*)Vs)[i] = src[i];
        }
        __syncthreads();

        {
            float c[4][4];
#pragma unroll
            for (int i = 0; i < 4; i++)
#pragma unroll
                for (int j = 0; j < 4; j++) c[i][j] = 0.0f;
#pragma unroll 8
            for (int d = 0; d < HD_; d++) {
                float4 a = *(const float4*)&Qs[d * SQ + qy * 4];
                float4 b = *(const float4*)&Ks[d * SQ + kx * 4];
                float av[4] = {a.x, a.y, a.z, a.w};
                float bv[4] = {b.x, b.y, b.z, b.w};
#pragma unroll
                for (int i = 0; i < 4; i++)
#pragma unroll
                    for (int j = 0; j < 4; j++) c[i][j] += av[i] * bv[j];
            }
            bool diag = (kc == q0);
#pragma unroll
            for (int j = 0; j < 4; j++) {
                float4 st;
                if (diag) {
                    int kg = kc + kx * 4 + j;
                    st.x = (kg <= q0 + qy * 4 + 0) ? c[0][j] : 0.0f;
                    st.y = (kg <= q0 + qy * 4 + 1) ? c[1][j] : 0.0f;
                    st.z = (kg <= q0 + qy * 4 + 2) ? c[2][j] : 0.0f;
                    st.w = (kg <= q0 + qy * 4 + 3) ? c[3][j] : 0.0f;
                } else {
                    st = make_float4(c[0][j], c[1][j], c[2][j], c[3][j]);
                }
                *(float4*)&Ss[(kx * 4 + j) * SQ + qy * 4] = st;
            }
        }
        __syncthreads();

#pragma unroll 8
        for (int k = 0; k < AK; k++) {
            float4 s = *(const float4*)&Ss[k * SQ + qy2 * 4];
            float4 v0 = *(const float4*)&Vs[k * HD_ + dx * 8];
            float4 v1 = *(const float4*)&Vs[k * HD_ + dx * 8 + 4];
            float sv[4] = {s.x, s.y, s.z, s.w};
            float vv[8] = {v0.x, v0.y, v0.z, v0.w, v1.x, v1.y, v1.z, v1.w};
#pragma unroll
            for (int i = 0; i < 4; i++)
#pragma unroll
                for (int j = 0; j < 8; j++) o[i][j] += sv[i] * vv[j];
        }
        __syncthreads();
    }

    int b = bh / H_;
    int h = bh % H_;
#pragma unroll
    for (int i = 0; i < 4; i++) {
        int q = q0 + qy2 * 4 + i;
        float* op = O + ((size_t)(b * S_ + q)) * E_ + h * HD_ + dx * 8;
        float4 c0 = {o[i][0], o[i][1], o[i][2], o[i][3]};
        float4 c1 = {o[i][4], o[i][5], o[i][6], o[i][7]};
        *(float4*)(op) = c0;
        *(float4*)(op + 4) = c1;
    }
}

// ---------------- launcher ---------------------------------------------------
extern "C" void kernel_launch(void* const* d_in, const int* in_sizes, int n_in,
                              void* d_out, int out_size) {
    const float* hs        = (const float*)d_in[0];
    const float* w_q       = (const float*)d_in[1];
    const float* w_k       = (const float*)d_in[2];
    const float* w_v       = (const float*)d_in[3];
    const float* w_o       = (const float*)d_in[4];
    const float* norm_c    = (const float*)d_in[5];
    const float* attn_mask = (const float*)d_in[6];
    const int*   pos_ids   = (const int*)d_in[7];
    float* out = (float*)d_out;

    float *tq, *tk, *tv, *qn, *kn, *vs, *ao, *cnts;
    cudaGetSymbolAddress((void**)&tq, g_tq);
    cudaGetSymbolAddress((void**)&tk, g_tk);
    cudaGetSymbolAddress((void**)&tv, g_tv);
    cudaGetSymbolAddress((void**)&qn, g_qn);
    cudaGetSymbolAddress((void**)&kn, g_kn);
    cudaGetSymbolAddress((void**)&vs, g_vs);
    cudaGetSymbolAddress((void**)&ao, g_ao);
    cudaGetSymbolAddress((void**)&cnts, g_counts);

    __nv_bfloat16 *hs0, *hs1, *wq0, *wq1, *wk0, *wk1, *wv0, *wv1, *wo0, *wo1, *ao0, *ao1;
    cudaGetSymbolAddress((void**)&hs0, g_hs0);
    cudaGetSymbolAddress((void**)&hs1, g_hs1);
    cudaGetSymbolAddress((void**)&wq0, g_wq0);
    cudaGetSymbolAddress((void**)&wq1, g_wq1);
    cudaGetSymbolAddress((void**)&wk0, g_wk0);
    cudaGetSymbolAddress((void**)&wk1, g_wk1);
    cudaGetSymbolAddress((void**)&wv0, g_wv0);
    cudaGetSymbolAddress((void**)&wv1, g_wv1);
    cudaGetSymbolAddress((void**)&wo0, g_wo0);
    cudaGetSymbolAddress((void**)&wo1, g_wo1);
    cudaGetSymbolAddress((void**)&ao0, g_ao0);
    cudaGetSymbolAddress((void**)&ao1, g_ao1);

    static bool attr_set = false;
    if (!attr_set) {
        cudaFuncSetAttribute(attn_kernel, cudaFuncAttributeMaxDynamicSharedMemorySize,
                             SM_TOT * (int)sizeof(float));
        cudaFuncSetAttribute(mma_gemm_qkv, cudaFuncAttributeMaxDynamicSharedMemorySize, MMA_SMEM);
        cudaFuncSetAttribute(mma_gemm_one, cudaFuncAttributeMaxDynamicSharedMemorySize, MMA_SMEM);
        attr_set = true;
    }

    const int NEL4 = NROWS * E_ / 4;

    counts_kernel<<<B_, S_>>>(attn_mask, cnts);

    split_kernel<<<1024, 256>>>(hs,  hs0, hs1, NEL4);
    split_kernel<<<1024, 256>>>(w_q, wq0, wq1, NEL4);
    split_kernel<<<1024, 256>>>(w_k, wk0, wk1, NEL4);
    split_kernel<<<1024, 256>>>(w_v, wv0, wv1, NEL4);
    split_kernel<<<1024, 256>>>(w_o, wo0, wo1, NEL4);

    mma_gemm_qkv<<<dim3(E_ / 128, NROWS / 128, 3), 256, MMA_SMEM>>>(
        hs0, hs1, wq0, wq1, wk0, wk1, wv0, wv1, tq, tk, tv);

    rope_norm_kernel<<<(B_ * S_ * H_) / 4, 128>>>(tq, tk, tv, attn_mask, norm_c,
                                                  pos_ids, cnts, qn, kn, vs);

    attn_kernel<<<dim3(S_ / AQ, B_ * H_), 256, SM_TOT * sizeof(float)>>>(qn, kn, vs, ao);

    split_kernel<<<1024, 256>>>(ao, ao0, ao1, NEL4);

    mma_gemm_one<<<dim3(E_ / 128, NROWS / 128, 1), 256, MMA_SMEM>>>(ao0, ao1, wo0, wo1, out);
}

// round 5
// speedup vs baseline: 5.6181x; 1.3319x over previous
#include <cuda_runtime.h>
#include <cuda_bf16.h>
#include <math.h>
#include <stdint.h>

#define B_  2
#define S_  1024
#define E_  2048
#define H_  16
#define HD_ 128
#define ROT_ 64
#define NROWS (B_ * S_)
#define EPS_ 1e-12f

// ---------------- scratch ----------------------------------------------------
__device__ float g_tq[NROWS * E_];
__device__ float g_tk[NROWS * E_];
__device__ float g_tv[NROWS * E_];
__device__ float g_counts[B_ * S_];

// bf16 split scratch (hi / lo)
__device__ __nv_bfloat16 g_hs0[NROWS * E_], g_hs1[NROWS * E_];
__device__ __nv_bfloat16 g_wq0[E_ * E_],   g_wq1[E_ * E_];
__device__ __nv_bfloat16 g_wk0[E_ * E_],   g_wk1[E_ * E_];
__device__ __nv_bfloat16 g_wv0[E_ * E_],   g_wv1[E_ * E_];
__device__ __nv_bfloat16 g_wo0[E_ * E_],   g_wo1[E_ * E_];
__device__ __nv_bfloat16 g_ao0[NROWS * E_], g_ao1[NROWS * E_];

// attention inputs, (b,h,s,d) bf16 hi/lo
__device__ __nv_bfloat16 g_q0[B_ * H_ * S_ * HD_], g_q1[B_ * H_ * S_ * HD_];
__device__ __nv_bfloat16 g_k0[B_ * H_ * S_ * HD_], g_k1[B_ * H_ * S_ * HD_];
__device__ __nv_bfloat16 g_v0[B_ * H_ * S_ * HD_], g_v1[B_ * H_ * S_ * HD_];

// ---------------- PTX helpers ------------------------------------------------
__device__ __forceinline__ uint32_t smem_u32(const void* p) {
    uint32_t a;
    asm("{ .reg .u64 t; cvta.to.shared.u64 t, %1; cvt.u32.u64 %0, t; }" : "=r"(a) : "l"(p));
    return a;
}
#define CP16(dst, src) asm volatile("cp.async.cg.shared.global [%0], [%1], 16;" :: "r"(dst), "l"(src) : "memory")
#define CP_COMMIT() asm volatile("cp.async.commit_group;" ::: "memory")

#define LDSM4(r0, r1, r2, r3, addr) \
    asm volatile("ldmatrix.sync.aligned.m8n8.x4.shared.b16 {%0,%1,%2,%3}, [%4];" \
        : "=r"(r0), "=r"(r1), "=r"(r2), "=r"(r3) : "r"(addr))

#define LDSM4T(r0, r1, r2, r3, addr) \
    asm volatile("ldmatrix.sync.aligned.m8n8.x4.trans.shared.b16 {%0,%1,%2,%3}, [%4];" \
        : "=r"(r0), "=r"(r1), "=r"(r2), "=r"(r3) : "r"(addr))

#define MMA16816(c, a, br0, br1) \
    asm volatile("mma.sync.aligned.m16n8k16.row.col.f32.bf16.bf16.f32 " \
        "{%0,%1,%2,%3}, {%4,%5,%6,%7}, {%8,%9}, {%0,%1,%2,%3};" \
        : "+f"((c)[0]), "+f"((c)[1]), "+f"((c)[2]), "+f"((c)[3]) \
        : "r"((a)[0]), "r"((a)[1]), "r"((a)[2]), "r"((a)[3]), "r"(br0), "r"(br1))

__device__ __forceinline__ void split2(float x, float y, uint32_t& hi, uint32_t& lo) {
    __nv_bfloat16 hx = __float2bfloat16(x), hy = __float2bfloat16(y);
    __nv_bfloat16 lx = __float2bfloat16(x - __bfloat162float(hx));
    __nv_bfloat16 ly = __float2bfloat16(y - __bfloat162float(hy));
    hi = (uint32_t)__bfloat16_as_ushort(hx) | ((uint32_t)__bfloat16_as_ushort(hy) << 16);
    lo = (uint32_t)__bfloat16_as_ushort(lx) | ((uint32_t)__bfloat16_as_ushort(ly) << 16);
}

// ---------------- split fp32 -> bf16 hi/lo ----------------------------------
__global__ __launch_bounds__(256) void split_kernel(const float* __restrict__ x,
                                                    __nv_bfloat16* __restrict__ hi,
                                                    __nv_bfloat16* __restrict__ lo,
                                                    int n4) {
    for (int i = blockIdx.x * blockDim.x + threadIdx.x; i < n4; i += gridDim.x * blockDim.x) {
        float4 v = ((const float4*)x)[i];
        float vv[4] = {v.x, v.y, v.z, v.w};
        unsigned short hs[4], ls[4];
#pragma unroll
        for (int j = 0; j < 4; j++) {
            __nv_bfloat16 h = __float2bfloat16(vv[j]);
            __nv_bfloat16 l = __float2bfloat16(vv[j] - __bfloat162float(h));
            hs[j] = __bfloat16_as_ushort(h);
            ls[j] = __bfloat16_as_ushort(l);
        }
        uint2 ph = {(uint32_t)hs[0] | ((uint32_t)hs[1] << 16),
                    (uint32_t)hs[2] | ((uint32_t)hs[3] << 16)};
        uint2 pl = {(uint32_t)ls[0] | ((uint32_t)ls[1] << 16),
                    (uint32_t)ls[2] | ((uint32_t)ls[3] << 16)};
        ((uint2*)hi)[i] = ph;
        ((uint2*)lo)[i] = pl;
    }
}

// ---------------- mma.sync bf16x3 GEMM: C[M,N] = A[M,K] . B[N,K]^T ----------
#define KCH 32
#define NCHK (E_ / KCH)
#define ROWB 80
#define MAT_B (128 * ROWB)
#define STG_B (4 * MAT_B)
#define MMA_SMEM (2 * STG_B)

__device__ __forceinline__ void mma_load_chunk(uint32_t base, int t, int tid,
                                               const __nv_bfloat16* a0, const __nv_bfloat16* a1,
                                               const __nv_bfloat16* b0, const __nv_bfloat16* b1) {
    for (int i = tid; i < 512; i += 256) {
        int r = i >> 2, c = i & 3;
        size_t g = (size_t)r * E_ + t * KCH + c * 8;
        uint32_t d = base + r * ROWB + c * 16;
        CP16(d,             a0 + g);
        CP16(d + MAT_B,     a1 + g);
        CP16(d + 2 * MAT_B, b0 + g);
        CP16(d + 3 * MAT_B, b1 + g);
    }
    CP_COMMIT();
}

__device__ __forceinline__ void mma_gemm_body(const __nv_bfloat16* A0, const __nv_bfloat16* A1,
                                              const __nv_bfloat16* B0, const __nv_bfloat16* B1,
                                              float* C, int bm, int bn) {
    extern __shared__ char smc[];
    uint32_t sb = smem_u32(smc);
    int tid = threadIdx.x;
    int lane = tid & 31;
    int wid = tid >> 5;
    int wm = wid >> 2;
    int wn = wid & 3;

    const __nv_bfloat16* a0 = A0 + (size_t)bm * E_;
    const __nv_bfloat16* a1 = A1 + (size_t)bm * E_;
    const __nv_bfloat16* b0 = B0 + (size_t)bn * E_;
    const __nv_bfloat16* b1 = B1 + (size_t)bn * E_;

    float acc[4][4][4];
#pragma unroll
    for (int i = 0; i < 4; i++)
#pragma unroll
        for (int j = 0; j < 4; j++)
#pragma unroll
            for (int k = 0; k < 4; k++) acc[i][j][k] = 0.0f;

    mma_load_chunk(sb, 0, tid, a0, a1, b0, b1);

    int arow = lane & 15;
    int acolb = ((lane >> 4) & 1) * 16;
    int brow = (lane & 7) + ((lane >> 4) << 3);
    int bcolb = ((lane >> 3) & 1) * 16;

    for (int t = 0; t < NCHK; t++) {
        int cur = t & 1;
        if (t + 1 < NCHK) {
            mma_load_chunk(sb + (cur ^ 1) * STG_B, t + 1, tid, a0, a1, b0, b1);
            asm volatile("cp.async.wait_group 1;" ::: "memory");
        } else {
            asm volatile("cp.async.wait_group 0;" ::: "memory");
        }
        __syncthreads();

        uint32_t st = sb + cur * STG_B;
        uint32_t aA0 = st + (wm * 64 + arow) * ROWB + acolb;
        uint32_t aA1 = aA0 + MAT_B;
        uint32_t aB0 = st + 2 * MAT_B + (wn * 32 + brow) * ROWB + bcolb;
        uint32_t aB1 = aB0 + MAT_B;

#pragma unroll
        for (int ks = 0; ks < 2; ks++) {
            uint32_t a0f[4][4], a1f[4][4], b0f[2][4], b1f[2][4];
#pragma unroll
            for (int mt = 0; mt < 4; mt++) {
                uint32_t ad = aA0 + mt * 16 * ROWB + ks * 32;
                LDSM4(a0f[mt][0], a0f[mt][1], a0f[mt][2], a0f[mt][3], ad);
                uint32_t ad1 = aA1 + mt * 16 * ROWB + ks * 32;
                LDSM4(a1f[mt][0], a1f[mt][1], a1f[mt][2], a1f[mt][3], ad1);
            }
#pragma unroll
            for (int np = 0; np < 2; np++) {
                uint32_t bd = aB0 + np * 16 * ROWB + ks * 32;
                LDSM4(b0f[np][0], b0f[np][1], b0f[np][2], b0f[np][3], bd);
                uint32_t bd1 = aB1 + np * 16 * ROWB + ks * 32;
                LDSM4(b1f[np][0], b1f[np][1], b1f[np][2], b1f[np][3], bd1);
            }
#pragma unroll
            for (int mt = 0; mt < 4; mt++) {
#pragma unroll
                for (int nt = 0; nt < 4; nt++) {
                    uint32_t* p0 = &b0f[nt >> 1][(nt & 1) * 2];
                    uint32_t* p1 = &b1f[nt >> 1][(nt & 1) * 2];
                    MMA16816(acc[mt][nt], a0f[mt], p0[0], p0[1]);
                    MMA16816(acc[mt][nt], a0f[mt], p1[0], p1[1]);
                    MMA16816(acc[mt][nt], a1f[mt], p0[0], p0[1]);
                }
            }
        }
        __syncthreads();
    }

    int row0 = bm + wm * 64 + (lane >> 2);
    int col0 = bn + wn * 32 + (lane & 3) * 2;
#pragma unroll
    for (int mt = 0; mt < 4; mt++) {
#pragma unroll
        for (int nt = 0; nt < 4; nt++) {
            int r = row0 + mt * 16;
            int c = col0 + nt * 8;
            float2 v0 = {acc[mt][nt][0], acc[mt][nt][1]};
            float2 v1 = {acc[mt][nt][2], acc[mt][nt][3]};
            *(float2*)&C[(size_t)r * E_ + c] = v0;
            *(float2*)&C[(size_t)(r + 8) * E_ + c] = v1;
        }
    }
}

__global__ __launch_bounds__(256, 1) void mma_gemm_qkv(
    const __nv_bfloat16* __restrict__ a0, const __nv_bfloat16* __restrict__ a1,
    const __nv_bfloat16* __restrict__ q0, const __nv_bfloat16* __restrict__ q1,
    const __nv_bfloat16* __restrict__ k0, const __nv_bfloat16* __restrict__ k1,
    const __nv_bfloat16* __restrict__ v0, const __nv_bfloat16* __restrict__ v1,
    float* __restrict__ cq, float* __restrict__ ck, float* __restrict__ cv) {
    const __nv_bfloat16* b0 = (blockIdx.z == 0) ? q0 : (blockIdx.z == 1) ? k0 : v0;
    const __nv_bfloat16* b1 = (blockIdx.z == 0) ? q1 : (blockIdx.z == 1) ? k1 : v1;
    float* C = (blockIdx.z == 0) ? cq : (blockIdx.z == 1) ? ck : cv;
    mma_gemm_body(a0, a1, b0, b1, C, blockIdx.y * 128, blockIdx.x * 128);
}

__global__ __launch_bounds__(256, 1) void mma_gemm_one(
    const __nv_bfloat16* __restrict__ a0, const __nv_bfloat16* __restrict__ a1,
    const __nv_bfloat16* __restrict__ b0, const __nv_bfloat16* __restrict__ b1,
    float* __restrict__ C) {
    mma_gemm_body(a0, a1, b0, b1, C, blockIdx.y * 128, blockIdx.x * 128);
}

// ---------------- mask prefix scan ------------------------------------------
__global__ void counts_kernel(const float* __restrict__ mask, float* __restrict__ counts) {
    __shared__ float sh[S_];
    int b = blockIdx.x;
    int t = threadIdx.x;
    sh[t] = (mask[b * S_ + t] == 0.0f) ? 1.0f : 0.0f;
    __syncthreads();
    for (int off = 1; off < S_; off <<= 1) {
        float add = (t >= off) ? sh[t - off] : 0.0f;
        __syncthreads();
        sh[t] += add;
        __syncthreads();
    }
    counts[b * S_ + t] = sh[t];
}

// ---------------- RoPE + L2 norm + mask + v scaling -> bf16 hi/lo -----------
__global__ __launch_bounds__(128) void rope_norm_kernel(
    const float* __restrict__ tq, const float* __restrict__ tk,
    const float* __restrict__ tv, const float* __restrict__ mask,
    const float* __restrict__ norm_const, const int* __restrict__ pos_ids,
    const float* __restrict__ counts,
    __nv_bfloat16* __restrict__ Qh, __nv_bfloat16* __restrict__ Ql,
    __nv_bfloat16* __restrict__ Kh, __nv_bfloat16* __restrict__ Kl,
    __nv_bfloat16* __restrict__ Vh, __nv_bfloat16* __restrict__ Vl) {
    int warp = threadIdx.x >> 5;
    int lane = threadIdx.x & 31;
    int gw = blockIdx.x * 4 + warp;
    int h = gw % H_;
    int bs = gw / H_;
    int b = bs / S_;
    int s = bs % S_;

    int d0 = lane * 4;
    size_t src = (size_t)bs * E_ + h * HD_ + d0;
    float4 q4 = *(const float4*)(tq + src);
    float4 k4 = *(const float4*)(tk + src);
    float4 v4 = *(const float4*)(tv + src);

    if (d0 < ROT_) {
        float fpos = (float)pos_ids[bs];
        int i0 = lane * 2, i1 = lane * 2 + 1;
        float log1e4 = 9.210340371976184f;
        float th0 = fpos * __expf(-log1e4 * (2.0f * i0) / (float)ROT_);
        float th1 = fpos * __expf(-log1e4 * (2.0f * i1) / (float)ROT_);
        float c0 = cosf(th0), s0 = sinf(th0);
        float c1 = cosf(th1), s1 = sinf(th1);
        q4 = make_float4(q4.x * c0 - q4.y * s0, q4.y * c0 + q4.x * s0,
                         q4.z * c1 - q4.w * s1, q4.w * c1 + q4.z * s1);
        k4 = make_float4(k4.x * c0 - k4.y * s0, k4.y * c0 + k4.x * s0,
                         k4.z * c1 - k4.w * s1, k4.w * c1 + k4.z * s1);
    }

    float sq = q4.x * q4.x + q4.y * q4.y + q4.z * q4.z + q4.w * q4.w;
    float sk = k4.x * k4.x + k4.y * k4.y + k4.z * k4.z + k4.w * k4.w;
#pragma unroll
    for (int off = 16; off > 0; off >>= 1) {
        sq += __shfl_xor_sync(0xffffffffu, sq, off);
        sk += __shfl_xor_sync(0xffffffffu, sk, off);
    }
    float nq = fmaxf(sqrtf(sq), EPS_);
    float nk = fmaxf(sqrtf(sk), EPS_);

    float m = (mask[bs] == 0.0f) ? 1.0f : 0.0f;
    float sclq = m / nq;
    float sclk = m / nk;

    float nc = norm_const[h];
    float p = 1.0f / (1.0f + expf(-nc));
    float den = fmaxf(powf(counts[bs], p), 1.0f);
    float sclv = m / den;

    float qv[4] = {q4.x * sclq, q4.y * sclq, q4.z * sclq, q4.w * sclq};
    float kv[4] = {k4.x * sclk, k4.y * sclk, k4.z * sclk, k4.w * sclk};
    float vv[4] = {v4.x * sclv, v4.y * sclv, v4.z * sclv, v4.w * sclv};

    size_t dst = (((size_t)(b * H_ + h)) * S_ + s) * HD_ + d0;
    uint32_t h0, l0, h1, l1;
    split2(qv[0], qv[1], h0, l0); split2(qv[2], qv[3], h1, l1);
    *(uint2*)(Qh + dst) = make_uint2(h0, h1);
    *(uint2*)(Ql + dst) = make_uint2(l0, l1);
    split2(kv[0], kv[1], h0, l0); split2(kv[2], kv[3], h1, l1);
    *(uint2*)(Kh + dst) = make_uint2(h0, h1);
    *(uint2*)(Kl + dst) = make_uint2(l0, l1);
    split2(vv[0], vv[1], h0, l0); split2(vv[2], vv[3], h1, l1);
    *(uint2*)(Vh + dst) = make_uint2(h0, h1);
    *(uint2*)(Vl + dst) = make_uint2(l0, l1);
}

// ---------------- causal no-softmax attention via mma.sync -------------------
// CTA: 128 q-rows x HD=128, 8 warps x 16 rows. K/V chunks of 64, double-buffered.
#define AQM 128
#define AKC 64
#define RB 272                 // 128 bf16 cols (256B) + 16B pad
#define QMAT (128 * RB)        // 34816
#define KVMAT (64 * RB)        // 17408
#define KVSTG (4 * KVMAT)      // 69632: Kh, Kl, Vh, Vl
#define ATT_SMEM (2 * QMAT + 2 * KVSTG)   // 208896

__global__ __launch_bounds__(256, 1) void attn_mma(
    const __nv_bfloat16* __restrict__ qh, const __nv_bfloat16* __restrict__ ql,
    const __nv_bfloat16* __restrict__ kh, const __nv_bfloat16* __restrict__ kl,
    const __nv_bfloat16* __restrict__ vh, const __nv_bfloat16* __restrict__ vl,
    __nv_bfloat16* __restrict__ aoh, __nv_bfloat16* __restrict__ aol) {
    extern __shared__ char smc[];
    uint32_t sb = smem_u32(smc);
    uint32_t sQh = sb, sQl = sb + QMAT;
    uint32_t sKV = sb + 2 * QMAT;

    int tid = threadIdx.x;
    int lane = tid & 31;
    int wid = tid >> 5;
    int bh = blockIdx.y;
    int qt = (int)gridDim.x - 1 - (int)blockIdx.x;   // big tiles first
    int q0 = qt * AQM;

    size_t base = (size_t)bh * S_ * HD_;
    const __nv_bfloat16* Qhb = qh + base;
    const __nv_bfloat16* Qlb = ql + base;
    const __nv_bfloat16* Khb = kh + base;
    const __nv_bfloat16* Klb = kl + base;
    const __nv_bfloat16* Vhb = vh + base;
    const __nv_bfloat16* Vlb = vl + base;

    // load Q tile (hi+lo)
    for (int i = tid; i < 2048; i += 256) {
        int r = i >> 4, c = i & 15;
        size_t g = (size_t)(q0 + r) * HD_ + c * 8;
        CP16(sQh + r * RB + c * 16, Qhb + g);
        CP16(sQl + r * RB + c * 16, Qlb + g);
    }
    // chunk 0
    for (int i = tid; i < 1024; i += 256) {
        int r = i >> 4, c = i & 15;
        size_t g = (size_t)r * HD_ + c * 8;
        uint32_t d = sKV + r * RB + c * 16;
        CP16(d, Khb + g);
        CP16(d + KVMAT, Klb + g);
        CP16(d + 2 * KVMAT, Vhb + g);
        CP16(d + 3 * KVMAT, Vlb + g);
    }
    CP_COMMIT();

    int nch = q0 / AKC + 2;
    float o[16][4];
#pragma unroll
    for (int i = 0; i < 16; i++)
#pragma unroll
        for (int j = 0; j < 4; j++) o[i][j] = 0.0f;

    int arow = lane & 15;
    int acolb = ((lane >> 4) & 1) * 16;
    int brow = (lane & 7) + ((lane >> 4) << 3);
    int bcolb = ((lane >> 3) & 1) * 16;
    int vrow = (lane & 7) + (((lane >> 3) & 1) << 3);
    int vcolb = ((lane >> 4) & 1) * 16;
    int m0w = q0 + wid * 16;

    for (int t = 0; t < nch; t++) {
        asm volatile("cp.async.wait_group 0;" ::: "memory");
        __syncthreads();
        if (t + 1 < nch) {
            uint32_t nstg = sKV + ((t + 1) & 1) * KVSTG;
            int kc = (t + 1) * AKC;
            for (int i = tid; i < 1024; i += 256) {
                int r = i >> 4, c = i & 15;
                size_t g = (size_t)(kc + r) * HD_ + c * 8;
                uint32_t d = nstg + r * RB + c * 16;
                CP16(d, Khb + g);
                CP16(d + KVMAT, Klb + g);
                CP16(d + 2 * KVMAT, Vhb + g);
                CP16(d + 3 * KVMAT, Vlb + g);
            }
            CP_COMMIT();
        }
        uint32_t stg = sKV + (t & 1) * KVSTG;

        // ---- phase 1: S[16 x 64] = Q . K^T (3-term split)
        float sacc[8][4];
#pragma unroll
        for (int i = 0; i < 8; i++)
#pragma unroll
            for (int j = 0; j < 4; j++) sacc[i][j] = 0.0f;

#pragma unroll
        for (int ds = 0; ds < 8; ds++) {
            uint32_t ah[4], al[4];
            uint32_t ad = sQh + (wid * 16 + arow) * RB + acolb + ds * 32;
            LDSM4(ah[0], ah[1], ah[2], ah[3], ad);
            LDSM4(al[0], al[1], al[2], al[3], ad + QMAT);
            uint32_t bhf[4][4], blf[4][4];
#pragma unroll
            for (int ng = 0; ng < 4; ng++) {
                uint32_t bd = stg + (ng * 16 + brow) * RB + bcolb + ds * 32;
                LDSM4(bhf[ng][0], bhf[ng][1], bhf[ng][2], bhf[ng][3], bd);
                LDSM4(blf[ng][0], blf[ng][1], blf[ng][2], blf[ng][3], bd + KVMAT);
            }
#pragma unroll
            for (int nt = 0; nt < 8; nt++) {
                uint32_t* ph = &bhf[nt >> 1][(nt & 1) * 2];
                uint32_t* pl = &blf[nt >> 1][(nt & 1) * 2];
                MMA16816(sacc[nt], ah, ph[0], ph[1]);
                MMA16816(sacc[nt], ah, pl[0], pl[1]);
                MMA16816(sacc[nt], al, ph[0], ph[1]);
            }
        }

        // ---- causal mask on fragments
        int kcg = t * AKC;
        if (kcg + AKC - 1 > m0w) {
            int r0m = m0w + (lane >> 2);
            int r1m = r0m + 8;
#pragma unroll
            for (int nt = 0; nt < 8; nt++) {
                int cb = kcg + nt * 8 + (lane & 3) * 2;
                if (cb > r0m) sacc[nt][0] = 0.0f;
                if (cb + 1 > r0m) sacc[nt][1] = 0.0f;
                if (cb > r1m) sacc[nt][2] = 0.0f;
                if (cb + 1 > r1m) sacc[nt][3] = 0.0f;
            }
        }

        // ---- phase 2: O[16 x 128] += S . V (S fragments reused as A operand)
#pragma unroll
        for (int ks = 0; ks < 4; ks++) {
            uint32_t ah[4], al[4];
            split2(sacc[2 * ks][0], sacc[2 * ks][1], ah[0], al[0]);
            split2(sacc[2 * ks][2], sacc[2 * ks][3], ah[1], al[1]);
            split2(sacc[2 * ks + 1][0], sacc[2 * ks + 1][1], ah[2], al[2]);
            split2(sacc[2 * ks + 1][2], sacc[2 * ks + 1][3], ah[3], al[3]);
#pragma unroll
            for (int ng = 0; ng < 8; ng++) {
                uint32_t bh4[4], bl4[4];
                uint32_t va = stg + 2 * KVMAT + (ks * 16 + vrow) * RB + vcolb + ng * 32;
                LDSM4T(bh4[0], bh4[1], bh4[2], bh4[3], va);
                LDSM4T(bl4[0], bl4[1], bl4[2], bl4[3], va + KVMAT);
                MMA16816(o[2 * ng], ah, bh4[0], bh4[1]);
                MMA16816(o[2 * ng], ah, bl4[0], bl4[1]);
                MMA16816(o[2 * ng], al, bh4[0], bh4[1]);
                MMA16816(o[2 * ng + 1], ah, bh4[2], bh4[3]);
                MMA16816(o[2 * ng + 1], ah, bl4[2], bl4[3]);
                MMA16816(o[2 * ng + 1], al, bh4[2], bh4[3]);
            }
        }
    }

    // ---- epilogue: write ao as bf16 hi/lo, layout (b*S+q)*E + h*HD + d
    int b = bh / H_;
    int h = bh % H_;
    int r0 = m0w + (lane >> 2);
#pragma unroll
    for (int nt = 0; nt < 16; nt++) {
        int col = nt * 8 + (lane & 3) * 2;
        size_t g0 = ((size_t)(b * S_ + r0)) * E_ + h * HD_ + col;
        size_t g1 = ((size_t)(b * S_ + r0 + 8)) * E_ + h * HD_ + col;
        uint32_t hi0, lo0, hi1, lo1;
        split2(o[nt][0], o[nt][1], hi0, lo0);
        split2(o[nt][2], o[nt][3], hi1, lo1);
        *(uint32_t*)(aoh + g0) = hi0;
        *(uint32_t*)(aol + g0) = lo0;
        *(uint32_t*)(aoh + g1) = hi1;
        *(uint32_t*)(aol + g1) = lo1;
    }
}

// ---------------- launcher ---------------------------------------------------
extern "C" void kernel_launch(void* const* d_in, const int* in_sizes, int n_in,
                              void* d_out, int out_size) {
    const float* hs        = (const float*)d_in[0];
    const float* w_q       = (const float*)d_in[1];
    const float* w_k       = (const float*)d_in[2];
    const float* w_v       = (const float*)d_in[3];
    const float* w_o       = (const float*)d_in[4];
    const float* norm_c    = (const float*)d_in[5];
    const float* attn_mask = (const float*)d_in[6];
    const int*   pos_ids   = (const int*)d_in[7];
    float* out = (float*)d_out;

    float *tq, *tk, *tv, *cnts;
    cudaGetSymbolAddress((void**)&tq, g_tq);
    cudaGetSymbolAddress((void**)&tk, g_tk);
    cudaGetSymbolAddress((void**)&tv, g_tv);
    cudaGetSymbolAddress((void**)&cnts, g_counts);

    __nv_bfloat16 *hs0, *hs1, *wq0, *wq1, *wk0, *wk1, *wv0, *wv1, *wo0, *wo1, *ao0, *ao1;
    __nv_bfloat16 *q0, *q1, *k0, *k1, *v0, *v1;
    cudaGetSymbolAddress((void**)&hs0, g_hs0);
    cudaGetSymbolAddress((void**)&hs1, g_hs1);
    cudaGetSymbolAddress((void**)&wq0, g_wq0);
    cudaGetSymbolAddress((void**)&wq1, g_wq1);
    cudaGetSymbolAddress((void**)&wk0, g_wk0);
    cudaGetSymbolAddress((void**)&wk1, g_wk1);
    cudaGetSymbolAddress((void**)&wv0, g_wv0);
    cudaGetSymbolAddress((void**)&wv1, g_wv1);
    cudaGetSymbolAddress((void**)&wo0, g_wo0);
    cudaGetSymbolAddress((void**)&wo1, g_wo1);
    cudaGetSymbolAddress((void**)&ao0, g_ao0);
    cudaGetSymbolAddress((void**)&ao1, g_ao1);
    cudaGetSymbolAddress((void**)&q0, g_q0);
    cudaGetSymbolAddress((void**)&q1, g_q1);
    cudaGetSymbolAddress((void**)&k0, g_k0);
    cudaGetSymbolAddress((void**)&k1, g_k1);
    cudaGetSymbolAddress((void**)&v0, g_v0);
    cudaGetSymbolAddress((void**)&v1, g_v1);

    static bool attr_set = false;
    if (!attr_set) {
        cudaFuncSetAttribute(mma_gemm_qkv, cudaFuncAttributeMaxDynamicSharedMemorySize, MMA_SMEM);
        cudaFuncSetAttribute(mma_gemm_one, cudaFuncAttributeMaxDynamicSharedMemorySize, MMA_SMEM);
        cudaFuncSetAttribute(attn_mma, cudaFuncAttributeMaxDynamicSharedMemorySize, ATT_SMEM);
        attr_set = true;
    }

    const int NEL4 = NROWS * E_ / 4;

    counts_kernel<<<B_, S_>>>(attn_mask, cnts);

    split_kernel<<<1024, 256>>>(hs,  hs0, hs1, NEL4);
    split_kernel<<<1024, 256>>>(w_q, wq0, wq1, NEL4);
    split_kernel<<<1024, 256>>>(w_k, wk0, wk1, NEL4);
    split_kernel<<<1024, 256>>>(w_v, wv0, wv1, NEL4);
    split_kernel<<<1024, 256>>>(w_o, wo0, wo1, NEL4);

    mma_gemm_qkv<<<dim3(E_ / 128, NROWS / 128, 3), 256, MMA_SMEM>>>(
        hs0, hs1, wq0, wq1, wk0, wk1, wv0, wv1, tq, tk, tv);

    rope_norm_kernel<<<(B_ * S_ * H_) / 4, 128>>>(tq, tk, tv, attn_mask, norm_c,
                                                  pos_ids, cnts, q0, q1, k0, k1, v0, v1);

    attn_mma<<<dim3(S_ / AQM, B_ * H_), 256, ATT_SMEM>>>(q0, q1, k0, k1, v0, v1, ao0, ao1);

    mma_gemm_one<<<dim3(E_ / 128, NROWS / 128, 1), 256, MMA_SMEM>>>(ao0, ao1, wo0, wo1, out);
}

// round 6
// speedup vs baseline: 5.6185x; 1.0001x over previous
#include <cuda_runtime.h>
#include <cuda_bf16.h>
#include <math.h>
#include <stdint.h>

#define B_  2
#define S_  1024
#define E_  2048
#define H_  16
#define HD_ 128
#define ROT_ 64
#define NROWS (B_ * S_)
#define EPS_ 1e-12f

// ---------------- scratch ----------------------------------------------------
__device__ float g_counts[B_ * S_];

// bf16 split scratch (hi / lo)
__device__ __nv_bfloat16 g_hs0[NROWS * E_], g_hs1[NROWS * E_];
__device__ __nv_bfloat16 g_wq0[E_ * E_],   g_wq1[E_ * E_];
__device__ __nv_bfloat16 g_wk0[E_ * E_],   g_wk1[E_ * E_];
__device__ __nv_bfloat16 g_wv0[E_ * E_],   g_wv1[E_ * E_];
__device__ __nv_bfloat16 g_wo0[E_ * E_],   g_wo1[E_ * E_];
__device__ __nv_bfloat16 g_ao0[NROWS * E_], g_ao1[NROWS * E_];

// attention inputs, (b,h,s,d) bf16 hi/lo
__device__ __nv_bfloat16 g_q0[B_ * H_ * S_ * HD_], g_q1[B_ * H_ * S_ * HD_];
__device__ __nv_bfloat16 g_k0[B_ * H_ * S_ * HD_], g_k1[B_ * H_ * S_ * HD_];
__device__ __nv_bfloat16 g_v0[B_ * H_ * S_ * HD_], g_v1[B_ * H_ * S_ * HD_];

// ---------------- PTX helpers ------------------------------------------------
__device__ __forceinline__ uint32_t smem_u32(const void* p) {
    uint32_t a;
    asm("{ .reg .u64 t; cvta.to.shared.u64 t, %1; cvt.u32.u64 %0, t; }" : "=r"(a) : "l"(p));
    return a;
}
#define CP16(dst, src) asm volatile("cp.async.cg.shared.global [%0], [%1], 16;" :: "r"(dst), "l"(src) : "memory")
#define CP_COMMIT() asm volatile("cp.async.commit_group;" ::: "memory")

#define LDSM4(r0, r1, r2, r3, addr) \
    asm volatile("ldmatrix.sync.aligned.m8n8.x4.shared.b16 {%0,%1,%2,%3}, [%4];" \
        : "=r"(r0), "=r"(r1), "=r"(r2), "=r"(r3) : "r"(addr))

#define LDSM4T(r0, r1, r2, r3, addr) \
    asm volatile("ldmatrix.sync.aligned.m8n8.x4.trans.shared.b16 {%0,%1,%2,%3}, [%4];" \
        : "=r"(r0), "=r"(r1), "=r"(r2), "=r"(r3) : "r"(addr))

#define MMA16816(c, a, br0, br1) \
    asm volatile("mma.sync.aligned.m16n8k16.row.col.f32.bf16.bf16.f32 " \
        "{%0,%1,%2,%3}, {%4,%5,%6,%7}, {%8,%9}, {%0,%1,%2,%3};" \
        : "+f"((c)[0]), "+f"((c)[1]), "+f"((c)[2]), "+f"((c)[3]) \
        : "r"((a)[0]), "r"((a)[1]), "r"((a)[2]), "r"((a)[3]), "r"(br0), "r"(br1))

__device__ __forceinline__ void split2(float x, float y, uint32_t& hi, uint32_t& lo) {
    __nv_bfloat16 hx = __float2bfloat16(x), hy = __float2bfloat16(y);
    __nv_bfloat16 lx = __float2bfloat16(x - __bfloat162float(hx));
    __nv_bfloat16 ly = __float2bfloat16(y - __bfloat162float(hy));
    hi = (uint32_t)__bfloat16_as_ushort(hx) | ((uint32_t)__bfloat16_as_ushort(hy) << 16);
    lo = (uint32_t)__bfloat16_as_ushort(lx) | ((uint32_t)__bfloat16_as_ushort(ly) << 16);
}

// ---------------- fused split fp32 -> bf16 hi/lo (5 tensors, 1 launch) -------
__global__ __launch_bounds__(256) void split5_kernel(
    const float* __restrict__ x0, const float* __restrict__ x1,
    const float* __restrict__ x2, const float* __restrict__ x3,
    const float* __restrict__ x4,
    __nv_bfloat16* __restrict__ h0, __nv_bfloat16* __restrict__ l0,
    __nv_bfloat16* __restrict__ h1, __nv_bfloat16* __restrict__ l1,
    __nv_bfloat16* __restrict__ h2, __nv_bfloat16* __restrict__ l2,
    __nv_bfloat16* __restrict__ h3, __nv_bfloat16* __restrict__ l3,
    __nv_bfloat16* __restrict__ h4, __nv_bfloat16* __restrict__ l4) {
    int z = blockIdx.y;
    const float* x = (z == 0) ? x0 : (z == 1) ? x1 : (z == 2) ? x2 : (z == 3) ? x3 : x4;
    __nv_bfloat16* hi = (z == 0) ? h0 : (z == 1) ? h1 : (z == 2) ? h2 : (z == 3) ? h3 : h4;
    __nv_bfloat16* lo = (z == 0) ? l0 : (z == 1) ? l1 : (z == 2) ? l2 : (z == 3) ? l3 : l4;
    const int n4 = NROWS * E_ / 4;
    for (int i = blockIdx.x * blockDim.x + threadIdx.x; i < n4; i += gridDim.x * blockDim.x) {
        float4 v = ((const float4*)x)[i];
        float vv[4] = {v.x, v.y, v.z, v.w};
        unsigned short hs[4], ls[4];
#pragma unroll
        for (int j = 0; j < 4; j++) {
            __nv_bfloat16 h = __float2bfloat16(vv[j]);
            __nv_bfloat16 l = __float2bfloat16(vv[j] - __bfloat162float(h));
            hs[j] = __bfloat16_as_ushort(h);
            ls[j] = __bfloat16_as_ushort(l);
        }
        uint2 ph = {(uint32_t)hs[0] | ((uint32_t)hs[1] << 16),
                    (uint32_t)hs[2] | ((uint32_t)hs[3] << 16)};
        uint2 pl = {(uint32_t)ls[0] | ((uint32_t)ls[1] << 16),
                    (uint32_t)ls[2] | ((uint32_t)ls[3] << 16)};
        ((uint2*)hi)[i] = ph;
        ((uint2*)lo)[i] = pl;
    }
}

// ---------------- mma.sync bf16x3 GEMM mainloop ------------------------------
// CTA tile 128x128, 8 warps (2x4), warp tile 64x32, K-chunk 32, 3-stage pipe.
#define KCH 32
#define NCHK (E_ / KCH)
#define ROWB 80
#define MAT_B (128 * ROWB)
#define STG_B (4 * MAT_B)       // 40960
#define NSTG 3
#define MMA_SMEM (NSTG * STG_B) // 122880

__device__ __forceinline__ void mma_load_chunk(uint32_t base, int t, int tid,
                                               const __nv_bfloat16* a0, const __nv_bfloat16* a1,
                                               const __nv_bfloat16* b0, const __nv_bfloat16* b1) {
    for (int i = tid; i < 512; i += 256) {
        int r = i >> 2, c = i & 3;
        size_t g = (size_t)r * E_ + t * KCH + c * 8;
        uint32_t d = base + r * ROWB + c * 16;
        CP16(d,             a0 + g);
        CP16(d + MAT_B,     a1 + g);
        CP16(d + 2 * MAT_B, b0 + g);
        CP16(d + 3 * MAT_B, b1 + g);
    }
    CP_COMMIT();
}

__device__ __forceinline__ void mma_mainloop(uint32_t sb, int tid, int lane, int wid,
                                             const __nv_bfloat16* a0, const __nv_bfloat16* a1,
                                             const __nv_bfloat16* b0, const __nv_bfloat16* b1,
                                             float acc[4][4][4]) {
    int wm = wid >> 2;
    int wn = wid & 3;

    mma_load_chunk(sb, 0, tid, a0, a1, b0, b1);
    mma_load_chunk(sb + STG_B, 1, tid, a0, a1, b0, b1);

    int arow = lane & 15;
    int acolb = ((lane >> 4) & 1) * 16;
    int brow = (lane & 7) + ((lane >> 4) << 3);
    int bcolb = ((lane >> 3) & 1) * 16;

    for (int t = 0; t < NCHK; t++) {
        if (t + 1 < NCHK) asm volatile("cp.async.wait_group 1;" ::: "memory");
        else              asm volatile("cp.async.wait_group 0;" ::: "memory");
        __syncthreads();
        if (t + 2 < NCHK) {
            int ns = (t + 2) % NSTG;
            mma_load_chunk(sb + ns * STG_B, t + 2, tid, a0, a1, b0, b1);
        }

        uint32_t st = sb + (t % NSTG) * STG_B;
        uint32_t aA0 = st + (wm * 64 + arow) * ROWB + acolb;
        uint32_t aA1 = aA0 + MAT_B;
        uint32_t aB0 = st + 2 * MAT_B + (wn * 32 + brow) * ROWB + bcolb;
        uint32_t aB1 = aB0 + MAT_B;

#pragma unroll
        for (int ks = 0; ks < 2; ks++) {
            uint32_t a0f[4][4], a1f[4][4], b0f[2][4], b1f[2][4];
#pragma unroll
            for (int mt = 0; mt < 4; mt++) {
                uint32_t ad = aA0 + mt * 16 * ROWB + ks * 32;
                LDSM4(a0f[mt][0], a0f[mt][1], a0f[mt][2], a0f[mt][3], ad);
                uint32_t ad1 = aA1 + mt * 16 * ROWB + ks * 32;
                LDSM4(a1f[mt][0], a1f[mt][1], a1f[mt][2], a1f[mt][3], ad1);
            }
#pragma unroll
            for (int np = 0; np < 2; np++) {
                uint32_t bd = aB0 + np * 16 * ROWB + ks * 32;
                LDSM4(b0f[np][0], b0f[np][1], b0f[np][2], b0f[np][3], bd);
                uint32_t bd1 = aB1 + np * 16 * ROWB + ks * 32;
                LDSM4(b1f[np][0], b1f[np][1], b1f[np][2], b1f[np][3], bd1);
            }
#pragma unroll
            for (int mt = 0; mt < 4; mt++) {
#pragma unroll
                for (int nt = 0; nt < 4; nt++) {
                    uint32_t* p0 = &b0f[nt >> 1][(nt & 1) * 2];
                    uint32_t* p1 = &b1f[nt >> 1][(nt & 1) * 2];
                    MMA16816(acc[mt][nt], a0f[mt], p0[0], p0[1]);
                    MMA16816(acc[mt][nt], a0f[mt], p1[0], p1[1]);
                    MMA16816(acc[mt][nt], a1f[mt], p0[0], p0[1]);
                }
            }
        }
    }
    __syncthreads();
}

// ---------------- QKV GEMM with fused rope/norm/mask/scale/split epilogue ----
__global__ __launch_bounds__(256, 1) void mma_gemm_qkv_fused(
    const __nv_bfloat16* __restrict__ a0, const __nv_bfloat16* __restrict__ a1,
    const __nv_bfloat16* __restrict__ wq0, const __nv_bfloat16* __restrict__ wq1,
    const __nv_bfloat16* __restrict__ wk0, const __nv_bfloat16* __restrict__ wk1,
    const __nv_bfloat16* __restrict__ wv0, const __nv_bfloat16* __restrict__ wv1,
    const float* __restrict__ mask, const float* __restrict__ norm_const,
    const int* __restrict__ pos_ids, const float* __restrict__ counts,
    __nv_bfloat16* __restrict__ Qh, __nv_bfloat16* __restrict__ Ql,
    __nv_bfloat16* __restrict__ Kh, __nv_bfloat16* __restrict__ Kl,
    __nv_bfloat16* __restrict__ Vh, __nv_bfloat16* __restrict__ Vl) {
    extern __shared__ char smc[];
    uint32_t sb = smem_u32(smc);
    int tid = threadIdx.x;
    int lane = tid & 31;
    int wid = tid >> 5;
    int wm = wid >> 2;
    int wn = wid & 3;
    int z = blockIdx.z;
    int bm = blockIdx.y * 128;
    int bn = blockIdx.x * 128;

    const __nv_bfloat16* b0 = (z == 0) ? wq0 : (z == 1) ? wk0 : wv0;
    const __nv_bfloat16* b1 = (z == 0) ? wq1 : (z == 1) ? wk1 : wv1;

    float acc[4][4][4];
#pragma unroll
    for (int i = 0; i < 4; i++)
#pragma unroll
        for (int j = 0; j < 4; j++)
#pragma unroll
            for (int k = 0; k < 4; k++) acc[i][j][k] = 0.0f;

    mma_mainloop(sb, tid, lane, wid,
                 a0 + (size_t)bm * E_, a1 + (size_t)bm * E_,
                 b0 + (size_t)bn * E_, b1 + (size_t)bn * E_, acc);

    // ---- fused epilogue ----
    float* rs = (float*)smc;     // [128 rows][4 wn] partial sumsq
    int lr = lane >> 2;          // 0..7
    int lc = lane & 3;
    int col0 = wn * 32 + lc * 2;

    if (z < 2) {
        // RoPE on cols < ROT (wn 0,1 only; warp-uniform branch)
        if (wn < 2) {
#pragma unroll
            for (int mt = 0; mt < 4; mt++) {
                int rg = bm + wm * 64 + mt * 16 + lr;
                float pos0 = (float)pos_ids[rg];
                float pos1 = (float)pos_ids[rg + 8];
#pragma unroll
                for (int nt = 0; nt < 4; nt++) {
                    float fi = (float)(wn * 16 + nt * 4 + lc);
                    float fr = __expf(-0.28782313662425575f * fi);  // ln(1e4)/32
                    float s0, c0, s1, c1;
                    sincosf(pos0 * fr, &s0, &c0);
                    sincosf(pos1 * fr, &s1, &c1);
                    float x = acc[mt][nt][0], y = acc[mt][nt][1];
                    acc[mt][nt][0] = x * c0 - y * s0;
                    acc[mt][nt][1] = y * c0 + x * s0;
                    x = acc[mt][nt][2]; y = acc[mt][nt][3];
                    acc[mt][nt][2] = x * c1 - y * s1;
                    acc[mt][nt][3] = y * c1 + x * s1;
                }
            }
        }
        // per-row sum of squares (post-rope), quad shfl then smem across wn
#pragma unroll
        for (int mt = 0; mt < 4; mt++) {
            float s0 = 0.0f, s1 = 0.0f;
#pragma unroll
            for (int nt = 0; nt < 4; nt++) {
                s0 += acc[mt][nt][0] * acc[mt][nt][0] + acc[mt][nt][1] * acc[mt][nt][1];
                s1 += acc[mt][nt][2] * acc[mt][nt][2] + acc[mt][nt][3] * acc[mt][nt][3];
            }
            s0 += __shfl_xor_sync(0xffffffffu, s0, 1);
            s0 += __shfl_xor_sync(0xffffffffu, s0, 2);
            s1 += __shfl_xor_sync(0xffffffffu, s1, 1);
            s1 += __shfl_xor_sync(0xffffffffu, s1, 2);
            if (lc == 0) {
                rs[(wm * 64 + mt * 16 + lr) * 4 + wn] = s0;
                rs[(wm * 64 + mt * 16 + lr + 8) * 4 + wn] = s1;
            }
        }
    }
    __syncthreads();

    int h = bn >> 7;   // N-tile of 128 == one head
    float sig = 1.0f / (1.0f + __expf(-norm_const[h]));
    __nv_bfloat16* OH = (z == 0) ? Qh : (z == 1) ? Kh : Vh;
    __nv_bfloat16* OL = (z == 0) ? Ql : (z == 1) ? Kl : Vl;

#pragma unroll
    for (int mt = 0; mt < 4; mt++) {
#pragma unroll
        for (int half = 0; half < 2; half++) {
            int rl = wm * 64 + mt * 16 + lr + half * 8;
            int rg = bm + rl;
            float m = (mask[rg] == 0.0f) ? 1.0f : 0.0f;
            float scl;
            if (z < 2) {
                float tot = rs[rl * 4] + rs[rl * 4 + 1] + rs[rl * 4 + 2] + rs[rl * 4 + 3];
                scl = m / fmaxf(sqrtf(tot), EPS_);
            } else {
                scl = m / fmaxf(powf(counts[rg], sig), 1.0f);
            }
            int b = rg >> 10;
            int s = rg & 1023;
            size_t dst = (((size_t)(b * H_ + h)) * S_ + s) * (size_t)HD_;
#pragma unroll
            for (int nt = 0; nt < 4; nt++) {
                int c = col0 + nt * 8;
                uint32_t hi, lo;
                split2(acc[mt][nt][2 * half] * scl, acc[mt][nt][2 * half + 1] * scl, hi, lo);
                *(uint32_t*)(OH + dst + c) = hi;
                *(uint32_t*)(OL + dst + c) = lo;
            }
        }
    }
}

// ---------------- output projection GEMM (fp32 epilogue) ---------------------
__global__ __launch_bounds__(256, 1) void mma_gemm_out(
    const __nv_bfloat16* __restrict__ a0, const __nv_bfloat16* __restrict__ a1,
    const __nv_bfloat16* __restrict__ b0, const __nv_bfloat16* __restrict__ b1,
    float* __restrict__ C) {
    extern __shared__ char smc[];
    uint32_t sb = smem_u32(smc);
    int tid = threadIdx.x;
    int lane = tid & 31;
    int wid = tid >> 5;
    int wm = wid >> 2;
    int wn = wid & 3;
    int bm = blockIdx.y * 128;
    int bn = blockIdx.x * 128;

    float acc[4][4][4];
#pragma unroll
    for (int i = 0; i < 4; i++)
#pragma unroll
        for (int j = 0; j < 4; j++)
#pragma unroll
            for (int k = 0; k < 4; k++) acc[i][j][k] = 0.0f;

    mma_mainloop(sb, tid, lane, wid,
                 a0 + (size_t)bm * E_, a1 + (size_t)bm * E_,
                 b0 + (size_t)bn * E_, b1 + (size_t)bn * E_, acc);

    int row0 = bm + wm * 64 + (lane >> 2);
    int col0 = bn + wn * 32 + (lane & 3) * 2;
#pragma unroll
    for (int mt = 0; mt < 4; mt++) {
#pragma unroll
        for (int nt = 0; nt < 4; nt++) {
            int r = row0 + mt * 16;
            int c = col0 + nt * 8;
            float2 v0 = {acc[mt][nt][0], acc[mt][nt][1]};
            float2 v1 = {acc[mt][nt][2], acc[mt][nt][3]};
            *(float2*)&C[(size_t)r * E_ + c] = v0;
            *(float2*)&C[(size_t)(r + 8) * E_ + c] = v1;
        }
    }
}

// ---------------- mask prefix scan ------------------------------------------
__global__ void counts_kernel(const float* __restrict__ mask, float* __restrict__ counts) {
    __shared__ float sh[S_];
    int b = blockIdx.x;
    int t = threadIdx.x;
    sh[t] = (mask[b * S_ + t] == 0.0f) ? 1.0f : 0.0f;
    __syncthreads();
    for (int off = 1; off < S_; off <<= 1) {
        float add = (t >= off) ? sh[t - off] : 0.0f;
        __syncthreads();
        sh[t] += add;
        __syncthreads();
    }
    counts[b * S_ + t] = sh[t];
}

// ---------------- causal no-softmax attention via mma.sync -------------------
#define AQM 128
#define AKC 64
#define RB 272
#define QMAT (128 * RB)
#define KVMAT (64 * RB)
#define KVSTG (4 * KVMAT)
#define ATT_SMEM (2 * QMAT + 2 * KVSTG)

__global__ __launch_bounds__(256, 1) void attn_mma(
    const __nv_bfloat16* __restrict__ qh, const __nv_bfloat16* __restrict__ ql,
    const __nv_bfloat16* __restrict__ kh, const __nv_bfloat16* __restrict__ kl,
    const __nv_bfloat16* __restrict__ vh, const __nv_bfloat16* __restrict__ vl,
    __nv_bfloat16* __restrict__ aoh, __nv_bfloat16* __restrict__ aol) {
    extern __shared__ char smc[];
    uint32_t sb = smem_u32(smc);
    uint32_t sQh = sb, sQl = sb + QMAT;
    uint32_t sKV = sb + 2 * QMAT;

    int tid = threadIdx.x;
    int lane = tid & 31;
    int wid = tid >> 5;
    int bh = blockIdx.y;
    int qt = (int)gridDim.x - 1 - (int)blockIdx.x;
    int q0 = qt * AQM;

    size_t base = (size_t)bh * S_ * HD_;
    const __nv_bfloat16* Qhb = qh + base;
    const __nv_bfloat16* Qlb = ql + base;
    const __nv_bfloat16* Khb = kh + base;
    const __nv_bfloat16* Klb = kl + base;
    const __nv_bfloat16* Vhb = vh + base;
    const __nv_bfloat16* Vlb = vl + base;

    for (int i = tid; i < 2048; i += 256) {
        int r = i >> 4, c = i & 15;
        size_t g = (size_t)(q0 + r) * HD_ + c * 8;
        CP16(sQh + r * RB + c * 16, Qhb + g);
        CP16(sQl + r * RB + c * 16, Qlb + g);
    }
    for (int i = tid; i < 1024; i += 256) {
        int r = i >> 4, c = i & 15;
        size_t g = (size_t)r * HD_ + c * 8;
        uint32_t d = sKV + r * RB + c * 16;
        CP16(d, Khb + g);
        CP16(d + KVMAT, Klb + g);
        CP16(d + 2 * KVMAT, Vhb + g);
        CP16(d + 3 * KVMAT, Vlb + g);
    }
    CP_COMMIT();

    int nch = q0 / AKC + 2;
    float o[16][4];
#pragma unroll
    for (int i = 0; i < 16; i++)
#pragma unroll
        for (int j = 0; j < 4; j++) o[i][j] = 0.0f;

    int arow = lane & 15;
    int acolb = ((lane >> 4) & 1) * 16;
    int brow = (lane & 7) + ((lane >> 4) << 3);
    int bcolb = ((lane >> 3) & 1) * 16;
    int vrow = (lane & 7) + (((lane >> 3) & 1) << 3);
    int vcolb = ((lane >> 4) & 1) * 16;
    int m0w = q0 + wid * 16;

    for (int t = 0; t < nch; t++) {
        asm volatile("cp.async.wait_group 0;" ::: "memory");
        __syncthreads();
        if (t + 1 < nch) {
            uint32_t nstg = sKV + ((t + 1) & 1) * KVSTG;
            int kc = (t + 1) * AKC;
            for (int i = tid; i < 1024; i += 256) {
                int r = i >> 4, c = i & 15;
                size_t g = (size_t)(kc + r) * HD_ + c * 8;
                uint32_t d = nstg + r * RB + c * 16;
                CP16(d, Khb + g);
                CP16(d + KVMAT, Klb + g);
                CP16(d + 2 * KVMAT, Vhb + g);
                CP16(d + 3 * KVMAT, Vlb + g);
            }
            CP_COMMIT();
        }
        uint32_t stg = sKV + (t & 1) * KVSTG;

        float sacc[8][4];
#pragma unroll
        for (int i = 0; i < 8; i++)
#pragma unroll
            for (int j = 0; j < 4; j++) sacc[i][j] = 0.0f;

#pragma unroll
        for (int ds = 0; ds < 8; ds++) {
            uint32_t ah[4], al[4];
            uint32_t ad = sQh + (wid * 16 + arow) * RB + acolb + ds * 32;
            LDSM4(ah[0], ah[1], ah[2], ah[3], ad);
            LDSM4(al[0], al[1], al[2], al[3], ad + QMAT);
            uint32_t bhf[4][4], blf[4][4];
#pragma unroll
            for (int ng = 0; ng < 4; ng++) {
                uint32_t bd = stg + (ng * 16 + brow) * RB + bcolb + ds * 32;
                LDSM4(bhf[ng][0], bhf[ng][1], bhf[ng][2], bhf[ng][3], bd);
                LDSM4(blf[ng][0], blf[ng][1], blf[ng][2], blf[ng][3], bd + KVMAT);
            }
#pragma unroll
            for (int nt = 0; nt < 8; nt++) {
                uint32_t* ph = &bhf[nt >> 1][(nt & 1) * 2];
                uint32_t* pl = &blf[nt >> 1][(nt & 1) * 2];
                MMA16816(sacc[nt], ah, ph[0], ph[1]);
                MMA16816(sacc[nt], ah, pl[0], pl[1]);
                MMA16816(sacc[nt], al, ph[0], ph[1]);
            }
        }

        int kcg = t * AKC;
        if (kcg + AKC - 1 > m0w) {
            int r0m = m0w + (lane >> 2);
            int r1m = r0m + 8;
#pragma unroll
            for (int nt = 0; nt < 8; nt++) {
                int cb = kcg + nt * 8 + (lane & 3) * 2;
                if (cb > r0m) sacc[nt][0] = 0.0f;
                if (cb + 1 > r0m) sacc[nt][1] = 0.0f;
                if (cb > r1m) sacc[nt][2] = 0.0f;
                if (cb + 1 > r1m) sacc[nt][3] = 0.0f;
            }
        }

#pragma unroll
        for (int ks = 0; ks < 4; ks++) {
            uint32_t ah[4], al[4];
            split2(sacc[2 * ks][0], sacc[2 * ks][1], ah[0], al[0]);
            split2(sacc[2 * ks][2], sacc[2 * ks][3], ah[1], al[1]);
            split2(sacc[2 * ks + 1][0], sacc[2 * ks + 1][1], ah[2], al[2]);
            split2(sacc[2 * ks + 1][2], sacc[2 * ks + 1][3], ah[3], al[3]);
#pragma unroll
            for (int ng = 0; ng < 8; ng++) {
                uint32_t bh4[4], bl4[4];
                uint32_t va = stg + 2 * KVMAT + (ks * 16 + vrow) * RB + vcolb + ng * 32;
                LDSM4T(bh4[0], bh4[1], bh4[2], bh4[3], va);
                LDSM4T(bl4[0], bl4[1], bl4[2], bl4[3], va + KVMAT);
                MMA16816(o[2 * ng], ah, bh4[0], bh4[1]);
                MMA16816(o[2 * ng], ah, bl4[0], bl4[1]);
                MMA16816(o[2 * ng], al, bh4[0], bh4[1]);
                MMA16816(o[2 * ng + 1], ah, bh4[2], bh4[3]);
                MMA16816(o[2 * ng + 1], ah, bl4[2], bl4[3]);
                MMA16816(o[2 * ng + 1], al, bh4[2], bh4[3]);
            }
        }
    }

    int b = bh / H_;
    int h = bh % H_;
    int r0 = m0w + (lane >> 2);
#pragma unroll
    for (int nt = 0; nt < 16; nt++) {
        int col = nt * 8 + (lane & 3) * 2;
        size_t g0 = ((size_t)(b * S_ + r0)) * E_ + h * HD_ + col;
        size_t g1 = ((size_t)(b * S_ + r0 + 8)) * E_ + h * HD_ + col;
        uint32_t hi0, lo0, hi1, lo1;
        split2(o[nt][0], o[nt][1], hi0, lo0);
        split2(o[nt][2], o[nt][3], hi1, lo1);
        *(uint32_t*)(aoh + g0) = hi0;
        *(uint32_t*)(aol + g0) = lo0;
        *(uint32_t*)(aoh + g1) = hi1;
        *(uint32_t*)(aol + g1) = lo1;
    }
}

// ---------------- launcher ---------------------------------------------------
extern "C" void kernel_launch(void* const* d_in, const int* in_sizes, int n_in,
                              void* d_out, int out_size) {
    const float* hs        = (const float*)d_in[0];
    const float* w_q       = (const float*)d_in[1];
    const float* w_k       = (const float*)d_in[2];
    const float* w_v       = (const float*)d_in[3];
    const float* w_o       = (const float*)d_in[4];
    const float* norm_c    = (const float*)d_in[5];
    const float* attn_mask = (const float*)d_in[6];
    const int*   pos_ids   = (const int*)d_in[7];
    float* out = (float*)d_out;

    float* cnts;
    cudaGetSymbolAddress((void**)&cnts, g_counts);

    __nv_bfloat16 *hs0, *hs1, *wq0, *wq1, *wk0, *wk1, *wv0, *wv1, *wo0, *wo1, *ao0, *ao1;
    __nv_bfloat16 *q0, *q1, *k0, *k1, *v0, *v1;
    cudaGetSymbolAddress((void**)&hs0, g_hs0);
    cudaGetSymbolAddress((void**)&hs1, g_hs1);
    cudaGetSymbolAddress((void**)&wq0, g_wq0);
    cudaGetSymbolAddress((void**)&wq1, g_wq1);
    cudaGetSymbolAddress((void**)&wk0, g_wk0);
    cudaGetSymbolAddress((void**)&wk1, g_wk1);
    cudaGetSymbolAddress((void**)&wv0, g_wv0);
    cudaGetSymbolAddress((void**)&wv1, g_wv1);
    cudaGetSymbolAddress((void**)&wo0, g_wo0);
    cudaGetSymbolAddress((void**)&wo1, g_wo1);
    cudaGetSymbolAddress((void**)&ao0, g_ao0);
    cudaGetSymbolAddress((void**)&ao1, g_ao1);
    cudaGetSymbolAddress((void**)&q0, g_q0);
    cudaGetSymbolAddress((void**)&q1, g_q1);
    cudaGetSymbolAddress((void**)&k0, g_k0);
    cudaGetSymbolAddress((void**)&k1, g_k1);
    cudaGetSymbolAddress((void**)&v0, g_v0);
    cudaGetSymbolAddress((void**)&v1, g_v1);

    static bool attr_set = false;
    if (!attr_set) {
        cudaFuncSetAttribute(mma_gemm_qkv_fused, cudaFuncAttributeMaxDynamicSharedMemorySize, MMA_SMEM);
        cudaFuncSetAttribute(mma_gemm_out, cudaFuncAttributeMaxDynamicSharedMemorySize, MMA_SMEM);
        cudaFuncSetAttribute(attn_mma, cudaFuncAttributeMaxDynamicSharedMemorySize, ATT_SMEM);
        attr_set = true;
    }

    counts_kernel<<<B_, S_>>>(attn_mask, cnts);

    split5_kernel<<<dim3(256, 5), 256>>>(hs, w_q, w_k, w_v, w_o,
                                         hs0, hs1, wq0, wq1, wk0, wk1,
                                         wv0, wv1, wo0, wo1);

    mma_gemm_qkv_fused<<<dim3(E_ / 128, NROWS / 128, 3), 256, MMA_SMEM>>>(
        hs0, hs1, wq0, wq1, wk0, wk1, wv0, wv1,
        attn_mask, norm_c, pos_ids, cnts,
        q0, q1, k0, k1, v0, v1);

    attn_mma<<<dim3(S_ / AQM, B_ * H_), 256, ATT_SMEM>>>(q0, q1, k0, k1, v0, v1, ao0, ao1);

    mma_gemm_out<<<dim3(E_ / 128, NROWS / 128), 256, MMA_SMEM>>>(ao0, ao1, wo0, wo1, out);
}

// round 7
// speedup vs baseline: 6.7722x; 1.2053x over previous
#include <cuda_runtime.h>
#include <cuda_bf16.h>
#include <math.h>
#include <stdint.h>

#define B_  2
#define S_  1024
#define E_  2048
#define H_  16
#define HD_ 128
#define ROT_ 64
#define NROWS (B_ * S_)
#define EPS_ 1e-12f

// ---------------- scratch ----------------------------------------------------
__device__ float g_counts[B_ * S_];

__device__ __nv_bfloat16 g_hs0[NROWS * E_], g_hs1[NROWS * E_];
__device__ __nv_bfloat16 g_wq0[E_ * E_],   g_wq1[E_ * E_];
__device__ __nv_bfloat16 g_wk0[E_ * E_],   g_wk1[E_ * E_];
__device__ __nv_bfloat16 g_wv0[E_ * E_],   g_wv1[E_ * E_];
__device__ __nv_bfloat16 g_wo0[E_ * E_],   g_wo1[E_ * E_];
__device__ __nv_bfloat16 g_ao0[NROWS * E_], g_ao1[NROWS * E_];

__device__ __nv_bfloat16 g_q0[B_ * H_ * S_ * HD_], g_q1[B_ * H_ * S_ * HD_];
__device__ __nv_bfloat16 g_k0[B_ * H_ * S_ * HD_], g_k1[B_ * H_ * S_ * HD_];
__device__ __nv_bfloat16 g_v0[B_ * H_ * S_ * HD_], g_v1[B_ * H_ * S_ * HD_];

// ---------------- PTX helpers ------------------------------------------------
__device__ __forceinline__ uint32_t smem_u32(const void* p) {
    uint32_t a;
    asm("{ .reg .u64 t; cvta.to.shared.u64 t, %1; cvt.u32.u64 %0, t; }" : "=r"(a) : "l"(p));
    return a;
}
#define CP16(dst, src) asm volatile("cp.async.cg.shared.global [%0], [%1], 16;" :: "r"(dst), "l"(src) : "memory")
#define CP_COMMIT() asm volatile("cp.async.commit_group;" ::: "memory")

#define LDSM4(r0, r1, r2, r3, addr) \
    asm volatile("ldmatrix.sync.aligned.m8n8.x4.shared.b16 {%0,%1,%2,%3}, [%4];" \
        : "=r"(r0), "=r"(r1), "=r"(r2), "=r"(r3) : "r"(addr))

#define LDSM4T(r0, r1, r2, r3, addr) \
    asm volatile("ldmatrix.sync.aligned.m8n8.x4.trans.shared.b16 {%0,%1,%2,%3}, [%4];" \
        : "=r"(r0), "=r"(r1), "=r"(r2), "=r"(r3) : "r"(addr))

#define MMA16816(c, a, br0, br1) \
    asm volatile("mma.sync.aligned.m16n8k16.row.col.f32.bf16.bf16.f32 " \
        "{%0,%1,%2,%3}, {%4,%5,%6,%7}, {%8,%9}, {%0,%1,%2,%3};" \
        : "+f"((c)[0]), "+f"((c)[1]), "+f"((c)[2]), "+f"((c)[3]) \
        : "r"((a)[0]), "r"((a)[1]), "r"((a)[2]), "r"((a)[3]), "r"(br0), "r"(br1))

__device__ __forceinline__ void split2(float x, float y, uint32_t& hi, uint32_t& lo) {
    __nv_bfloat16 hx = __float2bfloat16(x), hy = __float2bfloat16(y);
    __nv_bfloat16 lx = __float2bfloat16(x - __bfloat162float(hx));
    __nv_bfloat16 ly = __float2bfloat16(y - __bfloat162float(hy));
    hi = (uint32_t)__bfloat16_as_ushort(hx) | ((uint32_t)__bfloat16_as_ushort(hy) << 16);
    lo = (uint32_t)__bfloat16_as_ushort(lx) | ((uint32_t)__bfloat16_as_ushort(ly) << 16);
}

// ---------------- fused split fp32 -> bf16 hi/lo (5 tensors) -----------------
__global__ __launch_bounds__(256) void split5_kernel(
    const float* __restrict__ x0, const float* __restrict__ x1,
    const float* __restrict__ x2, const float* __restrict__ x3,
    const float* __restrict__ x4,
    __nv_bfloat16* __restrict__ h0, __nv_bfloat16* __restrict__ l0,
    __nv_bfloat16* __restrict__ h1, __nv_bfloat16* __restrict__ l1,
    __nv_bfloat16* __restrict__ h2, __nv_bfloat16* __restrict__ l2,
    __nv_bfloat16* __restrict__ h3, __nv_bfloat16* __restrict__ l3,
    __nv_bfloat16* __restrict__ h4, __nv_bfloat16* __restrict__ l4) {
    int z = blockIdx.y;
    const float* x = (z == 0) ? x0 : (z == 1) ? x1 : (z == 2) ? x2 : (z == 3) ? x3 : x4;
    __nv_bfloat16* hi = (z == 0) ? h0 : (z == 1) ? h1 : (z == 2) ? h2 : (z == 3) ? h3 : h4;
    __nv_bfloat16* lo = (z == 0) ? l0 : (z == 1) ? l1 : (z == 2) ? l2 : (z == 3) ? l3 : l4;
    const int n4 = NROWS * E_ / 4;
    for (int i = blockIdx.x * blockDim.x + threadIdx.x; i < n4; i += gridDim.x * blockDim.x) {
        float4 v = ((const float4*)x)[i];
        float vv[4] = {v.x, v.y, v.z, v.w};
        unsigned short hs[4], ls[4];
#pragma unroll
        for (int j = 0; j < 4; j++) {
            __nv_bfloat16 h = __float2bfloat16(vv[j]);
            __nv_bfloat16 l = __float2bfloat16(vv[j] - __bfloat162float(h));
            hs[j] = __bfloat16_as_ushort(h);
            ls[j] = __bfloat16_as_ushort(l);
        }
        uint2 ph = {(uint32_t)hs[0] | ((uint32_t)hs[1] << 16),
                    (uint32_t)hs[2] | ((uint32_t)hs[3] << 16)};
        uint2 pl = {(uint32_t)ls[0] | ((uint32_t)ls[1] << 16),
                    (uint32_t)ls[2] | ((uint32_t)ls[3] << 16)};
        ((uint2*)hi)[i] = ph;
        ((uint2*)lo)[i] = pl;
    }
}

// ============== QKV GEMM 64x128 tiles, fused epilogue ========================
// 8 warps: wm(2) x wn(4), warp tile 32x32. K-chunk 32, 3-stage cp.async.
#define KCH 32
#define NCHK (E_ / KCH)
#define ROWB 80
#define QAMAT (64 * ROWB)     // 5120
#define QBMAT (128 * ROWB)    // 10240
#define QSTG (2 * QAMAT + 2 * QBMAT)   // 30720
#define QKV_SMEM (3 * QSTG)   // 92160

__device__ __forceinline__ void qkv_load_chunk(uint32_t base, int t, int tid,
                                               const __nv_bfloat16* a0, const __nv_bfloat16* a1,
                                               const __nv_bfloat16* b0, const __nv_bfloat16* b1) {
    {
        int r = tid >> 2, c = tid & 3;               // 64 rows x 4
        size_t g = (size_t)r * E_ + t * KCH + c * 8;
        uint32_t d = base + r * ROWB + c * 16;
        CP16(d, a0 + g);
        CP16(d + QAMAT, a1 + g);
    }
    for (int i = tid; i < 512; i += 256) {
        int r = i >> 2, c = i & 3;                   // 128 rows x 4
        size_t g = (size_t)r * E_ + t * KCH + c * 8;
        uint32_t d = base + 2 * QAMAT + r * ROWB + c * 16;
        CP16(d, b0 + g);
        CP16(d + QBMAT, b1 + g);
    }
    CP_COMMIT();
}

__global__ __launch_bounds__(256, 1) void mma_gemm_qkv_fused(
    const __nv_bfloat16* __restrict__ ha0, const __nv_bfloat16* __restrict__ ha1,
    const __nv_bfloat16* __restrict__ wq0, const __nv_bfloat16* __restrict__ wq1,
    const __nv_bfloat16* __restrict__ wk0, const __nv_bfloat16* __restrict__ wk1,
    const __nv_bfloat16* __restrict__ wv0, const __nv_bfloat16* __restrict__ wv1,
    const float* __restrict__ mask, const float* __restrict__ norm_const,
    const int* __restrict__ pos_ids, const float* __restrict__ counts,
    __nv_bfloat16* __restrict__ Qh, __nv_bfloat16* __restrict__ Ql,
    __nv_bfloat16* __restrict__ Kh, __nv_bfloat16* __restrict__ Kl,
    __nv_bfloat16* __restrict__ Vh, __nv_bfloat16* __restrict__ Vl) {
    extern __shared__ char smc[];
    uint32_t sb = smem_u32(smc);
    int tid = threadIdx.x;
    int lane = tid & 31;
    int wid = tid >> 5;
    int wm = wid >> 2;           // 0..1 (32 rows)
    int wn = wid & 3;            // 0..3 (32 cols)
    int z = blockIdx.z;
    int bm = blockIdx.y * 64;
    int bn = blockIdx.x * 128;

    const __nv_bfloat16* a0 = ha0 + (size_t)bm * E_;
    const __nv_bfloat16* a1 = ha1 + (size_t)bm * E_;
    const __nv_bfloat16* b0 = ((z == 0) ? wq0 : (z == 1) ? wk0 : wv0) + (size_t)bn * E_;
    const __nv_bfloat16* b1 = ((z == 0) ? wq1 : (z == 1) ? wk1 : wv1) + (size_t)bn * E_;

    float acc[2][4][4];
#pragma unroll
    for (int i = 0; i < 2; i++)
#pragma unroll
        for (int j = 0; j < 4; j++)
#pragma unroll
            for (int k = 0; k < 4; k++) acc[i][j][k] = 0.0f;

    qkv_load_chunk(sb, 0, tid, a0, a1, b0, b1);
    qkv_load_chunk(sb + QSTG, 1, tid, a0, a1, b0, b1);

    int arow = lane & 15;
    int acolb = ((lane >> 4) & 1) * 16;
    int brow = (lane & 7) + ((lane >> 4) << 3);
    int bcolb = ((lane >> 3) & 1) * 16;

    for (int t = 0; t < NCHK; t++) {
        if (t + 1 < NCHK) asm volatile("cp.async.wait_group 1;" ::: "memory");
        else              asm volatile("cp.async.wait_group 0;" ::: "memory");
        __syncthreads();
        if (t + 2 < NCHK) qkv_load_chunk(sb + ((t + 2) % 3) * QSTG, t + 2, tid, a0, a1, b0, b1);

        uint32_t st = sb + (t % 3) * QSTG;
        uint32_t aA0 = st + (wm * 32 + arow) * ROWB + acolb;
        uint32_t aA1 = aA0 + QAMAT;
        uint32_t aB0 = st + 2 * QAMAT + (wn * 32 + brow) * ROWB + bcolb;
        uint32_t aB1 = aB0 + QBMAT;

#pragma unroll
        for (int ks = 0; ks < 2; ks++) {
            uint32_t a0f[2][4], a1f[2][4], b0f[2][4], b1f[2][4];
#pragma unroll
            for (int mt = 0; mt < 2; mt++) {
                LDSM4(a0f[mt][0], a0f[mt][1], a0f[mt][2], a0f[mt][3], aA0 + mt * 16 * ROWB + ks * 32);
                LDSM4(a1f[mt][0], a1f[mt][1], a1f[mt][2], a1f[mt][3], aA1 + mt * 16 * ROWB + ks * 32);
            }
#pragma unroll
            for (int np = 0; np < 2; np++) {
                LDSM4(b0f[np][0], b0f[np][1], b0f[np][2], b0f[np][3], aB0 + np * 16 * ROWB + ks * 32);
                LDSM4(b1f[np][0], b1f[np][1], b1f[np][2], b1f[np][3], aB1 + np * 16 * ROWB + ks * 32);
            }
#pragma unroll
            for (int mt = 0; mt < 2; mt++) {
#pragma unroll
                for (int nt = 0; nt < 4; nt++) {
                    uint32_t* p0 = &b0f[nt >> 1][(nt & 1) * 2];
                    uint32_t* p1 = &b1f[nt >> 1][(nt & 1) * 2];
                    MMA16816(acc[mt][nt], a0f[mt], p0[0], p0[1]);
                    MMA16816(acc[mt][nt], a0f[mt], p1[0], p1[1]);
                    MMA16816(acc[mt][nt], a1f[mt], p0[0], p0[1]);
                }
            }
        }
    }
    __syncthreads();

    // ---- fused epilogue: rope (cols<64) + L2 norm / count-scale + mask + split
    float* rs = (float*)smc;     // [64 rows][4 wn]
    int lr = lane >> 2;
    int lc = lane & 3;
    int col0 = wn * 32 + lc * 2;

    if (z < 2) {
        if (wn < 2) {
#pragma unroll
            for (int mt = 0; mt < 2; mt++) {
                int rg = bm + wm * 32 + mt * 16 + lr;
                float pos0 = (float)pos_ids[rg];
                float pos1 = (float)pos_ids[rg + 8];
#pragma unroll
                for (int nt = 0; nt < 4; nt++) {
                    float fi = (float)(wn * 16 + nt * 4 + lc);
                    float fr = __expf(-0.28782313662425575f * fi);
                    float s0, c0, s1, c1;
                    sincosf(pos0 * fr, &s0, &c0);
                    sincosf(pos1 * fr, &s1, &c1);
                    float x = acc[mt][nt][0], y = acc[mt][nt][1];
                    acc[mt][nt][0] = x * c0 - y * s0;
                    acc[mt][nt][1] = y * c0 + x * s0;
                    x = acc[mt][nt][2]; y = acc[mt][nt][3];
                    acc[mt][nt][2] = x * c1 - y * s1;
                    acc[mt][nt][3] = y * c1 + x * s1;
                }
            }
        }
#pragma unroll
        for (int mt = 0; mt < 2; mt++) {
            float s0 = 0.0f, s1 = 0.0f;
#pragma unroll
            for (int nt = 0; nt < 4; nt++) {
                s0 += acc[mt][nt][0] * acc[mt][nt][0] + acc[mt][nt][1] * acc[mt][nt][1];
                s1 += acc[mt][nt][2] * acc[mt][nt][2] + acc[mt][nt][3] * acc[mt][nt][3];
            }
            s0 += __shfl_xor_sync(0xffffffffu, s0, 1);
            s0 += __shfl_xor_sync(0xffffffffu, s0, 2);
            s1 += __shfl_xor_sync(0xffffffffu, s1, 1);
            s1 += __shfl_xor_sync(0xffffffffu, s1, 2);
            if (lc == 0) {
                rs[(wm * 32 + mt * 16 + lr) * 4 + wn] = s0;
                rs[(wm * 32 + mt * 16 + lr + 8) * 4 + wn] = s1;
            }
        }
    }
    __syncthreads();

    int h = bn >> 7;
    float sig = 1.0f / (1.0f + __expf(-norm_const[h]));
    __nv_bfloat16* OH = (z == 0) ? Qh : (z == 1) ? Kh : Vh;
    __nv_bfloat16* OL = (z == 0) ? Ql : (z == 1) ? Kl : Vl;

#pragma unroll
    for (int mt = 0; mt < 2; mt++) {
#pragma unroll
        for (int half = 0; half < 2; half++) {
            int rl = wm * 32 + mt * 16 + lr + half * 8;
            int rg = bm + rl;
            float m = (mask[rg] == 0.0f) ? 1.0f : 0.0f;
            float scl;
            if (z < 2) {
                float tot = rs[rl * 4] + rs[rl * 4 + 1] + rs[rl * 4 + 2] + rs[rl * 4 + 3];
                scl = m / fmaxf(sqrtf(tot), EPS_);
            } else {
                scl = m / fmaxf(powf(counts[rg], sig), 1.0f);
            }
            int b = rg >> 10;
            int s = rg & 1023;
            size_t dst = (((size_t)(b * H_ + h)) * S_ + s) * (size_t)HD_;
#pragma unroll
            for (int nt = 0; nt < 4; nt++) {
                int c = col0 + nt * 8;
                uint32_t hi, lo;
                split2(acc[mt][nt][2 * half] * scl, acc[mt][nt][2 * half + 1] * scl, hi, lo);
                *(uint32_t*)(OH + dst + c) = hi;
                *(uint32_t*)(OL + dst + c) = lo;
            }
        }
    }
}

// ============== Output projection GEMM 64x64 tiles ===========================
// 8 warps: wm(2) x wn(4), warp tile 32x16.
#define OMAT (64 * ROWB)       // 5120
#define OSTG (4 * OMAT)        // 20480
#define OUT_SMEM (3 * OSTG)    // 61440

__device__ __forceinline__ void out_load_chunk(uint32_t base, int t, int tid,
                                               const __nv_bfloat16* a0, const __nv_bfloat16* a1,
                                               const __nv_bfloat16* b0, const __nv_bfloat16* b1) {
    int r = tid >> 2, c = tid & 3;
    size_t g = (size_t)r * E_ + t * KCH + c * 8;
    uint32_t d = base + r * ROWB + c * 16;
    CP16(d,            a0 + g);
    CP16(d + OMAT,     a1 + g);
    CP16(d + 2 * OMAT, b0 + g);
    CP16(d + 3 * OMAT, b1 + g);
    CP_COMMIT();
}

__global__ __launch_bounds__(256, 1) void mma_gemm_out(
    const __nv_bfloat16* __restrict__ ha0, const __nv_bfloat16* __restrict__ ha1,
    const __nv_bfloat16* __restrict__ hb0, const __nv_bfloat16* __restrict__ hb1,
    float* __restrict__ C) {
    extern __shared__ char smc[];
    uint32_t sb = smem_u32(smc);
    int tid = threadIdx.x;
    int lane = tid & 31;
    int wid = tid >> 5;
    int wm = wid >> 2;     // 0..1 (32 rows)
    int wn = wid & 3;      // 0..3 (16 cols)
    int bm = blockIdx.y * 64;
    int bn = blockIdx.x * 64;

    const __nv_bfloat16* a0 = ha0 + (size_t)bm * E_;
    const __nv_bfloat16* a1 = ha1 + (size_t)bm * E_;
    const __nv_bfloat16* b0 = hb0 + (size_t)bn * E_;
    const __nv_bfloat16* b1 = hb1 + (size_t)bn * E_;

    float acc[2][2][4];
#pragma unroll
    for (int i = 0; i < 2; i++)
#pragma unroll
        for (int j = 0; j < 2; j++)
#pragma unroll
            for (int k = 0; k < 4; k++) acc[i][j][k] = 0.0f;

    out_load_chunk(sb, 0, tid, a0, a1, b0, b1);
    out_load_chunk(sb + OSTG, 1, tid, a0, a1, b0, b1);

    int arow = lane & 15;
    int acolb = ((lane >> 4) & 1) * 16;
    int brow = (lane & 7) + ((lane >> 4) << 3);
    int bcolb = ((lane >> 3) & 1) * 16;

    for (int t = 0; t < NCHK; t++) {
        if (t + 1 < NCHK) asm volatile("cp.async.wait_group 1;" ::: "memory");
        else              asm volatile("cp.async.wait_group 0;" ::: "memory");
        __syncthreads();
        if (t + 2 < NCHK) out_load_chunk(sb + ((t + 2) % 3) * OSTG, t + 2, tid, a0, a1, b0, b1);

        uint32_t st = sb + (t % 3) * OSTG;
        uint32_t aA0 = st + (wm * 32 + arow) * ROWB + acolb;
        uint32_t aA1 = aA0 + OMAT;
        uint32_t aB0 = st + 2 * OMAT + (wn * 16 + brow) * ROWB + bcolb;
        uint32_t aB1 = aB0 + OMAT;

#pragma unroll
        for (int ks = 0; ks < 2; ks++) {
            uint32_t a0f[2][4], a1f[2][4], b0f[4], b1f[4];
#pragma unroll
            for (int mt = 0; mt < 2; mt++) {
                LDSM4(a0f[mt][0], a0f[mt][1], a0f[mt][2], a0f[mt][3], aA0 + mt * 16 * ROWB + ks * 32);
                LDSM4(a1f[mt][0], a1f[mt][1], a1f[mt][2], a1f[mt][3], aA1 + mt * 16 * ROWB + ks * 32);
            }
            LDSM4(b0f[0], b0f[1], b0f[2], b0f[3], aB0 + ks * 32);
            LDSM4(b1f[0], b1f[1], b1f[2], b1f[3], aB1 + ks * 32);
#pragma unroll
            for (int mt = 0; mt < 2; mt++) {
#pragma unroll
                for (int nt = 0; nt < 2; nt++) {
                    MMA16816(acc[mt][nt], a0f[mt], b0f[nt * 2], b0f[nt * 2 + 1]);
                    MMA16816(acc[mt][nt], a0f[mt], b1f[nt * 2], b1f[nt * 2 + 1]);
                    MMA16816(acc[mt][nt], a1f[mt], b0f[nt * 2], b0f[nt * 2 + 1]);
                }
            }
        }
    }

    int row0 = bm + wm * 32 + (lane >> 2);
    int col0 = bn + wn * 16 + (lane & 3) * 2;
#pragma unroll
    for (int mt = 0; mt < 2; mt++) {
#pragma unroll
        for (int nt = 0; nt < 2; nt++) {
            int r = row0 + mt * 16;
            int c = col0 + nt * 8;
            float2 v0 = {acc[mt][nt][0], acc[mt][nt][1]};
            float2 v1 = {acc[mt][nt][2], acc[mt][nt][3]};
            *(float2*)&C[(size_t)r * E_ + c] = v0;
            *(float2*)&C[(size_t)(r + 8) * E_ + c] = v1;
        }
    }
}

// ---------------- mask prefix scan ------------------------------------------
__global__ void counts_kernel(const float* __restrict__ mask, float* __restrict__ counts) {
    __shared__ float sh[S_];
    int b = blockIdx.x;
    int t = threadIdx.x;
    sh[t] = (mask[b * S_ + t] == 0.0f) ? 1.0f : 0.0f;
    __syncthreads();
    for (int off = 1; off < S_; off <<= 1) {
        float add = (t >= off) ? sh[t - off] : 0.0f;
        __syncthreads();
        sh[t] += add;
        __syncthreads();
    }
    counts[b * S_ + t] = sh[t];
}

// ============== causal attention: 128 threads, AQM=64, AKC=32, 2 CTA/SM ======
#define AQM 64
#define AKC 32
#define RB 272
#define QMAT (AQM * RB)        // 17408
#define KVMAT (AKC * RB)       // 8704
#define KVSTG (4 * KVMAT)      // 34816
#define ATT_SMEM (2 * QMAT + 2 * KVSTG)   // 104448

__global__ __launch_bounds__(128, 2) void attn_mma(
    const __nv_bfloat16* __restrict__ qh, const __nv_bfloat16* __restrict__ ql,
    const __nv_bfloat16* __restrict__ kh, const __nv_bfloat16* __restrict__ kl,
    const __nv_bfloat16* __restrict__ vh, const __nv_bfloat16* __restrict__ vl,
    __nv_bfloat16* __restrict__ aoh, __nv_bfloat16* __restrict__ aol) {
    extern __shared__ char smc[];
    uint32_t sb = smem_u32(smc);
    uint32_t sQh = sb, sQl = sb + QMAT;
    uint32_t sKV = sb + 2 * QMAT;

    int tid = threadIdx.x;
    int lane = tid & 31;
    int wid = tid >> 5;                       // 0..3, 16 q-rows each
    int bh = blockIdx.x;                      // 0..31
    int qt = (int)gridDim.y - 1 - (int)blockIdx.y;   // big tiles first
    int q0 = qt * AQM;

    size_t base = (size_t)bh * S_ * HD_;
    const __nv_bfloat16* Qhb = qh + base;
    const __nv_bfloat16* Qlb = ql + base;
    const __nv_bfloat16* Khb = kh + base;
    const __nv_bfloat16* Klb = kl + base;
    const __nv_bfloat16* Vhb = vh + base;
    const __nv_bfloat16* Vlb = vl + base;

    // load Q tile (64 rows x 16 c-groups)
    for (int i = tid; i < 1024; i += 128) {
        int r = i >> 4, c = i & 15;
        size_t g = (size_t)(q0 + r) * HD_ + c * 8;
        CP16(sQh + r * RB + c * 16, Qhb + g);
        CP16(sQl + r * RB + c * 16, Qlb + g);
    }
    // chunk 0 (32 rows)
    for (int i = tid; i < 512; i += 128) {
        int r = i >> 4, c = i & 15;
        size_t g = (size_t)r * HD_ + c * 8;
        uint32_t d = sKV + r * RB + c * 16;
        CP16(d, Khb + g);
        CP16(d + KVMAT, Klb + g);
        CP16(d + 2 * KVMAT, Vhb + g);
        CP16(d + 3 * KVMAT, Vlb + g);
    }
    CP_COMMIT();

    int nch = (q0 + AQM) / AKC;
    float o[16][4];
#pragma unroll
    for (int i = 0; i < 16; i++)
#pragma unroll
        for (int j = 0; j < 4; j++) o[i][j] = 0.0f;

    int arow = lane & 15;
    int acolb = ((lane >> 4) & 1) * 16;
    int brow = (lane & 7) + ((lane >> 4) << 3);
    int bcolb = ((lane >> 3) & 1) * 16;
    int vrow = (lane & 7) + (((lane >> 3) & 1) << 3);
    int vcolb = ((lane >> 4) & 1) * 16;
    int m0w = q0 + wid * 16;

    for (int t = 0; t < nch; t++) {
        asm volatile("cp.async.wait_group 0;" ::: "memory");
        __syncthreads();
        if (t + 1 < nch) {
            uint32_t nstg = sKV + ((t + 1) & 1) * KVSTG;
            int kc = (t + 1) * AKC;
            for (int i = tid; i < 512; i += 128) {
                int r = i >> 4, c = i & 15;
                size_t g = (size_t)(kc + r) * HD_ + c * 8;
                uint32_t d = nstg + r * RB + c * 16;
                CP16(d, Khb + g);
                CP16(d + KVMAT, Klb + g);
                CP16(d + 2 * KVMAT, Vhb + g);
                CP16(d + 3 * KVMAT, Vlb + g);
            }
            CP_COMMIT();
        }
        uint32_t stg = sKV + (t & 1) * KVSTG;

        // ---- phase 1: S[16x32]
        float sacc[4][4];
#pragma unroll
        for (int i = 0; i < 4; i++)
#pragma unroll
            for (int j = 0; j < 4; j++) sacc[i][j] = 0.0f;

#pragma unroll
        for (int ds = 0; ds < 8; ds++) {
            uint32_t ah[4], al[4];
            uint32_t ad = sQh + (wid * 16 + arow) * RB + acolb + ds * 32;
            LDSM4(ah[0], ah[1], ah[2], ah[3], ad);
            LDSM4(al[0], al[1], al[2], al[3], ad + QMAT);
            uint32_t bhf[2][4], blf[2][4];
#pragma unroll
            for (int ng = 0; ng < 2; ng++) {
                uint32_t bd = stg + (ng * 16 + brow) * RB + bcolb + ds * 32;
                LDSM4(bhf[ng][0], bhf[ng][1], bhf[ng][2], bhf[ng][3], bd);
                LDSM4(blf[ng][0], blf[ng][1], blf[ng][2], blf[ng][3], bd + KVMAT);
            }
#pragma unroll
            for (int nt = 0; nt < 4; nt++) {
                uint32_t* ph = &bhf[nt >> 1][(nt & 1) * 2];
                uint32_t* pl = &blf[nt >> 1][(nt & 1) * 2];
                MMA16816(sacc[nt], ah, ph[0], ph[1]);
                MMA16816(sacc[nt], ah, pl[0], pl[1]);
                MMA16816(sacc[nt], al, ph[0], ph[1]);
            }
        }

        // ---- causal mask
        int kcg = t * AKC;
        if (kcg + AKC - 1 > m0w) {
            int r0m = m0w + (lane >> 2);
            int r1m = r0m + 8;
#pragma unroll
            for (int nt = 0; nt < 4; nt++) {
                int cb = kcg + nt * 8 + (lane & 3) * 2;
                if (cb > r0m) sacc[nt][0] = 0.0f;
                if (cb + 1 > r0m) sacc[nt][1] = 0.0f;
                if (cb > r1m) sacc[nt][2] = 0.0f;
                if (cb + 1 > r1m) sacc[nt][3] = 0.0f;
            }
        }

        // ---- phase 2: O += S . V
#pragma unroll
        for (int ks = 0; ks < 2; ks++) {
            uint32_t ah[4], al[4];
            split2(sacc[2 * ks][0], sacc[2 * ks][1], ah[0], al[0]);
            split2(sacc[2 * ks][2], sacc[2 * ks][3], ah[1], al[1]);
            split2(sacc[2 * ks + 1][0], sacc[2 * ks + 1][1], ah[2], al[2]);
            split2(sacc[2 * ks + 1][2], sacc[2 * ks + 1][3], ah[3], al[3]);
#pragma unroll
            for (int ng = 0; ng < 8; ng++) {
                uint32_t bh4[4], bl4[4];
                uint32_t va = stg + 2 * KVMAT + (ks * 16 + vrow) * RB + vcolb + ng * 32;
                LDSM4T(bh4[0], bh4[1], bh4[2], bh4[3], va);
                LDSM4T(bl4[0], bl4[1], bl4[2], bl4[3], va + KVMAT);
                MMA16816(o[2 * ng], ah, bh4[0], bh4[1]);
                MMA16816(o[2 * ng], ah, bl4[0], bl4[1]);
                MMA16816(o[2 * ng], al, bh4[0], bh4[1]);
                MMA16816(o[2 * ng + 1], ah, bh4[2], bh4[3]);
                MMA16816(o[2 * ng + 1], ah, bl4[2], bl4[3]);
                MMA16816(o[2 * ng + 1], al, bh4[2], bh4[3]);
            }
        }
        __syncthreads();     // protect buffer (t&1) before t+2 load
    }

    int b = bh / H_;
    int h = bh % H_;
    int r0 = m0w + (lane >> 2);
#pragma unroll
    for (int nt = 0; nt < 16; nt++) {
        int col = nt * 8 + (lane & 3) * 2;
        size_t g0 = ((size_t)(b * S_ + r0)) * E_ + h * HD_ + col;
        size_t g1 = ((size_t)(b * S_ + r0 + 8)) * E_ + h * HD_ + col;
        uint32_t hi0, lo0, hi1, lo1;
        split2(o[nt][0], o[nt][1], hi0, lo0);
        split2(o[nt][2], o[nt][3], hi1, lo1);
        *(uint32_t*)(aoh + g0) = hi0;
        *(uint32_t*)(aol + g0) = lo0;
        *(uint32_t*)(aoh + g1) = hi1;
        *(uint32_t*)(aol + g1) = lo1;
    }
}

// ---------------- launcher ---------------------------------------------------
extern "C" void kernel_launch(void* const* d_in, const int* in_sizes, int n_in,
                              void* d_out, int out_size) {
    const float* hs        = (const float*)d_in[0];
    const float* w_q       = (const float*)d_in[1];
    const float* w_k       = (const float*)d_in[2];
    const float* w_v       = (const float*)d_in[3];
    const float* w_o       = (const float*)d_in[4];
    const float* norm_c    = (const float*)d_in[5];
    const float* attn_mask = (const float*)d_in[6];
    const int*   pos_ids   = (const int*)d_in[7];
    float* out = (float*)d_out;

    float* cnts;
    cudaGetSymbolAddress((void**)&cnts, g_counts);

    __nv_bfloat16 *hs0, *hs1, *wq0, *wq1, *wk0, *wk1, *wv0, *wv1, *wo0, *wo1, *ao0, *ao1;
    __nv_bfloat16 *q0, *q1, *k0, *k1, *v0, *v1;
    cudaGetSymbolAddress((void**)&hs0, g_hs0);
    cudaGetSymbolAddress((void**)&hs1, g_hs1);
    cudaGetSymbolAddress((void**)&wq0, g_wq0);
    cudaGetSymbolAddress((void**)&wq1, g_wq1);
    cudaGetSymbolAddress((void**)&wk0, g_wk0);
    cudaGetSymbolAddress((void**)&wk1, g_wk1);
    cudaGetSymbolAddress((void**)&wv0, g_wv0);
    cudaGetSymbolAddress((void**)&wv1, g_wv1);
    cudaGetSymbolAddress((void**)&wo0, g_wo0);
    cudaGetSymbolAddress((void**)&wo1, g_wo1);
    cudaGetSymbolAddress((void**)&ao0, g_ao0);
    cudaGetSymbolAddress((void**)&ao1, g_ao1);
    cudaGetSymbolAddress((void**)&q0, g_q0);
    cudaGetSymbolAddress((void**)&q1, g_q1);
    cudaGetSymbolAddress((void**)&k0, g_k0);
    cudaGetSymbolAddress((void**)&k1, g_k1);
    cudaGetSymbolAddress((void**)&v0, g_v0);
    cudaGetSymbolAddress((void**)&v1, g_v1);

    static bool attr_set = false;
    if (!attr_set) {
        cudaFuncSetAttribute(mma_gemm_qkv_fused, cudaFuncAttributeMaxDynamicSharedMemorySize, QKV_SMEM);
        cudaFuncSetAttribute(mma_gemm_out, cudaFuncAttributeMaxDynamicSharedMemorySize, OUT_SMEM);
        cudaFuncSetAttribute(attn_mma, cudaFuncAttributeMaxDynamicSharedMemorySize, ATT_SMEM);
        attr_set = true;
    }

    counts_kernel<<<B_, S_>>>(attn_mask, cnts);

    split5_kernel<<<dim3(256, 5), 256>>>(hs, w_q, w_k, w_v, w_o,
                                         hs0, hs1, wq0, wq1, wk0, wk1,
                                         wv0, wv1, wo0, wo1);

    mma_gemm_qkv_fused<<<dim3(E_ / 128, NROWS / 64, 3), 256, QKV_SMEM>>>(
        hs0, hs1, wq0, wq1, wk0, wk1, wv0, wv1,
        attn_mask, norm_c, pos_ids, cnts,
        q0, q1, k0, k1, v0, v1);

    attn_mma<<<dim3(B_ * H_, S_ / AQM), 128, ATT_SMEM>>>(q0, q1, k0, k1, v0, v1, ao0, ao1);

    mma_gemm_out<<<dim3(E_ / 64, NROWS / 64), 256, OUT_SMEM>>>(ao0, ao1, wo0, wo1, out);
}

// round 8
// speedup vs baseline: 6.7760x; 1.0006x over previous
#include <cuda_runtime.h>
#include <cuda_bf16.h>
#include <math.h>
#include <stdint.h>

#define B_  2
#define S_  1024
#define E_  2048
#define H_  16
#define HD_ 128
#define ROT_ 64
#define NROWS (B_ * S_)
#define EPS_ 1e-12f

// ---------------- scratch ----------------------------------------------------
__device__ float g_counts[B_ * S_];

__device__ __nv_bfloat16 g_hs0[NROWS * E_], g_hs1[NROWS * E_];
__device__ __nv_bfloat16 g_wq0[E_ * E_],   g_wq1[E_ * E_];
__device__ __nv_bfloat16 g_wk0[E_ * E_],   g_wk1[E_ * E_];
__device__ __nv_bfloat16 g_wv0[E_ * E_],   g_wv1[E_ * E_];
__device__ __nv_bfloat16 g_wo0[E_ * E_],   g_wo1[E_ * E_];
__device__ __nv_bfloat16 g_ao0[NROWS * E_], g_ao1[NROWS * E_];

__device__ __nv_bfloat16 g_q0[B_ * H_ * S_ * HD_], g_q1[B_ * H_ * S_ * HD_];
__device__ __nv_bfloat16 g_k0[B_ * H_ * S_ * HD_], g_k1[B_ * H_ * S_ * HD_];
__device__ __nv_bfloat16 g_v0[B_ * H_ * S_ * HD_], g_v1[B_ * H_ * S_ * HD_];

// ---------------- PTX helpers ------------------------------------------------
__device__ __forceinline__ uint32_t smem_u32(const void* p) {
    uint32_t a;
    asm("{ .reg .u64 t; cvta.to.shared.u64 t, %1; cvt.u32.u64 %0, t; }" : "=r"(a) : "l"(p));
    return a;
}
#define CP16(dst, src) asm volatile("cp.async.cg.shared.global [%0], [%1], 16;" :: "r"(dst), "l"(src) : "memory")
#define CP_COMMIT() asm volatile("cp.async.commit_group;" ::: "memory")

#define LDSM4(r0, r1, r2, r3, addr) \
    asm volatile("ldmatrix.sync.aligned.m8n8.x4.shared.b16 {%0,%1,%2,%3}, [%4];" \
        : "=r"(r0), "=r"(r1), "=r"(r2), "=r"(r3) : "r"(addr))

#define LDSM4T(r0, r1, r2, r3, addr) \
    asm volatile("ldmatrix.sync.aligned.m8n8.x4.trans.shared.b16 {%0,%1,%2,%3}, [%4];" \
        : "=r"(r0), "=r"(r1), "=r"(r2), "=r"(r3) : "r"(addr))

#define MMA16816(c, a, br0, br1) \
    asm volatile("mma.sync.aligned.m16n8k16.row.col.f32.bf16.bf16.f32 " \
        "{%0,%1,%2,%3}, {%4,%5,%6,%7}, {%8,%9}, {%0,%1,%2,%3};" \
        : "+f"((c)[0]), "+f"((c)[1]), "+f"((c)[2]), "+f"((c)[3]) \
        : "r"((a)[0]), "r"((a)[1]), "r"((a)[2]), "r"((a)[3]), "r"(br0), "r"(br1))

__device__ __forceinline__ void split2(float x, float y, uint32_t& hi, uint32_t& lo) {
    __nv_bfloat16 hx = __float2bfloat16(x), hy = __float2bfloat16(y);
    __nv_bfloat16 lx = __float2bfloat16(x - __bfloat162float(hx));
    __nv_bfloat16 ly = __float2bfloat16(y - __bfloat162float(hy));
    hi = (uint32_t)__bfloat16_as_ushort(hx) | ((uint32_t)__bfloat16_as_ushort(hy) << 16);
    lo = (uint32_t)__bfloat16_as_ushort(lx) | ((uint32_t)__bfloat16_as_ushort(ly) << 16);
}

// ---------------- fused split fp32 -> bf16 hi/lo (5 tensors) -----------------
__global__ __launch_bounds__(256) void split5_kernel(
    const float* __restrict__ x0, const float* __restrict__ x1,
    const float* __restrict__ x2, const float* __restrict__ x3,
    const float* __restrict__ x4,
    __nv_bfloat16* __restrict__ h0, __nv_bfloat16* __restrict__ l0,
    __nv_bfloat16* __restrict__ h1, __nv_bfloat16* __restrict__ l1,
    __nv_bfloat16* __restrict__ h2, __nv_bfloat16* __restrict__ l2,
    __nv_bfloat16* __restrict__ h3, __nv_bfloat16* __restrict__ l3,
    __nv_bfloat16* __restrict__ h4, __nv_bfloat16* __restrict__ l4) {
    int z = blockIdx.y;
    const float* x = (z == 0) ? x0 : (z == 1) ? x1 : (z == 2) ? x2 : (z == 3) ? x3 : x4;
    __nv_bfloat16* hi = (z == 0) ? h0 : (z == 1) ? h1 : (z == 2) ? h2 : (z == 3) ? h3 : h4;
    __nv_bfloat16* lo = (z == 0) ? l0 : (z == 1) ? l1 : (z == 2) ? l2 : (z == 3) ? l3 : l4;
    const int n4 = NROWS * E_ / 4;
    for (int i = blockIdx.x * blockDim.x + threadIdx.x; i < n4; i += gridDim.x * blockDim.x) {
        float4 v = ((const float4*)x)[i];
        float vv[4] = {v.x, v.y, v.z, v.w};
        unsigned short hs[4], ls[4];
#pragma unroll
        for (int j = 0; j < 4; j++) {
            __nv_bfloat16 h = __float2bfloat16(vv[j]);
            __nv_bfloat16 l = __float2bfloat16(vv[j] - __bfloat162float(h));
            hs[j] = __bfloat16_as_ushort(h);
            ls[j] = __bfloat16_as_ushort(l);
        }
        uint2 ph = {(uint32_t)hs[0] | ((uint32_t)hs[1] << 16),
                    (uint32_t)hs[2] | ((uint32_t)hs[3] << 16)};
        uint2 pl = {(uint32_t)ls[0] | ((uint32_t)ls[1] << 16),
                    (uint32_t)ls[2] | ((uint32_t)ls[3] << 16)};
        ((uint2*)hi)[i] = ph;
        ((uint2*)lo)[i] = pl;
    }
}

// ============== QKV GEMM 64x128 tiles, fused epilogue, 2 CTA/SM ==============
#define KCH 32
#define NCHK (E_ / KCH)
#define ROWB 80
#define QAMAT (64 * ROWB)     // 5120
#define QBMAT (128 * ROWB)    // 10240
#define QSTG (2 * QAMAT + 2 * QBMAT)   // 30720
#define QKV_SMEM (3 * QSTG)   // 92160

__device__ __forceinline__ void qkv_load_chunk(uint32_t base, int t, int tid,
                                               const __nv_bfloat16* a0, const __nv_bfloat16* a1,
                                               const __nv_bfloat16* b0, const __nv_bfloat16* b1) {
    {
        int r = tid >> 2, c = tid & 3;
        size_t g = (size_t)r * E_ + t * KCH + c * 8;
        uint32_t d = base + r * ROWB + c * 16;
        CP16(d, a0 + g);
        CP16(d + QAMAT, a1 + g);
    }
    for (int i = tid; i < 512; i += 256) {
        int r = i >> 2, c = i & 3;
        size_t g = (size_t)r * E_ + t * KCH + c * 8;
        uint32_t d = base + 2 * QAMAT + r * ROWB + c * 16;
        CP16(d, b0 + g);
        CP16(d + QBMAT, b1 + g);
    }
    CP_COMMIT();
}

__global__ __launch_bounds__(256, 2) void mma_gemm_qkv_fused(
    const __nv_bfloat16* __restrict__ ha0, const __nv_bfloat16* __restrict__ ha1,
    const __nv_bfloat16* __restrict__ wq0, const __nv_bfloat16* __restrict__ wq1,
    const __nv_bfloat16* __restrict__ wk0, const __nv_bfloat16* __restrict__ wk1,
    const __nv_bfloat16* __restrict__ wv0, const __nv_bfloat16* __restrict__ wv1,
    const float* __restrict__ mask, const float* __restrict__ norm_const,
    const int* __restrict__ pos_ids, const float* __restrict__ counts,
    __nv_bfloat16* __restrict__ Qh, __nv_bfloat16* __restrict__ Ql,
    __nv_bfloat16* __restrict__ Kh, __nv_bfloat16* __restrict__ Kl,
    __nv_bfloat16* __restrict__ Vh, __nv_bfloat16* __restrict__ Vl) {
    extern __shared__ char smc[];
    uint32_t sb = smem_u32(smc);
    int tid = threadIdx.x;
    int lane = tid & 31;
    int wid = tid >> 5;
    int wm = wid >> 2;
    int wn = wid & 3;
    int z = blockIdx.z;
    int bm = blockIdx.y * 64;
    int bn = blockIdx.x * 128;

    const __nv_bfloat16* a0 = ha0 + (size_t)bm * E_;
    const __nv_bfloat16* a1 = ha1 + (size_t)bm * E_;
    const __nv_bfloat16* b0 = ((z == 0) ? wq0 : (z == 1) ? wk0 : wv0) + (size_t)bn * E_;
    const __nv_bfloat16* b1 = ((z == 0) ? wq1 : (z == 1) ? wk1 : wv1) + (size_t)bn * E_;

    float acc[2][4][4];
#pragma unroll
    for (int i = 0; i < 2; i++)
#pragma unroll
        for (int j = 0; j < 4; j++)
#pragma unroll
            for (int k = 0; k < 4; k++) acc[i][j][k] = 0.0f;

    qkv_load_chunk(sb, 0, tid, a0, a1, b0, b1);
    qkv_load_chunk(sb + QSTG, 1, tid, a0, a1, b0, b1);

    int arow = lane & 15;
    int acolb = ((lane >> 4) & 1) * 16;
    int brow = (lane & 7) + ((lane >> 4) << 3);
    int bcolb = ((lane >> 3) & 1) * 16;

    for (int t = 0; t < NCHK; t++) {
        if (t + 1 < NCHK) asm volatile("cp.async.wait_group 1;" ::: "memory");
        else              asm volatile("cp.async.wait_group 0;" ::: "memory");
        __syncthreads();
        if (t + 2 < NCHK) qkv_load_chunk(sb + ((t + 2) % 3) * QSTG, t + 2, tid, a0, a1, b0, b1);

        uint32_t st = sb + (t % 3) * QSTG;
        uint32_t aA0 = st + (wm * 32 + arow) * ROWB + acolb;
        uint32_t aA1 = aA0 + QAMAT;
        uint32_t aB0 = st + 2 * QAMAT + (wn * 32 + brow) * ROWB + bcolb;
        uint32_t aB1 = aB0 + QBMAT;

#pragma unroll
        for (int ks = 0; ks < 2; ks++) {
            uint32_t a0f[2][4], a1f[2][4], b0f[2][4], b1f[2][4];
#pragma unroll
            for (int mt = 0; mt < 2; mt++) {
                LDSM4(a0f[mt][0], a0f[mt][1], a0f[mt][2], a0f[mt][3], aA0 + mt * 16 * ROWB + ks * 32);
                LDSM4(a1f[mt][0], a1f[mt][1], a1f[mt][2], a1f[mt][3], aA1 + mt * 16 * ROWB + ks * 32);
            }
#pragma unroll
            for (int np = 0; np < 2; np++) {
                LDSM4(b0f[np][0], b0f[np][1], b0f[np][2], b0f[np][3], aB0 + np * 16 * ROWB + ks * 32);
                LDSM4(b1f[np][0], b1f[np][1], b1f[np][2], b1f[np][3], aB1 + np * 16 * ROWB + ks * 32);
            }
#pragma unroll
            for (int mt = 0; mt < 2; mt++) {
#pragma unroll
                for (int nt = 0; nt < 4; nt++) {
                    uint32_t* p0 = &b0f[nt >> 1][(nt & 1) * 2];
                    uint32_t* p1 = &b1f[nt >> 1][(nt & 1) * 2];
                    MMA16816(acc[mt][nt], a0f[mt], p0[0], p0[1]);
                    MMA16816(acc[mt][nt], a0f[mt], p1[0], p1[1]);
                    MMA16816(acc[mt][nt], a1f[mt], p0[0], p0[1]);
                }
            }
        }
    }
    __syncthreads();

    // ---- fused epilogue
    float* rs = (float*)smc;
    int lr = lane >> 2;
    int lc = lane & 3;
    int col0 = wn * 32 + lc * 2;

    if (z < 2) {
        if (wn < 2) {
#pragma unroll
            for (int mt = 0; mt < 2; mt++) {
                int rg = bm + wm * 32 + mt * 16 + lr;
                float pos0 = (float)pos_ids[rg];
                float pos1 = (float)pos_ids[rg + 8];
#pragma unroll
                for (int nt = 0; nt < 4; nt++) {
                    float fi = (float)(wn * 16 + nt * 4 + lc);
                    float fr = __expf(-0.28782313662425575f * fi);
                    float s0, c0, s1, c1;
                    sincosf(pos0 * fr, &s0, &c0);
                    sincosf(pos1 * fr, &s1, &c1);
                    float x = acc[mt][nt][0], y = acc[mt][nt][1];
                    acc[mt][nt][0] = x * c0 - y * s0;
                    acc[mt][nt][1] = y * c0 + x * s0;
                    x = acc[mt][nt][2]; y = acc[mt][nt][3];
                    acc[mt][nt][2] = x * c1 - y * s1;
                    acc[mt][nt][3] = y * c1 + x * s1;
                }
            }
        }
#pragma unroll
        for (int mt = 0; mt < 2; mt++) {
            float s0 = 0.0f, s1 = 0.0f;
#pragma unroll
            for (int nt = 0; nt < 4; nt++) {
                s0 += acc[mt][nt][0] * acc[mt][nt][0] + acc[mt][nt][1] * acc[mt][nt][1];
                s1 += acc[mt][nt][2] * acc[mt][nt][2] + acc[mt][nt][3] * acc[mt][nt][3];
            }
            s0 += __shfl_xor_sync(0xffffffffu, s0, 1);
            s0 += __shfl_xor_sync(0xffffffffu, s0, 2);
            s1 += __shfl_xor_sync(0xffffffffu, s1, 1);
            s1 += __shfl_xor_sync(0xffffffffu, s1, 2);
            if (lc == 0) {
                rs[(wm * 32 + mt * 16 + lr) * 4 + wn] = s0;
                rs[(wm * 32 + mt * 16 + lr + 8) * 4 + wn] = s1;
            }
        }
    }
    __syncthreads();

    int h = bn >> 7;
    float sig = 1.0f / (1.0f + __expf(-norm_const[h]));
    __nv_bfloat16* OH = (z == 0) ? Qh : (z == 1) ? Kh : Vh;
    __nv_bfloat16* OL = (z == 0) ? Ql : (z == 1) ? Kl : Vl;

#pragma unroll
    for (int mt = 0; mt < 2; mt++) {
#pragma unroll
        for (int half = 0; half < 2; half++) {
            int rl = wm * 32 + mt * 16 + lr + half * 8;
            int rg = bm + rl;
            float m = (mask[rg] == 0.0f) ? 1.0f : 0.0f;
            float scl;
            if (z < 2) {
                float tot = rs[rl * 4] + rs[rl * 4 + 1] + rs[rl * 4 + 2] + rs[rl * 4 + 3];
                scl = m / fmaxf(sqrtf(tot), EPS_);
            } else {
                scl = m / fmaxf(powf(counts[rg], sig), 1.0f);
            }
            int b = rg >> 10;
            int s = rg & 1023;
            size_t dst = (((size_t)(b * H_ + h)) * S_ + s) * (size_t)HD_;
#pragma unroll
            for (int nt = 0; nt < 4; nt++) {
                int c = col0 + nt * 8;
                uint32_t hi, lo;
                split2(acc[mt][nt][2 * half] * scl, acc[mt][nt][2 * half + 1] * scl, hi, lo);
                *(uint32_t*)(OH + dst + c) = hi;
                *(uint32_t*)(OL + dst + c) = lo;
            }
        }
    }
}

// ============== Output projection GEMM 64x64 tiles, 2 CTA/SM =================
#define OMAT (64 * ROWB)
#define OSTG (4 * OMAT)
#define OUT_SMEM (3 * OSTG)

__device__ __forceinline__ void out_load_chunk(uint32_t base, int t, int tid,
                                               const __nv_bfloat16* a0, const __nv_bfloat16* a1,
                                               const __nv_bfloat16* b0, const __nv_bfloat16* b1) {
    int r = tid >> 2, c = tid & 3;
    size_t g = (size_t)r * E_ + t * KCH + c * 8;
    uint32_t d = base + r * ROWB + c * 16;
    CP16(d,            a0 + g);
    CP16(d + OMAT,     a1 + g);
    CP16(d + 2 * OMAT, b0 + g);
    CP16(d + 3 * OMAT, b1 + g);
    CP_COMMIT();
}

__global__ __launch_bounds__(256, 2) void mma_gemm_out(
    const __nv_bfloat16* __restrict__ ha0, const __nv_bfloat16* __restrict__ ha1,
    const __nv_bfloat16* __restrict__ hb0, const __nv_bfloat16* __restrict__ hb1,
    float* __restrict__ C) {
    extern __shared__ char smc[];
    uint32_t sb = smem_u32(smc);
    int tid = threadIdx.x;
    int lane = tid & 31;
    int wid = tid >> 5;
    int wm = wid >> 2;
    int wn = wid & 3;
    int bm = blockIdx.y * 64;
    int bn = blockIdx.x * 64;

    const __nv_bfloat16* a0 = ha0 + (size_t)bm * E_;
    const __nv_bfloat16* a1 = ha1 + (size_t)bm * E_;
    const __nv_bfloat16* b0 = hb0 + (size_t)bn * E_;
    const __nv_bfloat16* b1 = hb1 + (size_t)bn * E_;

    float acc[2][2][4];
#pragma unroll
    for (int i = 0; i < 2; i++)
#pragma unroll
        for (int j = 0; j < 2; j++)
#pragma unroll
            for (int k = 0; k < 4; k++) acc[i][j][k] = 0.0f;

    out_load_chunk(sb, 0, tid, a0, a1, b0, b1);
    out_load_chunk(sb + OSTG, 1, tid, a0, a1, b0, b1);

    int arow = lane & 15;
    int acolb = ((lane >> 4) & 1) * 16;
    int brow = (lane & 7) + ((lane >> 4) << 3);
    int bcolb = ((lane >> 3) & 1) * 16;

    for (int t = 0; t < NCHK; t++) {
        if (t + 1 < NCHK) asm volatile("cp.async.wait_group 1;" ::: "memory");
        else              asm volatile("cp.async.wait_group 0;" ::: "memory");
        __syncthreads();
        if (t + 2 < NCHK) out_load_chunk(sb + ((t + 2) % 3) * OSTG, t + 2, tid, a0, a1, b0, b1);

        uint32_t st = sb + (t % 3) * OSTG;
        uint32_t aA0 = st + (wm * 32 + arow) * ROWB + acolb;
        uint32_t aA1 = aA0 + OMAT;
        uint32_t aB0 = st + 2 * OMAT + (wn * 16 + brow) * ROWB + bcolb;
        uint32_t aB1 = aB0 + OMAT;

#pragma unroll
        for (int ks = 0; ks < 2; ks++) {
            uint32_t a0f[2][4], a1f[2][4], b0f[4], b1f[4];
#pragma unroll
            for (int mt = 0; mt < 2; mt++) {
                LDSM4(a0f[mt][0], a0f[mt][1], a0f[mt][2], a0f[mt][3], aA0 + mt * 16 * ROWB + ks * 32);
                LDSM4(a1f[mt][0], a1f[mt][1], a1f[mt][2], a1f[mt][3], aA1 + mt * 16 * ROWB + ks * 32);
            }
            LDSM4(b0f[0], b0f[1], b0f[2], b0f[3], aB0 + ks * 32);
            LDSM4(b1f[0], b1f[1], b1f[2], b1f[3], aB1 + ks * 32);
#pragma unroll
            for (int mt = 0; mt < 2; mt++) {
#pragma unroll
                for (int nt = 0; nt < 2; nt++) {
                    MMA16816(acc[mt][nt], a0f[mt], b0f[nt * 2], b0f[nt * 2 + 1]);
                    MMA16816(acc[mt][nt], a0f[mt], b1f[nt * 2], b1f[nt * 2 + 1]);
                    MMA16816(acc[mt][nt], a1f[mt], b0f[nt * 2], b0f[nt * 2 + 1]);
                }
            }
        }
    }

    int row0 = bm + wm * 32 + (lane >> 2);
    int col0 = bn + wn * 16 + (lane & 3) * 2;
#pragma unroll
    for (int mt = 0; mt < 2; mt++) {
#pragma unroll
        for (int nt = 0; nt < 2; nt++) {
            int r = row0 + mt * 16;
            int c = col0 + nt * 8;
            float2 v0 = {acc[mt][nt][0], acc[mt][nt][1]};
            float2 v1 = {acc[mt][nt][2], acc[mt][nt][3]};
            *(float2*)&C[(size_t)r * E_ + c] = v0;
            *(float2*)&C[(size_t)(r + 8) * E_ + c] = v1;
        }
    }
}

// ---------------- mask prefix scan ------------------------------------------
__global__ void counts_kernel(const float* __restrict__ mask, float* __restrict__ counts) {
    __shared__ float sh[S_];
    int b = blockIdx.x;
    int t = threadIdx.x;
    sh[t] = (mask[b * S_ + t] == 0.0f) ? 1.0f : 0.0f;
    __syncthreads();
    for (int off = 1; off < S_; off <<= 1) {
        float add = (t >= off) ? sh[t - off] : 0.0f;
        __syncthreads();
        sh[t] += add;
        __syncthreads();
    }
    counts[b * S_ + t] = sh[t];
}

// ============== causal attention: 128 threads, AQM=64, AKC=32, 2 CTA/SM ======
#define AQM 64
#define AKC 32
#define RB 272
#define QMAT (AQM * RB)
#define KVMAT (AKC * RB)
#define KVSTG (4 * KVMAT)
#define ATT_SMEM (2 * QMAT + 2 * KVSTG)

__global__ __launch_bounds__(128, 2) void attn_mma(
    const __nv_bfloat16* __restrict__ qh, const __nv_bfloat16* __restrict__ ql,
    const __nv_bfloat16* __restrict__ kh, const __nv_bfloat16* __restrict__ kl,
    const __nv_bfloat16* __restrict__ vh, const __nv_bfloat16* __restrict__ vl,
    __nv_bfloat16* __restrict__ aoh, __nv_bfloat16* __restrict__ aol) {
    extern __shared__ char smc[];
    uint32_t sb = smem_u32(smc);
    uint32_t sQh = sb, sQl = sb + QMAT;
    uint32_t sKV = sb + 2 * QMAT;

    int tid = threadIdx.x;
    int lane = tid & 31;
    int wid = tid >> 5;
    int bh = blockIdx.x;
    int qt = (int)gridDim.y - 1 - (int)blockIdx.y;
    int q0 = qt * AQM;

    size_t base = (size_t)bh * S_ * HD_;
    const __nv_bfloat16* Qhb = qh + base;
    const __nv_bfloat16* Qlb = ql + base;
    const __nv_bfloat16* Khb = kh + base;
    const __nv_bfloat16* Klb = kl + base;
    const __nv_bfloat16* Vhb = vh + base;
    const __nv_bfloat16* Vlb = vl + base;

    for (int i = tid; i < 1024; i += 128) {
        int r = i >> 4, c = i & 15;
        size_t g = (size_t)(q0 + r) * HD_ + c * 8;
        CP16(sQh + r * RB + c * 16, Qhb + g);
        CP16(sQl + r * RB + c * 16, Qlb + g);
    }
    for (int i = tid; i < 512; i += 128) {
        int r = i >> 4, c = i & 15;
        size_t g = (size_t)r * HD_ + c * 8;
        uint32_t d = sKV + r * RB + c * 16;
        CP16(d, Khb + g);
        CP16(d + KVMAT, Klb + g);
        CP16(d + 2 * KVMAT, Vhb + g);
        CP16(d + 3 * KVMAT, Vlb + g);
    }
    CP_COMMIT();

    int nch = (q0 + AQM) / AKC;
    float o[16][4];
#pragma unroll
    for (int i = 0; i < 16; i++)
#pragma unroll
        for (int j = 0; j < 4; j++) o[i][j] = 0.0f;

    int arow = lane & 15;
    int acolb = ((lane >> 4) & 1) * 16;
    int brow = (lane & 7) + ((lane >> 4) << 3);
    int bcolb = ((lane >> 3) & 1) * 16;
    int vrow = (lane & 7) + (((lane >> 3) & 1) << 3);
    int vcolb = ((lane >> 4) & 1) * 16;
    int m0w = q0 + wid * 16;

    for (int t = 0; t < nch; t++) {
        asm volatile("cp.async.wait_group 0;" ::: "memory");
        __syncthreads();
        if (t + 1 < nch) {
            uint32_t nstg = sKV + ((t + 1) & 1) * KVSTG;
            int kc = (t + 1) * AKC;
            for (int i = tid; i < 512; i += 128) {
                int r = i >> 4, c = i & 15;
                size_t g = (size_t)(kc + r) * HD_ + c * 8;
                uint32_t d = nstg + r * RB + c * 16;
                CP16(d, Khb + g);
                CP16(d + KVMAT, Klb + g);
                CP16(d + 2 * KVMAT, Vhb + g);
                CP16(d + 3 * KVMAT, Vlb + g);
            }
            CP_COMMIT();
        }
        uint32_t stg = sKV + (t & 1) * KVSTG;

        float sacc[4][4];
#pragma unroll
        for (int i = 0; i < 4; i++)
#pragma unroll
            for (int j = 0; j < 4; j++) sacc[i][j] = 0.0f;

#pragma unroll
        for (int ds = 0; ds < 8; ds++) {
            uint32_t ah[4], al[4];
            uint32_t ad = sQh + (wid * 16 + arow) * RB + acolb + ds * 32;
            LDSM4(ah[0], ah[1], ah[2], ah[3], ad);
            LDSM4(al[0], al[1], al[2], al[3], ad + QMAT);
            uint32_t bhf[2][4], blf[2][4];
#pragma unroll
            for (int ng = 0; ng < 2; ng++) {
                uint32_t bd = stg + (ng * 16 + brow) * RB + bcolb + ds * 32;
                LDSM4(bhf[ng][0], bhf[ng][1], bhf[ng][2], bhf[ng][3], bd);
                LDSM4(blf[ng][0], blf[ng][1], blf[ng][2], blf[ng][3], bd + KVMAT);
            }
#pragma unroll
            for (int nt = 0; nt < 4; nt++) {
                uint32_t* ph = &bhf[nt >> 1][(nt & 1) * 2];
                uint32_t* pl = &blf[nt >> 1][(nt & 1) * 2];
                MMA16816(sacc[nt], ah, ph[0], ph[1]);
                MMA16816(sacc[nt], ah, pl[0], pl[1]);
                MMA16816(sacc[nt], al, ph[0], ph[1]);
            }
        }

        int kcg = t * AKC;
        if (kcg + AKC - 1 > m0w) {
            int r0m = m0w + (lane >> 2);
            int r1m = r0m + 8;
#pragma unroll
            for (int nt = 0; nt < 4; nt++) {
                int cb = kcg + nt * 8 + (lane & 3) * 2;
                if (cb > r0m) sacc[nt][0] = 0.0f;
                if (cb + 1 > r0m) sacc[nt][1] = 0.0f;
                if (cb > r1m) sacc[nt][2] = 0.0f;
                if (cb + 1 > r1m) sacc[nt][3] = 0.0f;
            }
        }

#pragma unroll
        for (int ks = 0; ks < 2; ks++) {
            uint32_t ah[4], al[4];
            split2(sacc[2 * ks][0], sacc[2 * ks][1], ah[0], al[0]);
            split2(sacc[2 * ks][2], sacc[2 * ks][3], ah[1], al[1]);
            split2(sacc[2 * ks + 1][0], sacc[2 * ks + 1][1], ah[2], al[2]);
            split2(sacc[2 * ks + 1][2], sacc[2 * ks + 1][3], ah[3], al[3]);
#pragma unroll
            for (int ng = 0; ng < 8; ng++) {
                uint32_t bh4[4], bl4[4];
                uint32_t va = stg + 2 * KVMAT + (ks * 16 + vrow) * RB + vcolb + ng * 32;
                LDSM4T(bh4[0], bh4[1], bh4[2], bh4[3], va);
                LDSM4T(bl4[0], bl4[1], bl4[2], bl4[3], va + KVMAT);
                MMA16816(o[2 * ng], ah, bh4[0], bh4[1]);
                MMA16816(o[2 * ng], ah, bl4[0], bl4[1]);
                MMA16816(o[2 * ng], al, bh4[0], bh4[1]);
                MMA16816(o[2 * ng + 1], ah, bh4[2], bh4[3]);
                MMA16816(o[2 * ng + 1], ah, bl4[2], bl4[3]);
                MMA16816(o[2 * ng + 1], al, bh4[2], bh4[3]);
            }
        }
        __syncthreads();
    }

    int b = bh / H_;
    int h = bh % H_;
    int r0 = m0w + (lane >> 2);
#pragma unroll
    for (int nt = 0; nt < 16; nt++) {
        int col = nt * 8 + (lane & 3) * 2;
        size_t g0 = ((size_t)(b * S_ + r0)) * E_ + h * HD_ + col;
        size_t g1 = ((size_t)(b * S_ + r0 + 8)) * E_ + h * HD_ + col;
        uint32_t hi0, lo0, hi1, lo1;
        split2(o[nt][0], o[nt][1], hi0, lo0);
        split2(o[nt][2], o[nt][3], hi1, lo1);
        *(uint32_t*)(aoh + g0) = hi0;
        *(uint32_t*)(aol + g0) = lo0;
        *(uint32_t*)(aoh + g1) = hi1;
        *(uint32_t*)(aol + g1) = lo1;
    }
}

// ---------------- launcher ---------------------------------------------------
extern "C" void kernel_launch(void* const* d_in, const int* in_sizes, int n_in,
                              void* d_out, int out_size) {
    const float* hs        = (const float*)d_in[0];
    const float* w_q       = (const float*)d_in[1];
    const float* w_k       = (const float*)d_in[2];
    const float* w_v       = (const float*)d_in[3];
    const float* w_o       = (const float*)d_in[4];
    const float* norm_c    = (const float*)d_in[5];
    const float* attn_mask = (const float*)d_in[6];
    const int*   pos_ids   = (const int*)d_in[7];
    float* out = (float*)d_out;

    float* cnts;
    cudaGetSymbolAddress((void**)&cnts, g_counts);

    __nv_bfloat16 *hs0, *hs1, *wq0, *wq1, *wk0, *wk1, *wv0, *wv1, *wo0, *wo1, *ao0, *ao1;
    __nv_bfloat16 *q0, *q1, *k0, *k1, *v0, *v1;
    cudaGetSymbolAddress((void**)&hs0, g_hs0);
    cudaGetSymbolAddress((void**)&hs1, g_hs1);
    cudaGetSymbolAddress((void**)&wq0, g_wq0);
    cudaGetSymbolAddress((void**)&wq1, g_wq1);
    cudaGetSymbolAddress((void**)&wk0, g_wk0);
    cudaGetSymbolAddress((void**)&wk1, g_wk1);
    cudaGetSymbolAddress((void**)&wv0, g_wv0);
    cudaGetSymbolAddress((void**)&wv1, g_wv1);
    cudaGetSymbolAddress((void**)&wo0, g_wo0);
    cudaGetSymbolAddress((void**)&wo1, g_wo1);
    cudaGetSymbolAddress((void**)&ao0, g_ao0);
    cudaGetSymbolAddress((void**)&ao1, g_ao1);
    cudaGetSymbolAddress((void**)&q0, g_q0);
    cudaGetSymbolAddress((void**)&q1, g_q1);
    cudaGetSymbolAddress((void**)&k0, g_k0);
    cudaGetSymbolAddress((void**)&k1, g_k1);
    cudaGetSymbolAddress((void**)&v0, g_v0);
    cudaGetSymbolAddress((void**)&v1, g_v1);

    static bool attr_set = false;
    if (!attr_set) {
        cudaFuncSetAttribute(mma_gemm_qkv_fused, cudaFuncAttributeMaxDynamicSharedMemorySize, QKV_SMEM);
        cudaFuncSetAttribute(mma_gemm_out, cudaFuncAttributeMaxDynamicSharedMemorySize, OUT_SMEM);
        cudaFuncSetAttribute(attn_mma, cudaFuncAttributeMaxDynamicSharedMemorySize, ATT_SMEM);
        attr_set = true;
    }

    counts_kernel<<<B_, S_>>>(attn_mask, cnts);

    split5_kernel<<<dim3(256, 5), 256>>>(hs, w_q, w_k, w_v, w_o,
                                         hs0, hs1, wq0, wq1, wk0, wk1,
                                         wv0, wv1, wo0, wo1);

    mma_gemm_qkv_fused<<<dim3(E_ / 128, NROWS / 64, 3), 256, QKV_SMEM>>>(
        hs0, hs1, wq0, wq1, wk0, wk1, wv0, wv1,
        attn_mask, norm_c, pos_ids, cnts,
        q0, q1, k0, k1, v0, v1);

    attn_mma<<<dim3(B_ * H_, S_ / AQM), 128, ATT_SMEM>>>(q0, q1, k0, k1, v0, v1, ao0, ao1);

    mma_gemm_out<<<dim3(E_ / 64, NROWS / 64), 256, OUT_SMEM>>>(ao0, ao1, wo0, wo1, out);
}

// round 9
// speedup vs baseline: 6.7775x; 1.0002x over previous
#include <cuda_runtime.h>
#include <cuda_bf16.h>
#include <math.h>
#include <stdint.h>

#define B_  2
#define S_  1024
#define E_  2048
#define H_  16
#define HD_ 128
#define ROT_ 64
#define NROWS (B_ * S_)
#define EPS_ 1e-12f

// ---------------- scratch ----------------------------------------------------
__device__ float g_counts[B_ * S_];

__device__ __nv_bfloat16 g_hs0[NROWS * E_], g_hs1[NROWS * E_];
__device__ __nv_bfloat16 g_wq0[E_ * E_],   g_wq1[E_ * E_];
__device__ __nv_bfloat16 g_wk0[E_ * E_],   g_wk1[E_ * E_];
__device__ __nv_bfloat16 g_wv0[E_ * E_],   g_wv1[E_ * E_];
__device__ __nv_bfloat16 g_wo0[E_ * E_],   g_wo1[E_ * E_];
__device__ __nv_bfloat16 g_ao0[NROWS * E_], g_ao1[NROWS * E_];

__device__ __nv_bfloat16 g_q0[B_ * H_ * S_ * HD_], g_q1[B_ * H_ * S_ * HD_];
__device__ __nv_bfloat16 g_k0[B_ * H_ * S_ * HD_], g_k1[B_ * H_ * S_ * HD_];
__device__ __nv_bfloat16 g_v0[B_ * H_ * S_ * HD_], g_v1[B_ * H_ * S_ * HD_];

// ---------------- PTX helpers ------------------------------------------------
__device__ __forceinline__ uint32_t smem_u32(const void* p) {
    uint32_t a;
    asm("{ .reg .u64 t; cvta.to.shared.u64 t, %1; cvt.u32.u64 %0, t; }" : "=r"(a) : "l"(p));
    return a;
}
#define CP16(dst, src) asm volatile("cp.async.cg.shared.global [%0], [%1], 16;" :: "r"(dst), "l"(src) : "memory")
#define CP_COMMIT() asm volatile("cp.async.commit_group;" ::: "memory")

#define LDSM4(r0, r1, r2, r3, addr) \
    asm volatile("ldmatrix.sync.aligned.m8n8.x4.shared.b16 {%0,%1,%2,%3}, [%4];" \
        : "=r"(r0), "=r"(r1), "=r"(r2), "=r"(r3) : "r"(addr))

#define LDSM4T(r0, r1, r2, r3, addr) \
    asm volatile("ldmatrix.sync.aligned.m8n8.x4.trans.shared.b16 {%0,%1,%2,%3}, [%4];" \
        : "=r"(r0), "=r"(r1), "=r"(r2), "=r"(r3) : "r"(addr))

#define MMA16816(c, a, br0, br1) \
    asm volatile("mma.sync.aligned.m16n8k16.row.col.f32.bf16.bf16.f32 " \
        "{%0,%1,%2,%3}, {%4,%5,%6,%7}, {%8,%9}, {%0,%1,%2,%3};" \
        : "+f"((c)[0]), "+f"((c)[1]), "+f"((c)[2]), "+f"((c)[3]) \
        : "r"((a)[0]), "r"((a)[1]), "r"((a)[2]), "r"((a)[3]), "r"(br0), "r"(br1))

__device__ __forceinline__ void split2(float x, float y, uint32_t& hi, uint32_t& lo) {
    __nv_bfloat16 hx = __float2bfloat16(x), hy = __float2bfloat16(y);
    __nv_bfloat16 lx = __float2bfloat16(x - __bfloat162float(hx));
    __nv_bfloat16 ly = __float2bfloat16(y - __bfloat162float(hy));
    hi = (uint32_t)__bfloat16_as_ushort(hx) | ((uint32_t)__bfloat16_as_ushort(hy) << 16);
    lo = (uint32_t)__bfloat16_as_ushort(lx) | ((uint32_t)__bfloat16_as_ushort(ly) << 16);
}

// ---------------- fused split fp32 -> bf16 hi/lo (5 tensors) -----------------
__global__ __launch_bounds__(256) void split5_kernel(
    const float* __restrict__ x0, const float* __restrict__ x1,
    const float* __restrict__ x2, const float* __restrict__ x3,
    const float* __restrict__ x4,
    __nv_bfloat16* __restrict__ h0, __nv_bfloat16* __restrict__ l0,
    __nv_bfloat16* __restrict__ h1, __nv_bfloat16* __restrict__ l1,
    __nv_bfloat16* __restrict__ h2, __nv_bfloat16* __restrict__ l2,
    __nv_bfloat16* __restrict__ h3, __nv_bfloat16* __restrict__ l3,
    __nv_bfloat16* __restrict__ h4, __nv_bfloat16* __restrict__ l4) {
    int z = blockIdx.y;
    const float* x = (z == 0) ? x0 : (z == 1) ? x1 : (z == 2) ? x2 : (z == 3) ? x3 : x4;
    __nv_bfloat16* hi = (z == 0) ? h0 : (z == 1) ? h1 : (z == 2) ? h2 : (z == 3) ? h3 : h4;
    __nv_bfloat16* lo = (z == 0) ? l0 : (z == 1) ? l1 : (z == 2) ? l2 : (z == 3) ? l3 : l4;
    const int n4 = NROWS * E_ / 4;
    for (int i = blockIdx.x * blockDim.x + threadIdx.x; i < n4; i += gridDim.x * blockDim.x) {
        float4 v = ((const float4*)x)[i];
        float vv[4] = {v.x, v.y, v.z, v.w};
        unsigned short hs[4], ls[4];
#pragma unroll
        for (int j = 0; j < 4; j++) {
            __nv_bfloat16 h = __float2bfloat16(vv[j]);
            __nv_bfloat16 l = __float2bfloat16(vv[j] - __bfloat162float(h));
            hs[j] = __bfloat16_as_ushort(h);
            ls[j] = __bfloat16_as_ushort(l);
        }
        uint2 ph = {(uint32_t)hs[0] | ((uint32_t)hs[1] << 16),
                    (uint32_t)hs[2] | ((uint32_t)hs[3] << 16)};
        uint2 pl = {(uint32_t)ls[0] | ((uint32_t)ls[1] << 16),
                    (uint32_t)ls[2] | ((uint32_t)ls[3] << 16)};
        ((uint2*)hi)[i] = ph;
        ((uint2*)lo)[i] = pl;
    }
}

// ============== QKV GEMM 64x128 tiles, fused epilogue ========================
#define KCH 32
#define NCHK (E_ / KCH)
#define ROWB 80
#define QAMAT (64 * ROWB)
#define QBMAT (128 * ROWB)
#define QSTG (2 * QAMAT + 2 * QBMAT)
#define QKV_SMEM (3 * QSTG)

__device__ __forceinline__ void qkv_load_chunk(uint32_t base, int t, int tid,
                                               const __nv_bfloat16* a0, const __nv_bfloat16* a1,
                                               const __nv_bfloat16* b0, const __nv_bfloat16* b1) {
    {
        int r = tid >> 2, c = tid & 3;
        size_t g = (size_t)r * E_ + t * KCH + c * 8;
        uint32_t d = base + r * ROWB + c * 16;
        CP16(d, a0 + g);
        CP16(d + QAMAT, a1 + g);
    }
    for (int i = tid; i < 512; i += 256) {
        int r = i >> 2, c = i & 3;
        size_t g = (size_t)r * E_ + t * KCH + c * 8;
        uint32_t d = base + 2 * QAMAT + r * ROWB + c * 16;
        CP16(d, b0 + g);
        CP16(d + QBMAT, b1 + g);
    }
    CP_COMMIT();
}

__global__ __launch_bounds__(256, 2) void mma_gemm_qkv_fused(
    const __nv_bfloat16* __restrict__ ha0, const __nv_bfloat16* __restrict__ ha1,
    const __nv_bfloat16* __restrict__ wq0, const __nv_bfloat16* __restrict__ wq1,
    const __nv_bfloat16* __restrict__ wk0, const __nv_bfloat16* __restrict__ wk1,
    const __nv_bfloat16* __restrict__ wv0, const __nv_bfloat16* __restrict__ wv1,
    const float* __restrict__ mask, const float* __restrict__ norm_const,
    const int* __restrict__ pos_ids, const float* __restrict__ counts,
    __nv_bfloat16* __restrict__ Qh, __nv_bfloat16* __restrict__ Ql,
    __nv_bfloat16* __restrict__ Kh, __nv_bfloat16* __restrict__ Kl,
    __nv_bfloat16* __restrict__ Vh, __nv_bfloat16* __restrict__ Vl) {
    extern __shared__ char smc[];
    uint32_t sb = smem_u32(smc);
    int tid = threadIdx.x;
    int lane = tid & 31;
    int wid = tid >> 5;
    int wm = wid >> 2;
    int wn = wid & 3;
    int z = blockIdx.z;
    int bm = blockIdx.y * 64;
    int bn = blockIdx.x * 128;

    const __nv_bfloat16* a0 = ha0 + (size_t)bm * E_;
    const __nv_bfloat16* a1 = ha1 + (size_t)bm * E_;
    const __nv_bfloat16* b0 = ((z == 0) ? wq0 : (z == 1) ? wk0 : wv0) + (size_t)bn * E_;
    const __nv_bfloat16* b1 = ((z == 0) ? wq1 : (z == 1) ? wk1 : wv1) + (size_t)bn * E_;

    float acc[2][4][4];
#pragma unroll
    for (int i = 0; i < 2; i++)
#pragma unroll
        for (int j = 0; j < 4; j++)
#pragma unroll
            for (int k = 0; k < 4; k++) acc[i][j][k] = 0.0f;

    qkv_load_chunk(sb, 0, tid, a0, a1, b0, b1);
    qkv_load_chunk(sb + QSTG, 1, tid, a0, a1, b0, b1);

    int arow = lane & 15;
    int acolb = ((lane >> 4) & 1) * 16;
    int brow = (lane & 7) + ((lane >> 4) << 3);
    int bcolb = ((lane >> 3) & 1) * 16;

    for (int t = 0; t < NCHK; t++) {
        if (t + 1 < NCHK) asm volatile("cp.async.wait_group 1;" ::: "memory");
        else              asm volatile("cp.async.wait_group 0;" ::: "memory");
        __syncthreads();
        if (t + 2 < NCHK) qkv_load_chunk(sb + ((t + 2) % 3) * QSTG, t + 2, tid, a0, a1, b0, b1);

        uint32_t st = sb + (t % 3) * QSTG;
        uint32_t aA0 = st + (wm * 32 + arow) * ROWB + acolb;
        uint32_t aA1 = aA0 + QAMAT;
        uint32_t aB0 = st + 2 * QAMAT + (wn * 32 + brow) * ROWB + bcolb;
        uint32_t aB1 = aB0 + QBMAT;

#pragma unroll
        for (int ks = 0; ks < 2; ks++) {
            uint32_t a0f[2][4], a1f[2][4], b0f[2][4], b1f[2][4];
#pragma unroll
            for (int mt = 0; mt < 2; mt++) {
                LDSM4(a0f[mt][0], a0f[mt][1], a0f[mt][2], a0f[mt][3], aA0 + mt * 16 * ROWB + ks * 32);
                LDSM4(a1f[mt][0], a1f[mt][1], a1f[mt][2], a1f[mt][3], aA1 + mt * 16 * ROWB + ks * 32);
            }
#pragma unroll
            for (int np = 0; np < 2; np++) {
                LDSM4(b0f[np][0], b0f[np][1], b0f[np][2], b0f[np][3], aB0 + np * 16 * ROWB + ks * 32);
                LDSM4(b1f[np][0], b1f[np][1], b1f[np][2], b1f[np][3], aB1 + np * 16 * ROWB + ks * 32);
            }
            // term-major issue: same-acc distance = 8 MMAs
#pragma unroll
            for (int mt = 0; mt < 2; mt++)
#pragma unroll
                for (int nt = 0; nt < 4; nt++) {
                    uint32_t* p0 = &b0f[nt >> 1][(nt & 1) * 2];
                    MMA16816(acc[mt][nt], a0f[mt], p0[0], p0[1]);
                }
#pragma unroll
            for (int mt = 0; mt < 2; mt++)
#pragma unroll
                for (int nt = 0; nt < 4; nt++) {
                    uint32_t* p1 = &b1f[nt >> 1][(nt & 1) * 2];
                    MMA16816(acc[mt][nt], a0f[mt], p1[0], p1[1]);
                }
#pragma unroll
            for (int mt = 0; mt < 2; mt++)
#pragma unroll
                for (int nt = 0; nt < 4; nt++) {
                    uint32_t* p0 = &b0f[nt >> 1][(nt & 1) * 2];
                    MMA16816(acc[mt][nt], a1f[mt], p0[0], p0[1]);
                }
        }
    }
    __syncthreads();

    // ---- fused epilogue
    float* rs = (float*)smc;
    int lr = lane >> 2;
    int lc = lane & 3;
    int col0 = wn * 32 + lc * 2;

    if (z < 2) {
        if (wn < 2) {
#pragma unroll
            for (int mt = 0; mt < 2; mt++) {
                int rg = bm + wm * 32 + mt * 16 + lr;
                float pos0 = (float)pos_ids[rg];
                float pos1 = (float)pos_ids[rg + 8];
#pragma unroll
                for (int nt = 0; nt < 4; nt++) {
                    float fi = (float)(wn * 16 + nt * 4 + lc);
                    float fr = __expf(-0.28782313662425575f * fi);
                    float s0, c0, s1, c1;
                    sincosf(pos0 * fr, &s0, &c0);
                    sincosf(pos1 * fr, &s1, &c1);
                    float x = acc[mt][nt][0], y = acc[mt][nt][1];
                    acc[mt][nt][0] = x * c0 - y * s0;
                    acc[mt][nt][1] = y * c0 + x * s0;
                    x = acc[mt][nt][2]; y = acc[mt][nt][3];
                    acc[mt][nt][2] = x * c1 - y * s1;
                    acc[mt][nt][3] = y * c1 + x * s1;
                }
            }
        }
#pragma unroll
        for (int mt = 0; mt < 2; mt++) {
            float s0 = 0.0f, s1 = 0.0f;
#pragma unroll
            for (int nt = 0; nt < 4; nt++) {
                s0 += acc[mt][nt][0] * acc[mt][nt][0] + acc[mt][nt][1] * acc[mt][nt][1];
                s1 += acc[mt][nt][2] * acc[mt][nt][2] + acc[mt][nt][3] * acc[mt][nt][3];
            }
            s0 += __shfl_xor_sync(0xffffffffu, s0, 1);
            s0 += __shfl_xor_sync(0xffffffffu, s0, 2);
            s1 += __shfl_xor_sync(0xffffffffu, s1, 1);
            s1 += __shfl_xor_sync(0xffffffffu, s1, 2);
            if (lc == 0) {
                rs[(wm * 32 + mt * 16 + lr) * 4 + wn] = s0;
                rs[(wm * 32 + mt * 16 + lr + 8) * 4 + wn] = s1;
            }
        }
    }
    __syncthreads();

    int h = bn >> 7;
    float sig = 1.0f / (1.0f + __expf(-norm_const[h]));
    __nv_bfloat16* OH = (z == 0) ? Qh : (z == 1) ? Kh : Vh;
    __nv_bfloat16* OL = (z == 0) ? Ql : (z == 1) ? Kl : Vl;

#pragma unroll
    for (int mt = 0; mt < 2; mt++) {
#pragma unroll
        for (int half = 0; half < 2; half++) {
            int rl = wm * 32 + mt * 16 + lr + half * 8;
            int rg = bm + rl;
            float m = (mask[rg] == 0.0f) ? 1.0f : 0.0f;
            float scl;
            if (z < 2) {
                float tot = rs[rl * 4] + rs[rl * 4 + 1] + rs[rl * 4 + 2] + rs[rl * 4 + 3];
                scl = m / fmaxf(sqrtf(tot), EPS_);
            } else {
                scl = m / fmaxf(powf(counts[rg], sig), 1.0f);
            }
            int b = rg >> 10;
            int s = rg & 1023;
            size_t dst = (((size_t)(b * H_ + h)) * S_ + s) * (size_t)HD_;
#pragma unroll
            for (int nt = 0; nt < 4; nt++) {
                int c = col0 + nt * 8;
                uint32_t hi, lo;
                split2(acc[mt][nt][2 * half] * scl, acc[mt][nt][2 * half + 1] * scl, hi, lo);
                *(uint32_t*)(OH + dst + c) = hi;
                *(uint32_t*)(OL + dst + c) = lo;
            }
        }
    }
}

// ============== Output projection GEMM 64x64 tiles ===========================
#define OMAT (64 * ROWB)
#define OSTG (4 * OMAT)
#define OUT_SMEM (3 * OSTG)

__device__ __forceinline__ void out_load_chunk(uint32_t base, int t, int tid,
                                               const __nv_bfloat16* a0, const __nv_bfloat16* a1,
                                               const __nv_bfloat16* b0, const __nv_bfloat16* b1) {
    int r = tid >> 2, c = tid & 3;
    size_t g = (size_t)r * E_ + t * KCH + c * 8;
    uint32_t d = base + r * ROWB + c * 16;
    CP16(d,            a0 + g);
    CP16(d + OMAT,     a1 + g);
    CP16(d + 2 * OMAT, b0 + g);
    CP16(d + 3 * OMAT, b1 + g);
    CP_COMMIT();
}

__global__ __launch_bounds__(256, 2) void mma_gemm_out(
    const __nv_bfloat16* __restrict__ ha0, const __nv_bfloat16* __restrict__ ha1,
    const __nv_bfloat16* __restrict__ hb0, const __nv_bfloat16* __restrict__ hb1,
    float* __restrict__ C) {
    extern __shared__ char smc[];
    uint32_t sb = smem_u32(smc);
    int tid = threadIdx.x;
    int lane = tid & 31;
    int wid = tid >> 5;
    int wm = wid >> 2;
    int wn = wid & 3;
    int bm = blockIdx.y * 64;
    int bn = blockIdx.x * 64;

    const __nv_bfloat16* a0 = ha0 + (size_t)bm * E_;
    const __nv_bfloat16* a1 = ha1 + (size_t)bm * E_;
    const __nv_bfloat16* b0 = hb0 + (size_t)bn * E_;
    const __nv_bfloat16* b1 = hb1 + (size_t)bn * E_;

    float acc[2][2][4];
#pragma unroll
    for (int i = 0; i < 2; i++)
#pragma unroll
        for (int j = 0; j < 2; j++)
#pragma unroll
            for (int k = 0; k < 4; k++) acc[i][j][k] = 0.0f;

    out_load_chunk(sb, 0, tid, a0, a1, b0, b1);
    out_load_chunk(sb + OSTG, 1, tid, a0, a1, b0, b1);

    int arow = lane & 15;
    int acolb = ((lane >> 4) & 1) * 16;
    int brow = (lane & 7) + ((lane >> 4) << 3);
    int bcolb = ((lane >> 3) & 1) * 16;

    for (int t = 0; t < NCHK; t++) {
        if (t + 1 < NCHK) asm volatile("cp.async.wait_group 1;" ::: "memory");
        else              asm volatile("cp.async.wait_group 0;" ::: "memory");
        __syncthreads();
        if (t + 2 < NCHK) out_load_chunk(sb + ((t + 2) % 3) * OSTG, t + 2, tid, a0, a1, b0, b1);

        uint32_t st = sb + (t % 3) * OSTG;
        uint32_t aA0 = st + (wm * 32 + arow) * ROWB + acolb;
        uint32_t aA1 = aA0 + OMAT;
        uint32_t aB0 = st + 2 * OMAT + (wn * 16 + brow) * ROWB + bcolb;
        uint32_t aB1 = aB0 + OMAT;

#pragma unroll
        for (int ks = 0; ks < 2; ks++) {
            uint32_t a0f[2][4], a1f[2][4], b0f[4], b1f[4];
#pragma unroll
            for (int mt = 0; mt < 2; mt++) {
                LDSM4(a0f[mt][0], a0f[mt][1], a0f[mt][2], a0f[mt][3], aA0 + mt * 16 * ROWB + ks * 32);
                LDSM4(a1f[mt][0], a1f[mt][1], a1f[mt][2], a1f[mt][3], aA1 + mt * 16 * ROWB + ks * 32);
            }
            LDSM4(b0f[0], b0f[1], b0f[2], b0f[3], aB0 + ks * 32);
            LDSM4(b1f[0], b1f[1], b1f[2], b1f[3], aB1 + ks * 32);
            // term-major issue: same-acc distance = 4 MMAs
#pragma unroll
            for (int mt = 0; mt < 2; mt++)
#pragma unroll
                for (int nt = 0; nt < 2; nt++)
                    MMA16816(acc[mt][nt], a0f[mt], b0f[nt * 2], b0f[nt * 2 + 1]);
#pragma unroll
            for (int mt = 0; mt < 2; mt++)
#pragma unroll
                for (int nt = 0; nt < 2; nt++)
                    MMA16816(acc[mt][nt], a0f[mt], b1f[nt * 2], b1f[nt * 2 + 1]);
#pragma unroll
            for (int mt = 0; mt < 2; mt++)
#pragma unroll
                for (int nt = 0; nt < 2; nt++)
                    MMA16816(acc[mt][nt], a1f[mt], b0f[nt * 2], b0f[nt * 2 + 1]);
        }
    }

    int row0 = bm + wm * 32 + (lane >> 2);
    int col0 = bn + wn * 16 + (lane & 3) * 2;
#pragma unroll
    for (int mt = 0; mt < 2; mt++) {
#pragma unroll
        for (int nt = 0; nt < 2; nt++) {
            int r = row0 + mt * 16;
            int c = col0 + nt * 8;
            float2 v0 = {acc[mt][nt][0], acc[mt][nt][1]};
            float2 v1 = {acc[mt][nt][2], acc[mt][nt][3]};
            *(float2*)&C[(size_t)r * E_ + c] = v0;
            *(float2*)&C[(size_t)(r + 8) * E_ + c] = v1;
        }
    }
}

// ---------------- mask prefix scan ------------------------------------------
__global__ void counts_kernel(const float* __restrict__ mask, float* __restrict__ counts) {
    __shared__ float sh[S_];
    int b = blockIdx.x;
    int t = threadIdx.x;
    sh[t] = (mask[b * S_ + t] == 0.0f) ? 1.0f : 0.0f;
    __syncthreads();
    for (int off = 1; off < S_; off <<= 1) {
        float add = (t >= off) ? sh[t - off] : 0.0f;
        __syncthreads();
        sh[t] += add;
        __syncthreads();
    }
    counts[b * S_ + t] = sh[t];
}

// ============== causal attention: 128 threads, AQM=64, AKC=32, 2 CTA/SM ======
#define AQM 64
#define AKC 32
#define RB 272
#define QMAT (AQM * RB)
#define KVMAT (AKC * RB)
#define KVSTG (4 * KVMAT)
#define ATT_SMEM (2 * QMAT + 2 * KVSTG)

__global__ __launch_bounds__(128, 2) void attn_mma(
    const __nv_bfloat16* __restrict__ qh, const __nv_bfloat16* __restrict__ ql,
    const __nv_bfloat16* __restrict__ kh, const __nv_bfloat16* __restrict__ kl,
    const __nv_bfloat16* __restrict__ vh, const __nv_bfloat16* __restrict__ vl,
    __nv_bfloat16* __restrict__ aoh, __nv_bfloat16* __restrict__ aol) {
    extern __shared__ char smc[];
    uint32_t sb = smem_u32(smc);
    uint32_t sQh = sb, sQl = sb + QMAT;
    uint32_t sKV = sb + 2 * QMAT;

    int tid = threadIdx.x;
    int lane = tid & 31;
    int wid = tid >> 5;
    int bh = blockIdx.x;
    int qt = (int)gridDim.y - 1 - (int)blockIdx.y;
    int q0 = qt * AQM;

    size_t base = (size_t)bh * S_ * HD_;
    const __nv_bfloat16* Qhb = qh + base;
    const __nv_bfloat16* Qlb = ql + base;
    const __nv_bfloat16* Khb = kh + base;
    const __nv_bfloat16* Klb = kl + base;
    const __nv_bfloat16* Vhb = vh + base;
    const __nv_bfloat16* Vlb = vl + base;

    for (int i = tid; i < 1024; i += 128) {
        int r = i >> 4, c = i & 15;
        size_t g = (size_t)(q0 + r) * HD_ + c * 8;
        CP16(sQh + r * RB + c * 16, Qhb + g);
        CP16(sQl + r * RB + c * 16, Qlb + g);
    }
    for (int i = tid; i < 512; i += 128) {
        int r = i >> 4, c = i & 15;
        size_t g = (size_t)r * HD_ + c * 8;
        uint32_t d = sKV + r * RB + c * 16;
        CP16(d, Khb + g);
        CP16(d + KVMAT, Klb + g);
        CP16(d + 2 * KVMAT, Vhb + g);
        CP16(d + 3 * KVMAT, Vlb + g);
    }
    CP_COMMIT();

    int nch = (q0 + AQM) / AKC;
    float o[16][4];
#pragma unroll
    for (int i = 0; i < 16; i++)
#pragma unroll
        for (int j = 0; j < 4; j++) o[i][j] = 0.0f;

    int arow = lane & 15;
    int acolb = ((lane >> 4) & 1) * 16;
    int brow = (lane & 7) + ((lane >> 4) << 3);
    int bcolb = ((lane >> 3) & 1) * 16;
    int vrow = (lane & 7) + (((lane >> 3) & 1) << 3);
    int vcolb = ((lane >> 4) & 1) * 16;
    int m0w = q0 + wid * 16;

    for (int t = 0; t < nch; t++) {
        asm volatile("cp.async.wait_group 0;" ::: "memory");
        __syncthreads();
        if (t + 1 < nch) {
            uint32_t nstg = sKV + ((t + 1) & 1) * KVSTG;
            int kc = (t + 1) * AKC;
            for (int i = tid; i < 512; i += 128) {
                int r = i >> 4, c = i & 15;
                size_t g = (size_t)(kc + r) * HD_ + c * 8;
                uint32_t d = nstg + r * RB + c * 16;
                CP16(d, Khb + g);
                CP16(d + KVMAT, Klb + g);
                CP16(d + 2 * KVMAT, Vhb + g);
                CP16(d + 3 * KVMAT, Vlb + g);
            }
            CP_COMMIT();
        }
        uint32_t stg = sKV + (t & 1) * KVSTG;

        float sacc[4][4];
#pragma unroll
        for (int i = 0; i < 4; i++)
#pragma unroll
            for (int j = 0; j < 4; j++) sacc[i][j] = 0.0f;

#pragma unroll
        for (int ds = 0; ds < 8; ds++) {
            uint32_t ah[4], al[4];
            uint32_t ad = sQh + (wid * 16 + arow) * RB + acolb + ds * 32;
            LDSM4(ah[0], ah[1], ah[2], ah[3], ad);
            LDSM4(al[0], al[1], al[2], al[3], ad + QMAT);
            uint32_t bhf[2][4], blf[2][4];
#pragma unroll
            for (int ng = 0; ng < 2; ng++) {
                uint32_t bd = stg + (ng * 16 + brow) * RB + bcolb + ds * 32;
                LDSM4(bhf[ng][0], bhf[ng][1], bhf[ng][2], bhf[ng][3], bd);
                LDSM4(blf[ng][0], blf[ng][1], blf[ng][2], blf[ng][3], bd + KVMAT);
            }
            // term-major: same-acc distance = 4 MMAs
#pragma unroll
            for (int nt = 0; nt < 4; nt++) {
                uint32_t* ph = &bhf[nt >> 1][(nt & 1) * 2];
                MMA16816(sacc[nt], ah, ph[0], ph[1]);
            }
#pragma unroll
            for (int nt = 0; nt < 4; nt++) {
                uint32_t* pl = &blf[nt >> 1][(nt & 1) * 2];
                MMA16816(sacc[nt], ah, pl[0], pl[1]);
            }
#pragma unroll
            for (int nt = 0; nt < 4; nt++) {
                uint32_t* ph = &bhf[nt >> 1][(nt & 1) * 2];
                MMA16816(sacc[nt], al, ph[0], ph[1]);
            }
        }

        int kcg = t * AKC;
        if (kcg + AKC - 1 > m0w) {
            int r0m = m0w + (lane >> 2);
            int r1m = r0m + 8;
#pragma unroll
            for (int nt = 0; nt < 4; nt++) {
                int cb = kcg + nt * 8 + (lane & 3) * 2;
                if (cb > r0m) sacc[nt][0] = 0.0f;
                if (cb + 1 > r0m) sacc[nt][1] = 0.0f;
                if (cb > r1m) sacc[nt][2] = 0.0f;
                if (cb + 1 > r1m) sacc[nt][3] = 0.0f;
            }
        }

#pragma unroll
        for (int ks = 0; ks < 2; ks++) {
            uint32_t ah[4], al[4];
            split2(sacc[2 * ks][0], sacc[2 * ks][1], ah[0], al[0]);
            split2(sacc[2 * ks][2], sacc[2 * ks][3], ah[1], al[1]);
            split2(sacc[2 * ks + 1][0], sacc[2 * ks + 1][1], ah[2], al[2]);
            split2(sacc[2 * ks + 1][2], sacc[2 * ks + 1][3], ah[3], al[3]);
#pragma unroll
            for (int ng = 0; ng < 8; ng++) {
                uint32_t bh4[4], bl4[4];
                uint32_t va = stg + 2 * KVMAT + (ks * 16 + vrow) * RB + vcolb + ng * 32;
                LDSM4T(bh4[0], bh4[1], bh4[2], bh4[3], va);
                LDSM4T(bl4[0], bl4[1], bl4[2], bl4[3], va + KVMAT);
                // interleave the two accs: same-acc distance = 2
                MMA16816(o[2 * ng], ah, bh4[0], bh4[1]);
                MMA16816(o[2 * ng + 1], ah, bh4[2], bh4[3]);
                MMA16816(o[2 * ng], ah, bl4[0], bl4[1]);
                MMA16816(o[2 * ng + 1], ah, bl4[2], bl4[3]);
                MMA16816(o[2 * ng], al, bh4[0], bh4[1]);
                MMA16816(o[2 * ng + 1], al, bh4[2], bh4[3]);
            }
        }
        __syncthreads();
    }

    int b = bh / H_;
    int h = bh % H_;
    int r0 = m0w + (lane >> 2);
#pragma unroll
    for (int nt = 0; nt < 16; nt++) {
        int col = nt * 8 + (lane & 3) * 2;
        size_t g0 = ((size_t)(b * S_ + r0)) * E_ + h * HD_ + col;
        size_t g1 = ((size_t)(b * S_ + r0 + 8)) * E_ + h * HD_ + col;
        uint32_t hi0, lo0, hi1, lo1;
        split2(o[nt][0], o[nt][1], hi0, lo0);
        split2(o[nt][2], o[nt][3], hi1, lo1);
        *(uint32_t*)(aoh + g0) = hi0;
        *(uint32_t*)(aol + g0) = lo0;
        *(uint32_t*)(aoh + g1) = hi1;
        *(uint32_t*)(aol + g1) = lo1;
    }
}

// ---------------- launcher ---------------------------------------------------
extern "C" void kernel_launch(void* const* d_in, const int* in_sizes, int n_in,
                              void* d_out, int out_size) {
    const float* hs        = (const float*)d_in[0];
    const float* w_q       = (const float*)d_in[1];
    const float* w_k       = (const float*)d_in[2];
    const float* w_v       = (const float*)d_in[3];
    const float* w_o       = (const float*)d_in[4];
    const float* norm_c    = (const float*)d_in[5];
    const float* attn_mask = (const float*)d_in[6];
    const int*   pos_ids   = (const int*)d_in[7];
    float* out = (float*)d_out;

    float* cnts;
    cudaGetSymbolAddress((void**)&cnts, g_counts);

    __nv_bfloat16 *hs0, *hs1, *wq0, *wq1, *wk0, *wk1, *wv0, *wv1, *wo0, *wo1, *ao0, *ao1;
    __nv_bfloat16 *q0, *q1, *k0, *k1, *v0, *v1;
    cudaGetSymbolAddress((void**)&hs0, g_hs0);
    cudaGetSymbolAddress((void**)&hs1, g_hs1);
    cudaGetSymbolAddress((void**)&wq0, g_wq0);
    cudaGetSymbolAddress((void**)&wq1, g_wq1);
    cudaGetSymbolAddress((void**)&wk0, g_wk0);
    cudaGetSymbolAddress((void**)&wk1, g_wk1);
    cudaGetSymbolAddress((void**)&wv0, g_wv0);
    cudaGetSymbolAddress((void**)&wv1, g_wv1);
    cudaGetSymbolAddress((void**)&wo0, g_wo0);
    cudaGetSymbolAddress((void**)&wo1, g_wo1);
    cudaGetSymbolAddress((void**)&ao0, g_ao0);
    cudaGetSymbolAddress((void**)&ao1, g_ao1);
    cudaGetSymbolAddress((void**)&q0, g_q0);
    cudaGetSymbolAddress((void**)&q1, g_q1);
    cudaGetSymbolAddress((void**)&k0, g_k0);
    cudaGetSymbolAddress((void**)&k1, g_k1);
    cudaGetSymbolAddress((void**)&v0, g_v0);
    cudaGetSymbolAddress((void**)&v1, g_v1);

    static bool attr_set = false;
    if (!attr_set) {
        cudaFuncSetAttribute(mma_gemm_qkv_fused, cudaFuncAttributeMaxDynamicSharedMemorySize, QKV_SMEM);
        cudaFuncSetAttribute(mma_gemm_out, cudaFuncAttributeMaxDynamicSharedMemorySize, OUT_SMEM);
        cudaFuncSetAttribute(attn_mma, cudaFuncAttributeMaxDynamicSharedMemorySize, ATT_SMEM);
        attr_set = true;
    }

    counts_kernel<<<B_, S_>>>(attn_mask, cnts);

    split5_kernel<<<dim3(256, 5), 256>>>(hs, w_q, w_k, w_v, w_o,
                                         hs0, hs1, wq0, wq1, wk0, wk1,
                                         wv0, wv1, wo0, wo1);

    mma_gemm_qkv_fused<<<dim3(E_ / 128, NROWS / 64, 3), 256, QKV_SMEM>>>(
        hs0, hs1, wq0, wq1, wk0, wk1, wv0, wv1,
        attn_mask, norm_c, pos_ids, cnts,
        q0, q1, k0, k1, v0, v1);

    attn_mma<<<dim3(B_ * H_, S_ / AQM), 128, ATT_SMEM>>>(q0, q1, k0, k1, v0, v1, ao0, ao1);

    mma_gemm_out<<<dim3(E_ / 64, NROWS / 64), 256, OUT_SMEM>>>(ao0, ao1, wo0, wo1, out);
}

// round 10
// speedup vs baseline: 9.8550x; 1.4541x over previous
#include <cuda_runtime.h>
#include <cuda_fp16.h>
#include <math.h>
#include <stdint.h>

#define B_  2
#define S_  1024
#define E_  2048
#define H_  16
#define HD_ 128
#define ROT_ 64
#define NROWS (B_ * S_)
#define EPS_ 1e-12f

// ---------------- scratch ----------------------------------------------------
__device__ float g_counts[B_ * S_];

// fp16 operands: left operands split hi/lo, right operands single
__device__ __half g_hs0[NROWS * E_], g_hs1[NROWS * E_];
__device__ __half g_wq0[E_ * E_];
__device__ __half g_wk0[E_ * E_];
__device__ __half g_wv0[E_ * E_];
__device__ __half g_wo0[E_ * E_];
__device__ __half g_ao0[NROWS * E_], g_ao1[NROWS * E_];

__device__ __half g_q0[B_ * H_ * S_ * HD_], g_q1[B_ * H_ * S_ * HD_];
__device__ __half g_k0[B_ * H_ * S_ * HD_];
__device__ __half g_v0[B_ * H_ * S_ * HD_];

// ---------------- PTX helpers ------------------------------------------------
__device__ __forceinline__ uint32_t smem_u32(const void* p) {
    uint32_t a;
    asm("{ .reg .u64 t; cvta.to.shared.u64 t, %1; cvt.u32.u64 %0, t; }" : "=r"(a) : "l"(p));
    return a;
}
#define CP16(dst, src) asm volatile("cp.async.cg.shared.global [%0], [%1], 16;" :: "r"(dst), "l"(src) : "memory")
#define CP_COMMIT() asm volatile("cp.async.commit_group;" ::: "memory")

#define LDSM4(r0, r1, r2, r3, addr) \
    asm volatile("ldmatrix.sync.aligned.m8n8.x4.shared.b16 {%0,%1,%2,%3}, [%4];" \
        : "=r"(r0), "=r"(r1), "=r"(r2), "=r"(r3) : "r"(addr))

#define LDSM4T(r0, r1, r2, r3, addr) \
    asm volatile("ldmatrix.sync.aligned.m8n8.x4.trans.shared.b16 {%0,%1,%2,%3}, [%4];" \
        : "=r"(r0), "=r"(r1), "=r"(r2), "=r"(r3) : "r"(addr))

#define MMAH(c, a, br0, br1) \
    asm volatile("mma.sync.aligned.m16n8k16.row.col.f32.f16.f16.f32 " \
        "{%0,%1,%2,%3}, {%4,%5,%6,%7}, {%8,%9}, {%0,%1,%2,%3};" \
        : "+f"((c)[0]), "+f"((c)[1]), "+f"((c)[2]), "+f"((c)[3]) \
        : "r"((a)[0]), "r"((a)[1]), "r"((a)[2]), "r"((a)[3]), "r"(br0), "r"(br1))

__device__ __forceinline__ uint32_t pack2h(float x, float y) {
    __half hx = __float2half_rn(x), hy = __float2half_rn(y);
    return (uint32_t)__half_as_ushort(hx) | ((uint32_t)__half_as_ushort(hy) << 16);
}
__device__ __forceinline__ void split2h(float x, float y, uint32_t& hi, uint32_t& lo) {
    __half hx = __float2half_rn(x), hy = __float2half_rn(y);
    __half lx = __float2half_rn(x - __half2float(hx));
    __half ly = __float2half_rn(y - __half2float(hy));
    hi = (uint32_t)__half_as_ushort(hx) | ((uint32_t)__half_as_ushort(hy) << 16);
    lo = (uint32_t)__half_as_ushort(lx) | ((uint32_t)__half_as_ushort(ly) << 16);
}

// ---------------- fused convert: hs -> hi/lo, weights -> hi only -------------
__global__ __launch_bounds__(256) void split5_kernel(
    const float* __restrict__ x0, const float* __restrict__ x1,
    const float* __restrict__ x2, const float* __restrict__ x3,
    const float* __restrict__ x4,
    __half* __restrict__ h0, __half* __restrict__ l0,
    __half* __restrict__ h1, __half* __restrict__ h2,
    __half* __restrict__ h3, __half* __restrict__ h4) {
    int z = blockIdx.y;
    const float* x = (z == 0) ? x0 : (z == 1) ? x1 : (z == 2) ? x2 : (z == 3) ? x3 : x4;
    __half* hi = (z == 0) ? h0 : (z == 1) ? h1 : (z == 2) ? h2 : (z == 3) ? h3 : h4;
    bool do_lo = (z == 0);
    const int n4 = NROWS * E_ / 4;
    for (int i = blockIdx.x * blockDim.x + threadIdx.x; i < n4; i += gridDim.x * blockDim.x) {
        float4 v = ((const float4*)x)[i];
        if (do_lo) {
            uint32_t ph0, pl0, ph1, pl1;
            split2h(v.x, v.y, ph0, pl0);
            split2h(v.z, v.w, ph1, pl1);
            ((uint2*)hi)[i] = make_uint2(ph0, ph1);
            ((uint2*)l0)[i] = make_uint2(pl0, pl1);
        } else {
            ((uint2*)hi)[i] = make_uint2(pack2h(v.x, v.y), pack2h(v.z, v.w));
        }
    }
}

// ============== QKV GEMM 64x128 tiles, fused epilogue ========================
// A = hs hi/lo (2 mats, 64 rows), B = weight single (1 mat, 128 rows).
#define KCH 32
#define NCHK (E_ / KCH)
#define ROWB 80
#define QAMAT (64 * ROWB)              // 5120
#define QBMAT (128 * ROWB)             // 10240
#define QSTG (2 * QAMAT + QBMAT)       // 20480
#define QKV_SMEM (3 * QSTG)            // 61440

__device__ __forceinline__ void qkv_load_chunk(uint32_t base, int t, int tid,
                                               const __half* a0, const __half* a1,
                                               const __half* b0) {
    {
        int r = tid >> 2, c = tid & 3;
        size_t g = (size_t)r * E_ + t * KCH + c * 8;
        uint32_t d = base + r * ROWB + c * 16;
        CP16(d, a0 + g);
        CP16(d + QAMAT, a1 + g);
    }
    for (int i = tid; i < 512; i += 256) {
        int r = i >> 2, c = i & 3;
        size_t g = (size_t)r * E_ + t * KCH + c * 8;
        CP16(base + 2 * QAMAT + r * ROWB + c * 16, b0 + g);
    }
    CP_COMMIT();
}

__global__ __launch_bounds__(256, 2) void mma_gemm_qkv_fused(
    const __half* __restrict__ ha0, const __half* __restrict__ ha1,
    const __half* __restrict__ wq0, const __half* __restrict__ wk0,
    const __half* __restrict__ wv0,
    const float* __restrict__ mask, const float* __restrict__ norm_const,
    const int* __restrict__ pos_ids, const float* __restrict__ counts,
    __half* __restrict__ Qh, __half* __restrict__ Ql,
    __half* __restrict__ Kh, __half* __restrict__ Vh) {
    extern __shared__ char smc[];
    uint32_t sb = smem_u32(smc);
    int tid = threadIdx.x;
    int lane = tid & 31;
    int wid = tid >> 5;
    int wm = wid >> 2;
    int wn = wid & 3;
    int z = blockIdx.z;
    int bm = blockIdx.y * 64;
    int bn = blockIdx.x * 128;

    const __half* a0 = ha0 + (size_t)bm * E_;
    const __half* a1 = ha1 + (size_t)bm * E_;
    const __half* b0 = ((z == 0) ? wq0 : (z == 1) ? wk0 : wv0) + (size_t)bn * E_;

    float acc[2][4][4];
#pragma unroll
    for (int i = 0; i < 2; i++)
#pragma unroll
        for (int j = 0; j < 4; j++)
#pragma unroll
            for (int k = 0; k < 4; k++) acc[i][j][k] = 0.0f;

    qkv_load_chunk(sb, 0, tid, a0, a1, b0);
    qkv_load_chunk(sb + QSTG, 1, tid, a0, a1, b0);

    int arow = lane & 15;
    int acolb = ((lane >> 4) & 1) * 16;
    int brow = (lane & 7) + ((lane >> 4) << 3);
    int bcolb = ((lane >> 3) & 1) * 16;

    for (int t = 0; t < NCHK; t++) {
        if (t + 1 < NCHK) asm volatile("cp.async.wait_group 1;" ::: "memory");
        else              asm volatile("cp.async.wait_group 0;" ::: "memory");
        __syncthreads();
        if (t + 2 < NCHK) qkv_load_chunk(sb + ((t + 2) % 3) * QSTG, t + 2, tid, a0, a1, b0);

        uint32_t st = sb + (t % 3) * QSTG;
        uint32_t aA0 = st + (wm * 32 + arow) * ROWB + acolb;
        uint32_t aA1 = aA0 + QAMAT;
        uint32_t aB0 = st + 2 * QAMAT + (wn * 32 + brow) * ROWB + bcolb;

#pragma unroll
        for (int ks = 0; ks < 2; ks++) {
            uint32_t a0f[2][4], a1f[2][4], b0f[2][4];
#pragma unroll
            for (int mt = 0; mt < 2; mt++) {
                LDSM4(a0f[mt][0], a0f[mt][1], a0f[mt][2], a0f[mt][3], aA0 + mt * 16 * ROWB + ks * 32);
                LDSM4(a1f[mt][0], a1f[mt][1], a1f[mt][2], a1f[mt][3], aA1 + mt * 16 * ROWB + ks * 32);
            }
#pragma unroll
            for (int np = 0; np < 2; np++)
                LDSM4(b0f[np][0], b0f[np][1], b0f[np][2], b0f[np][3], aB0 + np * 16 * ROWB + ks * 32);
            // term-major: hi term then lo term
#pragma unroll
            for (int mt = 0; mt < 2; mt++)
#pragma unroll
                for (int nt = 0; nt < 4; nt++) {
                    uint32_t* p0 = &b0f[nt >> 1][(nt & 1) * 2];
                    MMAH(acc[mt][nt], a0f[mt], p0[0], p0[1]);
                }
#pragma unroll
            for (int mt = 0; mt < 2; mt++)
#pragma unroll
                for (int nt = 0; nt < 4; nt++) {
                    uint32_t* p0 = &b0f[nt >> 1][(nt & 1) * 2];
                    MMAH(acc[mt][nt], a1f[mt], p0[0], p0[1]);
                }
        }
    }
    __syncthreads();

    // ---- fused epilogue: rope (cols<64, q/k) + L2 norm / count-scale + mask
    float* rs = (float*)smc;
    int lr = lane >> 2;
    int lc = lane & 3;
    int col0 = wn * 32 + lc * 2;

    if (z < 2) {
        if (wn < 2) {
#pragma unroll
            for (int mt = 0; mt < 2; mt++) {
                int rg = bm + wm * 32 + mt * 16 + lr;
                float pos0 = (float)pos_ids[rg];
                float pos1 = (float)pos_ids[rg + 8];
#pragma unroll
                for (int nt = 0; nt < 4; nt++) {
                    float fi = (float)(wn * 16 + nt * 4 + lc);
                    float fr = __expf(-0.28782313662425575f * fi);
                    float s0, c0, s1, c1;
                    sincosf(pos0 * fr, &s0, &c0);
                    sincosf(pos1 * fr, &s1, &c1);
                    float x = acc[mt][nt][0], y = acc[mt][nt][1];
                    acc[mt][nt][0] = x * c0 - y * s0;
                    acc[mt][nt][1] = y * c0 + x * s0;
                    x = acc[mt][nt][2]; y = acc[mt][nt][3];
                    acc[mt][nt][2] = x * c1 - y * s1;
                    acc[mt][nt][3] = y * c1 + x * s1;
                }
            }
        }
#pragma unroll
        for (int mt = 0; mt < 2; mt++) {
            float s0 = 0.0f, s1 = 0.0f;
#pragma unroll
            for (int nt = 0; nt < 4; nt++) {
                s0 += acc[mt][nt][0] * acc[mt][nt][0] + acc[mt][nt][1] * acc[mt][nt][1];
                s1 += acc[mt][nt][2] * acc[mt][nt][2] + acc[mt][nt][3] * acc[mt][nt][3];
            }
            s0 += __shfl_xor_sync(0xffffffffu, s0, 1);
            s0 += __shfl_xor_sync(0xffffffffu, s0, 2);
            s1 += __shfl_xor_sync(0xffffffffu, s1, 1);
            s1 += __shfl_xor_sync(0xffffffffu, s1, 2);
            if (lc == 0) {
                rs[(wm * 32 + mt * 16 + lr) * 4 + wn] = s0;
                rs[(wm * 32 + mt * 16 + lr + 8) * 4 + wn] = s1;
            }
        }
    }
    __syncthreads();

    int h = bn >> 7;
    float sig = 1.0f / (1.0f + __expf(-norm_const[h]));

#pragma unroll
    for (int mt = 0; mt < 2; mt++) {
#pragma unroll
        for (int half = 0; half < 2; half++) {
            int rl = wm * 32 + mt * 16 + lr + half * 8;
            int rg = bm + rl;
            float m = (mask[rg] == 0.0f) ? 1.0f : 0.0f;
            float scl;
            if (z < 2) {
                float tot = rs[rl * 4] + rs[rl * 4 + 1] + rs[rl * 4 + 2] + rs[rl * 4 + 3];
                scl = m / fmaxf(sqrtf(tot), EPS_);
            } else {
                scl = m / fmaxf(powf(counts[rg], sig), 1.0f);
            }
            int b = rg >> 10;
            int s = rg & 1023;
            size_t dst = (((size_t)(b * H_ + h)) * S_ + s) * (size_t)HD_;
            if (z == 0) {
#pragma unroll
                for (int nt = 0; nt < 4; nt++) {
                    int c = col0 + nt * 8;
                    uint32_t hi, lo;
                    split2h(acc[mt][nt][2 * half] * scl, acc[mt][nt][2 * half + 1] * scl, hi, lo);
                    *(uint32_t*)(Qh + dst + c) = hi;
                    *(uint32_t*)(Ql + dst + c) = lo;
                }
            } else {
                __half* O = (z == 1) ? Kh : Vh;
#pragma unroll
                for (int nt = 0; nt < 4; nt++) {
                    int c = col0 + nt * 8;
                    *(uint32_t*)(O + dst + c) =
                        pack2h(acc[mt][nt][2 * half] * scl, acc[mt][nt][2 * half + 1] * scl);
                }
            }
        }
    }
}

// ============== Output projection GEMM 64x64 tiles ===========================
// A = ao hi/lo (2 mats), B = wo single (1 mat).
#define OMAT (64 * ROWB)           // 5120
#define OSTG (3 * OMAT)            // 15360
#define OUT_SMEM (3 * OSTG)        // 46080

__device__ __forceinline__ void out_load_chunk(uint32_t base, int t, int tid,
                                               const __half* a0, const __half* a1,
                                               const __half* b0) {
    int r = tid >> 2, c = tid & 3;
    size_t g = (size_t)r * E_ + t * KCH + c * 8;
    uint32_t d = base + r * ROWB + c * 16;
    CP16(d,            a0 + g);
    CP16(d + OMAT,     a1 + g);
    CP16(d + 2 * OMAT, b0 + g);
    CP_COMMIT();
}

__global__ __launch_bounds__(256, 2) void mma_gemm_out(
    const __half* __restrict__ ha0, const __half* __restrict__ ha1,
    const __half* __restrict__ hb0,
    float* __restrict__ C) {
    extern __shared__ char smc[];
    uint32_t sb = smem_u32(smc);
    int tid = threadIdx.x;
    int lane = tid & 31;
    int wid = tid >> 5;
    int wm = wid >> 2;
    int wn = wid & 3;
    int bm = blockIdx.y * 64;
    int bn = blockIdx.x * 64;

    const __half* a0 = ha0 + (size_t)bm * E_;
    const __half* a1 = ha1 + (size_t)bm * E_;
    const __half* b0 = hb0 + (size_t)bn * E_;

    float acc[2][2][4];
#pragma unroll
    for (int i = 0; i < 2; i++)
#pragma unroll
        for (int j = 0; j < 2; j++)
#pragma unroll
            for (int k = 0; k < 4; k++) acc[i][j][k] = 0.0f;

    out_load_chunk(sb, 0, tid, a0, a1, b0);
    out_load_chunk(sb + OSTG, 1, tid, a0, a1, b0);

    int arow = lane & 15;
    int acolb = ((lane >> 4) & 1) * 16;
    int brow = (lane & 7) + ((lane >> 4) << 3);
    int bcolb = ((lane >> 3) & 1) * 16;

    for (int t = 0; t < NCHK; t++) {
        if (t + 1 < NCHK) asm volatile("cp.async.wait_group 1;" ::: "memory");
        else              asm volatile("cp.async.wait_group 0;" ::: "memory");
        __syncthreads();
        if (t + 2 < NCHK) out_load_chunk(sb + ((t + 2) % 3) * OSTG, t + 2, tid, a0, a1, b0);

        uint32_t st = sb + (t % 3) * OSTG;
        uint32_t aA0 = st + (wm * 32 + arow) * ROWB + acolb;
        uint32_t aA1 = aA0 + OMAT;
        uint32_t aB0 = st + 2 * OMAT + (wn * 16 + brow) * ROWB + bcolb;

#pragma unroll
        for (int ks = 0; ks < 2; ks++) {
            uint32_t a0f[2][4], a1f[2][4], b0f[4];
#pragma unroll
            for (int mt = 0; mt < 2; mt++) {
                LDSM4(a0f[mt][0], a0f[mt][1], a0f[mt][2], a0f[mt][3], aA0 + mt * 16 * ROWB + ks * 32);
                LDSM4(a1f[mt][0], a1f[mt][1], a1f[mt][2], a1f[mt][3], aA1 + mt * 16 * ROWB + ks * 32);
            }
            LDSM4(b0f[0], b0f[1], b0f[2], b0f[3], aB0 + ks * 32);
#pragma unroll
            for (int mt = 0; mt < 2; mt++)
#pragma unroll
                for (int nt = 0; nt < 2; nt++)
                    MMAH(acc[mt][nt], a0f[mt], b0f[nt * 2], b0f[nt * 2 + 1]);
#pragma unroll
            for (int mt = 0; mt < 2; mt++)
#pragma unroll
                for (int nt = 0; nt < 2; nt++)
                    MMAH(acc[mt][nt], a1f[mt], b0f[nt * 2], b0f[nt * 2 + 1]);
        }
    }

    int row0 = bm + wm * 32 + (lane >> 2);
    int col0 = bn + wn * 16 + (lane & 3) * 2;
#pragma unroll
    for (int mt = 0; mt < 2; mt++) {
#pragma unroll
        for (int nt = 0; nt < 2; nt++) {
            int r = row0 + mt * 16;
            int c = col0 + nt * 8;
            float2 v0 = {acc[mt][nt][0], acc[mt][nt][1]};
            float2 v1 = {acc[mt][nt][2], acc[mt][nt][3]};
            *(float2*)&C[(size_t)r * E_ + c] = v0;
            *(float2*)&C[(size_t)(r + 8) * E_ + c] = v1;
        }
    }
}

// ---------------- mask prefix scan ------------------------------------------
__global__ void counts_kernel(const float* __restrict__ mask, float* __restrict__ counts) {
    __shared__ float sh[S_];
    int b = blockIdx.x;
    int t = threadIdx.x;
    sh[t] = (mask[b * S_ + t] == 0.0f) ? 1.0f : 0.0f;
    __syncthreads();
    for (int off = 1; off < S_; off <<= 1) {
        float add = (t >= off) ? sh[t - off] : 0.0f;
        __syncthreads();
        sh[t] += add;
        __syncthreads();
    }
    counts[b * S_ + t] = sh[t];
}

// ============== causal attention: 128 threads, AQM=64, AKC=32, 2 CTA/SM ======
// Q hi/lo split; K, V single fp16.
#define AQM 64
#define AKC 32
#define RB 272
#define QMAT (AQM * RB)            // 17408
#define KVMAT (AKC * RB)           // 8704
#define KVSTG (2 * KVMAT)          // 17408: K, V
#define ATT_SMEM (2 * QMAT + 2 * KVSTG)   // 69632

__global__ __launch_bounds__(128, 2) void attn_mma(
    const __half* __restrict__ qh, const __half* __restrict__ ql,
    const __half* __restrict__ kh, const __half* __restrict__ vh,
    __half* __restrict__ aoh, __half* __restrict__ aol) {
    extern __shared__ char smc[];
    uint32_t sb = smem_u32(smc);
    uint32_t sQh = sb, sQl = sb + QMAT;
    uint32_t sKV = sb + 2 * QMAT;

    int tid = threadIdx.x;
    int lane = tid & 31;
    int wid = tid >> 5;
    int bh = blockIdx.x;
    int qt = (int)gridDim.y - 1 - (int)blockIdx.y;
    int q0 = qt * AQM;

    size_t base = (size_t)bh * S_ * HD_;
    const __half* Qhb = qh + base;
    const __half* Qlb = ql + base;
    const __half* Khb = kh + base;
    const __half* Vhb = vh + base;

    for (int i = tid; i < 1024; i += 128) {
        int r = i >> 4, c = i & 15;
        size_t g = (size_t)(q0 + r) * HD_ + c * 8;
        CP16(sQh + r * RB + c * 16, Qhb + g);
        CP16(sQl + r * RB + c * 16, Qlb + g);
    }
    for (int i = tid; i < 512; i += 128) {
        int r = i >> 4, c = i & 15;
        size_t g = (size_t)r * HD_ + c * 8;
        uint32_t d = sKV + r * RB + c * 16;
        CP16(d, Khb + g);
        CP16(d + KVMAT, Vhb + g);
    }
    CP_COMMIT();

    int nch = (q0 + AQM) / AKC;
    float o[16][4];
#pragma unroll
    for (int i = 0; i < 16; i++)
#pragma unroll
        for (int j = 0; j < 4; j++) o[i][j] = 0.0f;

    int arow = lane & 15;
    int acolb = ((lane >> 4) & 1) * 16;
    int brow = (lane & 7) + ((lane >> 4) << 3);
    int bcolb = ((lane >> 3) & 1) * 16;
    int vrow = (lane & 7) + (((lane >> 3) & 1) << 3);
    int vcolb = ((lane >> 4) & 1) * 16;
    int m0w = q0 + wid * 16;

    for (int t = 0; t < nch; t++) {
        asm volatile("cp.async.wait_group 0;" ::: "memory");
        __syncthreads();
        if (t + 1 < nch) {
            uint32_t nstg = sKV + ((t + 1) & 1) * KVSTG;
            int kc = (t + 1) * AKC;
            for (int i = tid; i < 512; i += 128) {
                int r = i >> 4, c = i & 15;
                size_t g = (size_t)(kc + r) * HD_ + c * 8;
                uint32_t d = nstg + r * RB + c * 16;
                CP16(d, Khb + g);
                CP16(d + KVMAT, Vhb + g);
            }
            CP_COMMIT();
        }
        uint32_t stg = sKV + (t & 1) * KVSTG;

        // ---- phase 1: S[16x32] = Q . K^T, 2-term
        float sacc[4][4];
#pragma unroll
        for (int i = 0; i < 4; i++)
#pragma unroll
            for (int j = 0; j < 4; j++) sacc[i][j] = 0.0f;

#pragma unroll
        for (int ds = 0; ds < 8; ds++) {
            uint32_t ah[4], al[4];
            uint32_t ad = sQh + (wid * 16 + arow) * RB + acolb + ds * 32;
            LDSM4(ah[0], ah[1], ah[2], ah[3], ad);
            LDSM4(al[0], al[1], al[2], al[3], ad + QMAT);
            uint32_t bhf[2][4];
#pragma unroll
            for (int ng = 0; ng < 2; ng++) {
                uint32_t bd = stg + (ng * 16 + brow) * RB + bcolb + ds * 32;
                LDSM4(bhf[ng][0], bhf[ng][1], bhf[ng][2], bhf[ng][3], bd);
            }
#pragma unroll
            for (int nt = 0; nt < 4; nt++) {
                uint32_t* ph = &bhf[nt >> 1][(nt & 1) * 2];
                MMAH(sacc[nt], ah, ph[0], ph[1]);
            }
#pragma unroll
            for (int nt = 0; nt < 4; nt++) {
                uint32_t* ph = &bhf[nt >> 1][(nt & 1) * 2];
                MMAH(sacc[nt], al, ph[0], ph[1]);
            }
        }

        // ---- causal mask
        int kcg = t * AKC;
        if (kcg + AKC - 1 > m0w) {
            int r0m = m0w + (lane >> 2);
            int r1m = r0m + 8;
#pragma unroll
            for (int nt = 0; nt < 4; nt++) {
                int cb = kcg + nt * 8 + (lane & 3) * 2;
                if (cb > r0m) sacc[nt][0] = 0.0f;
                if (cb + 1 > r0m) sacc[nt][1] = 0.0f;
                if (cb > r1m) sacc[nt][2] = 0.0f;
                if (cb + 1 > r1m) sacc[nt][3] = 0.0f;
            }
        }

        // ---- phase 2: O += S . V  (S split hi/lo, V single)
#pragma unroll
        for (int ks = 0; ks < 2; ks++) {
            uint32_t ah[4], al[4];
            split2h(sacc[2 * ks][0], sacc[2 * ks][1], ah[0], al[0]);
            split2h(sacc[2 * ks][2], sacc[2 * ks][3], ah[1], al[1]);
            split2h(sacc[2 * ks + 1][0], sacc[2 * ks + 1][1], ah[2], al[2]);
            split2h(sacc[2 * ks + 1][2], sacc[2 * ks + 1][3], ah[3], al[3]);
#pragma unroll
            for (int ng = 0; ng < 8; ng++) {
                uint32_t bv[4];
                uint32_t va = stg + KVMAT + (ks * 16 + vrow) * RB + vcolb + ng * 32;
                LDSM4T(bv[0], bv[1], bv[2], bv[3], va);
                MMAH(o[2 * ng], ah, bv[0], bv[1]);
                MMAH(o[2 * ng + 1], ah, bv[2], bv[3]);
                MMAH(o[2 * ng], al, bv[0], bv[1]);
                MMAH(o[2 * ng + 1], al, bv[2], bv[3]);
            }
        }
        __syncthreads();
    }

    int b = bh / H_;
    int h = bh % H_;
    int r0 = m0w + (lane >> 2);
#pragma unroll
    for (int nt = 0; nt < 16; nt++) {
        int col = nt * 8 + (lane & 3) * 2;
        size_t g0 = ((size_t)(b * S_ + r0)) * E_ + h * HD_ + col;
        size_t g1 = ((size_t)(b * S_ + r0 + 8)) * E_ + h * HD_ + col;
        uint32_t hi0, lo0, hi1, lo1;
        split2h(o[nt][0], o[nt][1], hi0, lo0);
        split2h(o[nt][2], o[nt][3], hi1, lo1);
        *(uint32_t*)(aoh + g0) = hi0;
        *(uint32_t*)(aol + g0) = lo0;
        *(uint32_t*)(aoh + g1) = hi1;
        *(uint32_t*)(aol + g1) = lo1;
    }
}

// ---------------- launcher ---------------------------------------------------
extern "C" void kernel_launch(void* const* d_in, const int* in_sizes, int n_in,
                              void* d_out, int out_size) {
    const float* hs        = (const float*)d_in[0];
    const float* w_q       = (const float*)d_in[1];
    const float* w_k       = (const float*)d_in[2];
    const float* w_v       = (const float*)d_in[3];
    const float* w_o       = (const float*)d_in[4];
    const float* norm_c    = (const float*)d_in[5];
    const float* attn_mask = (const float*)d_in[6];
    const int*   pos_ids   = (const int*)d_in[7];
    float* out = (float*)d_out;

    float* cnts;
    cudaGetSymbolAddress((void**)&cnts, g_counts);

    __half *hs0, *hs1, *wq0, *wk0, *wv0, *wo0, *ao0, *ao1;
    __half *q0, *q1, *k0, *v0;
    cudaGetSymbolAddress((void**)&hs0, g_hs0);
    cudaGetSymbolAddress((void**)&hs1, g_hs1);
    cudaGetSymbolAddress((void**)&wq0, g_wq0);
    cudaGetSymbolAddress((void**)&wk0, g_wk0);
    cudaGetSymbolAddress((void**)&wv0, g_wv0);
    cudaGetSymbolAddress((void**)&wo0, g_wo0);
    cudaGetSymbolAddress((void**)&ao0, g_ao0);
    cudaGetSymbolAddress((void**)&ao1, g_ao1);
    cudaGetSymbolAddress((void**)&q0, g_q0);
    cudaGetSymbolAddress((void**)&q1, g_q1);
    cudaGetSymbolAddress((void**)&k0, g_k0);
    cudaGetSymbolAddress((void**)&v0, g_v0);

    static bool attr_set = false;
    if (!attr_set) {
        cudaFuncSetAttribute(mma_gemm_qkv_fused, cudaFuncAttributeMaxDynamicSharedMemorySize, QKV_SMEM);
        cudaFuncSetAttribute(mma_gemm_out, cudaFuncAttributeMaxDynamicSharedMemorySize, OUT_SMEM);
        cudaFuncSetAttribute(attn_mma, cudaFuncAttributeMaxDynamicSharedMemorySize, ATT_SMEM);
        attr_set = true;
    }

    counts_kernel<<<B_, S_>>>(attn_mask, cnts);

    split5_kernel<<<dim3(256, 5), 256>>>(hs, w_q, w_k, w_v, w_o,
                                         hs0, hs1, wq0, wk0, wv0, wo0);

    mma_gemm_qkv_fused<<<dim3(E_ / 128, NROWS / 64, 3), 256, QKV_SMEM>>>(
        hs0, hs1, wq0, wk0, wv0,
        attn_mask, norm_c, pos_ids, cnts,
        q0, q1, k0, v0);

    attn_mma<<<dim3(B_ * H_, S_ / AQM), 128, ATT_SMEM>>>(q0, q1, k0, v0, ao0, ao1);

    mma_gemm_out<<<dim3(E_ / 64, NROWS / 64), 256, OUT_SMEM>>>(ao0, ao1, wo0, out);
}

// round 11
// speedup vs baseline: 10.0169x; 1.0164x over previous
#include <cuda_runtime.h>
#include <cuda_fp16.h>
#include <math.h>
#include <stdint.h>

#define B_  2
#define S_  1024
#define E_  2048
#define H_  16
#define HD_ 128
#define ROT_ 64
#define NROWS (B_ * S_)
#define EPS_ 1e-12f

// ---------------- scratch ----------------------------------------------------
__device__ float g_counts[B_ * S_];

__device__ __half g_hs0[NROWS * E_], g_hs1[NROWS * E_];
__device__ __half g_wq0[E_ * E_];
__device__ __half g_wk0[E_ * E_];
__device__ __half g_wv0[E_ * E_];
__device__ __half g_wo0[E_ * E_];
__device__ __half g_ao0[NROWS * E_], g_ao1[NROWS * E_];

__device__ __half g_q0[B_ * H_ * S_ * HD_], g_q1[B_ * H_ * S_ * HD_];
__device__ __half g_k0[B_ * H_ * S_ * HD_];
__device__ __half g_v0[B_ * H_ * S_ * HD_];

// ---------------- PTX helpers ------------------------------------------------
__device__ __forceinline__ uint32_t smem_u32(const void* p) {
    uint32_t a;
    asm("{ .reg .u64 t; cvta.to.shared.u64 t, %1; cvt.u32.u64 %0, t; }" : "=r"(a) : "l"(p));
    return a;
}
#define CP16(dst, src) asm volatile("cp.async.cg.shared.global [%0], [%1], 16;" :: "r"(dst), "l"(src) : "memory")
#define CP_COMMIT() asm volatile("cp.async.commit_group;" ::: "memory")

#define LDSM4(r0, r1, r2, r3, addr) \
    asm volatile("ldmatrix.sync.aligned.m8n8.x4.shared.b16 {%0,%1,%2,%3}, [%4];" \
        : "=r"(r0), "=r"(r1), "=r"(r2), "=r"(r3) : "r"(addr))

#define LDSM4T(r0, r1, r2, r3, addr) \
    asm volatile("ldmatrix.sync.aligned.m8n8.x4.trans.shared.b16 {%0,%1,%2,%3}, [%4];" \
        : "=r"(r0), "=r"(r1), "=r"(r2), "=r"(r3) : "r"(addr))

#define MMAH(c, a, br0, br1) \
    asm volatile("mma.sync.aligned.m16n8k16.row.col.f32.f16.f16.f32 " \
        "{%0,%1,%2,%3}, {%4,%5,%6,%7}, {%8,%9}, {%0,%1,%2,%3};" \
        : "+f"((c)[0]), "+f"((c)[1]), "+f"((c)[2]), "+f"((c)[3]) \
        : "r"((a)[0]), "r"((a)[1]), "r"((a)[2]), "r"((a)[3]), "r"(br0), "r"(br1))

__device__ __forceinline__ uint32_t pack2h(float x, float y) {
    __half hx = __float2half_rn(x), hy = __float2half_rn(y);
    return (uint32_t)__half_as_ushort(hx) | ((uint32_t)__half_as_ushort(hy) << 16);
}
__device__ __forceinline__ void split2h(float x, float y, uint32_t& hi, uint32_t& lo) {
    __half hx = __float2half_rn(x), hy = __float2half_rn(y);
    __half lx = __float2half_rn(x - __half2float(hx));
    __half ly = __float2half_rn(y - __half2float(hy));
    hi = (uint32_t)__half_as_ushort(hx) | ((uint32_t)__half_as_ushort(hy) << 16);
    lo = (uint32_t)__half_as_ushort(lx) | ((uint32_t)__half_as_ushort(ly) << 16);
}

// ---------------- fused convert ----------------------------------------------
__global__ __launch_bounds__(256) void split5_kernel(
    const float* __restrict__ x0, const float* __restrict__ x1,
    const float* __restrict__ x2, const float* __restrict__ x3,
    const float* __restrict__ x4,
    __half* __restrict__ h0, __half* __restrict__ l0,
    __half* __restrict__ h1, __half* __restrict__ h2,
    __half* __restrict__ h3, __half* __restrict__ h4) {
    int z = blockIdx.y;
    const float* x = (z == 0) ? x0 : (z == 1) ? x1 : (z == 2) ? x2 : (z == 3) ? x3 : x4;
    __half* hi = (z == 0) ? h0 : (z == 1) ? h1 : (z == 2) ? h2 : (z == 3) ? h3 : h4;
    bool do_lo = (z == 0);
    const int n4 = NROWS * E_ / 4;
    for (int i = blockIdx.x * blockDim.x + threadIdx.x; i < n4; i += gridDim.x * blockDim.x) {
        float4 v = ((const float4*)x)[i];
        if (do_lo) {
            uint32_t ph0, pl0, ph1, pl1;
            split2h(v.x, v.y, ph0, pl0);
            split2h(v.z, v.w, ph1, pl1);
            ((uint2*)hi)[i] = make_uint2(ph0, ph1);
            ((uint2*)l0)[i] = make_uint2(pl0, pl1);
        } else {
            ((uint2*)hi)[i] = make_uint2(pack2h(v.x, v.y), pack2h(v.z, v.w));
        }
    }
}

// ============== shared GEMM mainloop: CTA 64x128, 4 warps, warp 32x64 ========
// A = hi/lo split (2 mats, 64 rows), B = single (1 mat, 128 rows). K-chunk 32.
#define KCH 32
#define NCHK (E_ / KCH)
#define ROWB 80
#define GAMAT (64 * ROWB)              // 5120
#define GBMAT (128 * ROWB)             // 10240
#define GSTG (2 * GAMAT + GBMAT)       // 20480
#define GEMM_SMEM (3 * GSTG)           // 61440

__device__ __forceinline__ void g_load_chunk(uint32_t base, int t, int tid,
                                             const __half* a0, const __half* a1,
                                             const __half* b0) {
    for (int i = tid; i < 256; i += 128) {
        int r = i >> 2, c = i & 3;
        size_t g = (size_t)r * E_ + t * KCH + c * 8;
        uint32_t d = base + r * ROWB + c * 16;
        CP16(d, a0 + g);
        CP16(d + GAMAT, a1 + g);
    }
    for (int i = tid; i < 512; i += 128) {
        int r = i >> 2, c = i & 3;
        size_t g = (size_t)r * E_ + t * KCH + c * 8;
        CP16(base + 2 * GAMAT + r * ROWB + c * 16, b0 + g);
    }
    CP_COMMIT();
}

__device__ __forceinline__ void g_mainloop(uint32_t sb, int tid, int lane, int wid,
                                           const __half* a0, const __half* a1,
                                           const __half* b0, float acc[2][8][4]) {
    int wm = wid >> 1;     // 0..1 (32 rows)
    int wn = wid & 1;      // 0..1 (64 cols)

    g_load_chunk(sb, 0, tid, a0, a1, b0);
    g_load_chunk(sb + GSTG, 1, tid, a0, a1, b0);

    int arow = lane & 15;
    int acolb = ((lane >> 4) & 1) * 16;
    int brow = (lane & 7) + ((lane >> 4) << 3);
    int bcolb = ((lane >> 3) & 1) * 16;

    for (int t = 0; t < NCHK; t++) {
        if (t + 1 < NCHK) asm volatile("cp.async.wait_group 1;" ::: "memory");
        else              asm volatile("cp.async.wait_group 0;" ::: "memory");
        __syncthreads();
        if (t + 2 < NCHK) g_load_chunk(sb + ((t + 2) % 3) * GSTG, t + 2, tid, a0, a1, b0);

        uint32_t st = sb + (t % 3) * GSTG;
        uint32_t aA0 = st + (wm * 32 + arow) * ROWB + acolb;
        uint32_t aA1 = aA0 + GAMAT;
        uint32_t aB0 = st + 2 * GAMAT + (wn * 64 + brow) * ROWB + bcolb;

#pragma unroll
        for (int ks = 0; ks < 2; ks++) {
            uint32_t a0f[2][4], a1f[2][4], b0f[4][4];
#pragma unroll
            for (int mt = 0; mt < 2; mt++) {
                LDSM4(a0f[mt][0], a0f[mt][1], a0f[mt][2], a0f[mt][3], aA0 + mt * 16 * ROWB + ks * 32);
                LDSM4(a1f[mt][0], a1f[mt][1], a1f[mt][2], a1f[mt][3], aA1 + mt * 16 * ROWB + ks * 32);
            }
#pragma unroll
            for (int ng = 0; ng < 4; ng++)
                LDSM4(b0f[ng][0], b0f[ng][1], b0f[ng][2], b0f[ng][3], aB0 + ng * 16 * ROWB + ks * 32);
            // term-major: hi then lo
#pragma unroll
            for (int mt = 0; mt < 2; mt++)
#pragma unroll
                for (int nt = 0; nt < 8; nt++) {
                    uint32_t* p = &b0f[nt >> 1][(nt & 1) * 2];
                    MMAH(acc[mt][nt], a0f[mt], p[0], p[1]);
                }
#pragma unroll
            for (int mt = 0; mt < 2; mt++)
#pragma unroll
                for (int nt = 0; nt < 8; nt++) {
                    uint32_t* p = &b0f[nt >> 1][(nt & 1) * 2];
                    MMAH(acc[mt][nt], a1f[mt], p[0], p[1]);
                }
        }
    }
    __syncthreads();
}

// ============== QKV GEMM with fused rope/norm/scale epilogue =================
__global__ __launch_bounds__(128, 2) void mma_gemm_qkv_fused(
    const __half* __restrict__ ha0, const __half* __restrict__ ha1,
    const __half* __restrict__ wq0, const __half* __restrict__ wk0,
    const __half* __restrict__ wv0,
    const float* __restrict__ mask, const float* __restrict__ norm_const,
    const int* __restrict__ pos_ids, const float* __restrict__ counts,
    __half* __restrict__ Qh, __half* __restrict__ Ql,
    __half* __restrict__ Kh, __half* __restrict__ Vh) {
    extern __shared__ char smc[];
    uint32_t sb = smem_u32(smc);
    int tid = threadIdx.x;
    int lane = tid & 31;
    int wid = tid >> 5;
    int wm = wid >> 1;
    int wn = wid & 1;
    int z = blockIdx.z;
    int bm = blockIdx.y * 64;
    int bn = blockIdx.x * 128;

    const __half* a0 = ha0 + (size_t)bm * E_;
    const __half* a1 = ha1 + (size_t)bm * E_;
    const __half* b0 = ((z == 0) ? wq0 : (z == 1) ? wk0 : wv0) + (size_t)bn * E_;

    float acc[2][8][4];
#pragma unroll
    for (int i = 0; i < 2; i++)
#pragma unroll
        for (int j = 0; j < 8; j++)
#pragma unroll
            for (int k = 0; k < 4; k++) acc[i][j][k] = 0.0f;

    g_mainloop(sb, tid, lane, wid, a0, a1, b0, acc);

    // ---- fused epilogue: rope (cols<64) + L2 norm / count-scale + mask ------
    float* rs = (float*)smc;          // [64 rows][2 wn]
    int lr = lane >> 2;
    int lc = lane & 3;

    if (z < 2) {
        if (wn == 0) {                 // this warp owns cols 0..63 = all rotary
#pragma unroll
            for (int mt = 0; mt < 2; mt++) {
                int rg = bm + wm * 32 + mt * 16 + lr;
                float pos0 = (float)pos_ids[rg];
                float pos1 = (float)pos_ids[rg + 8];
#pragma unroll
                for (int nt = 0; nt < 8; nt++) {
                    float fi = (float)(nt * 4 + lc);
                    float fr = __expf(-0.28782313662425575f * fi);
                    float s0, c0, s1, c1;
                    sincosf(pos0 * fr, &s0, &c0);
                    sincosf(pos1 * fr, &s1, &c1);
                    float x = acc[mt][nt][0], y = acc[mt][nt][1];
                    acc[mt][nt][0] = x * c0 - y * s0;
                    acc[mt][nt][1] = y * c0 + x * s0;
                    x = acc[mt][nt][2]; y = acc[mt][nt][3];
                    acc[mt][nt][2] = x * c1 - y * s1;
                    acc[mt][nt][3] = y * c1 + x * s1;
                }
            }
        }
#pragma unroll
        for (int mt = 0; mt < 2; mt++) {
            float s0 = 0.0f, s1 = 0.0f;
#pragma unroll
            for (int nt = 0; nt < 8; nt++) {
                s0 += acc[mt][nt][0] * acc[mt][nt][0] + acc[mt][nt][1] * acc[mt][nt][1];
                s1 += acc[mt][nt][2] * acc[mt][nt][2] + acc[mt][nt][3] * acc[mt][nt][3];
            }
            s0 += __shfl_xor_sync(0xffffffffu, s0, 1);
            s0 += __shfl_xor_sync(0xffffffffu, s0, 2);
            s1 += __shfl_xor_sync(0xffffffffu, s1, 1);
            s1 += __shfl_xor_sync(0xffffffffu, s1, 2);
            if (lc == 0) {
                rs[(wm * 32 + mt * 16 + lr) * 2 + wn] = s0;
                rs[(wm * 32 + mt * 16 + lr + 8) * 2 + wn] = s1;
            }
        }
    }
    __syncthreads();

    int h = bn >> 7;
    float sig = 1.0f / (1.0f + __expf(-norm_const[h]));
    int col0 = wn * 64 + lc * 2;

#pragma unroll
    for (int mt = 0; mt < 2; mt++) {
#pragma unroll
        for (int half = 0; half < 2; half++) {
            int rl = wm * 32 + mt * 16 + lr + half * 8;
            int rg = bm + rl;
            float m = (mask[rg] == 0.0f) ? 1.0f : 0.0f;
            float scl;
            if (z < 2) {
                float tot = rs[rl * 2] + rs[rl * 2 + 1];
                scl = m / fmaxf(sqrtf(tot), EPS_);
            } else {
                scl = m / fmaxf(powf(counts[rg], sig), 1.0f);
            }
            int b = rg >> 10;
            int s = rg & 1023;
            size_t dst = (((size_t)(b * H_ + h)) * S_ + s) * (size_t)HD_;
            if (z == 0) {
#pragma unroll
                for (int nt = 0; nt < 8; nt++) {
                    int c = col0 + nt * 8;
                    uint32_t hi, lo;
                    split2h(acc[mt][nt][2 * half] * scl, acc[mt][nt][2 * half + 1] * scl, hi, lo);
                    *(uint32_t*)(Qh + dst + c) = hi;
                    *(uint32_t*)(Ql + dst + c) = lo;
                }
            } else {
                __half* O = (z == 1) ? Kh : Vh;
#pragma unroll
                for (int nt = 0; nt < 8; nt++) {
                    int c = col0 + nt * 8;
                    *(uint32_t*)(O + dst + c) =
                        pack2h(acc[mt][nt][2 * half] * scl, acc[mt][nt][2 * half + 1] * scl);
                }
            }
        }
    }
}

// ============== Output projection (same tile shape, fp32 epilogue) ===========
__global__ __launch_bounds__(128, 2) void mma_gemm_out(
    const __half* __restrict__ ha0, const __half* __restrict__ ha1,
    const __half* __restrict__ hb0,
    float* __restrict__ C) {
    extern __shared__ char smc[];
    uint32_t sb = smem_u32(smc);
    int tid = threadIdx.x;
    int lane = tid & 31;
    int wid = tid >> 5;
    int wm = wid >> 1;
    int wn = wid & 1;
    int bm = blockIdx.y * 64;
    int bn = blockIdx.x * 128;

    const __half* a0 = ha0 + (size_t)bm * E_;
    const __half* a1 = ha1 + (size_t)bm * E_;
    const __half* b0 = hb0 + (size_t)bn * E_;

    float acc[2][8][4];
#pragma unroll
    for (int i = 0; i < 2; i++)
#pragma unroll
        for (int j = 0; j < 8; j++)
#pragma unroll
            for (int k = 0; k < 4; k++) acc[i][j][k] = 0.0f;

    g_mainloop(sb, tid, lane, wid, a0, a1, b0, acc);

    int row0 = bm + wm * 32 + (lane >> 2);
    int col0 = bn + wn * 64 + (lane & 3) * 2;
#pragma unroll
    for (int mt = 0; mt < 2; mt++) {
#pragma unroll
        for (int nt = 0; nt < 8; nt++) {
            int r = row0 + mt * 16;
            int c = col0 + nt * 8;
            float2 v0 = {acc[mt][nt][0], acc[mt][nt][1]};
            float2 v1 = {acc[mt][nt][2], acc[mt][nt][3]};
            *(float2*)&C[(size_t)r * E_ + c] = v0;
            *(float2*)&C[(size_t)(r + 8) * E_ + c] = v1;
        }
    }
}

// ---------------- mask prefix scan ------------------------------------------
__global__ void counts_kernel(const float* __restrict__ mask, float* __restrict__ counts) {
    __shared__ float sh[S_];
    int b = blockIdx.x;
    int t = threadIdx.x;
    sh[t] = (mask[b * S_ + t] == 0.0f) ? 1.0f : 0.0f;
    __syncthreads();
    for (int off = 1; off < S_; off <<= 1) {
        float add = (t >= off) ? sh[t - off] : 0.0f;
        __syncthreads();
        sh[t] += add;
        __syncthreads();
    }
    counts[b * S_ + t] = sh[t];
}

// ============== causal attention (unchanged from R10) ========================
#define AQM 64
#define AKC 32
#define RB 272
#define QMAT (AQM * RB)
#define KVMAT (AKC * RB)
#define KVSTG (2 * KVMAT)
#define ATT_SMEM (2 * QMAT + 2 * KVSTG)

__global__ __launch_bounds__(128, 2) void attn_mma(
    const __half* __restrict__ qh, const __half* __restrict__ ql,
    const __half* __restrict__ kh, const __half* __restrict__ vh,
    __half* __restrict__ aoh, __half* __restrict__ aol) {
    extern __shared__ char smc[];
    uint32_t sb = smem_u32(smc);
    uint32_t sQh = sb, sQl = sb + QMAT;
    uint32_t sKV = sb + 2 * QMAT;

    int tid = threadIdx.x;
    int lane = tid & 31;
    int wid = tid >> 5;
    int bh = blockIdx.x;
    int qt = (int)gridDim.y - 1 - (int)blockIdx.y;
    int q0 = qt * AQM;

    size_t base = (size_t)bh * S_ * HD_;
    const __half* Qhb = qh + base;
    const __half* Qlb = ql + base;
    const __half* Khb = kh + base;
    const __half* Vhb = vh + base;

    for (int i = tid; i < 1024; i += 128) {
        int r = i >> 4, c = i & 15;
        size_t g = (size_t)(q0 + r) * HD_ + c * 8;
        CP16(sQh + r * RB + c * 16, Qhb + g);
        CP16(sQl + r * RB + c * 16, Qlb + g);
    }
    for (int i = tid; i < 512; i += 128) {
        int r = i >> 4, c = i & 15;
        size_t g = (size_t)r * HD_ + c * 8;
        uint32_t d = sKV + r * RB + c * 16;
        CP16(d, Khb + g);
        CP16(d + KVMAT, Vhb + g);
    }
    CP_COMMIT();

    int nch = (q0 + AQM) / AKC;
    float o[16][4];
#pragma unroll
    for (int i = 0; i < 16; i++)
#pragma unroll
        for (int j = 0; j < 4; j++) o[i][j] = 0.0f;

    int arow = lane & 15;
    int acolb = ((lane >> 4) & 1) * 16;
    int brow = (lane & 7) + ((lane >> 4) << 3);
    int bcolb = ((lane >> 3) & 1) * 16;
    int vrow = (lane & 7) + (((lane >> 3) & 1) << 3);
    int vcolb = ((lane >> 4) & 1) * 16;
    int m0w = q0 + wid * 16;

    for (int t = 0; t < nch; t++) {
        asm volatile("cp.async.wait_group 0;" ::: "memory");
        __syncthreads();
        if (t + 1 < nch) {
            uint32_t nstg = sKV + ((t + 1) & 1) * KVSTG;
            int kc = (t + 1) * AKC;
            for (int i = tid; i < 512; i += 128) {
                int r = i >> 4, c = i & 15;
                size_t g = (size_t)(kc + r) * HD_ + c * 8;
                uint32_t d = nstg + r * RB + c * 16;
                CP16(d, Khb + g);
                CP16(d + KVMAT, Vhb + g);
            }
            CP_COMMIT();
        }
        uint32_t stg = sKV + (t & 1) * KVSTG;

        float sacc[4][4];
#pragma unroll
        for (int i = 0; i < 4; i++)
#pragma unroll
            for (int j = 0; j < 4; j++) sacc[i][j] = 0.0f;

#pragma unroll
        for (int ds = 0; ds < 8; ds++) {
            uint32_t ah[4], al[4];
            uint32_t ad = sQh + (wid * 16 + arow) * RB + acolb + ds * 32;
            LDSM4(ah[0], ah[1], ah[2], ah[3], ad);
            LDSM4(al[0], al[1], al[2], al[3], ad + QMAT);
            uint32_t bhf[2][4];
#pragma unroll
            for (int ng = 0; ng < 2; ng++) {
                uint32_t bd = stg + (ng * 16 + brow) * RB + bcolb + ds * 32;
                LDSM4(bhf[ng][0], bhf[ng][1], bhf[ng][2], bhf[ng][3], bd);
            }
#pragma unroll
            for (int nt = 0; nt < 4; nt++) {
                uint32_t* ph = &bhf[nt >> 1][(nt & 1) * 2];
                MMAH(sacc[nt], ah, ph[0], ph[1]);
            }
#pragma unroll
            for (int nt = 0; nt < 4; nt++) {
                uint32_t* ph = &bhf[nt >> 1][(nt & 1) * 2];
                MMAH(sacc[nt], al, ph[0], ph[1]);
            }
        }

        int kcg = t * AKC;
        if (kcg + AKC - 1 > m0w) {
            int r0m = m0w + (lane >> 2);
            int r1m = r0m + 8;
#pragma unroll
            for (int nt = 0; nt < 4; nt++) {
                int cb = kcg + nt * 8 + (lane & 3) * 2;
                if (cb > r0m) sacc[nt][0] = 0.0f;
                if (cb + 1 > r0m) sacc[nt][1] = 0.0f;
                if (cb > r1m) sacc[nt][2] = 0.0f;
                if (cb + 1 > r1m) sacc[nt][3] = 0.0f;
            }
        }

#pragma unroll
        for (int ks = 0; ks < 2; ks++) {
            uint32_t ah[4], al[4];
            split2h(sacc[2 * ks][0], sacc[2 * ks][1], ah[0], al[0]);
            split2h(sacc[2 * ks][2], sacc[2 * ks][3], ah[1], al[1]);
            split2h(sacc[2 * ks + 1][0], sacc[2 * ks + 1][1], ah[2], al[2]);
            split2h(sacc[2 * ks + 1][2], sacc[2 * ks + 1][3], ah[3], al[3]);
#pragma unroll
            for (int ng = 0; ng < 8; ng++) {
                uint32_t bv[4];
                uint32_t va = stg + KVMAT + (ks * 16 + vrow) * RB + vcolb + ng * 32;
                LDSM4T(bv[0], bv[1], bv[2], bv[3], va);
                MMAH(o[2 * ng], ah, bv[0], bv[1]);
                MMAH(o[2 * ng + 1], ah, bv[2], bv[3]);
                MMAH(o[2 * ng], al, bv[0], bv[1]);
                MMAH(o[2 * ng + 1], al, bv[2], bv[3]);
            }
        }
        __syncthreads();
    }

    int b = bh / H_;
    int h = bh % H_;
    int r0 = m0w + (lane >> 2);
#pragma unroll
    for (int nt = 0; nt < 16; nt++) {
        int col = nt * 8 + (lane & 3) * 2;
        size_t g0 = ((size_t)(b * S_ + r0)) * E_ + h * HD_ + col;
        size_t g1 = ((size_t)(b * S_ + r0 + 8)) * E_ + h * HD_ + col;
        uint32_t hi0, lo0, hi1, lo1;
        split2h(o[nt][0], o[nt][1], hi0, lo0);
        split2h(o[nt][2], o[nt][3], hi1, lo1);
        *(uint32_t*)(aoh + g0) = hi0;
        *(uint32_t*)(aol + g0) = lo0;
        *(uint32_t*)(aoh + g1) = hi1;
        *(uint32_t*)(aol + g1) = lo1;
    }
}

// ---------------- launcher ---------------------------------------------------
extern "C" void kernel_launch(void* const* d_in, const int* in_sizes, int n_in,
                              void* d_out, int out_size) {
    const float* hs        = (const float*)d_in[0];
    const float* w_q       = (const float*)d_in[1];
    const float* w_k       = (const float*)d_in[2];
    const float* w_v       = (const float*)d_in[3];
    const float* w_o       = (const float*)d_in[4];
    const float* norm_c    = (const float*)d_in[5];
    const float* attn_mask = (const float*)d_in[6];
    const int*   pos_ids   = (const int*)d_in[7];
    float* out = (float*)d_out;

    float* cnts;
    cudaGetSymbolAddress((void**)&cnts, g_counts);

    __half *hs0, *hs1, *wq0, *wk0, *wv0, *wo0, *ao0, *ao1;
    __half *q0, *q1, *k0, *v0;
    cudaGetSymbolAddress((void**)&hs0, g_hs0);
    cudaGetSymbolAddress((void**)&hs1, g_hs1);
    cudaGetSymbolAddress((void**)&wq0, g_wq0);
    cudaGetSymbolAddress((void**)&wk0, g_wk0);
    cudaGetSymbolAddress((void**)&wv0, g_wv0);
    cudaGetSymbolAddress((void**)&wo0, g_wo0);
    cudaGetSymbolAddress((void**)&ao0, g_ao0);
    cudaGetSymbolAddress((void**)&ao1, g_ao1);
    cudaGetSymbolAddress((void**)&q0, g_q0);
    cudaGetSymbolAddress((void**)&q1, g_q1);
    cudaGetSymbolAddress((void**)&k0, g_k0);
    cudaGetSymbolAddress((void**)&v0, g_v0);

    static bool attr_set = false;
    if (!attr_set) {
        cudaFuncSetAttribute(mma_gemm_qkv_fused, cudaFuncAttributeMaxDynamicSharedMemorySize, GEMM_SMEM);
        cudaFuncSetAttribute(mma_gemm_out, cudaFuncAttributeMaxDynamicSharedMemorySize, GEMM_SMEM);
        cudaFuncSetAttribute(attn_mma, cudaFuncAttributeMaxDynamicSharedMemorySize, ATT_SMEM);
        attr_set = true;
    }

    counts_kernel<<<B_, S_>>>(attn_mask, cnts);

    split5_kernel<<<dim3(256, 5), 256>>>(hs, w_q, w_k, w_v, w_o,
                                         hs0, hs1, wq0, wk0, wv0, wo0);

    mma_gemm_qkv_fused<<<dim3(E_ / 128, NROWS / 64, 3), 128, GEMM_SMEM>>>(
        hs0, hs1, wq0, wk0, wv0,
        attn_mask, norm_c, pos_ids, cnts,
        q0, q1, k0, v0);

    attn_mma<<<dim3(B_ * H_, S_ / AQM), 128, ATT_SMEM>>>(q0, q1, k0, v0, ao0, ao1);

    mma_gemm_out<<<dim3(E_ / 128, NROWS / 64), 128, GEMM_SMEM>>>(ao0, ao1, wo0, out);
}

// round 12
// speedup vs baseline: 10.2929x; 1.0276x over previous
#include <cuda_runtime.h>
#include <cuda_fp16.h>
#include <math.h>
#include <stdint.h>

#define B_  2
#define S_  1024
#define E_  2048
#define H_  16
#define HD_ 128
#define ROT_ 64
#define NROWS (B_ * S_)
#define EPS_ 1e-12f
#define LSC 1024.0f
#define LSCI (1.0f / 1024.0f)

// ---------------- scratch ----------------------------------------------------
__device__ float g_counts[B_ * S_];

__device__ __half g_hs0[NROWS * E_], g_hs1[NROWS * E_];   // hs1 scaled x1024
__device__ __half g_wq0[E_ * E_];
__device__ __half g_wk0[E_ * E_];
__device__ __half g_wv0[E_ * E_];
__device__ __half g_wo0[E_ * E_];
__device__ __half g_ao0[NROWS * E_], g_ao1[NROWS * E_];   // ao1 scaled x1024

__device__ __half g_q0[B_ * H_ * S_ * HD_], g_q1[B_ * H_ * S_ * HD_];  // q1 scaled
__device__ __half g_k0[B_ * H_ * S_ * HD_];
__device__ __half g_v0[B_ * H_ * S_ * HD_];

// ---------------- PTX helpers ------------------------------------------------
__device__ __forceinline__ uint32_t smem_u32(const void* p) {
    uint32_t a;
    asm("{ .reg .u64 t; cvta.to.shared.u64 t, %1; cvt.u32.u64 %0, t; }" : "=r"(a) : "l"(p));
    return a;
}
#define CP16(dst, src) asm volatile("cp.async.cg.shared.global [%0], [%1], 16;" :: "r"(dst), "l"(src) : "memory")
#define CP_COMMIT() asm volatile("cp.async.commit_group;" ::: "memory")

#define LDSM4(r0, r1, r2, r3, addr) \
    asm volatile("ldmatrix.sync.aligned.m8n8.x4.shared.b16 {%0,%1,%2,%3}, [%4];" \
        : "=r"(r0), "=r"(r1), "=r"(r2), "=r"(r3) : "r"(addr))

#define LDSM4T(r0, r1, r2, r3, addr) \
    asm volatile("ldmatrix.sync.aligned.m8n8.x4.trans.shared.b16 {%0,%1,%2,%3}, [%4];" \
        : "=r"(r0), "=r"(r1), "=r"(r2), "=r"(r3) : "r"(addr))

// fp32-accumulate HMMA
#define MMAH(c, a, br0, br1) \
    asm volatile("mma.sync.aligned.m16n8k16.row.col.f32.f16.f16.f32 " \
        "{%0,%1,%2,%3}, {%4,%5,%6,%7}, {%8,%9}, {%0,%1,%2,%3};" \
        : "+f"((c)[0]), "+f"((c)[1]), "+f"((c)[2]), "+f"((c)[3]) \
        : "r"((a)[0]), "r"((a)[1]), "r"((a)[2]), "r"((a)[3]), "r"(br0), "r"(br1))

// fp16-accumulate HMMA (lo terms)
#define MMAH2(c, a, br0, br1) \
    asm volatile("mma.sync.aligned.m16n8k16.row.col.f16.f16.f16.f16 " \
        "{%0,%1}, {%2,%3,%4,%5}, {%6,%7}, {%0,%1};" \
        : "+r"((c)[0]), "+r"((c)[1]) \
        : "r"((a)[0]), "r"((a)[1]), "r"((a)[2]), "r"((a)[3]), "r"(br0), "r"(br1))

__device__ __forceinline__ void combine_lo(float* c, const uint32_t* cl) {
    __half2 h0 = *(const __half2*)&cl[0];
    __half2 h1 = *(const __half2*)&cl[1];
    float2 f0 = __half22float2(h0);
    float2 f1 = __half22float2(h1);
    c[0] += f0.x * LSCI;
    c[1] += f0.y * LSCI;
    c[2] += f1.x * LSCI;
    c[3] += f1.y * LSCI;
}

__device__ __forceinline__ uint32_t pack2h(float x, float y) {
    __half hx = __float2half_rn(x), hy = __float2half_rn(y);
    return (uint32_t)__half_as_ushort(hx) | ((uint32_t)__half_as_ushort(hy) << 16);
}
// lo scaled by 1024 (avoids fp16 denormals in lo-term accumulation)
__device__ __forceinline__ void split2h(float x, float y, uint32_t& hi, uint32_t& lo) {
    __half hx = __float2half_rn(x), hy = __float2half_rn(y);
    __half lx = __float2half_rn((x - __half2float(hx)) * LSC);
    __half ly = __float2half_rn((y - __half2float(hy)) * LSC);
    hi = (uint32_t)__half_as_ushort(hx) | ((uint32_t)__half_as_ushort(hy) << 16);
    lo = (uint32_t)__half_as_ushort(lx) | ((uint32_t)__half_as_ushort(ly) << 16);
}

// ---------------- fused convert ----------------------------------------------
__global__ __launch_bounds__(256) void split5_kernel(
    const float* __restrict__ x0, const float* __restrict__ x1,
    const float* __restrict__ x2, const float* __restrict__ x3,
    const float* __restrict__ x4,
    __half* __restrict__ h0, __half* __restrict__ l0,
    __half* __restrict__ h1, __half* __restrict__ h2,
    __half* __restrict__ h3, __half* __restrict__ h4) {
    int z = blockIdx.y;
    const float* x = (z == 0) ? x0 : (z == 1) ? x1 : (z == 2) ? x2 : (z == 3) ? x3 : x4;
    __half* hi = (z == 0) ? h0 : (z == 1) ? h1 : (z == 2) ? h2 : (z == 3) ? h3 : h4;
    bool do_lo = (z == 0);
    const int n4 = NROWS * E_ / 4;
    for (int i = blockIdx.x * blockDim.x + threadIdx.x; i < n4; i += gridDim.x * blockDim.x) {
        float4 v = ((const float4*)x)[i];
        if (do_lo) {
            uint32_t ph0, pl0, ph1, pl1;
            split2h(v.x, v.y, ph0, pl0);
            split2h(v.z, v.w, ph1, pl1);
            ((uint2*)hi)[i] = make_uint2(ph0, ph1);
            ((uint2*)l0)[i] = make_uint2(pl0, pl1);
        } else {
            ((uint2*)hi)[i] = make_uint2(pack2h(v.x, v.y), pack2h(v.z, v.w));
        }
    }
}

// ============== shared GEMM mainloop: CTA 64x128, 4 warps, warp 32x64 ========
#define KCH 32
#define NCHK (E_ / KCH)
#define ROWB 80
#define GAMAT (64 * ROWB)
#define GBMAT (128 * ROWB)
#define GSTG (2 * GAMAT + GBMAT)
#define GEMM_SMEM (3 * GSTG)

__device__ __forceinline__ void g_load_chunk(uint32_t base, int t, int tid,
                                             const __half* a0, const __half* a1,
                                             const __half* b0) {
    for (int i = tid; i < 256; i += 128) {
        int r = i >> 2, c = i & 3;
        size_t g = (size_t)r * E_ + t * KCH + c * 8;
        uint32_t d = base + r * ROWB + c * 16;
        CP16(d, a0 + g);
        CP16(d + GAMAT, a1 + g);
    }
    for (int i = tid; i < 512; i += 128) {
        int r = i >> 2, c = i & 3;
        size_t g = (size_t)r * E_ + t * KCH + c * 8;
        CP16(base + 2 * GAMAT + r * ROWB + c * 16, b0 + g);
    }
    CP_COMMIT();
}

__device__ __forceinline__ void g_mainloop(uint32_t sb, int tid, int lane, int wid,
                                           const __half* a0, const __half* a1,
                                           const __half* b0, float acc[2][8][4]) {
    int wm = wid >> 1;
    int wn = wid & 1;

    uint32_t accl[2][8][2];
#pragma unroll
    for (int i = 0; i < 2; i++)
#pragma unroll
        for (int j = 0; j < 8; j++) { accl[i][j][0] = 0u; accl[i][j][1] = 0u; }

    g_load_chunk(sb, 0, tid, a0, a1, b0);
    g_load_chunk(sb + GSTG, 1, tid, a0, a1, b0);

    int arow = lane & 15;
    int acolb = ((lane >> 4) & 1) * 16;
    int brow = (lane & 7) + ((lane >> 4) << 3);
    int bcolb = ((lane >> 3) & 1) * 16;

    for (int t = 0; t < NCHK; t++) {
        if (t + 1 < NCHK) asm volatile("cp.async.wait_group 1;" ::: "memory");
        else              asm volatile("cp.async.wait_group 0;" ::: "memory");
        __syncthreads();
        if (t + 2 < NCHK) g_load_chunk(sb + ((t + 2) % 3) * GSTG, t + 2, tid, a0, a1, b0);

        uint32_t st = sb + (t % 3) * GSTG;
        uint32_t aA0 = st + (wm * 32 + arow) * ROWB + acolb;
        uint32_t aA1 = aA0 + GAMAT;
        uint32_t aB0 = st + 2 * GAMAT + (wn * 64 + brow) * ROWB + bcolb;

#pragma unroll
        for (int ks = 0; ks < 2; ks++) {
            uint32_t a0f[2][4], a1f[2][4], b0f[4][4];
#pragma unroll
            for (int mt = 0; mt < 2; mt++) {
                LDSM4(a0f[mt][0], a0f[mt][1], a0f[mt][2], a0f[mt][3], aA0 + mt * 16 * ROWB + ks * 32);
                LDSM4(a1f[mt][0], a1f[mt][1], a1f[mt][2], a1f[mt][3], aA1 + mt * 16 * ROWB + ks * 32);
            }
#pragma unroll
            for (int ng = 0; ng < 4; ng++)
                LDSM4(b0f[ng][0], b0f[ng][1], b0f[ng][2], b0f[ng][3], aB0 + ng * 16 * ROWB + ks * 32);
            // hi term: fp32 accumulate
#pragma unroll
            for (int mt = 0; mt < 2; mt++)
#pragma unroll
                for (int nt = 0; nt < 8; nt++) {
                    uint32_t* p = &b0f[nt >> 1][(nt & 1) * 2];
                    MMAH(acc[mt][nt], a0f[mt], p[0], p[1]);
                }
            // lo term: fp16 accumulate (scaled x1024)
#pragma unroll
            for (int mt = 0; mt < 2; mt++)
#pragma unroll
                for (int nt = 0; nt < 8; nt++) {
                    uint32_t* p = &b0f[nt >> 1][(nt & 1) * 2];
                    MMAH2(accl[mt][nt], a1f[mt], p[0], p[1]);
                }
        }
    }
#pragma unroll
    for (int mt = 0; mt < 2; mt++)
#pragma unroll
        for (int nt = 0; nt < 8; nt++)
            combine_lo(acc[mt][nt], accl[mt][nt]);
    __syncthreads();
}

// ============== QKV GEMM with fused rope/norm/scale epilogue =================
__global__ __launch_bounds__(128, 2) void mma_gemm_qkv_fused(
    const __half* __restrict__ ha0, const __half* __restrict__ ha1,
    const __half* __restrict__ wq0, const __half* __restrict__ wk0,
    const __half* __restrict__ wv0,
    const float* __restrict__ mask, const float* __restrict__ norm_const,
    const int* __restrict__ pos_ids, const float* __restrict__ counts,
    __half* __restrict__ Qh, __half* __restrict__ Ql,
    __half* __restrict__ Kh, __half* __restrict__ Vh) {
    extern __shared__ char smc[];
    uint32_t sb = smem_u32(smc);
    int tid = threadIdx.x;
    int lane = tid & 31;
    int wid = tid >> 5;
    int wm = wid >> 1;
    int wn = wid & 1;
    int z = blockIdx.z;
    int bm = blockIdx.y * 64;
    int bn = blockIdx.x * 128;

    const __half* a0 = ha0 + (size_t)bm * E_;
    const __half* a1 = ha1 + (size_t)bm * E_;
    const __half* b0 = ((z == 0) ? wq0 : (z == 1) ? wk0 : wv0) + (size_t)bn * E_;

    float acc[2][8][4];
#pragma unroll
    for (int i = 0; i < 2; i++)
#pragma unroll
        for (int j = 0; j < 8; j++)
#pragma unroll
            for (int k = 0; k < 4; k++) acc[i][j][k] = 0.0f;

    g_mainloop(sb, tid, lane, wid, a0, a1, b0, acc);

    float* rs = (float*)smc;
    int lr = lane >> 2;
    int lc = lane & 3;

    if (z < 2) {
        if (wn == 0) {
#pragma unroll
            for (int mt = 0; mt < 2; mt++) {
                int rg = bm + wm * 32 + mt * 16 + lr;
                float pos0 = (float)pos_ids[rg];
                float pos1 = (float)pos_ids[rg + 8];
#pragma unroll
                for (int nt = 0; nt < 8; nt++) {
                    float fi = (float)(nt * 4 + lc);
                    float fr = __expf(-0.28782313662425575f * fi);
                    float s0, c0, s1, c1;
                    sincosf(pos0 * fr, &s0, &c0);
                    sincosf(pos1 * fr, &s1, &c1);
                    float x = acc[mt][nt][0], y = acc[mt][nt][1];
                    acc[mt][nt][0] = x * c0 - y * s0;
                    acc[mt][nt][1] = y * c0 + x * s0;
                    x = acc[mt][nt][2]; y = acc[mt][nt][3];
                    acc[mt][nt][2] = x * c1 - y * s1;
                    acc[mt][nt][3] = y * c1 + x * s1;
                }
            }
        }
#pragma unroll
        for (int mt = 0; mt < 2; mt++) {
            float s0 = 0.0f, s1 = 0.0f;
#pragma unroll
            for (int nt = 0; nt < 8; nt++) {
                s0 += acc[mt][nt][0] * acc[mt][nt][0] + acc[mt][nt][1] * acc[mt][nt][1];
                s1 += acc[mt][nt][2] * acc[mt][nt][2] + acc[mt][nt][3] * acc[mt][nt][3];
            }
            s0 += __shfl_xor_sync(0xffffffffu, s0, 1);
            s0 += __shfl_xor_sync(0xffffffffu, s0, 2);
            s1 += __shfl_xor_sync(0xffffffffu, s1, 1);
            s1 += __shfl_xor_sync(0xffffffffu, s1, 2);
            if (lc == 0) {
                rs[(wm * 32 + mt * 16 + lr) * 2 + wn] = s0;
                rs[(wm * 32 + mt * 16 + lr + 8) * 2 + wn] = s1;
            }
        }
    }
    __syncthreads();

    int h = bn >> 7;
    float sig = 1.0f / (1.0f + __expf(-norm_const[h]));
    int col0 = wn * 64 + lc * 2;

#pragma unroll
    for (int mt = 0; mt < 2; mt++) {
#pragma unroll
        for (int half = 0; half < 2; half++) {
            int rl = wm * 32 + mt * 16 + lr + half * 8;
            int rg = bm + rl;
            float m = (mask[rg] == 0.0f) ? 1.0f : 0.0f;
            float scl;
            if (z < 2) {
                float tot = rs[rl * 2] + rs[rl * 2 + 1];
                scl = m / fmaxf(sqrtf(tot), EPS_);
            } else {
                scl = m / fmaxf(powf(counts[rg], sig), 1.0f);
            }
            int b = rg >> 10;
            int s = rg & 1023;
            size_t dst = (((size_t)(b * H_ + h)) * S_ + s) * (size_t)HD_;
            if (z == 0) {
#pragma unroll
                for (int nt = 0; nt < 8; nt++) {
                    int c = col0 + nt * 8;
                    uint32_t hi, lo;
                    split2h(acc[mt][nt][2 * half] * scl, acc[mt][nt][2 * half + 1] * scl, hi, lo);
                    *(uint32_t*)(Qh + dst + c) = hi;
                    *(uint32_t*)(Ql + dst + c) = lo;
                }
            } else {
                __half* O = (z == 1) ? Kh : Vh;
#pragma unroll
                for (int nt = 0; nt < 8; nt++) {
                    int c = col0 + nt * 8;
                    *(uint32_t*)(O + dst + c) =
                        pack2h(acc[mt][nt][2 * half] * scl, acc[mt][nt][2 * half + 1] * scl);
                }
            }
        }
    }
}

// ============== Output projection ============================================
__global__ __launch_bounds__(128, 2) void mma_gemm_out(
    const __half* __restrict__ ha0, const __half* __restrict__ ha1,
    const __half* __restrict__ hb0,
    float* __restrict__ C) {
    extern __shared__ char smc[];
    uint32_t sb = smem_u32(smc);
    int tid = threadIdx.x;
    int lane = tid & 31;
    int wid = tid >> 5;
    int wm = wid >> 1;
    int wn = wid & 1;
    int bm = blockIdx.y * 64;
    int bn = blockIdx.x * 128;

    const __half* a0 = ha0 + (size_t)bm * E_;
    const __half* a1 = ha1 + (size_t)bm * E_;
    const __half* b0 = hb0 + (size_t)bn * E_;

    float acc[2][8][4];
#pragma unroll
    for (int i = 0; i < 2; i++)
#pragma unroll
        for (int j = 0; j < 8; j++)
#pragma unroll
            for (int k = 0; k < 4; k++) acc[i][j][k] = 0.0f;

    g_mainloop(sb, tid, lane, wid, a0, a1, b0, acc);

    int row0 = bm + wm * 32 + (lane >> 2);
    int col0 = bn + wn * 64 + (lane & 3) * 2;
#pragma unroll
    for (int mt = 0; mt < 2; mt++) {
#pragma unroll
        for (int nt = 0; nt < 8; nt++) {
            int r = row0 + mt * 16;
            int c = col0 + nt * 8;
            float2 v0 = {acc[mt][nt][0], acc[mt][nt][1]};
            float2 v1 = {acc[mt][nt][2], acc[mt][nt][3]};
            *(float2*)&C[(size_t)r * E_ + c] = v0;
            *(float2*)&C[(size_t)(r + 8) * E_ + c] = v1;
        }
    }
}

// ---------------- mask prefix scan ------------------------------------------
__global__ void counts_kernel(const float* __restrict__ mask, float* __restrict__ counts) {
    __shared__ float sh[S_];
    int b = blockIdx.x;
    int t = threadIdx.x;
    sh[t] = (mask[b * S_ + t] == 0.0f) ? 1.0f : 0.0f;
    __syncthreads();
    for (int off = 1; off < S_; off <<= 1) {
        float add = (t >= off) ? sh[t - off] : 0.0f;
        __syncthreads();
        sh[t] += add;
        __syncthreads();
    }
    counts[b * S_ + t] = sh[t];
}

// ============== causal attention =============================================
#define AQM 64
#define AKC 32
#define RB 272
#define QMAT (AQM * RB)
#define KVMAT (AKC * RB)
#define KVSTG (2 * KVMAT)
#define ATT_SMEM (2 * QMAT + 2 * KVSTG)

__global__ __launch_bounds__(128, 2) void attn_mma(
    const __half* __restrict__ qh, const __half* __restrict__ ql,
    const __half* __restrict__ kh, const __half* __restrict__ vh,
    __half* __restrict__ aoh, __half* __restrict__ aol) {
    extern __shared__ char smc[];
    uint32_t sb = smem_u32(smc);
    uint32_t sQh = sb, sQl = sb + QMAT;
    uint32_t sKV = sb + 2 * QMAT;

    int tid = threadIdx.x;
    int lane = tid & 31;
    int wid = tid >> 5;
    int bh = blockIdx.x;
    int qt = (int)gridDim.y - 1 - (int)blockIdx.y;
    int q0 = qt * AQM;

    size_t base = (size_t)bh * S_ * HD_;
    const __half* Qhb = qh + base;
    const __half* Qlb = ql + base;
    const __half* Khb = kh + base;
    const __half* Vhb = vh + base;

    for (int i = tid; i < 1024; i += 128) {
        int r = i >> 4, c = i & 15;
        size_t g = (size_t)(q0 + r) * HD_ + c * 8;
        CP16(sQh + r * RB + c * 16, Qhb + g);
        CP16(sQl + r * RB + c * 16, Qlb + g);
    }
    for (int i = tid; i < 512; i += 128) {
        int r = i >> 4, c = i & 15;
        size_t g = (size_t)r * HD_ + c * 8;
        uint32_t d = sKV + r * RB + c * 16;
        CP16(d, Khb + g);
        CP16(d + KVMAT, Vhb + g);
    }
    CP_COMMIT();

    int nch = (q0 + AQM) / AKC;
    float o[16][4];
    uint32_t ol[16][2];
#pragma unroll
    for (int i = 0; i < 16; i++) {
#pragma unroll
        for (int j = 0; j < 4; j++) o[i][j] = 0.0f;
        ol[i][0] = 0u; ol[i][1] = 0u;
    }

    int arow = lane & 15;
    int acolb = ((lane >> 4) & 1) * 16;
    int brow = (lane & 7) + ((lane >> 4) << 3);
    int bcolb = ((lane >> 3) & 1) * 16;
    int vrow = (lane & 7) + (((lane >> 3) & 1) << 3);
    int vcolb = ((lane >> 4) & 1) * 16;
    int m0w = q0 + wid * 16;

    for (int t = 0; t < nch; t++) {
        asm volatile("cp.async.wait_group 0;" ::: "memory");
        __syncthreads();
        if (t + 1 < nch) {
            uint32_t nstg = sKV + ((t + 1) & 1) * KVSTG;
            int kc = (t + 1) * AKC;
            for (int i = tid; i < 512; i += 128) {
                int r = i >> 4, c = i & 15;
                size_t g = (size_t)(kc + r) * HD_ + c * 8;
                uint32_t d = nstg + r * RB + c * 16;
                CP16(d, Khb + g);
                CP16(d + KVMAT, Vhb + g);
            }
            CP_COMMIT();
        }
        uint32_t stg = sKV + (t & 1) * KVSTG;

        // ---- phase 1: S = Q.K^T  (hi fp32-acc, lo fp16-acc scaled)
        float sacc[4][4];
        uint32_t saccl[4][2];
#pragma unroll
        for (int i = 0; i < 4; i++) {
#pragma unroll
            for (int j = 0; j < 4; j++) sacc[i][j] = 0.0f;
            saccl[i][0] = 0u; saccl[i][1] = 0u;
        }

#pragma unroll
        for (int ds = 0; ds < 8; ds++) {
            uint32_t ah[4], al[4];
            uint32_t ad = sQh + (wid * 16 + arow) * RB + acolb + ds * 32;
            LDSM4(ah[0], ah[1], ah[2], ah[3], ad);
            LDSM4(al[0], al[1], al[2], al[3], ad + QMAT);
            uint32_t bhf[2][4];
#pragma unroll
            for (int ng = 0; ng < 2; ng++) {
                uint32_t bd = stg + (ng * 16 + brow) * RB + bcolb + ds * 32;
                LDSM4(bhf[ng][0], bhf[ng][1], bhf[ng][2], bhf[ng][3], bd);
            }
#pragma unroll
            for (int nt = 0; nt < 4; nt++) {
                uint32_t* ph = &bhf[nt >> 1][(nt & 1) * 2];
                MMAH(sacc[nt], ah, ph[0], ph[1]);
            }
#pragma unroll
            for (int nt = 0; nt < 4; nt++) {
                uint32_t* ph = &bhf[nt >> 1][(nt & 1) * 2];
                MMAH2(saccl[nt], al, ph[0], ph[1]);
            }
        }
#pragma unroll
        for (int nt = 0; nt < 4; nt++) combine_lo(sacc[nt], saccl[nt]);

        // ---- causal mask
        int kcg = t * AKC;
        if (kcg + AKC - 1 > m0w) {
            int r0m = m0w + (lane >> 2);
            int r1m = r0m + 8;
#pragma unroll
            for (int nt = 0; nt < 4; nt++) {
                int cb = kcg + nt * 8 + (lane & 3) * 2;
                if (cb > r0m) sacc[nt][0] = 0.0f;
                if (cb + 1 > r0m) sacc[nt][1] = 0.0f;
                if (cb > r1m) sacc[nt][2] = 0.0f;
                if (cb + 1 > r1m) sacc[nt][3] = 0.0f;
            }
        }

        // ---- phase 2: O += S.V  (hi fp32-acc, lo fp16-acc scaled)
#pragma unroll
        for (int ks = 0; ks < 2; ks++) {
            uint32_t ah[4], al[4];
            split2h(sacc[2 * ks][0], sacc[2 * ks][1], ah[0], al[0]);
            split2h(sacc[2 * ks][2], sacc[2 * ks][3], ah[1], al[1]);
            split2h(sacc[2 * ks + 1][0], sacc[2 * ks + 1][1], ah[2], al[2]);
            split2h(sacc[2 * ks + 1][2], sacc[2 * ks + 1][3], ah[3], al[3]);
#pragma unroll
            for (int ng = 0; ng < 8; ng++) {
                uint32_t bv[4];
                uint32_t va = stg + KVMAT + (ks * 16 + vrow) * RB + vcolb + ng * 32;
                LDSM4T(bv[0], bv[1], bv[2], bv[3], va);
                MMAH(o[2 * ng], ah, bv[0], bv[1]);
                MMAH(o[2 * ng + 1], ah, bv[2], bv[3]);
                MMAH2(ol[2 * ng], al, bv[0], bv[1]);
                MMAH2(ol[2 * ng + 1], al, bv[2], bv[3]);
            }
        }
        __syncthreads();
    }

#pragma unroll
    for (int nt = 0; nt < 16; nt++) combine_lo(o[nt], ol[nt]);

    int b = bh / H_;
    int h = bh % H_;
    int r0 = m0w + (lane >> 2);
#pragma unroll
    for (int nt = 0; nt < 16; nt++) {
        int col = nt * 8 + (lane & 3) * 2;
        size_t g0 = ((size_t)(b * S_ + r0)) * E_ + h * HD_ + col;
        size_t g1 = ((size_t)(b * S_ + r0 + 8)) * E_ + h * HD_ + col;
        uint32_t hi0, lo0, hi1, lo1;
        split2h(o[nt][0], o[nt][1], hi0, lo0);
        split2h(o[nt][2], o[nt][3], hi1, lo1);
        *(uint32_t*)(aoh + g0) = hi0;
        *(uint32_t*)(aol + g0) = lo0;
        *(uint32_t*)(aoh + g1) = hi1;
        *(uint32_t*)(aol + g1) = lo1;
    }
}

// ---------------- launcher ---------------------------------------------------
extern "C" void kernel_launch(void* const* d_in, const int* in_sizes, int n_in,
                              void* d_out, int out_size) {
    const float* hs        = (const float*)d_in[0];
    const float* w_q       = (const float*)d_in[1];
    const float* w_k       = (const float*)d_in[2];
    const float* w_v       = (const float*)d_in[3];
    const float* w_o       = (const float*)d_in[4];
    const float* norm_c    = (const float*)d_in[5];
    const float* attn_mask = (const float*)d_in[6];
    const int*   pos_ids   = (const int*)d_in[7];
    float* out = (float*)d_out;

    float* cnts;
    cudaGetSymbolAddress((void**)&cnts, g_counts);

    __half *hs0, *hs1, *wq0, *wk0, *wv0, *wo0, *ao0, *ao1;
    __half *q0, *q1, *k0, *v0;
    cudaGetSymbolAddress((void**)&hs0, g_hs0);
    cudaGetSymbolAddress((void**)&hs1, g_hs1);
    cudaGetSymbolAddress((void**)&wq0, g_wq0);
    cudaGetSymbolAddress((void**)&wk0, g_wk0);
    cudaGetSymbolAddress((void**)&wv0, g_wv0);
    cudaGetSymbolAddress((void**)&wo0, g_wo0);
    cudaGetSymbolAddress((void**)&ao0, g_ao0);
    cudaGetSymbolAddress((void**)&ao1, g_ao1);
    cudaGetSymbolAddress((void**)&q0, g_q0);
    cudaGetSymbolAddress((void**)&q1, g_q1);
    cudaGetSymbolAddress((void**)&k0, g_k0);
    cudaGetSymbolAddress((void**)&v0, g_v0);

    static bool attr_set = false;
    if (!attr_set) {
        cudaFuncSetAttribute(mma_gemm_qkv_fused, cudaFuncAttributeMaxDynamicSharedMemorySize, GEMM_SMEM);
        cudaFuncSetAttribute(mma_gemm_out, cudaFuncAttributeMaxDynamicSharedMemorySize, GEMM_SMEM);
        cudaFuncSetAttribute(attn_mma, cudaFuncAttributeMaxDynamicSharedMemorySize, ATT_SMEM);
        attr_set = true;
    }

    counts_kernel<<<B_, S_>>>(attn_mask, cnts);

    split5_kernel<<<dim3(256, 5), 256>>>(hs, w_q, w_k, w_v, w_o,
                                         hs0, hs1, wq0, wk0, wv0, wo0);

    mma_gemm_qkv_fused<<<dim3(E_ / 128, NROWS / 64, 3), 128, GEMM_SMEM>>>(
        hs0, hs1, wq0, wk0, wv0,
        attn_mask, norm_c, pos_ids, cnts,
        q0, q1, k0, v0);

    attn_mma<<<dim3(B_ * H_, S_ / AQM), 128, ATT_SMEM>>>(q0, q1, k0, v0, ao0, ao1);

    mma_gemm_out<<<dim3(E_ / 128, NROWS / 64), 128, GEMM_SMEM>>>(ao0, ao1, wo0, out);
}

// round 13
// speedup vs baseline: 10.3372x; 1.0043x over previous
#include <cuda_runtime.h>
#include <cuda_fp16.h>
#include <math.h>
#include <stdint.h>

#define B_  2
#define S_  1024
#define E_  2048
#define H_  16
#define HD_ 128
#define ROT_ 64
#define NROWS (B_ * S_)
#define EPS_ 1e-12f
#define LSC 1024.0f
#define LSCI (1.0f / 1024.0f)
#define NPERS 304          // persistent CTAs (2/SM x 152 SMs)

// ---------------- scratch ----------------------------------------------------
__device__ float g_counts[B_ * S_];
__device__ int g_ctr[4];

__device__ __half g_hs0[NROWS * E_], g_hs1[NROWS * E_];
__device__ __half g_wq0[E_ * E_];
__device__ __half g_wk0[E_ * E_];
__device__ __half g_wv0[E_ * E_];
__device__ __half g_wo0[E_ * E_];
__device__ __half g_ao0[NROWS * E_], g_ao1[NROWS * E_];

__device__ __half g_q0[B_ * H_ * S_ * HD_], g_q1[B_ * H_ * S_ * HD_];
__device__ __half g_k0[B_ * H_ * S_ * HD_];
__device__ __half g_v0[B_ * H_ * S_ * HD_];

// ---------------- PTX helpers ------------------------------------------------
__device__ __forceinline__ uint32_t smem_u32(const void* p) {
    uint32_t a;
    asm("{ .reg .u64 t; cvta.to.shared.u64 t, %1; cvt.u32.u64 %0, t; }" : "=r"(a) : "l"(p));
    return a;
}
#define CP16(dst, src) asm volatile("cp.async.cg.shared.global [%0], [%1], 16;" :: "r"(dst), "l"(src) : "memory")
#define CP_COMMIT() asm volatile("cp.async.commit_group;" ::: "memory")

#define LDSM4(r0, r1, r2, r3, addr) \
    asm volatile("ldmatrix.sync.aligned.m8n8.x4.shared.b16 {%0,%1,%2,%3}, [%4];" \
        : "=r"(r0), "=r"(r1), "=r"(r2), "=r"(r3) : "r"(addr))

#define LDSM4T(r0, r1, r2, r3, addr) \
    asm volatile("ldmatrix.sync.aligned.m8n8.x4.trans.shared.b16 {%0,%1,%2,%3}, [%4];" \
        : "=r"(r0), "=r"(r1), "=r"(r2), "=r"(r3) : "r"(addr))

#define MMAH(c, a, br0, br1) \
    asm volatile("mma.sync.aligned.m16n8k16.row.col.f32.f16.f16.f32 " \
        "{%0,%1,%2,%3}, {%4,%5,%6,%7}, {%8,%9}, {%0,%1,%2,%3};" \
        : "+f"((c)[0]), "+f"((c)[1]), "+f"((c)[2]), "+f"((c)[3]) \
        : "r"((a)[0]), "r"((a)[1]), "r"((a)[2]), "r"((a)[3]), "r"(br0), "r"(br1))

#define MMAH2(c, a, br0, br1) \
    asm volatile("mma.sync.aligned.m16n8k16.row.col.f16.f16.f16.f16 " \
        "{%0,%1}, {%2,%3,%4,%5}, {%6,%7}, {%0,%1};" \
        : "+r"((c)[0]), "+r"((c)[1]) \
        : "r"((a)[0]), "r"((a)[1]), "r"((a)[2]), "r"((a)[3]), "r"(br0), "r"(br1))

__device__ __forceinline__ void combine_lo(float* c, const uint32_t* cl) {
    __half2 h0 = *(const __half2*)&cl[0];
    __half2 h1 = *(const __half2*)&cl[1];
    float2 f0 = __half22float2(h0);
    float2 f1 = __half22float2(h1);
    c[0] += f0.x * LSCI;
    c[1] += f0.y * LSCI;
    c[2] += f1.x * LSCI;
    c[3] += f1.y * LSCI;
}

__device__ __forceinline__ uint32_t pack2h(float x, float y) {
    __half hx = __float2half_rn(x), hy = __float2half_rn(y);
    return (uint32_t)__half_as_ushort(hx) | ((uint32_t)__half_as_ushort(hy) << 16);
}
__device__ __forceinline__ void split2h(float x, float y, uint32_t& hi, uint32_t& lo) {
    __half hx = __float2half_rn(x), hy = __float2half_rn(y);
    __half lx = __float2half_rn((x - __half2float(hx)) * LSC);
    __half ly = __float2half_rn((y - __half2float(hy)) * LSC);
    hi = (uint32_t)__half_as_ushort(hx) | ((uint32_t)__half_as_ushort(hy) << 16);
    lo = (uint32_t)__half_as_ushort(lx) | ((uint32_t)__half_as_ushort(ly) << 16);
}

// ---------------- counter reset ----------------------------------------------
__global__ void reset_ctr_kernel() {
    if (threadIdx.x < 4) g_ctr[threadIdx.x] = 0;
}

// ---------------- fused convert ----------------------------------------------
__global__ __launch_bounds__(256) void split5_kernel(
    const float* __restrict__ x0, const float* __restrict__ x1,
    const float* __restrict__ x2, const float* __restrict__ x3,
    const float* __restrict__ x4,
    __half* __restrict__ h0, __half* __restrict__ l0,
    __half* __restrict__ h1, __half* __restrict__ h2,
    __half* __restrict__ h3, __half* __restrict__ h4) {
    int z = blockIdx.y;
    const float* x = (z == 0) ? x0 : (z == 1) ? x1 : (z == 2) ? x2 : (z == 3) ? x3 : x4;
    __half* hi = (z == 0) ? h0 : (z == 1) ? h1 : (z == 2) ? h2 : (z == 3) ? h3 : h4;
    bool do_lo = (z == 0);
    const int n4 = NROWS * E_ / 4;
    for (int i = blockIdx.x * blockDim.x + threadIdx.x; i < n4; i += gridDim.x * blockDim.x) {
        float4 v = ((const float4*)x)[i];
        if (do_lo) {
            uint32_t ph0, pl0, ph1, pl1;
            split2h(v.x, v.y, ph0, pl0);
            split2h(v.z, v.w, ph1, pl1);
            ((uint2*)hi)[i] = make_uint2(ph0, ph1);
            ((uint2*)l0)[i] = make_uint2(pl0, pl1);
        } else {
            ((uint2*)hi)[i] = make_uint2(pack2h(v.x, v.y), pack2h(v.z, v.w));
        }
    }
}

// ============== shared GEMM mainloop: CTA 64x128, 4 warps, warp 32x64 ========
#define KCH 32
#define NCHK (E_ / KCH)
#define ROWB 80
#define GAMAT (64 * ROWB)
#define GBMAT (128 * ROWB)
#define GSTG (2 * GAMAT + GBMAT)
#define GEMM_SMEM (3 * GSTG)

__device__ __forceinline__ void g_load_chunk(uint32_t base, int t, int tid,
                                             const __half* a0, const __half* a1,
                                             const __half* b0) {
    for (int i = tid; i < 256; i += 128) {
        int r = i >> 2, c = i & 3;
        size_t g = (size_t)r * E_ + t * KCH + c * 8;
        uint32_t d = base + r * ROWB + c * 16;
        CP16(d, a0 + g);
        CP16(d + GAMAT, a1 + g);
    }
    for (int i = tid; i < 512; i += 128) {
        int r = i >> 2, c = i & 3;
        size_t g = (size_t)r * E_ + t * KCH + c * 8;
        CP16(base + 2 * GAMAT + r * ROWB + c * 16, b0 + g);
    }
    CP_COMMIT();
}

__device__ __forceinline__ void g_mainloop(uint32_t sb, int tid, int lane, int wid,
                                           const __half* a0, const __half* a1,
                                           const __half* b0, float acc[2][8][4]) {
    int wm = wid >> 1;
    int wn = wid & 1;

    uint32_t accl[2][8][2];
#pragma unroll
    for (int i = 0; i < 2; i++)
#pragma unroll
        for (int j = 0; j < 8; j++) { accl[i][j][0] = 0u; accl[i][j][1] = 0u; }

    g_load_chunk(sb, 0, tid, a0, a1, b0);
    g_load_chunk(sb + GSTG, 1, tid, a0, a1, b0);

    int arow = lane & 15;
    int acolb = ((lane >> 4) & 1) * 16;
    int brow = (lane & 7) + ((lane >> 4) << 3);
    int bcolb = ((lane >> 3) & 1) * 16;

    for (int t = 0; t < NCHK; t++) {
        if (t + 1 < NCHK) asm volatile("cp.async.wait_group 1;" ::: "memory");
        else              asm volatile("cp.async.wait_group 0;" ::: "memory");
        __syncthreads();
        if (t + 2 < NCHK) g_load_chunk(sb + ((t + 2) % 3) * GSTG, t + 2, tid, a0, a1, b0);

        uint32_t st = sb + (t % 3) * GSTG;
        uint32_t aA0 = st + (wm * 32 + arow) * ROWB + acolb;
        uint32_t aA1 = aA0 + GAMAT;
        uint32_t aB0 = st + 2 * GAMAT + (wn * 64 + brow) * ROWB + bcolb;

#pragma unroll
        for (int ks = 0; ks < 2; ks++) {
            uint32_t a0f[2][4], a1f[2][4], b0f[4][4];
#pragma unroll
            for (int mt = 0; mt < 2; mt++) {
                LDSM4(a0f[mt][0], a0f[mt][1], a0f[mt][2], a0f[mt][3], aA0 + mt * 16 * ROWB + ks * 32);
                LDSM4(a1f[mt][0], a1f[mt][1], a1f[mt][2], a1f[mt][3], aA1 + mt * 16 * ROWB + ks * 32);
            }
#pragma unroll
            for (int ng = 0; ng < 4; ng++)
                LDSM4(b0f[ng][0], b0f[ng][1], b0f[ng][2], b0f[ng][3], aB0 + ng * 16 * ROWB + ks * 32);
#pragma unroll
            for (int mt = 0; mt < 2; mt++)
#pragma unroll
                for (int nt = 0; nt < 8; nt++) {
                    uint32_t* p = &b0f[nt >> 1][(nt & 1) * 2];
                    MMAH(acc[mt][nt], a0f[mt], p[0], p[1]);
                }
#pragma unroll
            for (int mt = 0; mt < 2; mt++)
#pragma unroll
                for (int nt = 0; nt < 8; nt++) {
                    uint32_t* p = &b0f[nt >> 1][(nt & 1) * 2];
                    MMAH2(accl[mt][nt], a1f[mt], p[0], p[1]);
                }
        }
    }
#pragma unroll
    for (int mt = 0; mt < 2; mt++)
#pragma unroll
        for (int nt = 0; nt < 8; nt++)
            combine_lo(acc[mt][nt], accl[mt][nt]);
    __syncthreads();
}

// ============== persistent QKV GEMM with fused epilogue ======================
#define QKV_TILES (16 * 32 * 3)

__global__ __launch_bounds__(128, 2) void mma_gemm_qkv_fused(
    const __half* __restrict__ ha0, const __half* __restrict__ ha1,
    const __half* __restrict__ wq0, const __half* __restrict__ wk0,
    const __half* __restrict__ wv0,
    const float* __restrict__ mask, const float* __restrict__ norm_const,
    const int* __restrict__ pos_ids, const float* __restrict__ counts,
    __half* __restrict__ Qh, __half* __restrict__ Ql,
    __half* __restrict__ Kh, __half* __restrict__ Vh) {
    extern __shared__ char smc[];
    uint32_t sb = smem_u32(smc);
    __shared__ int s_tile;
    int tid = threadIdx.x;
    int lane = tid & 31;
    int wid = tid >> 5;
    int wm = wid >> 1;
    int wn = wid & 1;

    for (;;) {
        if (tid == 0) s_tile = atomicAdd(&g_ctr[0], 1);
        __syncthreads();
        int tile = s_tile;
        if (tile >= QKV_TILES) return;
        int z = tile >> 9;              // /512
        int rem = tile & 511;
        int bm = (rem >> 4) * 64;       // y: 32 tiles
        int bn = (rem & 15) * 128;      // x: 16 tiles

        const __half* a0 = ha0 + (size_t)bm * E_;
        const __half* a1 = ha1 + (size_t)bm * E_;
        const __half* b0 = ((z == 0) ? wq0 : (z == 1) ? wk0 : wv0) + (size_t)bn * E_;

        float acc[2][8][4];
#pragma unroll
        for (int i = 0; i < 2; i++)
#pragma unroll
            for (int j = 0; j < 8; j++)
#pragma unroll
                for (int k = 0; k < 4; k++) acc[i][j][k] = 0.0f;

        g_mainloop(sb, tid, lane, wid, a0, a1, b0, acc);

        float* rs = (float*)smc;
        int lr = lane >> 2;
        int lc = lane & 3;

        if (z < 2) {
            if (wn == 0) {
#pragma unroll
                for (int mt = 0; mt < 2; mt++) {
                    int rg = bm + wm * 32 + mt * 16 + lr;
                    float pos0 = (float)pos_ids[rg];
                    float pos1 = (float)pos_ids[rg + 8];
#pragma unroll
                    for (int nt = 0; nt < 8; nt++) {
                        float fi = (float)(nt * 4 + lc);
                        float fr = __expf(-0.28782313662425575f * fi);
                        float s0, c0, s1, c1;
                        sincosf(pos0 * fr, &s0, &c0);
                        sincosf(pos1 * fr, &s1, &c1);
                        float x = acc[mt][nt][0], y = acc[mt][nt][1];
                        acc[mt][nt][0] = x * c0 - y * s0;
                        acc[mt][nt][1] = y * c0 + x * s0;
                        x = acc[mt][nt][2]; y = acc[mt][nt][3];
                        acc[mt][nt][2] = x * c1 - y * s1;
                        acc[mt][nt][3] = y * c1 + x * s1;
                    }
                }
            }
#pragma unroll
            for (int mt = 0; mt < 2; mt++) {
                float s0 = 0.0f, s1 = 0.0f;
#pragma unroll
                for (int nt = 0; nt < 8; nt++) {
                    s0 += acc[mt][nt][0] * acc[mt][nt][0] + acc[mt][nt][1] * acc[mt][nt][1];
                    s1 += acc[mt][nt][2] * acc[mt][nt][2] + acc[mt][nt][3] * acc[mt][nt][3];
                }
                s0 += __shfl_xor_sync(0xffffffffu, s0, 1);
                s0 += __shfl_xor_sync(0xffffffffu, s0, 2);
                s1 += __shfl_xor_sync(0xffffffffu, s1, 1);
                s1 += __shfl_xor_sync(0xffffffffu, s1, 2);
                if (lc == 0) {
                    rs[(wm * 32 + mt * 16 + lr) * 2 + wn] = s0;
                    rs[(wm * 32 + mt * 16 + lr + 8) * 2 + wn] = s1;
                }
            }
        }
        __syncthreads();

        int h = bn >> 7;
        float sig = 1.0f / (1.0f + __expf(-norm_const[h]));
        int col0 = wn * 64 + lc * 2;

#pragma unroll
        for (int mt = 0; mt < 2; mt++) {
#pragma unroll
            for (int half = 0; half < 2; half++) {
                int rl = wm * 32 + mt * 16 + lr + half * 8;
                int rg = bm + rl;
                float m = (mask[rg] == 0.0f) ? 1.0f : 0.0f;
                float scl;
                if (z < 2) {
                    float tot = rs[rl * 2] + rs[rl * 2 + 1];
                    scl = m / fmaxf(sqrtf(tot), EPS_);
                } else {
                    scl = m / fmaxf(powf(counts[rg], sig), 1.0f);
                }
                int b = rg >> 10;
                int s = rg & 1023;
                size_t dst = (((size_t)(b * H_ + h)) * S_ + s) * (size_t)HD_;
                if (z == 0) {
#pragma unroll
                    for (int nt = 0; nt < 8; nt++) {
                        int c = col0 + nt * 8;
                        uint32_t hi, lo;
                        split2h(acc[mt][nt][2 * half] * scl, acc[mt][nt][2 * half + 1] * scl, hi, lo);
                        *(uint32_t*)(Qh + dst + c) = hi;
                        *(uint32_t*)(Ql + dst + c) = lo;
                    }
                } else {
                    __half* O = (z == 1) ? Kh : Vh;
#pragma unroll
                    for (int nt = 0; nt < 8; nt++) {
                        int c = col0 + nt * 8;
                        *(uint32_t*)(O + dst + c) =
                            pack2h(acc[mt][nt][2 * half] * scl, acc[mt][nt][2 * half + 1] * scl);
                    }
                }
            }
        }
        __syncthreads();   // rs region is reused as pipeline smem next tile
    }
}

// ============== persistent output projection =================================
#define OUT_TILES (16 * 32)

__global__ __launch_bounds__(128, 2) void mma_gemm_out(
    const __half* __restrict__ ha0, const __half* __restrict__ ha1,
    const __half* __restrict__ hb0,
    float* __restrict__ C) {
    extern __shared__ char smc[];
    uint32_t sb = smem_u32(smc);
    __shared__ int s_tile;
    int tid = threadIdx.x;
    int lane = tid & 31;
    int wid = tid >> 5;
    int wm = wid >> 1;
    int wn = wid & 1;

    for (;;) {
        if (tid == 0) s_tile = atomicAdd(&g_ctr[1], 1);
        __syncthreads();
        int tile = s_tile;
        if (tile >= OUT_TILES) return;
        int bm = (tile >> 4) * 64;
        int bn = (tile & 15) * 128;

        const __half* a0 = ha0 + (size_t)bm * E_;
        const __half* a1 = ha1 + (size_t)bm * E_;
        const __half* b0 = hb0 + (size_t)bn * E_;

        float acc[2][8][4];
#pragma unroll
        for (int i = 0; i < 2; i++)
#pragma unroll
            for (int j = 0; j < 8; j++)
#pragma unroll
                for (int k = 0; k < 4; k++) acc[i][j][k] = 0.0f;

        g_mainloop(sb, tid, lane, wid, a0, a1, b0, acc);

        int row0 = bm + wm * 32 + (lane >> 2);
        int col0 = bn + wn * 64 + (lane & 3) * 2;
#pragma unroll
        for (int mt = 0; mt < 2; mt++) {
#pragma unroll
            for (int nt = 0; nt < 8; nt++) {
                int r = row0 + mt * 16;
                int c = col0 + nt * 8;
                float2 v0 = {acc[mt][nt][0], acc[mt][nt][1]};
                float2 v1 = {acc[mt][nt][2], acc[mt][nt][3]};
                *(float2*)&C[(size_t)r * E_ + c] = v0;
                *(float2*)&C[(size_t)(r + 8) * E_ + c] = v1;
            }
        }
        __syncthreads();
    }
}

// ---------------- mask prefix scan ------------------------------------------
__global__ void counts_kernel(const float* __restrict__ mask, float* __restrict__ counts) {
    __shared__ float sh[S_];
    int b = blockIdx.x;
    int t = threadIdx.x;
    sh[t] = (mask[b * S_ + t] == 0.0f) ? 1.0f : 0.0f;
    __syncthreads();
    for (int off = 1; off < S_; off <<= 1) {
        float add = (t >= off) ? sh[t - off] : 0.0f;
        __syncthreads();
        sh[t] += add;
        __syncthreads();
    }
    counts[b * S_ + t] = sh[t];
}

// ============== persistent causal attention ==================================
#define AQM 64
#define AKC 32
#define RB 272
#define QMAT (AQM * RB)
#define KVMAT (AKC * RB)
#define KVSTG (2 * KVMAT)
#define ATT_SMEM (2 * QMAT + 2 * KVSTG)
#define ATT_TILES (32 * 16)

__global__ __launch_bounds__(128, 2) void attn_mma(
    const __half* __restrict__ qh, const __half* __restrict__ ql,
    const __half* __restrict__ kh, const __half* __restrict__ vh,
    __half* __restrict__ aoh, __half* __restrict__ aol) {
    extern __shared__ char smc[];
    uint32_t sb = smem_u32(smc);
    uint32_t sQh = sb, sQl = sb + QMAT;
    uint32_t sKV = sb + 2 * QMAT;
    __shared__ int s_tile;

    int tid = threadIdx.x;
    int lane = tid & 31;
    int wid = tid >> 5;

    int arow = lane & 15;
    int acolb = ((lane >> 4) & 1) * 16;
    int brow = (lane & 7) + ((lane >> 4) << 3);
    int bcolb = ((lane >> 3) & 1) * 16;
    int vrow = (lane & 7) + (((lane >> 3) & 1) << 3);
    int vcolb = ((lane >> 4) & 1) * 16;

    for (;;) {
        if (tid == 0) s_tile = atomicAdd(&g_ctr[2], 1);
        __syncthreads();
        int tile = s_tile;
        if (tile >= ATT_TILES) return;
        int bh = tile & 31;
        int qt = 15 - (tile >> 5);           // big q-tiles dispensed first
        int q0 = qt * AQM;

        size_t base = (size_t)bh * S_ * HD_;
        const __half* Qhb = qh + base;
        const __half* Qlb = ql + base;
        const __half* Khb = kh + base;
        const __half* Vhb = vh + base;

        for (int i = tid; i < 1024; i += 128) {
            int r = i >> 4, c = i & 15;
            size_t g = (size_t)(q0 + r) * HD_ + c * 8;
            CP16(sQh + r * RB + c * 16, Qhb + g);
            CP16(sQl + r * RB + c * 16, Qlb + g);
        }
        for (int i = tid; i < 512; i += 128) {
            int r = i >> 4, c = i & 15;
            size_t g = (size_t)r * HD_ + c * 8;
            uint32_t d = sKV + r * RB + c * 16;
            CP16(d, Khb + g);
            CP16(d + KVMAT, Vhb + g);
        }
        CP_COMMIT();

        int nch = (q0 + AQM) / AKC;
        float o[16][4];
        uint32_t ol[16][2];
#pragma unroll
        for (int i = 0; i < 16; i++) {
#pragma unroll
            for (int j = 0; j < 4; j++) o[i][j] = 0.0f;
            ol[i][0] = 0u; ol[i][1] = 0u;
        }
        int m0w = q0 + wid * 16;

        for (int t = 0; t < nch; t++) {
            asm volatile("cp.async.wait_group 0;" ::: "memory");
            __syncthreads();
            if (t + 1 < nch) {
                uint32_t nstg = sKV + ((t + 1) & 1) * KVSTG;
                int kc = (t + 1) * AKC;
                for (int i = tid; i < 512; i += 128) {
                    int r = i >> 4, c = i & 15;
                    size_t g = (size_t)(kc + r) * HD_ + c * 8;
                    uint32_t d = nstg + r * RB + c * 16;
                    CP16(d, Khb + g);
                    CP16(d + KVMAT, Vhb + g);
                }
                CP_COMMIT();
            }
            uint32_t stg = sKV + (t & 1) * KVSTG;

            float sacc[4][4];
            uint32_t saccl[4][2];
#pragma unroll
            for (int i = 0; i < 4; i++) {
#pragma unroll
                for (int j = 0; j < 4; j++) sacc[i][j] = 0.0f;
                saccl[i][0] = 0u; saccl[i][1] = 0u;
            }

#pragma unroll
            for (int ds = 0; ds < 8; ds++) {
                uint32_t ah[4], al[4];
                uint32_t ad = sQh + (wid * 16 + arow) * RB + acolb + ds * 32;
                LDSM4(ah[0], ah[1], ah[2], ah[3], ad);
                LDSM4(al[0], al[1], al[2], al[3], ad + QMAT);
                uint32_t bhf[2][4];
#pragma unroll
                for (int ng = 0; ng < 2; ng++) {
                    uint32_t bd = stg + (ng * 16 + brow) * RB + bcolb + ds * 32;
                    LDSM4(bhf[ng][0], bhf[ng][1], bhf[ng][2], bhf[ng][3], bd);
                }
#pragma unroll
                for (int nt = 0; nt < 4; nt++) {
                    uint32_t* ph = &bhf[nt >> 1][(nt & 1) * 2];
                    MMAH(sacc[nt], ah, ph[0], ph[1]);
                }
#pragma unroll
                for (int nt = 0; nt < 4; nt++) {
                    uint32_t* ph = &bhf[nt >> 1][(nt & 1) * 2];
                    MMAH2(saccl[nt], al, ph[0], ph[1]);
                }
            }
#pragma unroll
            for (int nt = 0; nt < 4; nt++) combine_lo(sacc[nt], saccl[nt]);

            int kcg = t * AKC;
            if (kcg + AKC - 1 > m0w) {
                int r0m = m0w + (lane >> 2);
                int r1m = r0m + 8;
#pragma unroll
                for (int nt = 0; nt < 4; nt++) {
                    int cb = kcg + nt * 8 + (lane & 3) * 2;
                    if (cb > r0m) sacc[nt][0] = 0.0f;
                    if (cb + 1 > r0m) sacc[nt][1] = 0.0f;
                    if (cb > r1m) sacc[nt][2] = 0.0f;
                    if (cb + 1 > r1m) sacc[nt][3] = 0.0f;
                }
            }

#pragma unroll
            for (int ks = 0; ks < 2; ks++) {
                uint32_t ah[4], al[4];
                split2h(sacc[2 * ks][0], sacc[2 * ks][1], ah[0], al[0]);
                split2h(sacc[2 * ks][2], sacc[2 * ks][3], ah[1], al[1]);
                split2h(sacc[2 * ks + 1][0], sacc[2 * ks + 1][1], ah[2], al[2]);
                split2h(sacc[2 * ks + 1][2], sacc[2 * ks + 1][3], ah[3], al[3]);
#pragma unroll
                for (int ng = 0; ng < 8; ng++) {
                    uint32_t bv[4];
                    uint32_t va = stg + KVMAT + (ks * 16 + vrow) * RB + vcolb + ng * 32;
                    LDSM4T(bv[0], bv[1], bv[2], bv[3], va);
                    MMAH(o[2 * ng], ah, bv[0], bv[1]);
                    MMAH(o[2 * ng + 1], ah, bv[2], bv[3]);
                    MMAH2(ol[2 * ng], al, bv[0], bv[1]);
                    MMAH2(ol[2 * ng + 1], al, bv[2], bv[3]);
                }
            }
            __syncthreads();
        }

#pragma unroll
        for (int nt = 0; nt < 16; nt++) combine_lo(o[nt], ol[nt]);

        int b = bh / H_;
        int h = bh % H_;
        int r0 = m0w + (lane >> 2);
#pragma unroll
        for (int nt = 0; nt < 16; nt++) {
            int col = nt * 8 + (lane & 3) * 2;
            size_t g0 = ((size_t)(b * S_ + r0)) * E_ + h * HD_ + col;
            size_t g1 = ((size_t)(b * S_ + r0 + 8)) * E_ + h * HD_ + col;
            uint32_t hi0, lo0, hi1, lo1;
            split2h(o[nt][0], o[nt][1], hi0, lo0);
            split2h(o[nt][2], o[nt][3], hi1, lo1);
            *(uint32_t*)(aoh + g0) = hi0;
            *(uint32_t*)(aol + g0) = lo0;
            *(uint32_t*)(aoh + g1) = hi1;
            *(uint32_t*)(aol + g1) = lo1;
        }
        __syncthreads();
    }
}

// ---------------- launcher ---------------------------------------------------
extern "C" void kernel_launch(void* const* d_in, const int* in_sizes, int n_in,
                              void* d_out, int out_size) {
    const float* hs        = (const float*)d_in[0];
    const float* w_q       = (const float*)d_in[1];
    const float* w_k       = (const float*)d_in[2];
    const float* w_v       = (const float*)d_in[3];
    const float* w_o       = (const float*)d_in[4];
    const float* norm_c    = (const float*)d_in[5];
    const float* attn_mask = (const float*)d_in[6];
    const int*   pos_ids   = (const int*)d_in[7];
    float* out = (float*)d_out;

    float* cnts;
    cudaGetSymbolAddress((void**)&cnts, g_counts);

    __half *hs0, *hs1, *wq0, *wk0, *wv0, *wo0, *ao0, *ao1;
    __half *q0, *q1, *k0, *v0;
    cudaGetSymbolAddress((void**)&hs0, g_hs0);
    cudaGetSymbolAddress((void**)&hs1, g_hs1);
    cudaGetSymbolAddress((void**)&wq0, g_wq0);
    cudaGetSymbolAddress((void**)&wk0, g_wk0);
    cudaGetSymbolAddress((void**)&wv0, g_wv0);
    cudaGetSymbolAddress((void**)&wo0, g_wo0);
    cudaGetSymbolAddress((void**)&ao0, g_ao0);
    cudaGetSymbolAddress((void**)&ao1, g_ao1);
    cudaGetSymbolAddress((void**)&q0, g_q0);
    cudaGetSymbolAddress((void**)&q1, g_q1);
    cudaGetSymbolAddress((void**)&k0, g_k0);
    cudaGetSymbolAddress((void**)&v0, g_v0);

    static bool attr_set = false;
    if (!attr_set) {
        cudaFuncSetAttribute(mma_gemm_qkv_fused, cudaFuncAttributeMaxDynamicSharedMemorySize, GEMM_SMEM);
        cudaFuncSetAttribute(mma_gemm_out, cudaFuncAttributeMaxDynamicSharedMemorySize, GEMM_SMEM);
        cudaFuncSetAttribute(attn_mma, cudaFuncAttributeMaxDynamicSharedMemorySize, ATT_SMEM);
        attr_set = true;
    }

    reset_ctr_kernel<<<1, 32>>>();

    counts_kernel<<<B_, S_>>>(attn_mask, cnts);

    split5_kernel<<<dim3(256, 5), 256>>>(hs, w_q, w_k, w_v, w_o,
                                         hs0, hs1, wq0, wk0, wv0, wo0);

    mma_gemm_qkv_fused<<<NPERS, 128, GEMM_SMEM>>>(
        hs0, hs1, wq0, wk0, wv0,
        attn_mask, norm_c, pos_ids, cnts,
        q0, q1, k0, v0);

    attn_mma<<<NPERS, 128, ATT_SMEM>>>(q0, q1, k0, v0, ao0, ao1);

    mma_gemm_out<<<NPERS, 128, GEMM_SMEM>>>(ao0, ao1, wo0, out);
}

// round 14
// speedup vs baseline: 11.3982x; 1.1026x over previous
#include <cuda_runtime.h>
#include <cuda_fp16.h>
#include <math.h>
#include <stdint.h>

#define B_  2
#define S_  1024
#define E_  2048
#define H_  16
#define HD_ 128
#define ROT_ 64
#define NROWS (B_ * S_)
#define EPS_ 1e-12f
#define LSC 1024.0f
#define LSCI (1.0f / 1024.0f)
#define NPERS 304

// ---------------- scratch ----------------------------------------------------
__device__ float g_counts[B_ * S_];
__device__ int g_ctr[4];

__device__ __half g_hs0[NROWS * E_], g_hs1[NROWS * E_];
__device__ __half g_wq0[E_ * E_];
__device__ __half g_wk0[E_ * E_];
__device__ __half g_wv0[E_ * E_];
__device__ __half g_wo0[E_ * E_];
__device__ __half g_ao0[NROWS * E_];

__device__ __half g_q0[B_ * H_ * S_ * HD_];
__device__ __half g_k0[B_ * H_ * S_ * HD_];
__device__ __half g_v0[B_ * H_ * S_ * HD_];

// ---------------- PTX helpers ------------------------------------------------
__device__ __forceinline__ uint32_t smem_u32(const void* p) {
    uint32_t a;
    asm("{ .reg .u64 t; cvta.to.shared.u64 t, %1; cvt.u32.u64 %0, t; }" : "=r"(a) : "l"(p));
    return a;
}
#define CP16(dst, src) asm volatile("cp.async.cg.shared.global [%0], [%1], 16;" :: "r"(dst), "l"(src) : "memory")
#define CP_COMMIT() asm volatile("cp.async.commit_group;" ::: "memory")

#define LDSM4(r0, r1, r2, r3, addr) \
    asm volatile("ldmatrix.sync.aligned.m8n8.x4.shared.b16 {%0,%1,%2,%3}, [%4];" \
        : "=r"(r0), "=r"(r1), "=r"(r2), "=r"(r3) : "r"(addr))

#define LDSM4T(r0, r1, r2, r3, addr) \
    asm volatile("ldmatrix.sync.aligned.m8n8.x4.trans.shared.b16 {%0,%1,%2,%3}, [%4];" \
        : "=r"(r0), "=r"(r1), "=r"(r2), "=r"(r3) : "r"(addr))

#define MMAH(c, a, br0, br1) \
    asm volatile("mma.sync.aligned.m16n8k16.row.col.f32.f16.f16.f32 " \
        "{%0,%1,%2,%3}, {%4,%5,%6,%7}, {%8,%9}, {%0,%1,%2,%3};" \
        : "+f"((c)[0]), "+f"((c)[1]), "+f"((c)[2]), "+f"((c)[3]) \
        : "r"((a)[0]), "r"((a)[1]), "r"((a)[2]), "r"((a)[3]), "r"(br0), "r"(br1))

#define MMAH2(c, a, br0, br1) \
    asm volatile("mma.sync.aligned.m16n8k16.row.col.f16.f16.f16.f16 " \
        "{%0,%1}, {%2,%3,%4,%5}, {%6,%7}, {%0,%1};" \
        : "+r"((c)[0]), "+r"((c)[1]) \
        : "r"((a)[0]), "r"((a)[1]), "r"((a)[2]), "r"((a)[3]), "r"(br0), "r"(br1))

__device__ __forceinline__ void combine_lo(float* c, const uint32_t* cl) {
    __half2 h0 = *(const __half2*)&cl[0];
    __half2 h1 = *(const __half2*)&cl[1];
    float2 f0 = __half22float2(h0);
    float2 f1 = __half22float2(h1);
    c[0] += f0.x * LSCI;
    c[1] += f0.y * LSCI;
    c[2] += f1.x * LSCI;
    c[3] += f1.y * LSCI;
}

__device__ __forceinline__ uint32_t pack2h(float x, float y) {
    __half hx = __float2half_rn(x), hy = __float2half_rn(y);
    return (uint32_t)__half_as_ushort(hx) | ((uint32_t)__half_as_ushort(hy) << 16);
}
__device__ __forceinline__ void split2h(float x, float y, uint32_t& hi, uint32_t& lo) {
    __half hx = __float2half_rn(x), hy = __float2half_rn(y);
    __half lx = __float2half_rn((x - __half2float(hx)) * LSC);
    __half ly = __float2half_rn((y - __half2float(hy)) * LSC);
    hi = (uint32_t)__half_as_ushort(hx) | ((uint32_t)__half_as_ushort(hy) << 16);
    lo = (uint32_t)__half_as_ushort(lx) | ((uint32_t)__half_as_ushort(ly) << 16);
}

// ---------------- counter reset ----------------------------------------------
__global__ void reset_ctr_kernel() {
    if (threadIdx.x < 4) g_ctr[threadIdx.x] = 0;
}

// ---------------- fused convert ----------------------------------------------
__global__ __launch_bounds__(256) void split5_kernel(
    const float* __restrict__ x0, const float* __restrict__ x1,
    const float* __restrict__ x2, const float* __restrict__ x3,
    const float* __restrict__ x4,
    __half* __restrict__ h0, __half* __restrict__ l0,
    __half* __restrict__ h1, __half* __restrict__ h2,
    __half* __restrict__ h3, __half* __restrict__ h4) {
    int z = blockIdx.y;
    const float* x = (z == 0) ? x0 : (z == 1) ? x1 : (z == 2) ? x2 : (z == 3) ? x3 : x4;
    __half* hi = (z == 0) ? h0 : (z == 1) ? h1 : (z == 2) ? h2 : (z == 3) ? h3 : h4;
    bool do_lo = (z == 0);
    const int n4 = NROWS * E_ / 4;
    for (int i = blockIdx.x * blockDim.x + threadIdx.x; i < n4; i += gridDim.x * blockDim.x) {
        float4 v = ((const float4*)x)[i];
        if (do_lo) {
            uint32_t ph0, pl0, ph1, pl1;
            split2h(v.x, v.y, ph0, pl0);
            split2h(v.z, v.w, ph1, pl1);
            ((uint2*)hi)[i] = make_uint2(ph0, ph1);
            ((uint2*)l0)[i] = make_uint2(pl0, pl1);
        } else {
            ((uint2*)hi)[i] = make_uint2(pack2h(v.x, v.y), pack2h(v.z, v.w));
        }
    }
}

// ============== QKV GEMM (2-term A, single B), CTA 64x128 ====================
#define KCH 32
#define NCHK (E_ / KCH)
#define ROWB 80
#define GAMAT (64 * ROWB)
#define GBMAT (128 * ROWB)
#define GSTG (2 * GAMAT + GBMAT)
#define GEMM_SMEM (3 * GSTG)

__device__ __forceinline__ void g_load_chunk(uint32_t base, int t, int tid,
                                             const __half* a0, const __half* a1,
                                             const __half* b0) {
    for (int i = tid; i < 256; i += 128) {
        int r = i >> 2, c = i & 3;
        size_t g = (size_t)r * E_ + t * KCH + c * 8;
        uint32_t d = base + r * ROWB + c * 16;
        CP16(d, a0 + g);
        CP16(d + GAMAT, a1 + g);
    }
    for (int i = tid; i < 512; i += 128) {
        int r = i >> 2, c = i & 3;
        size_t g = (size_t)r * E_ + t * KCH + c * 8;
        CP16(base + 2 * GAMAT + r * ROWB + c * 16, b0 + g);
    }
    CP_COMMIT();
}

__device__ __forceinline__ void g_mainloop(uint32_t sb, int tid, int lane, int wid,
                                           const __half* a0, const __half* a1,
                                           const __half* b0, float acc[2][8][4]) {
    int wm = wid >> 1;
    int wn = wid & 1;

    uint32_t accl[2][8][2];
#pragma unroll
    for (int i = 0; i < 2; i++)
#pragma unroll
        for (int j = 0; j < 8; j++) { accl[i][j][0] = 0u; accl[i][j][1] = 0u; }

    g_load_chunk(sb, 0, tid, a0, a1, b0);
    g_load_chunk(sb + GSTG, 1, tid, a0, a1, b0);

    int arow = lane & 15;
    int acolb = ((lane >> 4) & 1) * 16;
    int brow = (lane & 7) + ((lane >> 4) << 3);
    int bcolb = ((lane >> 3) & 1) * 16;

    for (int t = 0; t < NCHK; t++) {
        if (t + 1 < NCHK) asm volatile("cp.async.wait_group 1;" ::: "memory");
        else              asm volatile("cp.async.wait_group 0;" ::: "memory");
        __syncthreads();
        if (t + 2 < NCHK) g_load_chunk(sb + ((t + 2) % 3) * GSTG, t + 2, tid, a0, a1, b0);

        uint32_t st = sb + (t % 3) * GSTG;
        uint32_t aA0 = st + (wm * 32 + arow) * ROWB + acolb;
        uint32_t aA1 = aA0 + GAMAT;
        uint32_t aB0 = st + 2 * GAMAT + (wn * 64 + brow) * ROWB + bcolb;

#pragma unroll
        for (int ks = 0; ks < 2; ks++) {
            uint32_t a0f[2][4], a1f[2][4], b0f[4][4];
#pragma unroll
            for (int mt = 0; mt < 2; mt++) {
                LDSM4(a0f[mt][0], a0f[mt][1], a0f[mt][2], a0f[mt][3], aA0 + mt * 16 * ROWB + ks * 32);
                LDSM4(a1f[mt][0], a1f[mt][1], a1f[mt][2], a1f[mt][3], aA1 + mt * 16 * ROWB + ks * 32);
            }
#pragma unroll
            for (int ng = 0; ng < 4; ng++)
                LDSM4(b0f[ng][0], b0f[ng][1], b0f[ng][2], b0f[ng][3], aB0 + ng * 16 * ROWB + ks * 32);
#pragma unroll
            for (int mt = 0; mt < 2; mt++)
#pragma unroll
                for (int nt = 0; nt < 8; nt++) {
                    uint32_t* p = &b0f[nt >> 1][(nt & 1) * 2];
                    MMAH(acc[mt][nt], a0f[mt], p[0], p[1]);
                }
#pragma unroll
            for (int mt = 0; mt < 2; mt++)
#pragma unroll
                for (int nt = 0; nt < 8; nt++) {
                    uint32_t* p = &b0f[nt >> 1][(nt & 1) * 2];
                    MMAH2(accl[mt][nt], a1f[mt], p[0], p[1]);
                }
        }
    }
#pragma unroll
    for (int mt = 0; mt < 2; mt++)
#pragma unroll
        for (int nt = 0; nt < 8; nt++)
            combine_lo(acc[mt][nt], accl[mt][nt]);
    __syncthreads();
}

#define QKV_TILES (16 * 32 * 3)

__global__ __launch_bounds__(128, 2) void mma_gemm_qkv_fused(
    const __half* __restrict__ ha0, const __half* __restrict__ ha1,
    const __half* __restrict__ wq0, const __half* __restrict__ wk0,
    const __half* __restrict__ wv0,
    const float* __restrict__ mask, const float* __restrict__ norm_const,
    const int* __restrict__ pos_ids, const float* __restrict__ counts,
    __half* __restrict__ Qh, __half* __restrict__ Kh, __half* __restrict__ Vh) {
    extern __shared__ char smc[];
    uint32_t sb = smem_u32(smc);
    __shared__ int s_tile;
    int tid = threadIdx.x;
    int lane = tid & 31;
    int wid = tid >> 5;
    int wm = wid >> 1;
    int wn = wid & 1;

    for (;;) {
        if (tid == 0) s_tile = atomicAdd(&g_ctr[0], 1);
        __syncthreads();
        int tile = s_tile;
        if (tile >= QKV_TILES) return;
        int z = tile >> 9;
        int rem = tile & 511;
        int bm = (rem >> 4) * 64;
        int bn = (rem & 15) * 128;

        const __half* a0 = ha0 + (size_t)bm * E_;
        const __half* a1 = ha1 + (size_t)bm * E_;
        const __half* b0 = ((z == 0) ? wq0 : (z == 1) ? wk0 : wv0) + (size_t)bn * E_;

        float acc[2][8][4];
#pragma unroll
        for (int i = 0; i < 2; i++)
#pragma unroll
            for (int j = 0; j < 8; j++)
#pragma unroll
                for (int k = 0; k < 4; k++) acc[i][j][k] = 0.0f;

        g_mainloop(sb, tid, lane, wid, a0, a1, b0, acc);

        float* rs = (float*)smc;
        int lr = lane >> 2;
        int lc = lane & 3;

        if (z < 2) {
            if (wn == 0) {
#pragma unroll
                for (int mt = 0; mt < 2; mt++) {
                    int rg = bm + wm * 32 + mt * 16 + lr;
                    float pos0 = (float)pos_ids[rg];
                    float pos1 = (float)pos_ids[rg + 8];
#pragma unroll
                    for (int nt = 0; nt < 8; nt++) {
                        float fi = (float)(nt * 4 + lc);
                        float fr = __expf(-0.28782313662425575f * fi);
                        float s0, c0, s1, c1;
                        sincosf(pos0 * fr, &s0, &c0);
                        sincosf(pos1 * fr, &s1, &c1);
                        float x = acc[mt][nt][0], y = acc[mt][nt][1];
                        acc[mt][nt][0] = x * c0 - y * s0;
                        acc[mt][nt][1] = y * c0 + x * s0;
                        x = acc[mt][nt][2]; y = acc[mt][nt][3];
                        acc[mt][nt][2] = x * c1 - y * s1;
                        acc[mt][nt][3] = y * c1 + x * s1;
                    }
                }
            }
#pragma unroll
            for (int mt = 0; mt < 2; mt++) {
                float s0 = 0.0f, s1 = 0.0f;
#pragma unroll
                for (int nt = 0; nt < 8; nt++) {
                    s0 += acc[mt][nt][0] * acc[mt][nt][0] + acc[mt][nt][1] * acc[mt][nt][1];
                    s1 += acc[mt][nt][2] * acc[mt][nt][2] + acc[mt][nt][3] * acc[mt][nt][3];
                }
                s0 += __shfl_xor_sync(0xffffffffu, s0, 1);
                s0 += __shfl_xor_sync(0xffffffffu, s0, 2);
                s1 += __shfl_xor_sync(0xffffffffu, s1, 1);
                s1 += __shfl_xor_sync(0xffffffffu, s1, 2);
                if (lc == 0) {
                    rs[(wm * 32 + mt * 16 + lr) * 2 + wn] = s0;
                    rs[(wm * 32 + mt * 16 + lr + 8) * 2 + wn] = s1;
                }
            }
        }
        __syncthreads();

        int h = bn >> 7;
        float sig = 1.0f / (1.0f + __expf(-norm_const[h]));
        int col0 = wn * 64 + lc * 2;
        __half* O = (z == 0) ? Qh : (z == 1) ? Kh : Vh;

#pragma unroll
        for (int mt = 0; mt < 2; mt++) {
#pragma unroll
            for (int half = 0; half < 2; half++) {
                int rl = wm * 32 + mt * 16 + lr + half * 8;
                int rg = bm + rl;
                float m = (mask[rg] == 0.0f) ? 1.0f : 0.0f;
                float scl;
                if (z < 2) {
                    float tot = rs[rl * 2] + rs[rl * 2 + 1];
                    scl = m / fmaxf(sqrtf(tot), EPS_);
                } else {
                    scl = m / fmaxf(powf(counts[rg], sig), 1.0f);
                }
                int b = rg >> 10;
                int s = rg & 1023;
                size_t dst = (((size_t)(b * H_ + h)) * S_ + s) * (size_t)HD_;
#pragma unroll
                for (int nt = 0; nt < 8; nt++) {
                    int c = col0 + nt * 8;
                    *(uint32_t*)(O + dst + c) =
                        pack2h(acc[mt][nt][2 * half] * scl, acc[mt][nt][2 * half + 1] * scl);
                }
            }
        }
        __syncthreads();
    }
}

// ============== output projection: single-fp16 A, 1-term =====================
#define OSTG (GAMAT + GBMAT)           // 15360
#define OUT_SMEM (3 * OSTG)            // 46080
#define OUT_TILES (16 * 32)

__device__ __forceinline__ void o_load_chunk(uint32_t base, int t, int tid,
                                             const __half* a0, const __half* b0) {
    for (int i = tid; i < 256; i += 128) {
        int r = i >> 2, c = i & 3;
        size_t g = (size_t)r * E_ + t * KCH + c * 8;
        CP16(base + r * ROWB + c * 16, a0 + g);
    }
    for (int i = tid; i < 512; i += 128) {
        int r = i >> 2, c = i & 3;
        size_t g = (size_t)r * E_ + t * KCH + c * 8;
        CP16(base + GAMAT + r * ROWB + c * 16, b0 + g);
    }
    CP_COMMIT();
}

__global__ __launch_bounds__(128, 2) void mma_gemm_out(
    const __half* __restrict__ ha0, const __half* __restrict__ hb0,
    float* __restrict__ C) {
    extern __shared__ char smc[];
    uint32_t sb = smem_u32(smc);
    __shared__ int s_tile;
    int tid = threadIdx.x;
    int lane = tid & 31;
    int wid = tid >> 5;
    int wm = wid >> 1;
    int wn = wid & 1;

    int arow = lane & 15;
    int acolb = ((lane >> 4) & 1) * 16;
    int brow = (lane & 7) + ((lane >> 4) << 3);
    int bcolb = ((lane >> 3) & 1) * 16;

    for (;;) {
        if (tid == 0) s_tile = atomicAdd(&g_ctr[1], 1);
        __syncthreads();
        int tile = s_tile;
        if (tile >= OUT_TILES) return;
        int bm = (tile >> 4) * 64;
        int bn = (tile & 15) * 128;

        const __half* a0 = ha0 + (size_t)bm * E_;
        const __half* b0 = hb0 + (size_t)bn * E_;

        float acc[2][8][4];
#pragma unroll
        for (int i = 0; i < 2; i++)
#pragma unroll
            for (int j = 0; j < 8; j++)
#pragma unroll
                for (int k = 0; k < 4; k++) acc[i][j][k] = 0.0f;

        o_load_chunk(sb, 0, tid, a0, b0);
        o_load_chunk(sb + OSTG, 1, tid, a0, b0);

        for (int t = 0; t < NCHK; t++) {
            if (t + 1 < NCHK) asm volatile("cp.async.wait_group 1;" ::: "memory");
            else              asm volatile("cp.async.wait_group 0;" ::: "memory");
            __syncthreads();
            if (t + 2 < NCHK) o_load_chunk(sb + ((t + 2) % 3) * OSTG, t + 2, tid, a0, b0);

            uint32_t st = sb + (t % 3) * OSTG;
            uint32_t aA0 = st + (wm * 32 + arow) * ROWB + acolb;
            uint32_t aB0 = st + GAMAT + (wn * 64 + brow) * ROWB + bcolb;

#pragma unroll
            for (int ks = 0; ks < 2; ks++) {
                uint32_t a0f[2][4], b0f[4][4];
#pragma unroll
                for (int mt = 0; mt < 2; mt++)
                    LDSM4(a0f[mt][0], a0f[mt][1], a0f[mt][2], a0f[mt][3], aA0 + mt * 16 * ROWB + ks * 32);
#pragma unroll
                for (int ng = 0; ng < 4; ng++)
                    LDSM4(b0f[ng][0], b0f[ng][1], b0f[ng][2], b0f[ng][3], aB0 + ng * 16 * ROWB + ks * 32);
#pragma unroll
                for (int mt = 0; mt < 2; mt++)
#pragma unroll
                    for (int nt = 0; nt < 8; nt++) {
                        uint32_t* p = &b0f[nt >> 1][(nt & 1) * 2];
                        MMAH(acc[mt][nt], a0f[mt], p[0], p[1]);
                    }
            }
        }
        __syncthreads();

        int row0 = bm + wm * 32 + (lane >> 2);
        int col0 = bn + wn * 64 + (lane & 3) * 2;
#pragma unroll
        for (int mt = 0; mt < 2; mt++) {
#pragma unroll
            for (int nt = 0; nt < 8; nt++) {
                int r = row0 + mt * 16;
                int c = col0 + nt * 8;
                float2 v0 = {acc[mt][nt][0], acc[mt][nt][1]};
                float2 v1 = {acc[mt][nt][2], acc[mt][nt][3]};
                *(float2*)&C[(size_t)r * E_ + c] = v0;
                *(float2*)&C[(size_t)(r + 8) * E_ + c] = v1;
            }
        }
        __syncthreads();
    }
}

// ---------------- mask prefix scan ------------------------------------------
__global__ void counts_kernel(const float* __restrict__ mask, float* __restrict__ counts) {
    __shared__ float sh[S_];
    int b = blockIdx.x;
    int t = threadIdx.x;
    sh[t] = (mask[b * S_ + t] == 0.0f) ? 1.0f : 0.0f;
    __syncthreads();
    for (int off = 1; off < S_; off <<= 1) {
        float add = (t >= off) ? sh[t - off] : 0.0f;
        __syncthreads();
        sh[t] += add;
        __syncthreads();
    }
    counts[b * S_ + t] = sh[t];
}

// ============== persistent causal attention (Q single fp16) ==================
#define AQM 64
#define AKC 32
#define RB 272
#define QMAT (AQM * RB)
#define KVMAT (AKC * RB)
#define KVSTG (2 * KVMAT)
#define ATT_SMEM (QMAT + 2 * KVSTG)    // 52224
#define ATT_TILES (32 * 16)

__global__ __launch_bounds__(128, 2) void attn_mma(
    const __half* __restrict__ qh,
    const __half* __restrict__ kh, const __half* __restrict__ vh,
    __half* __restrict__ aoh) {
    extern __shared__ char smc[];
    uint32_t sb = smem_u32(smc);
    uint32_t sQh = sb;
    uint32_t sKV = sb + QMAT;
    __shared__ int s_tile;

    int tid = threadIdx.x;
    int lane = tid & 31;
    int wid = tid >> 5;

    int arow = lane & 15;
    int acolb = ((lane >> 4) & 1) * 16;
    int brow = (lane & 7) + ((lane >> 4) << 3);
    int bcolb = ((lane >> 3) & 1) * 16;
    int vrow = (lane & 7) + (((lane >> 3) & 1) << 3);
    int vcolb = ((lane >> 4) & 1) * 16;

    for (;;) {
        if (tid == 0) s_tile = atomicAdd(&g_ctr[2], 1);
        __syncthreads();
        int tile = s_tile;
        if (tile >= ATT_TILES) return;
        int bh = tile & 31;
        int qt = 15 - (tile >> 5);
        int q0 = qt * AQM;

        size_t base = (size_t)bh * S_ * HD_;
        const __half* Qhb = qh + base;
        const __half* Khb = kh + base;
        const __half* Vhb = vh + base;

        for (int i = tid; i < 1024; i += 128) {
            int r = i >> 4, c = i & 15;
            size_t g = (size_t)(q0 + r) * HD_ + c * 8;
            CP16(sQh + r * RB + c * 16, Qhb + g);
        }
        for (int i = tid; i < 512; i += 128) {
            int r = i >> 4, c = i & 15;
            size_t g = (size_t)r * HD_ + c * 8;
            uint32_t d = sKV + r * RB + c * 16;
            CP16(d, Khb + g);
            CP16(d + KVMAT, Vhb + g);
        }
        CP_COMMIT();

        int nch = (q0 + AQM) / AKC;
        float o[16][4];
        uint32_t ol[16][2];
#pragma unroll
        for (int i = 0; i < 16; i++) {
#pragma unroll
            for (int j = 0; j < 4; j++) o[i][j] = 0.0f;
            ol[i][0] = 0u; ol[i][1] = 0u;
        }
        int m0w = q0 + wid * 16;

        for (int t = 0; t < nch; t++) {
            asm volatile("cp.async.wait_group 0;" ::: "memory");
            __syncthreads();
            if (t + 1 < nch) {
                uint32_t nstg = sKV + ((t + 1) & 1) * KVSTG;
                int kc = (t + 1) * AKC;
                for (int i = tid; i < 512; i += 128) {
                    int r = i >> 4, c = i & 15;
                    size_t g = (size_t)(kc + r) * HD_ + c * 8;
                    uint32_t d = nstg + r * RB + c * 16;
                    CP16(d, Khb + g);
                    CP16(d + KVMAT, Vhb + g);
                }
                CP_COMMIT();
            }
            uint32_t stg = sKV + (t & 1) * KVSTG;

            // ---- phase 1: S = Q.K^T (single-fp16 Q, fp32 acc)
            float sacc[4][4];
#pragma unroll
            for (int i = 0; i < 4; i++)
#pragma unroll
                for (int j = 0; j < 4; j++) sacc[i][j] = 0.0f;

#pragma unroll
            for (int ds = 0; ds < 8; ds++) {
                uint32_t ah[4];
                uint32_t ad = sQh + (wid * 16 + arow) * RB + acolb + ds * 32;
                LDSM4(ah[0], ah[1], ah[2], ah[3], ad);
                uint32_t bhf[2][4];
#pragma unroll
                for (int ng = 0; ng < 2; ng++) {
                    uint32_t bd = stg + (ng * 16 + brow) * RB + bcolb + ds * 32;
                    LDSM4(bhf[ng][0], bhf[ng][1], bhf[ng][2], bhf[ng][3], bd);
                }
#pragma unroll
                for (int nt = 0; nt < 4; nt++) {
                    uint32_t* ph = &bhf[nt >> 1][(nt & 1) * 2];
                    MMAH(sacc[nt], ah, ph[0], ph[1]);
                }
            }

            // ---- causal mask
            int kcg = t * AKC;
            if (kcg + AKC - 1 > m0w) {
                int r0m = m0w + (lane >> 2);
                int r1m = r0m + 8;
#pragma unroll
                for (int nt = 0; nt < 4; nt++) {
                    int cb = kcg + nt * 8 + (lane & 3) * 2;
                    if (cb > r0m) sacc[nt][0] = 0.0f;
                    if (cb + 1 > r0m) sacc[nt][1] = 0.0f;
                    if (cb > r1m) sacc[nt][2] = 0.0f;
                    if (cb + 1 > r1m) sacc[nt][3] = 0.0f;
                }
            }

            // ---- phase 2: O += S.V  (S split hi/lo; lo in fp16-acc)
#pragma unroll
            for (int ks = 0; ks < 2; ks++) {
                uint32_t ah[4], al[4];
                split2h(sacc[2 * ks][0], sacc[2 * ks][1], ah[0], al[0]);
                split2h(sacc[2 * ks][2], sacc[2 * ks][3], ah[1], al[1]);
                split2h(sacc[2 * ks + 1][0], sacc[2 * ks + 1][1], ah[2], al[2]);
                split2h(sacc[2 * ks + 1][2], sacc[2 * ks + 1][3], ah[3], al[3]);
#pragma unroll
                for (int ng = 0; ng < 8; ng++) {
                    uint32_t bv[4];
                    uint32_t va = stg + KVMAT + (ks * 16 + vrow) * RB + vcolb + ng * 32;
                    LDSM4T(bv[0], bv[1], bv[2], bv[3], va);
                    MMAH(o[2 * ng], ah, bv[0], bv[1]);
                    MMAH(o[2 * ng + 1], ah, bv[2], bv[3]);
                    MMAH2(ol[2 * ng], al, bv[0], bv[1]);
                    MMAH2(ol[2 * ng + 1], al, bv[2], bv[3]);
                }
            }
            __syncthreads();
        }

#pragma unroll
        for (int nt = 0; nt < 16; nt++) combine_lo(o[nt], ol[nt]);

        int b = bh / H_;
        int h = bh % H_;
        int r0 = m0w + (lane >> 2);
#pragma unroll
        for (int nt = 0; nt < 16; nt++) {
            int col = nt * 8 + (lane & 3) * 2;
            size_t g0 = ((size_t)(b * S_ + r0)) * E_ + h * HD_ + col;
            size_t g1 = ((size_t)(b * S_ + r0 + 8)) * E_ + h * HD_ + col;
            *(uint32_t*)(aoh + g0) = pack2h(o[nt][0], o[nt][1]);
            *(uint32_t*)(aoh + g1) = pack2h(o[nt][2], o[nt][3]);
        }
        __syncthreads();
    }
}

// ---------------- launcher ---------------------------------------------------
extern "C" void kernel_launch(void* const* d_in, const int* in_sizes, int n_in,
                              void* d_out, int out_size) {
    const float* hs        = (const float*)d_in[0];
    const float* w_q       = (const float*)d_in[1];
    const float* w_k       = (const float*)d_in[2];
    const float* w_v       = (const float*)d_in[3];
    const float* w_o       = (const float*)d_in[4];
    const float* norm_c    = (const float*)d_in[5];
    const float* attn_mask = (const float*)d_in[6];
    const int*   pos_ids   = (const int*)d_in[7];
    float* out = (float*)d_out;

    float* cnts;
    cudaGetSymbolAddress((void**)&cnts, g_counts);

    __half *hs0, *hs1, *wq0, *wk0, *wv0, *wo0, *ao0;
    __half *q0, *k0, *v0;
    cudaGetSymbolAddress((void**)&hs0, g_hs0);
    cudaGetSymbolAddress((void**)&hs1, g_hs1);
    cudaGetSymbolAddress((void**)&wq0, g_wq0);
    cudaGetSymbolAddress((void**)&wk0, g_wk0);
    cudaGetSymbolAddress((void**)&wv0, g_wv0);
    cudaGetSymbolAddress((void**)&wo0, g_wo0);
    cudaGetSymbolAddress((void**)&ao0, g_ao0);
    cudaGetSymbolAddress((void**)&q0, g_q0);
    cudaGetSymbolAddress((void**)&k0, g_k0);
    cudaGetSymbolAddress((void**)&v0, g_v0);

    static bool attr_set = false;
    if (!attr_set) {
        cudaFuncSetAttribute(mma_gemm_qkv_fused, cudaFuncAttributeMaxDynamicSharedMemorySize, GEMM_SMEM);
        cudaFuncSetAttribute(mma_gemm_out, cudaFuncAttributeMaxDynamicSharedMemorySize, OUT_SMEM);
        cudaFuncSetAttribute(attn_mma, cudaFuncAttributeMaxDynamicSharedMemorySize, ATT_SMEM);
        attr_set = true;
    }

    reset_ctr_kernel<<<1, 32>>>();

    counts_kernel<<<B_, S_>>>(attn_mask, cnts);

    split5_kernel<<<dim3(256, 5), 256>>>(hs, w_q, w_k, w_v, w_o,
                                         hs0, hs1, wq0, wk0, wv0, wo0);

    mma_gemm_qkv_fused<<<NPERS, 128, GEMM_SMEM>>>(
        hs0, hs1, wq0, wk0, wv0,
        attn_mask, norm_c, pos_ids, cnts,
        q0, k0, v0);

    attn_mma<<<NPERS, 128, ATT_SMEM>>>(q0, k0, v0, ao0);

    mma_gemm_out<<<NPERS, 128, OUT_SMEM>>>(ao0, wo0, out);
}

// round 15
// speedup vs baseline: 13.5473x; 1.1885x over previous
#include <cuda_runtime.h>
#include <cuda_fp16.h>
#include <math.h>
#include <stdint.h>

#define B_  2
#define S_  1024
#define E_  2048
#define H_  16
#define HD_ 128
#define ROT_ 64
#define NROWS (B_ * S_)
#define EPS_ 1e-12f
#define LSC 1024.0f
#define LSCI (1.0f / 1024.0f)
#define NPERS 304

// ---------------- scratch ----------------------------------------------------
__device__ float g_counts[B_ * S_];
__device__ int g_ctr[4];

__device__ __half g_hs0[NROWS * E_];
__device__ __half g_wq0[E_ * E_];
__device__ __half g_wk0[E_ * E_];
__device__ __half g_wv0[E_ * E_];
__device__ __half g_wo0[E_ * E_];
__device__ __half g_ao0[NROWS * E_];

__device__ __half g_q0[B_ * H_ * S_ * HD_];
__device__ __half g_k0[B_ * H_ * S_ * HD_];
__device__ __half g_v0[B_ * H_ * S_ * HD_];

// ---------------- PTX helpers ------------------------------------------------
__device__ __forceinline__ uint32_t smem_u32(const void* p) {
    uint32_t a;
    asm("{ .reg .u64 t; cvta.to.shared.u64 t, %1; cvt.u32.u64 %0, t; }" : "=r"(a) : "l"(p));
    return a;
}
#define CP16(dst, src) asm volatile("cp.async.cg.shared.global [%0], [%1], 16;" :: "r"(dst), "l"(src) : "memory")
#define CP_COMMIT() asm volatile("cp.async.commit_group;" ::: "memory")

#define LDSM4(r0, r1, r2, r3, addr) \
    asm volatile("ldmatrix.sync.aligned.m8n8.x4.shared.b16 {%0,%1,%2,%3}, [%4];" \
        : "=r"(r0), "=r"(r1), "=r"(r2), "=r"(r3) : "r"(addr))

#define LDSM4T(r0, r1, r2, r3, addr) \
    asm volatile("ldmatrix.sync.aligned.m8n8.x4.trans.shared.b16 {%0,%1,%2,%3}, [%4];" \
        : "=r"(r0), "=r"(r1), "=r"(r2), "=r"(r3) : "r"(addr))

#define MMAH(c, a, br0, br1) \
    asm volatile("mma.sync.aligned.m16n8k16.row.col.f32.f16.f16.f32 " \
        "{%0,%1,%2,%3}, {%4,%5,%6,%7}, {%8,%9}, {%0,%1,%2,%3};" \
        : "+f"((c)[0]), "+f"((c)[1]), "+f"((c)[2]), "+f"((c)[3]) \
        : "r"((a)[0]), "r"((a)[1]), "r"((a)[2]), "r"((a)[3]), "r"(br0), "r"(br1))

#define MMAH2(c, a, br0, br1) \
    asm volatile("mma.sync.aligned.m16n8k16.row.col.f16.f16.f16.f16 " \
        "{%0,%1}, {%2,%3,%4,%5}, {%6,%7}, {%0,%1};" \
        : "+r"((c)[0]), "+r"((c)[1]) \
        : "r"((a)[0]), "r"((a)[1]), "r"((a)[2]), "r"((a)[3]), "r"(br0), "r"(br1))

__device__ __forceinline__ void combine_lo(float* c, const uint32_t* cl) {
    __half2 h0 = *(const __half2*)&cl[0];
    __half2 h1 = *(const __half2*)&cl[1];
    float2 f0 = __half22float2(h0);
    float2 f1 = __half22float2(h1);
    c[0] += f0.x * LSCI;
    c[1] += f0.y * LSCI;
    c[2] += f1.x * LSCI;
    c[3] += f1.y * LSCI;
}

__device__ __forceinline__ uint32_t pack2h(float x, float y) {
    __half hx = __float2half_rn(x), hy = __float2half_rn(y);
    return (uint32_t)__half_as_ushort(hx) | ((uint32_t)__half_as_ushort(hy) << 16);
}
__device__ __forceinline__ void split2h(float x, float y, uint32_t& hi, uint32_t& lo) {
    __half hx = __float2half_rn(x), hy = __float2half_rn(y);
    __half lx = __float2half_rn((x - __half2float(hx)) * LSC);
    __half ly = __float2half_rn((y - __half2float(hy)) * LSC);
    hi = (uint32_t)__half_as_ushort(hx) | ((uint32_t)__half_as_ushort(hy) << 16);
    lo = (uint32_t)__half_as_ushort(lx) | ((uint32_t)__half_as_ushort(ly) << 16);
}

// ---------------- counter reset ----------------------------------------------
__global__ void reset_ctr_kernel() {
    if (threadIdx.x < 4) g_ctr[threadIdx.x] = 0;
}

// ---------------- fp32 -> fp16 convert (5 tensors) ---------------------------
__global__ __launch_bounds__(256) void cvt5_kernel(
    const float* __restrict__ x0, const float* __restrict__ x1,
    const float* __restrict__ x2, const float* __restrict__ x3,
    const float* __restrict__ x4,
    __half* __restrict__ h0, __half* __restrict__ h1, __half* __restrict__ h2,
    __half* __restrict__ h3, __half* __restrict__ h4) {
    int z = blockIdx.y;
    const float* x = (z == 0) ? x0 : (z == 1) ? x1 : (z == 2) ? x2 : (z == 3) ? x3 : x4;
    __half* hi = (z == 0) ? h0 : (z == 1) ? h1 : (z == 2) ? h2 : (z == 3) ? h3 : h4;
    const int n4 = NROWS * E_ / 4;
    for (int i = blockIdx.x * blockDim.x + threadIdx.x; i < n4; i += gridDim.x * blockDim.x) {
        float4 v = ((const float4*)x)[i];
        ((uint2*)hi)[i] = make_uint2(pack2h(v.x, v.y), pack2h(v.z, v.w));
    }
}

// ============== single-term fp16 GEMM mainloop: CTA 64x128, 4 warps ==========
#define KCH 32
#define NCHK (E_ / KCH)
#define ROWB 80
#define GAMAT (64 * ROWB)
#define GBMAT (128 * ROWB)
#define GSTG (GAMAT + GBMAT)           // 15360
#define GEMM_SMEM (3 * GSTG)           // 46080

__device__ __forceinline__ void g_load_chunk(uint32_t base, int t, int tid,
                                             const __half* a0, const __half* b0) {
    for (int i = tid; i < 256; i += 128) {
        int r = i >> 2, c = i & 3;
        size_t g = (size_t)r * E_ + t * KCH + c * 8;
        CP16(base + r * ROWB + c * 16, a0 + g);
    }
    for (int i = tid; i < 512; i += 128) {
        int r = i >> 2, c = i & 3;
        size_t g = (size_t)r * E_ + t * KCH + c * 8;
        CP16(base + GAMAT + r * ROWB + c * 16, b0 + g);
    }
    CP_COMMIT();
}

__device__ __forceinline__ void g_mainloop(uint32_t sb, int tid, int lane, int wid,
                                           const __half* a0, const __half* b0,
                                           float acc[2][8][4]) {
    int wm = wid >> 1;
    int wn = wid & 1;

    g_load_chunk(sb, 0, tid, a0, b0);
    g_load_chunk(sb + GSTG, 1, tid, a0, b0);

    int arow = lane & 15;
    int acolb = ((lane >> 4) & 1) * 16;
    int brow = (lane & 7) + ((lane >> 4) << 3);
    int bcolb = ((lane >> 3) & 1) * 16;

    for (int t = 0; t < NCHK; t++) {
        if (t + 1 < NCHK) asm volatile("cp.async.wait_group 1;" ::: "memory");
        else              asm volatile("cp.async.wait_group 0;" ::: "memory");
        __syncthreads();
        if (t + 2 < NCHK) g_load_chunk(sb + ((t + 2) % 3) * GSTG, t + 2, tid, a0, b0);

        uint32_t st = sb + (t % 3) * GSTG;
        uint32_t aA0 = st + (wm * 32 + arow) * ROWB + acolb;
        uint32_t aB0 = st + GAMAT + (wn * 64 + brow) * ROWB + bcolb;

#pragma unroll
        for (int ks = 0; ks < 2; ks++) {
            uint32_t a0f[2][4], b0f[4][4];
#pragma unroll
            for (int mt = 0; mt < 2; mt++)
                LDSM4(a0f[mt][0], a0f[mt][1], a0f[mt][2], a0f[mt][3], aA0 + mt * 16 * ROWB + ks * 32);
#pragma unroll
            for (int ng = 0; ng < 4; ng++)
                LDSM4(b0f[ng][0], b0f[ng][1], b0f[ng][2], b0f[ng][3], aB0 + ng * 16 * ROWB + ks * 32);
#pragma unroll
            for (int mt = 0; mt < 2; mt++)
#pragma unroll
                for (int nt = 0; nt < 8; nt++) {
                    uint32_t* p = &b0f[nt >> 1][(nt & 1) * 2];
                    MMAH(acc[mt][nt], a0f[mt], p[0], p[1]);
                }
        }
    }
    __syncthreads();
}

// ============== persistent QKV GEMM with fused epilogue ======================
#define QKV_TILES (16 * 32 * 3)

__global__ __launch_bounds__(128, 2) void mma_gemm_qkv_fused(
    const __half* __restrict__ ha0,
    const __half* __restrict__ wq0, const __half* __restrict__ wk0,
    const __half* __restrict__ wv0,
    const float* __restrict__ mask, const float* __restrict__ norm_const,
    const int* __restrict__ pos_ids, const float* __restrict__ counts,
    __half* __restrict__ Qh, __half* __restrict__ Kh, __half* __restrict__ Vh) {
    extern __shared__ char smc[];
    uint32_t sb = smem_u32(smc);
    __shared__ int s_tile;
    int tid = threadIdx.x;
    int lane = tid & 31;
    int wid = tid >> 5;
    int wm = wid >> 1;
    int wn = wid & 1;

    for (;;) {
        if (tid == 0) s_tile = atomicAdd(&g_ctr[0], 1);
        __syncthreads();
        int tile = s_tile;
        if (tile >= QKV_TILES) return;
        int z = tile >> 9;
        int rem = tile & 511;
        int bm = (rem >> 4) * 64;
        int bn = (rem & 15) * 128;

        const __half* a0 = ha0 + (size_t)bm * E_;
        const __half* b0 = ((z == 0) ? wq0 : (z == 1) ? wk0 : wv0) + (size_t)bn * E_;

        float acc[2][8][4];
#pragma unroll
        for (int i = 0; i < 2; i++)
#pragma unroll
            for (int j = 0; j < 8; j++)
#pragma unroll
                for (int k = 0; k < 4; k++) acc[i][j][k] = 0.0f;

        g_mainloop(sb, tid, lane, wid, a0, b0, acc);

        float* rs = (float*)smc;
        int lr = lane >> 2;
        int lc = lane & 3;

        if (z < 2) {
            if (wn == 0) {
#pragma unroll
                for (int mt = 0; mt < 2; mt++) {
                    int rg = bm + wm * 32 + mt * 16 + lr;
                    float pos0 = (float)pos_ids[rg];
                    float pos1 = (float)pos_ids[rg + 8];
#pragma unroll
                    for (int nt = 0; nt < 8; nt++) {
                        float fi = (float)(nt * 4 + lc);
                        float fr = __expf(-0.28782313662425575f * fi);
                        float s0, c0, s1, c1;
                        sincosf(pos0 * fr, &s0, &c0);
                        sincosf(pos1 * fr, &s1, &c1);
                        float x = acc[mt][nt][0], y = acc[mt][nt][1];
                        acc[mt][nt][0] = x * c0 - y * s0;
                        acc[mt][nt][1] = y * c0 + x * s0;
                        x = acc[mt][nt][2]; y = acc[mt][nt][3];
                        acc[mt][nt][2] = x * c1 - y * s1;
                        acc[mt][nt][3] = y * c1 + x * s1;
                    }
                }
            }
#pragma unroll
            for (int mt = 0; mt < 2; mt++) {
                float s0 = 0.0f, s1 = 0.0f;
#pragma unroll
                for (int nt = 0; nt < 8; nt++) {
                    s0 += acc[mt][nt][0] * acc[mt][nt][0] + acc[mt][nt][1] * acc[mt][nt][1];
                    s1 += acc[mt][nt][2] * acc[mt][nt][2] + acc[mt][nt][3] * acc[mt][nt][3];
                }
                s0 += __shfl_xor_sync(0xffffffffu, s0, 1);
                s0 += __shfl_xor_sync(0xffffffffu, s0, 2);
                s1 += __shfl_xor_sync(0xffffffffu, s1, 1);
                s1 += __shfl_xor_sync(0xffffffffu, s1, 2);
                if (lc == 0) {
                    rs[(wm * 32 + mt * 16 + lr) * 2 + wn] = s0;
                    rs[(wm * 32 + mt * 16 + lr + 8) * 2 + wn] = s1;
                }
            }
        }
        __syncthreads();

        int h = bn >> 7;
        float sig = 1.0f / (1.0f + __expf(-norm_const[h]));
        int col0 = wn * 64 + lc * 2;
        __half* O = (z == 0) ? Qh : (z == 1) ? Kh : Vh;

#pragma unroll
        for (int mt = 0; mt < 2; mt++) {
#pragma unroll
            for (int half = 0; half < 2; half++) {
                int rl = wm * 32 + mt * 16 + lr + half * 8;
                int rg = bm + rl;
                float m = (mask[rg] == 0.0f) ? 1.0f : 0.0f;
                float scl;
                if (z < 2) {
                    float tot = rs[rl * 2] + rs[rl * 2 + 1];
                    scl = m / fmaxf(sqrtf(tot), EPS_);
                } else {
                    scl = m / fmaxf(powf(counts[rg], sig), 1.0f);
                }
                int b = rg >> 10;
                int s = rg & 1023;
                size_t dst = (((size_t)(b * H_ + h)) * S_ + s) * (size_t)HD_;
#pragma unroll
                for (int nt = 0; nt < 8; nt++) {
                    int c = col0 + nt * 8;
                    *(uint32_t*)(O + dst + c) =
                        pack2h(acc[mt][nt][2 * half] * scl, acc[mt][nt][2 * half + 1] * scl);
                }
            }
        }
        __syncthreads();
    }
}

// ============== persistent output projection (single-term) ===================
#define OUT_TILES (16 * 32)

__global__ __launch_bounds__(128, 2) void mma_gemm_out(
    const __half* __restrict__ ha0, const __half* __restrict__ hb0,
    float* __restrict__ C) {
    extern __shared__ char smc[];
    uint32_t sb = smem_u32(smc);
    __shared__ int s_tile;
    int tid = threadIdx.x;
    int lane = tid & 31;
    int wid = tid >> 5;
    int wm = wid >> 1;
    int wn = wid & 1;

    for (;;) {
        if (tid == 0) s_tile = atomicAdd(&g_ctr[1], 1);
        __syncthreads();
        int tile = s_tile;
        if (tile >= OUT_TILES) return;
        int bm = (tile >> 4) * 64;
        int bn = (tile & 15) * 128;

        const __half* a0 = ha0 + (size_t)bm * E_;
        const __half* b0 = hb0 + (size_t)bn * E_;

        float acc[2][8][4];
#pragma unroll
        for (int i = 0; i < 2; i++)
#pragma unroll
            for (int j = 0; j < 8; j++)
#pragma unroll
                for (int k = 0; k < 4; k++) acc[i][j][k] = 0.0f;

        g_mainloop(sb, tid, lane, wid, a0, b0, acc);

        int row0 = bm + wm * 32 + (lane >> 2);
        int col0 = bn + wn * 64 + (lane & 3) * 2;
#pragma unroll
        for (int mt = 0; mt < 2; mt++) {
#pragma unroll
            for (int nt = 0; nt < 8; nt++) {
                int r = row0 + mt * 16;
                int c = col0 + nt * 8;
                float2 v0 = {acc[mt][nt][0], acc[mt][nt][1]};
                float2 v1 = {acc[mt][nt][2], acc[mt][nt][3]};
                *(float2*)&C[(size_t)r * E_ + c] = v0;
                *(float2*)&C[(size_t)(r + 8) * E_ + c] = v1;
            }
        }
        __syncthreads();
    }
}

// ---------------- mask prefix scan ------------------------------------------
__global__ void counts_kernel(const float* __restrict__ mask, float* __restrict__ counts) {
    __shared__ float sh[S_];
    int b = blockIdx.x;
    int t = threadIdx.x;
    sh[t] = (mask[b * S_ + t] == 0.0f) ? 1.0f : 0.0f;
    __syncthreads();
    for (int off = 1; off < S_; off <<= 1) {
        float add = (t >= off) ? sh[t - off] : 0.0f;
        __syncthreads();
        sh[t] += add;
        __syncthreads();
    }
    counts[b * S_ + t] = sh[t];
}

// ============== persistent causal attention ==================================
#define AQM 64
#define AKC 32
#define RB 272
#define QMAT (AQM * RB)
#define KVMAT (AKC * RB)
#define KVSTG (2 * KVMAT)
#define ATT_SMEM (QMAT + 2 * KVSTG)
#define ATT_TILES (32 * 16)

__global__ __launch_bounds__(128, 2) void attn_mma(
    const __half* __restrict__ qh,
    const __half* __restrict__ kh, const __half* __restrict__ vh,
    __half* __restrict__ aoh) {
    extern __shared__ char smc[];
    uint32_t sb = smem_u32(smc);
    uint32_t sQh = sb;
    uint32_t sKV = sb + QMAT;
    __shared__ int s_tile;

    int tid = threadIdx.x;
    int lane = tid & 31;
    int wid = tid >> 5;

    int arow = lane & 15;
    int acolb = ((lane >> 4) & 1) * 16;
    int brow = (lane & 7) + ((lane >> 4) << 3);
    int bcolb = ((lane >> 3) & 1) * 16;
    int vrow = (lane & 7) + (((lane >> 3) & 1) << 3);
    int vcolb = ((lane >> 4) & 1) * 16;

    for (;;) {
        if (tid == 0) s_tile = atomicAdd(&g_ctr[2], 1);
        __syncthreads();
        int tile = s_tile;
        if (tile >= ATT_TILES) return;
        int bh = tile & 31;
        int qt = 15 - (tile >> 5);
        int q0 = qt * AQM;

        size_t base = (size_t)bh * S_ * HD_;
        const __half* Qhb = qh + base;
        const __half* Khb = kh + base;
        const __half* Vhb = vh + base;

        for (int i = tid; i < 1024; i += 128) {
            int r = i >> 4, c = i & 15;
            size_t g = (size_t)(q0 + r) * HD_ + c * 8;
            CP16(sQh + r * RB + c * 16, Qhb + g);
        }
        for (int i = tid; i < 512; i += 128) {
            int r = i >> 4, c = i & 15;
            size_t g = (size_t)r * HD_ + c * 8;
            uint32_t d = sKV + r * RB + c * 16;
            CP16(d, Khb + g);
            CP16(d + KVMAT, Vhb + g);
        }
        CP_COMMIT();

        int nch = (q0 + AQM) / AKC;
        float o[16][4];
        uint32_t ol[16][2];
#pragma unroll
        for (int i = 0; i < 16; i++) {
#pragma unroll
            for (int j = 0; j < 4; j++) o[i][j] = 0.0f;
            ol[i][0] = 0u; ol[i][1] = 0u;
        }
        int m0w = q0 + wid * 16;

        for (int t = 0; t < nch; t++) {
            asm volatile("cp.async.wait_group 0;" ::: "memory");
            __syncthreads();
            if (t + 1 < nch) {
                uint32_t nstg = sKV + ((t + 1) & 1) * KVSTG;
                int kc = (t + 1) * AKC;
                for (int i = tid; i < 512; i += 128) {
                    int r = i >> 4, c = i & 15;
                    size_t g = (size_t)(kc + r) * HD_ + c * 8;
                    uint32_t d = nstg + r * RB + c * 16;
                    CP16(d, Khb + g);
                    CP16(d + KVMAT, Vhb + g);
                }
                CP_COMMIT();
            }
            uint32_t stg = sKV + (t & 1) * KVSTG;

            float sacc[4][4];
#pragma unroll
            for (int i = 0; i < 4; i++)
#pragma unroll
                for (int j = 0; j < 4; j++) sacc[i][j] = 0.0f;

#pragma unroll
            for (int ds = 0; ds < 8; ds++) {
                uint32_t ah[4];
                uint32_t ad = sQh + (wid * 16 + arow) * RB + acolb + ds * 32;
                LDSM4(ah[0], ah[1], ah[2], ah[3], ad);
                uint32_t bhf[2][4];
#pragma unroll
                for (int ng = 0; ng < 2; ng++) {
                    uint32_t bd = stg + (ng * 16 + brow) * RB + bcolb + ds * 32;
                    LDSM4(bhf[ng][0], bhf[ng][1], bhf[ng][2], bhf[ng][3], bd);
                }
#pragma unroll
                for (int nt = 0; nt < 4; nt++) {
                    uint32_t* ph = &bhf[nt >> 1][(nt & 1) * 2];
                    MMAH(sacc[nt], ah, ph[0], ph[1]);
                }
            }

            int kcg = t * AKC;
            if (kcg + AKC - 1 > m0w) {
                int r0m = m0w + (lane >> 2);
                int r1m = r0m + 8;
#pragma unroll
                for (int nt = 0; nt < 4; nt++) {
                    int cb = kcg + nt * 8 + (lane & 3) * 2;
                    if (cb > r0m) sacc[nt][0] = 0.0f;
                    if (cb + 1 > r0m) sacc[nt][1] = 0.0f;
                    if (cb > r1m) sacc[nt][2] = 0.0f;
                    if (cb + 1 > r1m) sacc[nt][3] = 0.0f;
                }
            }

#pragma unroll
            for (int ks = 0; ks < 2; ks++) {
                uint32_t ah[4], al[4];
                split2h(sacc[2 * ks][0], sacc[2 * ks][1], ah[0], al[0]);
                split2h(sacc[2 * ks][2], sacc[2 * ks][3], ah[1], al[1]);
                split2h(sacc[2 * ks + 1][0], sacc[2 * ks + 1][1], ah[2], al[2]);
                split2h(sacc[2 * ks + 1][2], sacc[2 * ks + 1][3], ah[3], al[3]);
#pragma unroll
                for (int ng = 0; ng < 8; ng++) {
                    uint32_t bv[4];
                    uint32_t va = stg + KVMAT + (ks * 16 + vrow) * RB + vcolb + ng * 32;
                    LDSM4T(bv[0], bv[1], bv[2], bv[3], va);
                    MMAH(o[2 * ng], ah, bv[0], bv[1]);
                    MMAH(o[2 * ng + 1], ah, bv[2], bv[3]);
                    MMAH2(ol[2 * ng], al, bv[0], bv[1]);
                    MMAH2(ol[2 * ng + 1], al, bv[2], bv[3]);
                }
            }
            __syncthreads();
        }

#pragma unroll
        for (int nt = 0; nt < 16; nt++) combine_lo(o[nt], ol[nt]);

        int b = bh / H_;
        int h = bh % H_;
        int r0 = m0w + (lane >> 2);
#pragma unroll
        for (int nt = 0; nt < 16; nt++) {
            int col = nt * 8 + (lane & 3) * 2;
            size_t g0 = ((size_t)(b * S_ + r0)) * E_ + h * HD_ + col;
            size_t g1 = ((size_t)(b * S_ + r0 + 8)) * E_ + h * HD_ + col;
            *(uint32_t*)(aoh + g0) = pack2h(o[nt][0], o[nt][1]);
            *(uint32_t*)(aoh + g1) = pack2h(o[nt][2], o[nt][3]);
        }
        __syncthreads();
    }
}

// ---------------- launcher ---------------------------------------------------
extern "C" void kernel_launch(void* const* d_in, const int* in_sizes, int n_in,
                              void* d_out, int out_size) {
    const float* hs        = (const float*)d_in[0];
    const float* w_q       = (const float*)d_in[1];
    const float* w_k       = (const float*)d_in[2];
    const float* w_v       = (const float*)d_in[3];
    const float* w_o       = (const float*)d_in[4];
    const float* norm_c    = (const float*)d_in[5];
    const float* attn_mask = (const float*)d_in[6];
    const int*   pos_ids   = (const int*)d_in[7];
    float* out = (float*)d_out;

    float* cnts;
    cudaGetSymbolAddress((void**)&cnts, g_counts);

    __half *hs0, *wq0, *wk0, *wv0, *wo0, *ao0;
    __half *q0, *k0, *v0;
    cudaGetSymbolAddress((void**)&hs0, g_hs0);
    cudaGetSymbolAddress((void**)&wq0, g_wq0);
    cudaGetSymbolAddress((void**)&wk0, g_wk0);
    cudaGetSymbolAddress((void**)&wv0, g_wv0);
    cudaGetSymbolAddress((void**)&wo0, g_wo0);
    cudaGetSymbolAddress((void**)&ao0, g_ao0);
    cudaGetSymbolAddress((void**)&q0, g_q0);
    cudaGetSymbolAddress((void**)&k0, g_k0);
    cudaGetSymbolAddress((void**)&v0, g_v0);

    static bool attr_set = false;
    if (!attr_set) {
        cudaFuncSetAttribute(mma_gemm_qkv_fused, cudaFuncAttributeMaxDynamicSharedMemorySize, GEMM_SMEM);
        cudaFuncSetAttribute(mma_gemm_out, cudaFuncAttributeMaxDynamicSharedMemorySize, GEMM_SMEM);
        cudaFuncSetAttribute(attn_mma, cudaFuncAttributeMaxDynamicSharedMemorySize, ATT_SMEM);
        attr_set = true;
    }

    reset_ctr_kernel<<<1, 32>>>();

    counts_kernel<<<B_, S_>>>(attn_mask, cnts);

    cvt5_kernel<<<dim3(256, 5), 256>>>(hs, w_q, w_k, w_v, w_o,
                                       hs0, wq0, wk0, wv0, wo0);

    mma_gemm_qkv_fused<<<NPERS, 128, GEMM_SMEM>>>(
        hs0, wq0, wk0, wv0,
        attn_mask, norm_c, pos_ids, cnts,
        q0, k0, v0);

    attn_mma<<<NPERS, 128, ATT_SMEM>>>(q0, k0, v0, ao0);

    mma_gemm_out<<<NPERS, 128, GEMM_SMEM>>>(ao0, wo0, out);
}

// round 16
// speedup vs baseline: 14.4300x; 1.0652x over previous
#include <cuda_runtime.h>
#include <cuda_fp16.h>
#include <math.h>
#include <stdint.h>

#define B_  2
#define S_  1024
#define E_  2048
#define H_  16
#define HD_ 128
#define ROT_ 64
#define NROWS (B_ * S_)
#define EPS_ 1e-12f
#define LSC 1024.0f
#define LSCI (1.0f / 1024.0f)
#define NPERS_G 456        // 3 CTAs/SM for GEMM kernels
#define NPERS_A 304        // 2 CTAs/SM for attention

// ---------------- scratch ----------------------------------------------------
__device__ float g_counts[B_ * S_];
__device__ int g_ctr[4];

__device__ __half g_hs0[NROWS * E_];
__device__ __half g_wq0[E_ * E_];
__device__ __half g_wk0[E_ * E_];
__device__ __half g_wv0[E_ * E_];
__device__ __half g_wo0[E_ * E_];
__device__ __half g_ao0[NROWS * E_];

__device__ __half g_q0[B_ * H_ * S_ * HD_];
__device__ __half g_k0[B_ * H_ * S_ * HD_];
__device__ __half g_v0[B_ * H_ * S_ * HD_];

// ---------------- PTX helpers ------------------------------------------------
__device__ __forceinline__ uint32_t smem_u32(const void* p) {
    uint32_t a;
    asm("{ .reg .u64 t; cvta.to.shared.u64 t, %1; cvt.u32.u64 %0, t; }" : "=r"(a) : "l"(p));
    return a;
}
#define CP16(dst, src) asm volatile("cp.async.cg.shared.global [%0], [%1], 16;" :: "r"(dst), "l"(src) : "memory")
#define CP_COMMIT() asm volatile("cp.async.commit_group;" ::: "memory")

#define LDSM4(r0, r1, r2, r3, addr) \
    asm volatile("ldmatrix.sync.aligned.m8n8.x4.shared.b16 {%0,%1,%2,%3}, [%4];" \
        : "=r"(r0), "=r"(r1), "=r"(r2), "=r"(r3) : "r"(addr))

#define LDSM4T(r0, r1, r2, r3, addr) \
    asm volatile("ldmatrix.sync.aligned.m8n8.x4.trans.shared.b16 {%0,%1,%2,%3}, [%4];" \
        : "=r"(r0), "=r"(r1), "=r"(r2), "=r"(r3) : "r"(addr))

#define MMAH(c, a, br0, br1) \
    asm volatile("mma.sync.aligned.m16n8k16.row.col.f32.f16.f16.f32 " \
        "{%0,%1,%2,%3}, {%4,%5,%6,%7}, {%8,%9}, {%0,%1,%2,%3};" \
        : "+f"((c)[0]), "+f"((c)[1]), "+f"((c)[2]), "+f"((c)[3]) \
        : "r"((a)[0]), "r"((a)[1]), "r"((a)[2]), "r"((a)[3]), "r"(br0), "r"(br1))

#define MMAH2(c, a, br0, br1) \
    asm volatile("mma.sync.aligned.m16n8k16.row.col.f16.f16.f16.f16 " \
        "{%0,%1}, {%2,%3,%4,%5}, {%6,%7}, {%0,%1};" \
        : "+r"((c)[0]), "+r"((c)[1]) \
        : "r"((a)[0]), "r"((a)[1]), "r"((a)[2]), "r"((a)[3]), "r"(br0), "r"(br1))

__device__ __forceinline__ void combine_lo(float* c, const uint32_t* cl) {
    __half2 h0 = *(const __half2*)&cl[0];
    __half2 h1 = *(const __half2*)&cl[1];
    float2 f0 = __half22float2(h0);
    float2 f1 = __half22float2(h1);
    c[0] += f0.x * LSCI;
    c[1] += f0.y * LSCI;
    c[2] += f1.x * LSCI;
    c[3] += f1.y * LSCI;
}

__device__ __forceinline__ uint32_t pack2h(float x, float y) {
    __half hx = __float2half_rn(x), hy = __float2half_rn(y);
    return (uint32_t)__half_as_ushort(hx) | ((uint32_t)__half_as_ushort(hy) << 16);
}
__device__ __forceinline__ void split2h(float x, float y, uint32_t& hi, uint32_t& lo) {
    __half hx = __float2half_rn(x), hy = __float2half_rn(y);
    __half lx = __float2half_rn((x - __half2float(hx)) * LSC);
    __half ly = __float2half_rn((y - __half2float(hy)) * LSC);
    hi = (uint32_t)__half_as_ushort(hx) | ((uint32_t)__half_as_ushort(hy) << 16);
    lo = (uint32_t)__half_as_ushort(lx) | ((uint32_t)__half_as_ushort(ly) << 16);
}

// ---------------- counter reset ----------------------------------------------
__global__ void reset_ctr_kernel() {
    if (threadIdx.x < 4) g_ctr[threadIdx.x] = 0;
}

// ---------------- fp32 -> fp16 convert (5 tensors) ---------------------------
__global__ __launch_bounds__(256) void cvt5_kernel(
    const float* __restrict__ x0, const float* __restrict__ x1,
    const float* __restrict__ x2, const float* __restrict__ x3,
    const float* __restrict__ x4,
    __half* __restrict__ h0, __half* __restrict__ h1, __half* __restrict__ h2,
    __half* __restrict__ h3, __half* __restrict__ h4) {
    int z = blockIdx.y;
    const float* x = (z == 0) ? x0 : (z == 1) ? x1 : (z == 2) ? x2 : (z == 3) ? x3 : x4;
    __half* hi = (z == 0) ? h0 : (z == 1) ? h1 : (z == 2) ? h2 : (z == 3) ? h3 : h4;
    const int n4 = NROWS * E_ / 4;
    for (int i = blockIdx.x * blockDim.x + threadIdx.x; i < n4; i += gridDim.x * blockDim.x) {
        float4 v = ((const float4*)x)[i];
        ((uint2*)hi)[i] = make_uint2(pack2h(v.x, v.y), pack2h(v.z, v.w));
    }
}

// ============== single-term fp16 GEMM mainloop: CTA 64x128, 4 warps ==========
#define KCH 32
#define NCHK (E_ / KCH)
#define ROWB 80
#define GAMAT (64 * ROWB)
#define GBMAT (128 * ROWB)
#define GSTG (GAMAT + GBMAT)           // 15360
#define GEMM_SMEM (3 * GSTG)           // 46080

__device__ __forceinline__ void g_load_chunk(uint32_t base, int t, int tid,
                                             const __half* a0, const __half* b0) {
    for (int i = tid; i < 256; i += 128) {
        int r = i >> 2, c = i & 3;
        size_t g = (size_t)r * E_ + t * KCH + c * 8;
        CP16(base + r * ROWB + c * 16, a0 + g);
    }
    for (int i = tid; i < 512; i += 128) {
        int r = i >> 2, c = i & 3;
        size_t g = (size_t)r * E_ + t * KCH + c * 8;
        CP16(base + GAMAT + r * ROWB + c * 16, b0 + g);
    }
    CP_COMMIT();
}

__device__ __forceinline__ void g_mainloop(uint32_t sb, int tid, int lane, int wid,
                                           const __half* a0, const __half* b0,
                                           float acc[2][8][4]) {
    int wm = wid >> 1;
    int wn = wid & 1;

    g_load_chunk(sb, 0, tid, a0, b0);
    g_load_chunk(sb + GSTG, 1, tid, a0, b0);

    int arow = lane & 15;
    int acolb = ((lane >> 4) & 1) * 16;
    int brow = (lane & 7) + ((lane >> 4) << 3);
    int bcolb = ((lane >> 3) & 1) * 16;

    for (int t = 0; t < NCHK; t++) {
        if (t + 1 < NCHK) asm volatile("cp.async.wait_group 1;" ::: "memory");
        else              asm volatile("cp.async.wait_group 0;" ::: "memory");
        __syncthreads();
        if (t + 2 < NCHK) g_load_chunk(sb + ((t + 2) % 3) * GSTG, t + 2, tid, a0, b0);

        uint32_t st = sb + (t % 3) * GSTG;
        uint32_t aA0 = st + (wm * 32 + arow) * ROWB + acolb;
        uint32_t aB0 = st + GAMAT + (wn * 64 + brow) * ROWB + bcolb;

#pragma unroll
        for (int ks = 0; ks < 2; ks++) {
            uint32_t a0f[2][4], b0f[4][4];
#pragma unroll
            for (int mt = 0; mt < 2; mt++)
                LDSM4(a0f[mt][0], a0f[mt][1], a0f[mt][2], a0f[mt][3], aA0 + mt * 16 * ROWB + ks * 32);
#pragma unroll
            for (int ng = 0; ng < 4; ng++)
                LDSM4(b0f[ng][0], b0f[ng][1], b0f[ng][2], b0f[ng][3], aB0 + ng * 16 * ROWB + ks * 32);
#pragma unroll
            for (int mt = 0; mt < 2; mt++)
#pragma unroll
                for (int nt = 0; nt < 8; nt++) {
                    uint32_t* p = &b0f[nt >> 1][(nt & 1) * 2];
                    MMAH(acc[mt][nt], a0f[mt], p[0], p[1]);
                }
        }
    }
    __syncthreads();
}

// ============== persistent QKV GEMM with fused epilogue, 3 CTA/SM ============
#define QKV_TILES (16 * 32 * 3)

__global__ __launch_bounds__(128, 3) void mma_gemm_qkv_fused(
    const __half* __restrict__ ha0,
    const __half* __restrict__ wq0, const __half* __restrict__ wk0,
    const __half* __restrict__ wv0,
    const float* __restrict__ mask, const float* __restrict__ norm_const,
    const int* __restrict__ pos_ids, const float* __restrict__ counts,
    __half* __restrict__ Qh, __half* __restrict__ Kh, __half* __restrict__ Vh) {
    extern __shared__ char smc[];
    uint32_t sb = smem_u32(smc);
    __shared__ int s_tile;
    int tid = threadIdx.x;
    int lane = tid & 31;
    int wid = tid >> 5;
    int wm = wid >> 1;
    int wn = wid & 1;

    for (;;) {
        if (tid == 0) s_tile = atomicAdd(&g_ctr[0], 1);
        __syncthreads();
        int tile = s_tile;
        if (tile >= QKV_TILES) return;
        int z = tile >> 9;
        int rem = tile & 511;
        int bm = (rem >> 4) * 64;
        int bn = (rem & 15) * 128;

        const __half* a0 = ha0 + (size_t)bm * E_;
        const __half* b0 = ((z == 0) ? wq0 : (z == 1) ? wk0 : wv0) + (size_t)bn * E_;

        float acc[2][8][4];
#pragma unroll
        for (int i = 0; i < 2; i++)
#pragma unroll
            for (int j = 0; j < 8; j++)
#pragma unroll
                for (int k = 0; k < 4; k++) acc[i][j][k] = 0.0f;

        g_mainloop(sb, tid, lane, wid, a0, b0, acc);

        float* rs = (float*)smc;
        int lr = lane >> 2;
        int lc = lane & 3;

        if (z < 2) {
            if (wn == 0) {
#pragma unroll
                for (int mt = 0; mt < 2; mt++) {
                    int rg = bm + wm * 32 + mt * 16 + lr;
                    float pos0 = (float)pos_ids[rg];
                    float pos1 = (float)pos_ids[rg + 8];
#pragma unroll
                    for (int nt = 0; nt < 8; nt++) {
                        float fi = (float)(nt * 4 + lc);
                        float fr = __expf(-0.28782313662425575f * fi);
                        float s0, c0, s1, c1;
                        sincosf(pos0 * fr, &s0, &c0);
                        sincosf(pos1 * fr, &s1, &c1);
                        float x = acc[mt][nt][0], y = acc[mt][nt][1];
                        acc[mt][nt][0] = x * c0 - y * s0;
                        acc[mt][nt][1] = y * c0 + x * s0;
                        x = acc[mt][nt][2]; y = acc[mt][nt][3];
                        acc[mt][nt][2] = x * c1 - y * s1;
                        acc[mt][nt][3] = y * c1 + x * s1;
                    }
                }
            }
#pragma unroll
            for (int mt = 0; mt < 2; mt++) {
                float s0 = 0.0f, s1 = 0.0f;
#pragma unroll
                for (int nt = 0; nt < 8; nt++) {
                    s0 += acc[mt][nt][0] * acc[mt][nt][0] + acc[mt][nt][1] * acc[mt][nt][1];
                    s1 += acc[mt][nt][2] * acc[mt][nt][2] + acc[mt][nt][3] * acc[mt][nt][3];
                }
                s0 += __shfl_xor_sync(0xffffffffu, s0, 1);
                s0 += __shfl_xor_sync(0xffffffffu, s0, 2);
                s1 += __shfl_xor_sync(0xffffffffu, s1, 1);
                s1 += __shfl_xor_sync(0xffffffffu, s1, 2);
                if (lc == 0) {
                    rs[(wm * 32 + mt * 16 + lr) * 2 + wn] = s0;
                    rs[(wm * 32 + mt * 16 + lr + 8) * 2 + wn] = s1;
                }
            }
        }
        __syncthreads();

        int h = bn >> 7;
        float sig = 1.0f / (1.0f + __expf(-norm_const[h]));
        int col0 = wn * 64 + lc * 2;
        __half* O = (z == 0) ? Qh : (z == 1) ? Kh : Vh;

#pragma unroll
        for (int mt = 0; mt < 2; mt++) {
#pragma unroll
            for (int half = 0; half < 2; half++) {
                int rl = wm * 32 + mt * 16 + lr + half * 8;
                int rg = bm + rl;
                float m = (mask[rg] == 0.0f) ? 1.0f : 0.0f;
                float scl;
                if (z < 2) {
                    float tot = rs[rl * 2] + rs[rl * 2 + 1];
                    scl = m / fmaxf(sqrtf(tot), EPS_);
                } else {
                    scl = m / fmaxf(powf(counts[rg], sig), 1.0f);
                }
                int b = rg >> 10;
                int s = rg & 1023;
                size_t dst = (((size_t)(b * H_ + h)) * S_ + s) * (size_t)HD_;
#pragma unroll
                for (int nt = 0; nt < 8; nt++) {
                    int c = col0 + nt * 8;
                    *(uint32_t*)(O + dst + c) =
                        pack2h(acc[mt][nt][2 * half] * scl, acc[mt][nt][2 * half + 1] * scl);
                }
            }
        }
        __syncthreads();
    }
}

// ============== persistent output projection, 3 CTA/SM =======================
#define OUT_TILES (16 * 32)

__global__ __launch_bounds__(128, 3) void mma_gemm_out(
    const __half* __restrict__ ha0, const __half* __restrict__ hb0,
    float* __restrict__ C) {
    extern __shared__ char smc[];
    uint32_t sb = smem_u32(smc);
    __shared__ int s_tile;
    int tid = threadIdx.x;
    int lane = tid & 31;
    int wid = tid >> 5;
    int wm = wid >> 1;
    int wn = wid & 1;

    for (;;) {
        if (tid == 0) s_tile = atomicAdd(&g_ctr[1], 1);
        __syncthreads();
        int tile = s_tile;
        if (tile >= OUT_TILES) return;
        int bm = (tile >> 4) * 64;
        int bn = (tile & 15) * 128;

        const __half* a0 = ha0 + (size_t)bm * E_;
        const __half* b0 = hb0 + (size_t)bn * E_;

        float acc[2][8][4];
#pragma unroll
        for (int i = 0; i < 2; i++)
#pragma unroll
            for (int j = 0; j < 8; j++)
#pragma unroll
                for (int k = 0; k < 4; k++) acc[i][j][k] = 0.0f;

        g_mainloop(sb, tid, lane, wid, a0, b0, acc);

        int row0 = bm + wm * 32 + (lane >> 2);
        int col0 = bn + wn * 64 + (lane & 3) * 2;
#pragma unroll
        for (int mt = 0; mt < 2; mt++) {
#pragma unroll
            for (int nt = 0; nt < 8; nt++) {
                int r = row0 + mt * 16;
                int c = col0 + nt * 8;
                float2 v0 = {acc[mt][nt][0], acc[mt][nt][1]};
                float2 v1 = {acc[mt][nt][2], acc[mt][nt][3]};
                *(float2*)&C[(size_t)r * E_ + c] = v0;
                *(float2*)&C[(size_t)(r + 8) * E_ + c] = v1;
            }
        }
        __syncthreads();
    }
}

// ---------------- mask prefix scan ------------------------------------------
__global__ void counts_kernel(const float* __restrict__ mask, float* __restrict__ counts) {
    __shared__ float sh[S_];
    int b = blockIdx.x;
    int t = threadIdx.x;
    sh[t] = (mask[b * S_ + t] == 0.0f) ? 1.0f : 0.0f;
    __syncthreads();
    for (int off = 1; off < S_; off <<= 1) {
        float add = (t >= off) ? sh[t - off] : 0.0f;
        __syncthreads();
        sh[t] += add;
        __syncthreads();
    }
    counts[b * S_ + t] = sh[t];
}

// ============== persistent causal attention, 2 CTA/SM ========================
#define AQM 64
#define AKC 32
#define RB 272
#define QMAT (AQM * RB)
#define KVMAT (AKC * RB)
#define KVSTG (2 * KVMAT)
#define ATT_SMEM (QMAT + 2 * KVSTG)
#define ATT_TILES (32 * 16)

__global__ __launch_bounds__(128, 2) void attn_mma(
    const __half* __restrict__ qh,
    const __half* __restrict__ kh, const __half* __restrict__ vh,
    __half* __restrict__ aoh) {
    extern __shared__ char smc[];
    uint32_t sb = smem_u32(smc);
    uint32_t sQh = sb;
    uint32_t sKV = sb + QMAT;
    __shared__ int s_tile;

    int tid = threadIdx.x;
    int lane = tid & 31;
    int wid = tid >> 5;

    int arow = lane & 15;
    int acolb = ((lane >> 4) & 1) * 16;
    int brow = (lane & 7) + ((lane >> 4) << 3);
    int bcolb = ((lane >> 3) & 1) * 16;
    int vrow = (lane & 7) + (((lane >> 3) & 1) << 3);
    int vcolb = ((lane >> 4) & 1) * 16;

    for (;;) {
        if (tid == 0) s_tile = atomicAdd(&g_ctr[2], 1);
        __syncthreads();
        int tile = s_tile;
        if (tile >= ATT_TILES) return;
        int bh = tile & 31;
        int qt = 15 - (tile >> 5);
        int q0 = qt * AQM;

        size_t base = (size_t)bh * S_ * HD_;
        const __half* Qhb = qh + base;
        const __half* Khb = kh + base;
        const __half* Vhb = vh + base;

        for (int i = tid; i < 1024; i += 128) {
            int r = i >> 4, c = i & 15;
            size_t g = (size_t)(q0 + r) * HD_ + c * 8;
            CP16(sQh + r * RB + c * 16, Qhb + g);
        }
        for (int i = tid; i < 512; i += 128) {
            int r = i >> 4, c = i & 15;
            size_t g = (size_t)r * HD_ + c * 8;
            uint32_t d = sKV + r * RB + c * 16;
            CP16(d, Khb + g);
            CP16(d + KVMAT, Vhb + g);
        }
        CP_COMMIT();

        int nch = (q0 + AQM) / AKC;
        float o[16][4];
        uint32_t ol[16][2];
#pragma unroll
        for (int i = 0; i < 16; i++) {
#pragma unroll
            for (int j = 0; j < 4; j++) o[i][j] = 0.0f;
            ol[i][0] = 0u; ol[i][1] = 0u;
        }
        int m0w = q0 + wid * 16;

        for (int t = 0; t < nch; t++) {
            asm volatile("cp.async.wait_group 0;" ::: "memory");
            __syncthreads();
            if (t + 1 < nch) {
                uint32_t nstg = sKV + ((t + 1) & 1) * KVSTG;
                int kc = (t + 1) * AKC;
                for (int i = tid; i < 512; i += 128) {
                    int r = i >> 4, c = i & 15;
                    size_t g = (size_t)(kc + r) * HD_ + c * 8;
                    uint32_t d = nstg + r * RB + c * 16;
                    CP16(d, Khb + g);
                    CP16(d + KVMAT, Vhb + g);
                }
                CP_COMMIT();
            }
            uint32_t stg = sKV + (t & 1) * KVSTG;

            float sacc[4][4];
#pragma unroll
            for (int i = 0; i < 4; i++)
#pragma unroll
                for (int j = 0; j < 4; j++) sacc[i][j] = 0.0f;

#pragma unroll
            for (int ds = 0; ds < 8; ds++) {
                uint32_t ah[4];
                uint32_t ad = sQh + (wid * 16 + arow) * RB + acolb + ds * 32;
                LDSM4(ah[0], ah[1], ah[2], ah[3], ad);
                uint32_t bhf[2][4];
#pragma unroll
                for (int ng = 0; ng < 2; ng++) {
                    uint32_t bd = stg + (ng * 16 + brow) * RB + bcolb + ds * 32;
                    LDSM4(bhf[ng][0], bhf[ng][1], bhf[ng][2], bhf[ng][3], bd);
                }
#pragma unroll
                for (int nt = 0; nt < 4; nt++) {
                    uint32_t* ph = &bhf[nt >> 1][(nt & 1) * 2];
                    MMAH(sacc[nt], ah, ph[0], ph[1]);
                }
            }

            int kcg = t * AKC;
            if (kcg + AKC - 1 > m0w) {
                int r0m = m0w + (lane >> 2);
                int r1m = r0m + 8;
#pragma unroll
                for (int nt = 0; nt < 4; nt++) {
                    int cb = kcg + nt * 8 + (lane & 3) * 2;
                    if (cb > r0m) sacc[nt][0] = 0.0f;
                    if (cb + 1 > r0m) sacc[nt][1] = 0.0f;
                    if (cb > r1m) sacc[nt][2] = 0.0f;
                    if (cb + 1 > r1m) sacc[nt][3] = 0.0f;
                }
            }

#pragma unroll
            for (int ks = 0; ks < 2; ks++) {
                uint32_t ah[4], al[4];
                split2h(sacc[2 * ks][0], sacc[2 * ks][1], ah[0], al[0]);
                split2h(sacc[2 * ks][2], sacc[2 * ks][3], ah[1], al[1]);
                split2h(sacc[2 * ks + 1][0], sacc[2 * ks + 1][1], ah[2], al[2]);
                split2h(sacc[2 * ks + 1][2], sacc[2 * ks + 1][3], ah[3], al[3]);
#pragma unroll
                for (int ng = 0; ng < 8; ng++) {
                    uint32_t bv[4];
                    uint32_t va = stg + KVMAT + (ks * 16 + vrow) * RB + vcolb + ng * 32;
                    LDSM4T(bv[0], bv[1], bv[2], bv[3], va);
                    MMAH(o[2 * ng], ah, bv[0], bv[1]);
                    MMAH(o[2 * ng + 1], ah, bv[2], bv[3]);
                    MMAH2(ol[2 * ng], al, bv[0], bv[1]);
                    MMAH2(ol[2 * ng + 1], al, bv[2], bv[3]);
                }
            }
            __syncthreads();
        }

#pragma unroll
        for (int nt = 0; nt < 16; nt++) combine_lo(o[nt], ol[nt]);

        int b = bh / H_;
        int h = bh % H_;
        int r0 = m0w + (lane >> 2);
#pragma unroll
        for (int nt = 0; nt < 16; nt++) {
            int col = nt * 8 + (lane & 3) * 2;
            size_t g0 = ((size_t)(b * S_ + r0)) * E_ + h * HD_ + col;
            size_t g1 = ((size_t)(b * S_ + r0 + 8)) * E_ + h * HD_ + col;
            *(uint32_t*)(aoh + g0) = pack2h(o[nt][0], o[nt][1]);
            *(uint32_t*)(aoh + g1) = pack2h(o[nt][2], o[nt][3]);
        }
        __syncthreads();
    }
}

// ---------------- launcher ---------------------------------------------------
extern "C" void kernel_launch(void* const* d_in, const int* in_sizes, int n_in,
                              void* d_out, int out_size) {
    const float* hs        = (const float*)d_in[0];
    const float* w_q       = (const float*)d_in[1];
    const float* w_k       = (const float*)d_in[2];
    const float* w_v       = (const float*)d_in[3];
    const float* w_o       = (const float*)d_in[4];
    const float* norm_c    = (const float*)d_in[5];
    const float* attn_mask = (const float*)d_in[6];
    const int*   pos_ids   = (const int*)d_in[7];
    float* out = (float*)d_out;

    float* cnts;
    cudaGetSymbolAddress((void**)&cnts, g_counts);

    __half *hs0, *wq0, *wk0, *wv0, *wo0, *ao0;
    __half *q0, *k0, *v0;
    cudaGetSymbolAddress((void**)&hs0, g_hs0);
    cudaGetSymbolAddress((void**)&wq0, g_wq0);
    cudaGetSymbolAddress((void**)&wk0, g_wk0);
    cudaGetSymbolAddress((void**)&wv0, g_wv0);
    cudaGetSymbolAddress((void**)&wo0, g_wo0);
    cudaGetSymbolAddress((void**)&ao0, g_ao0);
    cudaGetSymbolAddress((void**)&q0, g_q0);
    cudaGetSymbolAddress((void**)&k0, g_k0);
    cudaGetSymbolAddress((void**)&v0, g_v0);

    static bool attr_set = false;
    if (!attr_set) {
        cudaFuncSetAttribute(mma_gemm_qkv_fused, cudaFuncAttributeMaxDynamicSharedMemorySize, GEMM_SMEM);
        cudaFuncSetAttribute(mma_gemm_out, cudaFuncAttributeMaxDynamicSharedMemorySize, GEMM_SMEM);
        cudaFuncSetAttribute(attn_mma, cudaFuncAttributeMaxDynamicSharedMemorySize, ATT_SMEM);
        attr_set = true;
    }

    reset_ctr_kernel<<<1, 32>>>();

    counts_kernel<<<B_, S_>>>(attn_mask, cnts);

    cvt5_kernel<<<dim3(256, 5), 256>>>(hs, w_q, w_k, w_v, w_o,
                                       hs0, wq0, wk0, wv0, wo0);

    mma_gemm_qkv_fused<<<NPERS_G, 128, GEMM_SMEM>>>(
        hs0, wq0, wk0, wv0,
        attn_mask, norm_c, pos_ids, cnts,
        q0, k0, v0);

    attn_mma<<<NPERS_A, 128, ATT_SMEM>>>(q0, k0, v0, ao0);

    mma_gemm_out<<<NPERS_G, 128, GEMM_SMEM>>>(ao0, wo0, out);
}

// round 17
// speedup vs baseline: 15.8382x; 1.0976x over previous
#include <cuda_runtime.h>
#include <cuda_fp16.h>
#include <math.h>
#include <stdint.h>

#define B_  2
#define S_  1024
#define E_  2048
#define H_  16
#define HD_ 128
#define ROT_ 64
#define NROWS (B_ * S_)
#define EPS_ 1e-12f
#define NPERS_G 608        // 4 CTAs/SM for GEMM kernels
#define NPERS_A 456        // 3 CTAs/SM for attention

// ---------------- scratch ----------------------------------------------------
__device__ float g_counts[B_ * S_];
__device__ int g_ctr[4];

__device__ __half g_hs0[NROWS * E_];
__device__ __half g_wq0[E_ * E_];
__device__ __half g_wk0[E_ * E_];
__device__ __half g_wv0[E_ * E_];
__device__ __half g_wo0[E_ * E_];
__device__ __half g_ao0[NROWS * E_];

__device__ __half g_q0[B_ * H_ * S_ * HD_];
__device__ __half g_k0[B_ * H_ * S_ * HD_];
__device__ __half g_v0[B_ * H_ * S_ * HD_];

// ---------------- PTX helpers ------------------------------------------------
__device__ __forceinline__ uint32_t smem_u32(const void* p) {
    uint32_t a;
    asm("{ .reg .u64 t; cvta.to.shared.u64 t, %1; cvt.u32.u64 %0, t; }" : "=r"(a) : "l"(p));
    return a;
}
#define CP16(dst, src) asm volatile("cp.async.cg.shared.global [%0], [%1], 16;" :: "r"(dst), "l"(src) : "memory")
#define CP_COMMIT() asm volatile("cp.async.commit_group;" ::: "memory")

#define LDSM4(r0, r1, r2, r3, addr) \
    asm volatile("ldmatrix.sync.aligned.m8n8.x4.shared.b16 {%0,%1,%2,%3}, [%4];" \
        : "=r"(r0), "=r"(r1), "=r"(r2), "=r"(r3) : "r"(addr))

#define LDSM4T(r0, r1, r2, r3, addr) \
    asm volatile("ldmatrix.sync.aligned.m8n8.x4.trans.shared.b16 {%0,%1,%2,%3}, [%4];" \
        : "=r"(r0), "=r"(r1), "=r"(r2), "=r"(r3) : "r"(addr))

#define MMAH(c, a, br0, br1) \
    asm volatile("mma.sync.aligned.m16n8k16.row.col.f32.f16.f16.f32 " \
        "{%0,%1,%2,%3}, {%4,%5,%6,%7}, {%8,%9}, {%0,%1,%2,%3};" \
        : "+f"((c)[0]), "+f"((c)[1]), "+f"((c)[2]), "+f"((c)[3]) \
        : "r"((a)[0]), "r"((a)[1]), "r"((a)[2]), "r"((a)[3]), "r"(br0), "r"(br1))

__device__ __forceinline__ uint32_t pack2h(float x, float y) {
    __half hx = __float2half_rn(x), hy = __float2half_rn(y);
    return (uint32_t)__half_as_ushort(hx) | ((uint32_t)__half_as_ushort(hy) << 16);
}

// ---------------- counter reset ----------------------------------------------
__global__ void reset_ctr_kernel() {
    if (threadIdx.x < 4) g_ctr[threadIdx.x] = 0;
}

// ---------------- fp32 -> fp16 convert (5 tensors) ---------------------------
__global__ __launch_bounds__(256) void cvt5_kernel(
    const float* __restrict__ x0, const float* __restrict__ x1,
    const float* __restrict__ x2, const float* __restrict__ x3,
    const float* __restrict__ x4,
    __half* __restrict__ h0, __half* __restrict__ h1, __half* __restrict__ h2,
    __half* __restrict__ h3, __half* __restrict__ h4) {
    int z = blockIdx.y;
    const float* x = (z == 0) ? x0 : (z == 1) ? x1 : (z == 2) ? x2 : (z == 3) ? x3 : x4;
    __half* hi = (z == 0) ? h0 : (z == 1) ? h1 : (z == 2) ? h2 : (z == 3) ? h3 : h4;
    const int n4 = NROWS * E_ / 4;
    for (int i = blockIdx.x * blockDim.x + threadIdx.x; i < n4; i += gridDim.x * blockDim.x) {
        float4 v = ((const float4*)x)[i];
        ((uint2*)hi)[i] = make_uint2(pack2h(v.x, v.y), pack2h(v.z, v.w));
    }
}

// ============== single-term fp16 GEMM mainloop: CTA 64x128, 4 warps ==========
#define KCH 32
#define NCHK (E_ / KCH)
#define ROWB 80
#define GAMAT (64 * ROWB)
#define GBMAT (128 * ROWB)
#define GSTG (GAMAT + GBMAT)           // 15360
#define GEMM_SMEM (3 * GSTG)           // 46080

__device__ __forceinline__ void g_load_chunk(uint32_t base, int t, int tid,
                                             const __half* a0, const __half* b0) {
    for (int i = tid; i < 256; i += 128) {
        int r = i >> 2, c = i & 3;
        size_t g = (size_t)r * E_ + t * KCH + c * 8;
        CP16(base + r * ROWB + c * 16, a0 + g);
    }
    for (int i = tid; i < 512; i += 128) {
        int r = i >> 2, c = i & 3;
        size_t g = (size_t)r * E_ + t * KCH + c * 8;
        CP16(base + GAMAT + r * ROWB + c * 16, b0 + g);
    }
    CP_COMMIT();
}

__device__ __forceinline__ void g_mainloop(uint32_t sb, int tid, int lane, int wid,
                                           const __half* a0, const __half* b0,
                                           float acc[2][8][4]) {
    int wm = wid >> 1;
    int wn = wid & 1;

    g_load_chunk(sb, 0, tid, a0, b0);
    g_load_chunk(sb + GSTG, 1, tid, a0, b0);

    int arow = lane & 15;
    int acolb = ((lane >> 4) & 1) * 16;
    int brow = (lane & 7) + ((lane >> 4) << 3);
    int bcolb = ((lane >> 3) & 1) * 16;

    for (int t = 0; t < NCHK; t++) {
        if (t + 1 < NCHK) asm volatile("cp.async.wait_group 1;" ::: "memory");
        else              asm volatile("cp.async.wait_group 0;" ::: "memory");
        __syncthreads();
        if (t + 2 < NCHK) g_load_chunk(sb + ((t + 2) % 3) * GSTG, t + 2, tid, a0, b0);

        uint32_t st = sb + (t % 3) * GSTG;
        uint32_t aA0 = st + (wm * 32 + arow) * ROWB + acolb;
        uint32_t aB0 = st + GAMAT + (wn * 64 + brow) * ROWB + bcolb;

#pragma unroll
        for (int ks = 0; ks < 2; ks++) {
            uint32_t a0f[2][4], b0f[4][4];
#pragma unroll
            for (int mt = 0; mt < 2; mt++)
                LDSM4(a0f[mt][0], a0f[mt][1], a0f[mt][2], a0f[mt][3], aA0 + mt * 16 * ROWB + ks * 32);
#pragma unroll
            for (int ng = 0; ng < 4; ng++)
                LDSM4(b0f[ng][0], b0f[ng][1], b0f[ng][2], b0f[ng][3], aB0 + ng * 16 * ROWB + ks * 32);
#pragma unroll
            for (int mt = 0; mt < 2; mt++)
#pragma unroll
                for (int nt = 0; nt < 8; nt++) {
                    uint32_t* p = &b0f[nt >> 1][(nt & 1) * 2];
                    MMAH(acc[mt][nt], a0f[mt], p[0], p[1]);
                }
        }
    }
    __syncthreads();
}

// ============== persistent QKV GEMM with fused epilogue, 4 CTA/SM ============
#define QKV_TILES (16 * 32 * 3)

__global__ __launch_bounds__(128, 4) void mma_gemm_qkv_fused(
    const __half* __restrict__ ha0,
    const __half* __restrict__ wq0, const __half* __restrict__ wk0,
    const __half* __restrict__ wv0,
    const float* __restrict__ mask, const float* __restrict__ norm_const,
    const int* __restrict__ pos_ids, const float* __restrict__ counts,
    __half* __restrict__ Qh, __half* __restrict__ Kh, __half* __restrict__ Vh) {
    extern __shared__ char smc[];
    uint32_t sb = smem_u32(smc);
    __shared__ int s_tile;
    int tid = threadIdx.x;
    int lane = tid & 31;
    int wid = tid >> 5;
    int wm = wid >> 1;
    int wn = wid & 1;

    for (;;) {
        if (tid == 0) s_tile = atomicAdd(&g_ctr[0], 1);
        __syncthreads();
        int tile = s_tile;
        if (tile >= QKV_TILES) return;
        int z = tile >> 9;
        int rem = tile & 511;
        int bm = (rem >> 4) * 64;
        int bn = (rem & 15) * 128;

        const __half* a0 = ha0 + (size_t)bm * E_;
        const __half* b0 = ((z == 0) ? wq0 : (z == 1) ? wk0 : wv0) + (size_t)bn * E_;

        float acc[2][8][4];
#pragma unroll
        for (int i = 0; i < 2; i++)
#pragma unroll
            for (int j = 0; j < 8; j++)
#pragma unroll
                for (int k = 0; k < 4; k++) acc[i][j][k] = 0.0f;

        g_mainloop(sb, tid, lane, wid, a0, b0, acc);

        float* rs = (float*)smc;
        int lr = lane >> 2;
        int lc = lane & 3;

        if (z < 2) {
            if (wn == 0) {
#pragma unroll
                for (int mt = 0; mt < 2; mt++) {
                    int rg = bm + wm * 32 + mt * 16 + lr;
                    float pos0 = (float)pos_ids[rg];
                    float pos1 = (float)pos_ids[rg + 8];
#pragma unroll
                    for (int nt = 0; nt < 8; nt++) {
                        float fi = (float)(nt * 4 + lc);
                        float fr = __expf(-0.28782313662425575f * fi);
                        float s0, c0, s1, c1;
                        sincosf(pos0 * fr, &s0, &c0);
                        sincosf(pos1 * fr, &s1, &c1);
                        float x = acc[mt][nt][0], y = acc[mt][nt][1];
                        acc[mt][nt][0] = x * c0 - y * s0;
                        acc[mt][nt][1] = y * c0 + x * s0;
                        x = acc[mt][nt][2]; y = acc[mt][nt][3];
                        acc[mt][nt][2] = x * c1 - y * s1;
                        acc[mt][nt][3] = y * c1 + x * s1;
                    }
                }
            }
#pragma unroll
            for (int mt = 0; mt < 2; mt++) {
                float s0 = 0.0f, s1 = 0.0f;
#pragma unroll
                for (int nt = 0; nt < 8; nt++) {
                    s0 += acc[mt][nt][0] * acc[mt][nt][0] + acc[mt][nt][1] * acc[mt][nt][1];
                    s1 += acc[mt][nt][2] * acc[mt][nt][2] + acc[mt][nt][3] * acc[mt][nt][3];
                }
                s0 += __shfl_xor_sync(0xffffffffu, s0, 1);
                s0 += __shfl_xor_sync(0xffffffffu, s0, 2);
                s1 += __shfl_xor_sync(0xffffffffu, s1, 1);
                s1 += __shfl_xor_sync(0xffffffffu, s1, 2);
                if (lc == 0) {
                    rs[(wm * 32 + mt * 16 + lr) * 2 + wn] = s0;
                    rs[(wm * 32 + mt * 16 + lr + 8) * 2 + wn] = s1;
                }
            }
        }
        __syncthreads();

        int h = bn >> 7;
        float sig = 1.0f / (1.0f + __expf(-norm_const[h]));
        int col0 = wn * 64 + lc * 2;
        __half* O = (z == 0) ? Qh : (z == 1) ? Kh : Vh;

#pragma unroll
        for (int mt = 0; mt < 2; mt++) {
#pragma unroll
            for (int half = 0; half < 2; half++) {
                int rl = wm * 32 + mt * 16 + lr + half * 8;
                int rg = bm + rl;
                float m = (mask[rg] == 0.0f) ? 1.0f : 0.0f;
                float scl;
                if (z < 2) {
                    float tot = rs[rl * 2] + rs[rl * 2 + 1];
                    scl = m / fmaxf(sqrtf(tot), EPS_);
                } else {
                    scl = m / fmaxf(powf(counts[rg], sig), 1.0f);
                }
                int b = rg >> 10;
                int s = rg & 1023;
                size_t dst = (((size_t)(b * H_ + h)) * S_ + s) * (size_t)HD_;
#pragma unroll
                for (int nt = 0; nt < 8; nt++) {
                    int c = col0 + nt * 8;
                    *(uint32_t*)(O + dst + c) =
                        pack2h(acc[mt][nt][2 * half] * scl, acc[mt][nt][2 * half + 1] * scl);
                }
            }
        }
        __syncthreads();
    }
}

// ============== persistent output projection, 4 CTA/SM =======================
#define OUT_TILES (16 * 32)

__global__ __launch_bounds__(128, 4) void mma_gemm_out(
    const __half* __restrict__ ha0, const __half* __restrict__ hb0,
    float* __restrict__ C) {
    extern __shared__ char smc[];
    uint32_t sb = smem_u32(smc);
    __shared__ int s_tile;
    int tid = threadIdx.x;
    int lane = tid & 31;
    int wid = tid >> 5;
    int wm = wid >> 1;
    int wn = wid & 1;

    for (;;) {
        if (tid == 0) s_tile = atomicAdd(&g_ctr[1], 1);
        __syncthreads();
        int tile = s_tile;
        if (tile >= OUT_TILES) return;
        int bm = (tile >> 4) * 64;
        int bn = (tile & 15) * 128;

        const __half* a0 = ha0 + (size_t)bm * E_;
        const __half* b0 = hb0 + (size_t)bn * E_;

        float acc[2][8][4];
#pragma unroll
        for (int i = 0; i < 2; i++)
#pragma unroll
            for (int j = 0; j < 8; j++)
#pragma unroll
                for (int k = 0; k < 4; k++) acc[i][j][k] = 0.0f;

        g_mainloop(sb, tid, lane, wid, a0, b0, acc);

        int row0 = bm + wm * 32 + (lane >> 2);
        int col0 = bn + wn * 64 + (lane & 3) * 2;
#pragma unroll
        for (int mt = 0; mt < 2; mt++) {
#pragma unroll
            for (int nt = 0; nt < 8; nt++) {
                int r = row0 + mt * 16;
                int c = col0 + nt * 8;
                float2 v0 = {acc[mt][nt][0], acc[mt][nt][1]};
                float2 v1 = {acc[mt][nt][2], acc[mt][nt][3]};
                *(float2*)&C[(size_t)r * E_ + c] = v0;
                *(float2*)&C[(size_t)(r + 8) * E_ + c] = v1;
            }
        }
        __syncthreads();
    }
}

// ---------------- mask prefix scan ------------------------------------------
__global__ void counts_kernel(const float* __restrict__ mask, float* __restrict__ counts) {
    __shared__ float sh[S_];
    int b = blockIdx.x;
    int t = threadIdx.x;
    sh[t] = (mask[b * S_ + t] == 0.0f) ? 1.0f : 0.0f;
    __syncthreads();
    for (int off = 1; off < S_; off <<= 1) {
        float add = (t >= off) ? sh[t - off] : 0.0f;
        __syncthreads();
        sh[t] += add;
        __syncthreads();
    }
    counts[b * S_ + t] = sh[t];
}

// ============== persistent causal attention, 3 CTA/SM, single-fp16 S =========
#define AQM 64
#define AKC 32
#define RB 272
#define QMAT (AQM * RB)
#define KVMAT (AKC * RB)
#define KVSTG (2 * KVMAT)
#define ATT_SMEM (QMAT + 2 * KVSTG)
#define ATT_TILES (32 * 16)

__global__ __launch_bounds__(128, 3) void attn_mma(
    const __half* __restrict__ qh,
    const __half* __restrict__ kh, const __half* __restrict__ vh,
    __half* __restrict__ aoh) {
    extern __shared__ char smc[];
    uint32_t sb = smem_u32(smc);
    uint32_t sQh = sb;
    uint32_t sKV = sb + QMAT;
    __shared__ int s_tile;

    int tid = threadIdx.x;
    int lane = tid & 31;
    int wid = tid >> 5;

    int arow = lane & 15;
    int acolb = ((lane >> 4) & 1) * 16;
    int brow = (lane & 7) + ((lane >> 4) << 3);
    int bcolb = ((lane >> 3) & 1) * 16;
    int vrow = (lane & 7) + (((lane >> 3) & 1) << 3);
    int vcolb = ((lane >> 4) & 1) * 16;

    for (;;) {
        if (tid == 0) s_tile = atomicAdd(&g_ctr[2], 1);
        __syncthreads();
        int tile = s_tile;
        if (tile >= ATT_TILES) return;
        int bh = tile & 31;
        int qt = 15 - (tile >> 5);
        int q0 = qt * AQM;

        size_t base = (size_t)bh * S_ * HD_;
        const __half* Qhb = qh + base;
        const __half* Khb = kh + base;
        const __half* Vhb = vh + base;

        for (int i = tid; i < 1024; i += 128) {
            int r = i >> 4, c = i & 15;
            size_t g = (size_t)(q0 + r) * HD_ + c * 8;
            CP16(sQh + r * RB + c * 16, Qhb + g);
        }
        for (int i = tid; i < 512; i += 128) {
            int r = i >> 4, c = i & 15;
            size_t g = (size_t)r * HD_ + c * 8;
            uint32_t d = sKV + r * RB + c * 16;
            CP16(d, Khb + g);
            CP16(d + KVMAT, Vhb + g);
        }
        CP_COMMIT();

        int nch = (q0 + AQM) / AKC;
        float o[16][4];
#pragma unroll
        for (int i = 0; i < 16; i++)
#pragma unroll
            for (int j = 0; j < 4; j++) o[i][j] = 0.0f;
        int m0w = q0 + wid * 16;

        for (int t = 0; t < nch; t++) {
            asm volatile("cp.async.wait_group 0;" ::: "memory");
            __syncthreads();
            if (t + 1 < nch) {
                uint32_t nstg = sKV + ((t + 1) & 1) * KVSTG;
                int kc = (t + 1) * AKC;
                for (int i = tid; i < 512; i += 128) {
                    int r = i >> 4, c = i & 15;
                    size_t g = (size_t)(kc + r) * HD_ + c * 8;
                    uint32_t d = nstg + r * RB + c * 16;
                    CP16(d, Khb + g);
                    CP16(d + KVMAT, Vhb + g);
                }
                CP_COMMIT();
            }
            uint32_t stg = sKV + (t & 1) * KVSTG;

            float sacc[4][4];
#pragma unroll
            for (int i = 0; i < 4; i++)
#pragma unroll
                for (int j = 0; j < 4; j++) sacc[i][j] = 0.0f;

#pragma unroll
            for (int ds = 0; ds < 8; ds++) {
                uint32_t ah[4];
                uint32_t ad = sQh + (wid * 16 + arow) * RB + acolb + ds * 32;
                LDSM4(ah[0], ah[1], ah[2], ah[3], ad);
                uint32_t bhf[2][4];
#pragma unroll
                for (int ng = 0; ng < 2; ng++) {
                    uint32_t bd = stg + (ng * 16 + brow) * RB + bcolb + ds * 32;
                    LDSM4(bhf[ng][0], bhf[ng][1], bhf[ng][2], bhf[ng][3], bd);
                }
#pragma unroll
                for (int nt = 0; nt < 4; nt++) {
                    uint32_t* ph = &bhf[nt >> 1][(nt & 1) * 2];
                    MMAH(sacc[nt], ah, ph[0], ph[1]);
                }
            }

            int kcg = t * AKC;
            if (kcg + AKC - 1 > m0w) {
                int r0m = m0w + (lane >> 2);
                int r1m = r0m + 8;
#pragma unroll
                for (int nt = 0; nt < 4; nt++) {
                    int cb = kcg + nt * 8 + (lane & 3) * 2;
                    if (cb > r0m) sacc[nt][0] = 0.0f;
                    if (cb + 1 > r0m) sacc[nt][1] = 0.0f;
                    if (cb > r1m) sacc[nt][2] = 0.0f;
                    if (cb + 1 > r1m) sacc[nt][3] = 0.0f;
                }
            }

            // ---- phase 2: O += S.V  (single-fp16 S)
#pragma unroll
            for (int ks = 0; ks < 2; ks++) {
                uint32_t ah[4];
                ah[0] = pack2h(sacc[2 * ks][0], sacc[2 * ks][1]);
                ah[1] = pack2h(sacc[2 * ks][2], sacc[2 * ks][3]);
                ah[2] = pack2h(sacc[2 * ks + 1][0], sacc[2 * ks + 1][1]);
                ah[3] = pack2h(sacc[2 * ks + 1][2], sacc[2 * ks + 1][3]);
#pragma unroll
                for (int ng = 0; ng < 8; ng++) {
                    uint32_t bv[4];
                    uint32_t va = stg + KVMAT + (ks * 16 + vrow) * RB + vcolb + ng * 32;
                    LDSM4T(bv[0], bv[1], bv[2], bv[3], va);
                    MMAH(o[2 * ng], ah, bv[0], bv[1]);
                    MMAH(o[2 * ng + 1], ah, bv[2], bv[3]);
                }
            }
            __syncthreads();
        }

        int b = bh / H_;
        int h = bh % H_;
        int r0 = m0w + (lane >> 2);
#pragma unroll
        for (int nt = 0; nt < 16; nt++) {
            int col = nt * 8 + (lane & 3) * 2;
            size_t g0 = ((size_t)(b * S_ + r0)) * E_ + h * HD_ + col;
            size_t g1 = ((size_t)(b * S_ + r0 + 8)) * E_ + h * HD_ + col;
            *(uint32_t*)(aoh + g0) = pack2h(o[nt][0], o[nt][1]);
            *(uint32_t*)(aoh + g1) = pack2h(o[nt][2], o[nt][3]);
        }
        __syncthreads();
    }
}

// ---------------- launcher ---------------------------------------------------
extern "C" void kernel_launch(void* const* d_in, const int* in_sizes, int n_in,
                              void* d_out, int out_size) {
    const float* hs        = (const float*)d_in[0];
    const float* w_q       = (const float*)d_in[1];
    const float* w_k       = (const float*)d_in[2];
    const float* w_v       = (const float*)d_in[3];
    const float* w_o       = (const float*)d_in[4];
    const float* norm_c    = (const float*)d_in[5];
    const float* attn_mask = (const float*)d_in[6];
    const int*   pos_ids   = (const int*)d_in[7];
    float* out = (float*)d_out;

    float* cnts;
    cudaGetSymbolAddress((void**)&cnts, g_counts);

    __half *hs0, *wq0, *wk0, *wv0, *wo0, *ao0;
    __half *q0, *k0, *v0;
    cudaGetSymbolAddress((void**)&hs0, g_hs0);
    cudaGetSymbolAddress((void**)&wq0, g_wq0);
    cudaGetSymbolAddress((void**)&wk0, g_wk0);
    cudaGetSymbolAddress((void**)&wv0, g_wv0);
    cudaGetSymbolAddress((void**)&wo0, g_wo0);
    cudaGetSymbolAddress((void**)&ao0, g_ao0);
    cudaGetSymbolAddress((void**)&q0, g_q0);
    cudaGetSymbolAddress((void**)&k0, g_k0);
    cudaGetSymbolAddress((void**)&v0, g_v0);

    static bool attr_set = false;
    if (!attr_set) {
        cudaFuncSetAttribute(mma_gemm_qkv_fused, cudaFuncAttributeMaxDynamicSharedMemorySize, GEMM_SMEM);
        cudaFuncSetAttribute(mma_gemm_out, cudaFuncAttributeMaxDynamicSharedMemorySize, GEMM_SMEM);
        cudaFuncSetAttribute(attn_mma, cudaFuncAttributeMaxDynamicSharedMemorySize, ATT_SMEM);
        attr_set = true;
    }

    reset_ctr_kernel<<<1, 32>>>();

    counts_kernel<<<B_, S_>>>(attn_mask, cnts);

    cvt5_kernel<<<dim3(256, 5), 256>>>(hs, w_q, w_k, w_v, w_o,
                                       hs0, wq0, wk0, wv0, wo0);

    mma_gemm_qkv_fused<<<NPERS_G, 128, GEMM_SMEM>>>(
        hs0, wq0, wk0, wv0,
        attn_mask, norm_c, pos_ids, cnts,
        q0, k0, v0);

    attn_mma<<<NPERS_A, 128, ATT_SMEM>>>(q0, k0, v0, ao0);

    mma_gemm_out<<<NPERS_G, 128, GEMM_SMEM>>>(ao0, wo0, out);
}